// round 1
// baseline (speedup 1.0000x reference)
#include <cuda_runtime.h>
#include <math.h>
#include <stdint.h>

// ---------------- problem constants ----------------
#define Bb      2
#define Nn      4096
#define Cc      1024
#define Hh      16
#define DHd     64
#define BH      32          // Bb*Hh
#define NHASH   4
#define NBUCK   64          // Nn / BUCKET
#define NCHUNK  256         // NHASH*NBUCK
#define BS      64          // bucket size
#define Kdim    1024
#define Mrows   8192        // Bb*Nn

// ---------------- device scratch (static; no allocations allowed) ----------------
__device__ float g_qk  [BH * Nn * DHd];            // 32 MB  (bh, t, d)
__device__ float g_v   [BH * Nn * DHd];            // 32 MB
__device__ int   g_bucket[BH * NHASH * Nn];        // 2 MB
__device__ int   g_st  [BH * NHASH * Nn];          // 2 MB   sorted token idx per slot
__device__ float g_oph [BH * NHASH * Nn * DHd];    // 134 MB per-hash outputs (scattered)
__device__ float g_lse [BH * NHASH * Nn];          // 2 MB
__device__ float g_ocomb[Bb * Nn * Cc];            // 32 MB  combined heads, (b, t, c)

// ---------------- fp32 GEMM: out[m][n] = sum_k A[m][k] * W[n][k] (+bias) ----------------
// M=8192, N=1024, K=1024. Block 64x64, 256 threads, 4x4 per thread.
// head_layout=1: store to (b*Hh+head, t, dh) layout for per-head processing.
__global__ void gemm_kernel(const float* __restrict__ A, const float* __restrict__ W,
                            float* __restrict__ out, const float* __restrict__ bias,
                            int head_layout) {
    __shared__ __align__(16) float As[16 * 64];
    __shared__ __align__(16) float Bs[16 * 64];
    int tid = threadIdx.x;
    int bm = blockIdx.y * 64;
    int bn = blockIdx.x * 64;
    int ty = tid >> 4, tx = tid & 15;
    int lrow = tid >> 2, lq = tid & 3;

    float acc[4][4];
#pragma unroll
    for (int i = 0; i < 4; i++)
#pragma unroll
        for (int j = 0; j < 4; j++) acc[i][j] = 0.f;

    for (int k0 = 0; k0 < Kdim; k0 += 16) {
        float4 a4 = *(const float4*)(A + (size_t)(bm + lrow) * Kdim + k0 + lq * 4);
        float4 b4 = *(const float4*)(W + (size_t)(bn + lrow) * Kdim + k0 + lq * 4);
        __syncthreads();
        As[(lq * 4 + 0) * 64 + lrow] = a4.x;
        As[(lq * 4 + 1) * 64 + lrow] = a4.y;
        As[(lq * 4 + 2) * 64 + lrow] = a4.z;
        As[(lq * 4 + 3) * 64 + lrow] = a4.w;
        Bs[(lq * 4 + 0) * 64 + lrow] = b4.x;
        Bs[(lq * 4 + 1) * 64 + lrow] = b4.y;
        Bs[(lq * 4 + 2) * 64 + lrow] = b4.z;
        Bs[(lq * 4 + 3) * 64 + lrow] = b4.w;
        __syncthreads();
#pragma unroll
        for (int kk = 0; kk < 16; kk++) {
            float4 av = *(const float4*)(As + kk * 64 + ty * 4);
            float4 bv = *(const float4*)(Bs + kk * 64 + tx * 4);
            acc[0][0] += av.x * bv.x; acc[0][1] += av.x * bv.y; acc[0][2] += av.x * bv.z; acc[0][3] += av.x * bv.w;
            acc[1][0] += av.y * bv.x; acc[1][1] += av.y * bv.y; acc[1][2] += av.y * bv.z; acc[1][3] += av.y * bv.w;
            acc[2][0] += av.z * bv.x; acc[2][1] += av.z * bv.y; acc[2][2] += av.z * bv.z; acc[2][3] += av.z * bv.w;
            acc[3][0] += av.w * bv.x; acc[3][1] += av.w * bv.y; acc[3][2] += av.w * bv.z; acc[3][3] += av.w * bv.w;
        }
    }

#pragma unroll
    for (int i = 0; i < 4; i++) {
        int row = bm + ty * 4 + i;
#pragma unroll
        for (int j = 0; j < 4; j++) {
            int col = bn + tx * 4 + j;
            float v = acc[i][j];
            if (bias) v += bias[col];
            if (head_layout) {
                int b = row >> 12;            // / 4096
                int t = row & 4095;
                int hd = col >> 6;            // / 64
                int dh = col & 63;
                out[(((size_t)(b * Hh + hd)) * Nn + t) * DHd + dh] = v;
            } else {
                out[(size_t)row * Cc + col] = v;
            }
        }
    }
}

// ---------------- LSH bucketing ----------------
// grid (Nn/32, BH), 128 threads. Warp = hash round, lane = token within 32-token group.
__global__ void bucket_kernel(const float* __restrict__ rot) {
    __shared__ float rs[DHd * 128];   // rotations (d, h*32+i), 32 KB
    __shared__ float qs[32 * 65];     // 32 tokens x 64 dims (padded)
    int bh = blockIdx.y;
    int tb = blockIdx.x * 32;
    int tid = threadIdx.x;

    for (int i = tid; i < DHd * 128; i += 128) rs[i] = rot[i];
    {
        int row = tid >> 2, seg = tid & 3;
        const float* src = g_qk + ((size_t)bh * Nn + tb + row) * DHd + seg * 16;
#pragma unroll
        for (int k = 0; k < 16; k++) qs[row * 65 + seg * 16 + k] = src[k];
    }
    __syncthreads();

    int h = tid >> 5;
    int lane = tid & 31;
    int tok = tb + lane;

    float r[32];
#pragma unroll
    for (int i = 0; i < 32; i++) r[i] = 0.f;
    for (int d = 0; d < DHd; d++) {
        float qd = qs[lane * 65 + d];
        const float* rp = rs + d * 128 + h * 32;
#pragma unroll
        for (int i = 0; i < 32; i++) r[i] += qd * rp[i];
    }
    // argmax over [r, -r], first-index tie semantics (strict >)
    float best = r[0]; int bi = 0;
#pragma unroll
    for (int i = 1; i < 32; i++) if (r[i] > best) { best = r[i]; bi = i; }
#pragma unroll
    for (int i = 0; i < 32; i++) if (-r[i] > best) { best = -r[i]; bi = 32 + i; }
    g_bucket[((size_t)bh * NHASH + h) * Nn + tok] = bi;
}

// ---------------- stable counting sort per (bh, hash) ----------------
__global__ void sort_kernel() {
    __shared__ unsigned char sb[Nn];
    __shared__ int hist[NBUCK];
    __shared__ int offs[NBUCK];
    int bh = blockIdx.x, h = blockIdx.y;
    int tid = threadIdx.x;  // 256
    if (tid < NBUCK) hist[tid] = 0;
    __syncthreads();
    const int base = (bh * NHASH + h) * Nn;
    for (int t = tid; t < Nn; t += 256) {
        int b = g_bucket[base + t];
        sb[t] = (unsigned char)b;
        atomicAdd(&hist[b], 1);
    }
    __syncthreads();
    if (tid == 0) {
        int acc = 0;
        for (int b = 0; b < NBUCK; b++) { offs[b] = acc; acc += hist[b]; }
    }
    __syncthreads();
    if (tid < NBUCK) {  // one thread per bucket: sequential scan keeps stability (position order)
        unsigned char b = (unsigned char)tid;
        int w = offs[tid];
        for (int t = 0; t < Nn; t++)
            if (sb[t] == b) g_st[base + (w++)] = t;
    }
}

// ---------------- chunked LSH attention ----------------
// grid (NCHUNK, BH), 256 threads, dynamic smem.
// smem floats: qs 64*65 | ks 128*65 (reused as dots 64*129) | vs 128*65 | rsum 64 | rlse 64 | tq 64i | tkv 128i
#define ATTN_SMEM_BYTES ((64*65 + 128*65 + 128*65 + 64 + 64) * 4 + (64 + 128) * 4)

__global__ void attn_kernel() {
    extern __shared__ float sm[];
    float* qs   = sm;
    float* ks   = qs + 64 * 65;
    float* vs   = ks + 128 * 65;
    float* rsum = vs + 128 * 65;
    float* rlse = rsum + 64;
    int*   tq   = (int*)(rlse + 64);
    int*   tkv  = tq + 64;

    int c  = blockIdx.x;             // chunk 0..255 (crosses hash boundaries, as in reference)
    int bh = blockIdx.y;
    int h  = c >> 6;
    int tid = threadIdx.x;
    int pc = (c + NCHUNK - 1) & (NCHUNK - 1);   // look-one-back with wraparound over all 256 chunks

    const int stbase = bh * (NHASH * Nn);
    if (tid < 64)       { int t0 = g_st[stbase + c * BS + tid]; tq[tid] = t0; tkv[tid] = t0; }
    else if (tid < 128) { tkv[tid] = g_st[stbase + pc * BS + (tid - 64)]; }
    __syncthreads();

    // gather q (64x64): 4 threads/row x 16 floats
    {
        int i = tid >> 2, seg = tid & 3;
        const float* src = g_qk + ((size_t)bh * Nn + tq[i]) * DHd + seg * 16;
#pragma unroll
        for (int k = 0; k < 16; k++) qs[i * 65 + seg * 16 + k] = src[k];
    }
    // gather k/v (128x64): 2 threads/row x 32 floats
    {
        int j = tid >> 1, seg = tid & 1;
        size_t off = ((size_t)bh * Nn + tkv[j]) * DHd + seg * 32;
        const float* ksrc = g_qk + off;
        const float* vsrc = g_v + off;
#pragma unroll
        for (int k = 0; k < 32; k++) {
            ks[j * 65 + seg * 32 + k] = ksrc[k];
            vs[j * 65 + seg * 32 + k] = vsrc[k];
        }
    }
    __syncthreads();

    // normalize key rows (shared-QK: k = q / max(||q||, 1e-12))
    {
        int w = tid >> 5, lane = tid & 31;
        for (int rr = 0; rr < 16; rr++) {
            int j = w * 16 + rr;
            float a = ks[j * 65 + lane], b = ks[j * 65 + 32 + lane];
            float s = a * a + b * b;
#pragma unroll
            for (int o = 16; o > 0; o >>= 1) s += __shfl_xor_sync(0xffffffffu, s, o);
            float inv = 1.0f / fmaxf(sqrtf(s), 1e-12f);
            ks[j * 65 + lane] = a * inv;
            ks[j * 65 + 32 + lane] = b * inv;
        }
    }
    __syncthreads();

    // dots: each thread computes rows {ty, ty+32} x 16 cols {tx+8u}
    int ty = tid >> 3, tx = tid & 7;
    float acc0[16], acc1[16];
#pragma unroll
    for (int u = 0; u < 16; u++) { acc0[u] = 0.f; acc1[u] = 0.f; }
    for (int d = 0; d < DHd; d++) {
        float q0 = qs[ty * 65 + d];
        float q1 = qs[(ty + 32) * 65 + d];
#pragma unroll
        for (int u = 0; u < 16; u++) {
            float kv = ks[(tx + 8 * u) * 65 + d];
            acc0[u] += q0 * kv;
            acc1[u] += q1 * kv;
        }
    }
    __syncthreads();                  // done reading ks -> reuse as dots buffer
    float* dots = ks;                 // 64 x 129
    int tq0 = tq[ty], tq1 = tq[ty + 32];
#pragma unroll
    for (int u = 0; u < 16; u++) {
        int j = tx + 8 * u;
        int tk = tkv[j];
        dots[ty * 129 + j]        = (tq0 == tk) ? -5e4f : acc0[u] * 0.125f;
        dots[(ty + 32) * 129 + j] = (tq1 == tk) ? -5e4f : acc1[u] * 0.125f;
    }
    __syncthreads();

    // row softmax + lse: 8 warps x 8 rows
    {
        int w = tid >> 5, lane = tid & 31;
        for (int rr = 0; rr < 8; rr++) {
            int i = w * 8 + rr;
            float x0 = dots[i * 129 + lane];
            float x1 = dots[i * 129 + 32 + lane];
            float x2 = dots[i * 129 + 64 + lane];
            float x3 = dots[i * 129 + 96 + lane];
            float m = fmaxf(fmaxf(x0, x1), fmaxf(x2, x3));
#pragma unroll
            for (int o = 16; o > 0; o >>= 1) m = fmaxf(m, __shfl_xor_sync(0xffffffffu, m, o));
            float e0 = expf(x0 - m), e1 = expf(x1 - m), e2 = expf(x2 - m), e3 = expf(x3 - m);
            float s = e0 + e1 + e2 + e3;
#pragma unroll
            for (int o = 16; o > 0; o >>= 1) s += __shfl_xor_sync(0xffffffffu, s, o);
            dots[i * 129 + lane]      = e0;
            dots[i * 129 + 32 + lane] = e1;
            dots[i * 129 + 64 + lane] = e2;
            dots[i * 129 + 96 + lane] = e3;
            if (lane == 0) { rsum[i] = s; rlse[i] = m + logf(s); }
        }
    }
    __syncthreads();

    // bo = P @ V, then scatter by token id (unsort == scatter, permutation per hash)
    float o0[8], o1[8];
#pragma unroll
    for (int k = 0; k < 8; k++) { o0[k] = 0.f; o1[k] = 0.f; }
    for (int j = 0; j < 128; j++) {
        float p0 = dots[ty * 129 + j];
        float p1 = dots[(ty + 32) * 129 + j];
        const float* vr = vs + j * 65 + tx * 8;
#pragma unroll
        for (int k = 0; k < 8; k++) {
            float vv = vr[k];
            o0[k] += p0 * vv;
            o1[k] += p1 * vv;
        }
    }
    float inv0 = 1.0f / rsum[ty];
    float inv1 = 1.0f / rsum[ty + 32];
    size_t ob0 = (((size_t)(bh * NHASH + h)) * Nn + tq0) * DHd + tx * 8;
    size_t ob1 = (((size_t)(bh * NHASH + h)) * Nn + tq1) * DHd + tx * 8;
#pragma unroll
    for (int k = 0; k < 8; k++) {
        g_oph[ob0 + k] = o0[k] * inv0;
        g_oph[ob1 + k] = o1[k] * inv1;
    }
    if (tx == 0) {
        g_lse[(bh * NHASH + h) * Nn + tq0] = rlse[ty];
        g_lse[(bh * NHASH + h) * Nn + tq1] = rlse[ty + 32];
    }
}

// ---------------- combine hash rounds: softmax over per-round lse ----------------
__global__ void combine_kernel() {
    int gid = blockIdx.x * 256 + threadIdx.x;
    int slot = gid >> 6;          // (bh, t)
    int d = gid & 63;
    int bh = slot >> 12;          // / 4096
    int t = slot & 4095;
    int base = bh * NHASH * Nn + t;
    float l0 = g_lse[base + 0 * Nn];
    float l1 = g_lse[base + 1 * Nn];
    float l2 = g_lse[base + 2 * Nn];
    float l3 = g_lse[base + 3 * Nn];
    float m = fmaxf(fmaxf(l0, l1), fmaxf(l2, l3));
    float w0 = expf(l0 - m), w1 = expf(l1 - m), w2 = expf(l2 - m), w3 = expf(l3 - m);
    float s = w0 + w1 + w2 + w3;
    size_t ob = ((size_t)bh * NHASH * Nn + t) * DHd + d;
    float acc = w0 * g_oph[ob]
              + w1 * g_oph[ob + (size_t)Nn * DHd]
              + w2 * g_oph[ob + (size_t)2 * Nn * DHd]
              + w3 * g_oph[ob + (size_t)3 * Nn * DHd];
    acc /= s;
    int b = bh >> 4, head = bh & 15;
    g_ocomb[((size_t)b * Nn + t) * Cc + head * DHd + d] = acc;
}

// ---------------- launch ----------------
extern "C" void kernel_launch(void* const* d_in, const int* in_sizes, int n_in,
                              void* d_out, int out_size) {
    const float* queries = (const float*)d_in[0];
    // d_in[1]=keys, d_in[2]=values, d_in[3]=attn_mask: unused (as in reference)
    const float* Wqk  = (const float*)d_in[4];
    const float* Wv   = (const float*)d_in[5];
    const float* Wout = (const float*)d_in[6];
    const float* bout = (const float*)d_in[7];
    const float* rot  = (const float*)d_in[8];
    float* out = (float*)d_out;

    cudaFuncSetAttribute(attn_kernel, cudaFuncAttributeMaxDynamicSharedMemorySize,
                         ATTN_SMEM_BYTES);

    void *p_qk, *p_v, *p_ocomb;
    cudaGetSymbolAddress(&p_qk, g_qk);
    cudaGetSymbolAddress(&p_v, g_v);
    cudaGetSymbolAddress(&p_ocomb, g_ocomb);

    dim3 ggrid(Cc / 64, Mrows / 64);   // (16, 128)
    gemm_kernel<<<ggrid, 256>>>(queries, Wqk, (float*)p_qk, nullptr, 1);
    gemm_kernel<<<ggrid, 256>>>(queries, Wv,  (float*)p_v,  nullptr, 1);

    bucket_kernel<<<dim3(Nn / 32, BH), 128>>>(rot);
    sort_kernel<<<dim3(BH, NHASH), 256>>>();
    attn_kernel<<<dim3(NCHUNK, BH), 256, ATTN_SMEM_BYTES>>>();
    combine_kernel<<<(BH * Nn * DHd) / 256, 256>>>();

    gemm_kernel<<<ggrid, 256>>>((const float*)p_ocomb, Wout, out, bout, 0);
}

// round 4
// speedup vs baseline: 1.0089x; 1.0089x over previous
#include <cuda_runtime.h>
#include <cuda_bf16.h>
#include <math.h>
#include <stdint.h>

// ---------------- problem constants ----------------
#define Bb      2
#define Nn      4096
#define Cc      1024
#define Hh      16
#define DHd     64
#define BH      32          // Bb*Hh
#define NHASH   4
#define NBUCK   64          // Nn / BUCKET
#define NCHUNK  256         // NHASH*NBUCK
#define BS      64          // bucket size
#define Kdim    1024
#define Mrows   8192        // Bb*Nn

// ---------------- device scratch (static; no allocations allowed) ----------------
__device__ float g_qk  [BH * Nn * DHd];            // 32 MB  (bh, t, d)
__device__ float g_v   [BH * Nn * DHd];            // 32 MB
__device__ int   g_bucket[BH * NHASH * Nn];        // 2 MB
__device__ int   g_st  [BH * NHASH * Nn];          // 2 MB
__device__ float g_oph [BH * NHASH * Nn * DHd];    // 134 MB per-hash outputs (scattered)
__device__ float g_lse [BH * NHASH * Nn];          // 2 MB
__device__ float g_ocomb[Bb * Nn * Cc];            // 32 MB  combined heads, (b, t, c)

// bf16x3 limbs (activations for Wout GEMM + Wout weights)
#define APL ((size_t)Mrows * Kdim)
__device__ __nv_bfloat16 g_asp[3 * APL];                      // 48 MB
__device__ __nv_bfloat16 g_wout_sp[(size_t)3 * 1024 * 1024];  // 6 MB

// ================= fp32 FFMA GEMM (bit-identical to R1 baseline) =================
// out[m][n] = sum_k A[m][k] * W[n][k]; head_layout=1 -> (b*Hh+head, t, dh).
// Load-hoist only: per-thread FMA order unchanged -> identical bits -> identical buckets.
__global__ void gemm_kernel(const float* __restrict__ A, const float* __restrict__ W,
                            float* __restrict__ out, const float* __restrict__ bias,
                            int head_layout) {
    __shared__ __align__(16) float As[16 * 64];
    __shared__ __align__(16) float Bs[16 * 64];
    int tid = threadIdx.x;
    int bm = blockIdx.y * 64;
    int bn = blockIdx.x * 64;
    int ty = tid >> 4, tx = tid & 15;
    int lrow = tid >> 2, lq = tid & 3;

    float acc[4][4];
#pragma unroll
    for (int i = 0; i < 4; i++)
#pragma unroll
        for (int j = 0; j < 4; j++) acc[i][j] = 0.f;

    const float* aptr = A + (size_t)(bm + lrow) * Kdim + lq * 4;
    const float* bptr = W + (size_t)(bn + lrow) * Kdim + lq * 4;
    float4 a4 = *(const float4*)(aptr);
    float4 b4 = *(const float4*)(bptr);

    for (int k0 = 0; k0 < Kdim; k0 += 16) {
        __syncthreads();
        As[(lq * 4 + 0) * 64 + lrow] = a4.x;
        As[(lq * 4 + 1) * 64 + lrow] = a4.y;
        As[(lq * 4 + 2) * 64 + lrow] = a4.z;
        As[(lq * 4 + 3) * 64 + lrow] = a4.w;
        Bs[(lq * 4 + 0) * 64 + lrow] = b4.x;
        Bs[(lq * 4 + 1) * 64 + lrow] = b4.y;
        Bs[(lq * 4 + 2) * 64 + lrow] = b4.z;
        Bs[(lq * 4 + 3) * 64 + lrow] = b4.w;
        __syncthreads();
        int kn = (k0 + 16 < Kdim) ? (k0 + 16) : k0;   // hoisted next-tile load
        a4 = *(const float4*)(aptr + kn);
        b4 = *(const float4*)(bptr + kn);
#pragma unroll
        for (int kk = 0; kk < 16; kk++) {
            float4 av = *(const float4*)(As + kk * 64 + ty * 4);
            float4 bv = *(const float4*)(Bs + kk * 64 + tx * 4);
            acc[0][0] += av.x * bv.x; acc[0][1] += av.x * bv.y; acc[0][2] += av.x * bv.z; acc[0][3] += av.x * bv.w;
            acc[1][0] += av.y * bv.x; acc[1][1] += av.y * bv.y; acc[1][2] += av.y * bv.z; acc[1][3] += av.y * bv.w;
            acc[2][0] += av.z * bv.x; acc[2][1] += av.z * bv.y; acc[2][2] += av.z * bv.z; acc[2][3] += av.z * bv.w;
            acc[3][0] += av.w * bv.x; acc[3][1] += av.w * bv.y; acc[3][2] += av.w * bv.z; acc[3][3] += av.w * bv.w;
        }
    }

#pragma unroll
    for (int i = 0; i < 4; i++) {
        int row = bm + ty * 4 + i;
#pragma unroll
        for (int j = 0; j < 4; j++) {
            int col = bn + tx * 4 + j;
            float v = acc[i][j];
            if (bias) v += bias[col];
            if (head_layout) {
                int b = row >> 12;
                int t = row & 4095;
                int hd = col >> 6;
                int dh = col & 63;
                out[(((size_t)(b * Hh + hd)) * Nn + t) * DHd + dh] = v;
            } else {
                out[(size_t)row * Cc + col] = v;
            }
        }
    }
}

// ================= helpers (sm_103-safe) =================
__device__ __forceinline__ uint32_t smem_to_u32(const void* p) {
    uint32_t a;
    asm("{ .reg .u64 t; cvta.to.shared.u64 t, %1; cvt.u32.u64 %0, t; }" : "=r"(a) : "l"(p));
    return a;
}
#define CP_ASYNC16(saddr, gptr) \
    asm volatile("cp.async.cg.shared.global [%0], [%1], 16;" \
        :: "r"(saddr), "l"(__cvta_generic_to_global(gptr)))
#define CP_COMMIT() asm volatile("cp.async.commit_group;" ::: "memory")
#define CP_WAIT(n)  asm volatile("cp.async.wait_group %0;" :: "n"(n) : "memory")

__device__ __forceinline__ void ldmx4(uint32_t* r, uint32_t addr) {
    asm volatile("ldmatrix.sync.aligned.m8n8.x4.shared.b16 {%0,%1,%2,%3}, [%4];"
        : "=r"(r[0]), "=r"(r[1]), "=r"(r[2]), "=r"(r[3]) : "r"(addr));
}
__device__ __forceinline__ void mma16816(float* d, const uint32_t* a, uint32_t b0, uint32_t b1) {
    asm volatile("mma.sync.aligned.m16n8k16.row.col.f32.bf16.bf16.f32 "
        "{%0,%1,%2,%3}, {%4,%5,%6,%7}, {%8,%9}, {%0,%1,%2,%3};"
        : "+f"(d[0]), "+f"(d[1]), "+f"(d[2]), "+f"(d[3])
        : "r"(a[0]), "r"(a[1]), "r"(a[2]), "r"(a[3]), "r"(b0), "r"(b1));
}

// ================= bf16x3 limb split =================
__global__ void split3_kernel(const float* __restrict__ x,
                              __nv_bfloat16* __restrict__ hi,
                              __nv_bfloat16* __restrict__ mid,
                              __nv_bfloat16* __restrict__ lo, int n) {
    int i = (blockIdx.x * 256 + threadIdx.x) * 4;
    if (i >= n) return;
    float4 v = *(const float4*)(x + i);
    float a[4] = {v.x, v.y, v.z, v.w};
#pragma unroll
    for (int j = 0; j < 4; j++) {
        __nv_bfloat16 h = __float2bfloat16(a[j]);
        float r = a[j] - __bfloat162float(h);
        __nv_bfloat16 m = __float2bfloat16(r);
        float r2 = r - __bfloat162float(m);
        __nv_bfloat16 l = __float2bfloat16(r2);
        hi[i + j] = h; mid[i + j] = m; lo[i + j] = l;
    }
}

// ================= HMMA Wout GEMM (bf16x3, 8 limb cross-products) =================
#define ROWB     80
#define MATB     (128 * ROWB)
#define STAGEB   (2 * MATB)
#define GEMM_SMEM (3 * STAGEB)
#define NPROD    8
#define NSTAGE   (NPROD * 32)

__global__ __launch_bounds__(256, 2) void mma_wout(
        const __nv_bfloat16* __restrict__ Asp, size_t Apl,
        const __nv_bfloat16* __restrict__ Bsp, size_t Bpl,
        const float* __restrict__ bias, float* __restrict__ outp) {
    extern __shared__ char smem[];
    uint32_t sbase = smem_to_u32(smem);
    int tid = threadIdx.x;
    int lane = tid & 31, warp = tid >> 5;
    int wm = warp >> 2, wn = warp & 3;
    int bn = blockIdx.x * 128, bm = blockIdx.y * 128;

    const uint32_t PA = 0x21201100u;   // limb idx of A per pass (p0..p7): 0,0,1,1,0,2,1,2
    const uint32_t PW = 0x12021010u;   // limb idx of B per pass:          0,1,0,1,2,0,2,1

    int v0 = tid, v1 = tid + 256;
    int r0 = v0 >> 2, c0 = v0 & 3;
    int r1 = v1 >> 2, c1 = v1 & 3;
    uint32_t so0 = (uint32_t)(r0 * ROWB + c0 * 16);
    uint32_t so1 = (uint32_t)(r1 * ROWB + c1 * 16);

    uint32_t aoff = (uint32_t)((wm * 64 + (lane & 15)) * ROWB + (lane >> 4) * 16);
    uint32_t boff = (uint32_t)((wn * 32 + ((lane >> 4) & 1) * 8 + (lane & 7)) * ROWB
                               + ((lane >> 3) & 1) * 16);

    float D[4][4][4];
#pragma unroll
    for (int i = 0; i < 4; i++)
#pragma unroll
        for (int j = 0; j < 4; j++)
#pragma unroll
            for (int q = 0; q < 4; q++) D[i][j][q] = 0.f;

#pragma unroll
    for (int s = 0; s < 2; s++) {
        int k0 = s * 32;
        const __nv_bfloat16* Ap = Asp;
        const __nv_bfloat16* Bp = Bsp;
        uint32_t st = sbase + s * STAGEB;
        CP_ASYNC16(st + so0, Ap + (size_t)(bm + r0) * Kdim + k0 + c0 * 8);
        CP_ASYNC16(st + so1, Ap + (size_t)(bm + r1) * Kdim + k0 + c1 * 8);
        CP_ASYNC16(st + MATB + so0, Bp + (size_t)(bn + r0) * Kdim + k0 + c0 * 8);
        CP_ASYNC16(st + MATB + so1, Bp + (size_t)(bn + r1) * Kdim + k0 + c1 * 8);
        CP_COMMIT();
    }

    for (int s = 0; s < NSTAGE; s++) {
        if (s == NSTAGE - 1) { CP_WAIT(0); } else { CP_WAIT(1); }
        __syncthreads();
        if (s + 2 < NSTAGE) {
            int sn = s + 2;
            int p = sn >> 5, k0 = (sn & 31) << 5;
            const __nv_bfloat16* Ap = Asp + (size_t)((PA >> (p * 4)) & 7) * Apl;
            const __nv_bfloat16* Bp = Bsp + (size_t)((PW >> (p * 4)) & 7) * Bpl;
            uint32_t st = sbase + (uint32_t)(sn % 3) * STAGEB;
            CP_ASYNC16(st + so0, Ap + (size_t)(bm + r0) * Kdim + k0 + c0 * 8);
            CP_ASYNC16(st + so1, Ap + (size_t)(bm + r1) * Kdim + k0 + c1 * 8);
            CP_ASYNC16(st + MATB + so0, Bp + (size_t)(bn + r0) * Kdim + k0 + c0 * 8);
            CP_ASYNC16(st + MATB + so1, Bp + (size_t)(bn + r1) * Kdim + k0 + c1 * 8);
            CP_COMMIT();
        }
        uint32_t st = sbase + (uint32_t)(s % 3) * STAGEB;
        uint32_t ab = st + aoff;
        uint32_t bb = st + MATB + boff;
#pragma unroll
        for (int ks = 0; ks < 2; ks++) {
            uint32_t A4[4][4], B4[2][4];
#pragma unroll
            for (int i = 0; i < 4; i++) ldmx4(A4[i], ab + i * (16 * ROWB) + ks * 32);
#pragma unroll
            for (int jp = 0; jp < 2; jp++) ldmx4(B4[jp], bb + jp * (16 * ROWB) + ks * 32);
#pragma unroll
            for (int i = 0; i < 4; i++)
#pragma unroll
                for (int jn = 0; jn < 4; jn++)
                    mma16816(D[i][jn], A4[i], B4[jn >> 1][(jn & 1) * 2], B4[jn >> 1][(jn & 1) * 2 + 1]);
        }
    }

    int g = lane >> 2, t = lane & 3;
#pragma unroll
    for (int i = 0; i < 4; i++) {
#pragma unroll
        for (int jn = 0; jn < 4; jn++) {
            int m0 = bm + wm * 64 + i * 16 + g;
            int n0 = bn + wn * 32 + jn * 8 + t * 2;
            float2 bv = *(const float2*)(bias + n0);
            float2 va = make_float2(D[i][jn][0] + bv.x, D[i][jn][1] + bv.y);
            float2 vb = make_float2(D[i][jn][2] + bv.x, D[i][jn][3] + bv.y);
            *(float2*)(outp + (size_t)m0 * Cc + n0) = va;
            *(float2*)(outp + (size_t)(m0 + 8) * Cc + n0) = vb;
        }
    }
}

// ---------------- LSH bucketing ----------------
__global__ void bucket_kernel(const float* __restrict__ rot) {
    __shared__ float rs[DHd * 128];
    __shared__ float qs[32 * 65];
    int bh = blockIdx.y;
    int tb = blockIdx.x * 32;
    int tid = threadIdx.x;

    for (int i = tid; i < DHd * 128; i += 128) rs[i] = rot[i];
    {
        int row = tid >> 2, seg = tid & 3;
        const float* src = g_qk + ((size_t)bh * Nn + tb + row) * DHd + seg * 16;
#pragma unroll
        for (int k = 0; k < 16; k++) qs[row * 65 + seg * 16 + k] = src[k];
    }
    __syncthreads();

    int h = tid >> 5;
    int lane = tid & 31;
    int tok = tb + lane;

    float r[32];
#pragma unroll
    for (int i = 0; i < 32; i++) r[i] = 0.f;
    for (int d = 0; d < DHd; d++) {
        float qd = qs[lane * 65 + d];
        const float* rp = rs + d * 128 + h * 32;
#pragma unroll
        for (int i = 0; i < 32; i++) r[i] += qd * rp[i];
    }
    float best = r[0]; int bi = 0;
#pragma unroll
    for (int i = 1; i < 32; i++) if (r[i] > best) { best = r[i]; bi = i; }
#pragma unroll
    for (int i = 0; i < 32; i++) if (-r[i] > best) { best = -r[i]; bi = 32 + i; }
    g_bucket[((size_t)bh * NHASH + h) * Nn + tok] = bi;
}

// ---------------- stable counting sort per (bh, hash) ----------------
__global__ void sort_kernel() {
    __shared__ unsigned char sb[Nn];
    __shared__ int hist[NBUCK];
    __shared__ int offs[NBUCK];
    int bh = blockIdx.x, h = blockIdx.y;
    int tid = threadIdx.x;
    if (tid < NBUCK) hist[tid] = 0;
    __syncthreads();
    const int base = (bh * NHASH + h) * Nn;
    for (int t = tid; t < Nn; t += 256) {
        int b = g_bucket[base + t];
        sb[t] = (unsigned char)b;
        atomicAdd(&hist[b], 1);
    }
    __syncthreads();
    if (tid == 0) {
        int acc = 0;
        for (int b = 0; b < NBUCK; b++) { offs[b] = acc; acc += hist[b]; }
    }
    __syncthreads();
    if (tid < NBUCK) {
        unsigned char b = (unsigned char)tid;
        int w = offs[tid];
        for (int t = 0; t < Nn; t++)
            if (sb[t] == b) g_st[base + (w++)] = t;
    }
}

// ---------------- chunked LSH attention ----------------
#define ATTN_SMEM_BYTES ((64*65 + 128*65 + 128*65 + 64 + 64) * 4 + (64 + 128) * 4)

__global__ void attn_kernel() {
    extern __shared__ float sm[];
    float* qs   = sm;
    float* ks   = qs + 64 * 65;
    float* vs   = ks + 128 * 65;
    float* rsum = vs + 128 * 65;
    float* rlse = rsum + 64;
    int*   tq   = (int*)(rlse + 64);
    int*   tkv  = tq + 64;

    int c  = blockIdx.x;
    int bh = blockIdx.y;
    int h  = c >> 6;
    int tid = threadIdx.x;
    int pc = (c + NCHUNK - 1) & (NCHUNK - 1);

    const int stbase = bh * (NHASH * Nn);
    if (tid < 64)       { int t0 = g_st[stbase + c * BS + tid]; tq[tid] = t0; tkv[tid] = t0; }
    else if (tid < 128) { tkv[tid] = g_st[stbase + pc * BS + (tid - 64)]; }
    __syncthreads();

    {
        int i = tid >> 2, seg = tid & 3;
        const float* src = g_qk + ((size_t)bh * Nn + tq[i]) * DHd + seg * 16;
#pragma unroll
        for (int k = 0; k < 16; k++) qs[i * 65 + seg * 16 + k] = src[k];
    }
    {
        int j = tid >> 1, seg = tid & 1;
        size_t off = ((size_t)bh * Nn + tkv[j]) * DHd + seg * 32;
        const float* ksrc = g_qk + off;
        const float* vsrc = g_v + off;
#pragma unroll
        for (int k = 0; k < 32; k++) {
            ks[j * 65 + seg * 32 + k] = ksrc[k];
            vs[j * 65 + seg * 32 + k] = vsrc[k];
        }
    }
    __syncthreads();

    {
        int w = tid >> 5, lane = tid & 31;
        for (int rr = 0; rr < 16; rr++) {
            int j = w * 16 + rr;
            float a = ks[j * 65 + lane], b = ks[j * 65 + 32 + lane];
            float s = a * a + b * b;
#pragma unroll
            for (int o = 16; o > 0; o >>= 1) s += __shfl_xor_sync(0xffffffffu, s, o);
            float inv = 1.0f / fmaxf(sqrtf(s), 1e-12f);
            ks[j * 65 + lane] = a * inv;
            ks[j * 65 + 32 + lane] = b * inv;
        }
    }
    __syncthreads();

    int ty = tid >> 3, tx = tid & 7;
    float acc0[16], acc1[16];
#pragma unroll
    for (int u = 0; u < 16; u++) { acc0[u] = 0.f; acc1[u] = 0.f; }
    for (int d = 0; d < DHd; d++) {
        float q0 = qs[ty * 65 + d];
        float q1 = qs[(ty + 32) * 65 + d];
#pragma unroll
        for (int u = 0; u < 16; u++) {
            float kv = ks[(tx + 8 * u) * 65 + d];
            acc0[u] += q0 * kv;
            acc1[u] += q1 * kv;
        }
    }
    __syncthreads();
    float* dots = ks;
    int tq0 = tq[ty], tq1 = tq[ty + 32];
#pragma unroll
    for (int u = 0; u < 16; u++) {
        int j = tx + 8 * u;
        int tk = tkv[j];
        dots[ty * 129 + j]        = (tq0 == tk) ? -5e4f : acc0[u] * 0.125f;
        dots[(ty + 32) * 129 + j] = (tq1 == tk) ? -5e4f : acc1[u] * 0.125f;
    }
    __syncthreads();

    {
        int w = tid >> 5, lane = tid & 31;
        for (int rr = 0; rr < 8; rr++) {
            int i = w * 8 + rr;
            float x0 = dots[i * 129 + lane];
            float x1 = dots[i * 129 + 32 + lane];
            float x2 = dots[i * 129 + 64 + lane];
            float x3 = dots[i * 129 + 96 + lane];
            float m = fmaxf(fmaxf(x0, x1), fmaxf(x2, x3));
#pragma unroll
            for (int o = 16; o > 0; o >>= 1) m = fmaxf(m, __shfl_xor_sync(0xffffffffu, m, o));
            float e0 = expf(x0 - m), e1 = expf(x1 - m), e2 = expf(x2 - m), e3 = expf(x3 - m);
            float s = e0 + e1 + e2 + e3;
#pragma unroll
            for (int o = 16; o > 0; o >>= 1) s += __shfl_xor_sync(0xffffffffu, s, o);
            dots[i * 129 + lane]      = e0;
            dots[i * 129 + 32 + lane] = e1;
            dots[i * 129 + 64 + lane] = e2;
            dots[i * 129 + 96 + lane] = e3;
            if (lane == 0) { rsum[i] = s; rlse[i] = m + logf(s); }
        }
    }
    __syncthreads();

    float o0[8], o1[8];
#pragma unroll
    for (int k = 0; k < 8; k++) { o0[k] = 0.f; o1[k] = 0.f; }
    for (int j = 0; j < 128; j++) {
        float p0 = dots[ty * 129 + j];
        float p1 = dots[(ty + 32) * 129 + j];
        const float* vr = vs + j * 65 + tx * 8;
#pragma unroll
        for (int k = 0; k < 8; k++) {
            float vv = vr[k];
            o0[k] += p0 * vv;
            o1[k] += p1 * vv;
        }
    }
    float inv0 = 1.0f / rsum[ty];
    float inv1 = 1.0f / rsum[ty + 32];
    size_t ob0 = (((size_t)(bh * NHASH + h)) * Nn + tq0) * DHd + tx * 8;
    size_t ob1 = (((size_t)(bh * NHASH + h)) * Nn + tq1) * DHd + tx * 8;
#pragma unroll
    for (int k = 0; k < 8; k++) {
        g_oph[ob0 + k] = o0[k] * inv0;
        g_oph[ob1 + k] = o1[k] * inv1;
    }
    if (tx == 0) {
        g_lse[(bh * NHASH + h) * Nn + tq0] = rlse[ty];
        g_lse[(bh * NHASH + h) * Nn + tq1] = rlse[ty + 32];
    }
}

// ---------------- combine hash rounds ----------------
__global__ void combine_kernel() {
    int gid = blockIdx.x * 256 + threadIdx.x;
    int slot = gid >> 6;
    int d = gid & 63;
    int bh = slot >> 12;
    int t = slot & 4095;
    int base = bh * NHASH * Nn + t;
    float l0 = g_lse[base + 0 * Nn];
    float l1 = g_lse[base + 1 * Nn];
    float l2 = g_lse[base + 2 * Nn];
    float l3 = g_lse[base + 3 * Nn];
    float m = fmaxf(fmaxf(l0, l1), fmaxf(l2, l3));
    float w0 = expf(l0 - m), w1 = expf(l1 - m), w2 = expf(l2 - m), w3 = expf(l3 - m);
    float s = w0 + w1 + w2 + w3;
    size_t ob = ((size_t)bh * NHASH * Nn + t) * DHd + d;
    float acc = w0 * g_oph[ob]
              + w1 * g_oph[ob + (size_t)Nn * DHd]
              + w2 * g_oph[ob + (size_t)2 * Nn * DHd]
              + w3 * g_oph[ob + (size_t)3 * Nn * DHd];
    acc /= s;
    int b = bh >> 4, head = bh & 15;
    g_ocomb[((size_t)b * Nn + t) * Cc + head * DHd + d] = acc;
}

// ---------------- launch ----------------
extern "C" void kernel_launch(void* const* d_in, const int* in_sizes, int n_in,
                              void* d_out, int out_size) {
    const float* queries = (const float*)d_in[0];
    const float* Wqk  = (const float*)d_in[4];
    const float* Wv   = (const float*)d_in[5];
    const float* Wout = (const float*)d_in[6];
    const float* bout = (const float*)d_in[7];
    const float* rot  = (const float*)d_in[8];
    float* out = (float*)d_out;

    cudaFuncSetAttribute(attn_kernel, cudaFuncAttributeMaxDynamicSharedMemorySize, ATTN_SMEM_BYTES);
    cudaFuncSetAttribute(mma_wout, cudaFuncAttributeMaxDynamicSharedMemorySize, GEMM_SMEM);

    void *p_qk, *p_v, *p_ocomb, *p_asp, *p_wout;
    cudaGetSymbolAddress(&p_qk, g_qk);
    cudaGetSymbolAddress(&p_v, g_v);
    cudaGetSymbolAddress(&p_ocomb, g_ocomb);
    cudaGetSymbolAddress(&p_asp, g_asp);
    cudaGetSymbolAddress(&p_wout, g_wout_sp);
    __nv_bfloat16* asp  = (__nv_bfloat16*)p_asp;
    __nv_bfloat16* wout = (__nv_bfloat16*)p_wout;
    const size_t WOUT_PL = (size_t)1024 * 1024;
    const int NW = 1024 * 1024;
    const int NA = Mrows * Kdim;

    // QKV projections: fp32 FFMA, bit-identical to R1 baseline -> identical buckets
    dim3 ggrid(Cc / 64, Mrows / 64);   // (16, 128)
    gemm_kernel<<<ggrid, 256>>>(queries, Wqk, (float*)p_qk, nullptr, 1);
    gemm_kernel<<<ggrid, 256>>>(queries, Wv,  (float*)p_v,  nullptr, 1);

    // split Wout limbs early (independent)
    split3_kernel<<<NW / 1024, 256>>>(Wout, wout, wout + WOUT_PL, wout + 2 * WOUT_PL, NW);

    bucket_kernel<<<dim3(Nn / 32, BH), 128>>>(rot);
    sort_kernel<<<dim3(BH, NHASH), 256>>>();
    attn_kernel<<<dim3(NCHUNK, BH), 256, ATTN_SMEM_BYTES>>>();
    combine_kernel<<<(BH * Nn * DHd) / 256, 256>>>();

    // output GEMM via bf16x3 HMMA: split combined output, then M=8192, N=1024 (+bias)
    split3_kernel<<<NA / 1024, 256>>>((const float*)p_ocomb, asp, asp + APL, asp + 2 * APL, NA);
    mma_wout<<<dim3(8, 64), 256, GEMM_SMEM>>>(asp, APL, wout, WOUT_PL, bout, out);
}

// round 5
// speedup vs baseline: 1.1914x; 1.1809x over previous
#include <cuda_runtime.h>
#include <cuda_bf16.h>
#include <math.h>
#include <stdint.h>

// ---------------- problem constants ----------------
#define Bb      2
#define Nn      4096
#define Cc      1024
#define Hh      16
#define DHd     64
#define BH      32          // Bb*Hh
#define NHASH   4
#define NBUCK   64          // Nn / BUCKET
#define NCHUNK  256         // NHASH*NBUCK
#define BS      64          // bucket size
#define Kdim    1024
#define Mrows   8192        // Bb*Nn

// ---------------- device scratch (static; no allocations allowed) ----------------
__device__ float g_qk  [BH * Nn * DHd];            // 32 MB  (bh, t, d)
__device__ float g_v   [BH * Nn * DHd];            // 32 MB
__device__ int   g_bucket[BH * NHASH * Nn];        // 2 MB
__device__ int   g_st  [BH * NHASH * Nn];          // 2 MB
__device__ float g_oph [BH * NHASH * Nn * DHd];    // 134 MB per-hash outputs (scattered)
__device__ float g_lse [BH * NHASH * Nn];          // 2 MB
__device__ float g_ocomb[Bb * Nn * Cc];            // 32 MB  combined heads, (b, t, c)

// bf16x3 limbs
#define APL ((size_t)Mrows * Kdim)
__device__ __nv_bfloat16 g_asp[3 * APL];                      // 48 MB activations
__device__ __nv_bfloat16 g_wqkv_sp[(size_t)3 * 2048 * 1024];  // 12 MB (rows 0..1023 Wqk, 1024..2047 Wv)
__device__ __nv_bfloat16 g_wout_sp[(size_t)3 * 1024 * 1024];  // 6 MB

// ================= helpers (sm_103-safe) =================
__device__ __forceinline__ uint32_t smem_to_u32(const void* p) {
    uint32_t a;
    asm("{ .reg .u64 t; cvta.to.shared.u64 t, %1; cvt.u32.u64 %0, t; }" : "=r"(a) : "l"(p));
    return a;
}
#define CP_ASYNC16(saddr, gptr) \
    asm volatile("cp.async.cg.shared.global [%0], [%1], 16;" \
        :: "r"(saddr), "l"(__cvta_generic_to_global(gptr)))
#define CP_COMMIT() asm volatile("cp.async.commit_group;" ::: "memory")
#define CP_WAIT(n)  asm volatile("cp.async.wait_group %0;" :: "n"(n) : "memory")

__device__ __forceinline__ void ldmx4(uint32_t* r, uint32_t addr) {
    asm volatile("ldmatrix.sync.aligned.m8n8.x4.shared.b16 {%0,%1,%2,%3}, [%4];"
        : "=r"(r[0]), "=r"(r[1]), "=r"(r[2]), "=r"(r[3]) : "r"(addr));
}
__device__ __forceinline__ void mma16816(float* d, const uint32_t* a, uint32_t b0, uint32_t b1) {
    asm volatile("mma.sync.aligned.m16n8k16.row.col.f32.bf16.bf16.f32 "
        "{%0,%1,%2,%3}, {%4,%5,%6,%7}, {%8,%9}, {%0,%1,%2,%3};"
        : "+f"(d[0]), "+f"(d[1]), "+f"(d[2]), "+f"(d[3])
        : "r"(a[0]), "r"(a[1]), "r"(a[2]), "r"(a[3]), "r"(b0), "r"(b1));
}

// ================= bf16x3 limb split =================
__global__ void split3_kernel(const float* __restrict__ x,
                              __nv_bfloat16* __restrict__ hi,
                              __nv_bfloat16* __restrict__ mid,
                              __nv_bfloat16* __restrict__ lo, int n) {
    int i = (blockIdx.x * 256 + threadIdx.x) * 4;
    if (i >= n) return;
    float4 v = *(const float4*)(x + i);
    float a[4] = {v.x, v.y, v.z, v.w};
#pragma unroll
    for (int j = 0; j < 4; j++) {
        __nv_bfloat16 h = __float2bfloat16(a[j]);
        float r = a[j] - __bfloat162float(h);
        __nv_bfloat16 m = __float2bfloat16(r);
        float r2 = r - __bfloat162float(m);
        __nv_bfloat16 l = __float2bfloat16(r2);
        hi[i + j] = h; mid[i + j] = m; lo[i + j] = l;
    }
}

// ================= HMMA GEMM (bf16x3, 6 passes, small->large order) =================
// D[m][n] = sum_k A[m][k] * B[n][k]; fp32-equivalent (hi*hi accumulated LAST).
// Block 128x128, 8 warps (64x32 each), K-step 32, 3-stage cp.async pipeline.
// mode 0: fused QKV epilogue -> g_qk/g_v head layout. mode 1: +bias -> row-major outp.
#define ROWB     80
#define MATB     (128 * ROWB)
#define STAGEB   (2 * MATB)
#define GEMM_SMEM (3 * STAGEB)
#define NPROD    6
#define NSTAGE   (NPROD * 32)   // 192

// pass p -> limb index of A / W, ascending product magnitude:
// (1,1) (0,2) (2,0) (0,1) (1,0) (0,0)
#define PA_TBL 0x010201u
#define PW_TBL 0x001021u

__global__ __launch_bounds__(256, 2) void mma_gemm(
        const __nv_bfloat16* __restrict__ Asp, size_t Apl,
        const __nv_bfloat16* __restrict__ Bsp, size_t Bpl,
        const float* __restrict__ bias, int mode, float* __restrict__ outp) {
    extern __shared__ char smem[];
    uint32_t sbase = smem_to_u32(smem);
    int tid = threadIdx.x;
    int lane = tid & 31, warp = tid >> 5;
    int wm = warp >> 2, wn = warp & 3;
    int bn = blockIdx.x * 128, bm = blockIdx.y * 128;

    int v0 = tid, v1 = tid + 256;
    int r0 = v0 >> 2, c0 = v0 & 3;
    int r1 = v1 >> 2, c1 = v1 & 3;
    uint32_t so0 = (uint32_t)(r0 * ROWB + c0 * 16);
    uint32_t so1 = (uint32_t)(r1 * ROWB + c1 * 16);

    uint32_t aoff = (uint32_t)((wm * 64 + (lane & 15)) * ROWB + (lane >> 4) * 16);
    uint32_t boff = (uint32_t)((wn * 32 + ((lane >> 4) & 1) * 8 + (lane & 7)) * ROWB
                               + ((lane >> 3) & 1) * 16);

    float D[4][4][4];
#pragma unroll
    for (int i = 0; i < 4; i++)
#pragma unroll
        for (int j = 0; j < 4; j++)
#pragma unroll
            for (int q = 0; q < 4; q++) D[i][j][q] = 0.f;

    // prologue: stages 0,1 (both pass 0)
#pragma unroll
    for (int s = 0; s < 2; s++) {
        int k0 = s * 32;
        const __nv_bfloat16* Ap = Asp + (size_t)((PA_TBL) & 7) * Apl;
        const __nv_bfloat16* Bp = Bsp + (size_t)((PW_TBL) & 7) * Bpl;
        uint32_t st = sbase + s * STAGEB;
        CP_ASYNC16(st + so0, Ap + (size_t)(bm + r0) * Kdim + k0 + c0 * 8);
        CP_ASYNC16(st + so1, Ap + (size_t)(bm + r1) * Kdim + k0 + c1 * 8);
        CP_ASYNC16(st + MATB + so0, Bp + (size_t)(bn + r0) * Kdim + k0 + c0 * 8);
        CP_ASYNC16(st + MATB + so1, Bp + (size_t)(bn + r1) * Kdim + k0 + c1 * 8);
        CP_COMMIT();
    }

    for (int s = 0; s < NSTAGE; s++) {
        if (s == NSTAGE - 1) { CP_WAIT(0); } else { CP_WAIT(1); }
        __syncthreads();
        if (s + 2 < NSTAGE) {
            int sn = s + 2;
            int p = sn >> 5, k0 = (sn & 31) << 5;
            const __nv_bfloat16* Ap = Asp + (size_t)((PA_TBL >> (p * 4)) & 7) * Apl;
            const __nv_bfloat16* Bp = Bsp + (size_t)((PW_TBL >> (p * 4)) & 7) * Bpl;
            uint32_t st = sbase + (uint32_t)(sn % 3) * STAGEB;
            CP_ASYNC16(st + so0, Ap + (size_t)(bm + r0) * Kdim + k0 + c0 * 8);
            CP_ASYNC16(st + so1, Ap + (size_t)(bm + r1) * Kdim + k0 + c1 * 8);
            CP_ASYNC16(st + MATB + so0, Bp + (size_t)(bn + r0) * Kdim + k0 + c0 * 8);
            CP_ASYNC16(st + MATB + so1, Bp + (size_t)(bn + r1) * Kdim + k0 + c1 * 8);
            CP_COMMIT();
        }
        uint32_t st = sbase + (uint32_t)(s % 3) * STAGEB;
        uint32_t ab = st + aoff;
        uint32_t bb = st + MATB + boff;
#pragma unroll
        for (int ks = 0; ks < 2; ks++) {
            uint32_t A4[4][4], B4[2][4];
#pragma unroll
            for (int i = 0; i < 4; i++) ldmx4(A4[i], ab + i * (16 * ROWB) + ks * 32);
#pragma unroll
            for (int jp = 0; jp < 2; jp++) ldmx4(B4[jp], bb + jp * (16 * ROWB) + ks * 32);
#pragma unroll
            for (int i = 0; i < 4; i++)
#pragma unroll
                for (int jn = 0; jn < 4; jn++)
                    mma16816(D[i][jn], A4[i], B4[jn >> 1][(jn & 1) * 2], B4[jn >> 1][(jn & 1) * 2 + 1]);
        }
    }

    // epilogue
    int g = lane >> 2, t = lane & 3;
#pragma unroll
    for (int i = 0; i < 4; i++) {
#pragma unroll
        for (int jn = 0; jn < 4; jn++) {
            int m0 = bm + wm * 64 + i * 16 + g;
            int n0 = bn + wn * 32 + jn * 8 + t * 2;
            float2 va = make_float2(D[i][jn][0], D[i][jn][1]);   // row m0
            float2 vb = make_float2(D[i][jn][2], D[i][jn][3]);   // row m0+8
            if (mode == 0) {
                int bI = m0 >> 12;
                int t0 = m0 & 4095, t1 = (m0 + 8) & 4095;
                float* base;
                int nn = n0;
                if (n0 < 1024) base = g_qk;
                else { base = g_v; nn = n0 - 1024; }
                int hd = nn >> 6, dh = nn & 63;
                *(float2*)(base + (((size_t)(bI * Hh + hd)) * Nn + t0) * DHd + dh) = va;
                *(float2*)(base + (((size_t)(bI * Hh + hd)) * Nn + t1) * DHd + dh) = vb;
            } else {
                float2 bv = *(const float2*)(bias + n0);
                va.x += bv.x; va.y += bv.y; vb.x += bv.x; vb.y += bv.y;
                *(float2*)(outp + (size_t)m0 * Cc + n0) = va;
                *(float2*)(outp + (size_t)(m0 + 8) * Cc + n0) = vb;
            }
        }
    }
}

// ---------------- LSH bucketing ----------------
__global__ void bucket_kernel(const float* __restrict__ rot) {
    __shared__ float rs[DHd * 128];
    __shared__ float qs[32 * 65];
    int bh = blockIdx.y;
    int tb = blockIdx.x * 32;
    int tid = threadIdx.x;

    for (int i = tid; i < DHd * 128; i += 128) rs[i] = rot[i];
    {
        int row = tid >> 2, seg = tid & 3;
        const float* src = g_qk + ((size_t)bh * Nn + tb + row) * DHd + seg * 16;
#pragma unroll
        for (int k = 0; k < 16; k++) qs[row * 65 + seg * 16 + k] = src[k];
    }
    __syncthreads();

    int h = tid >> 5;
    int lane = tid & 31;
    int tok = tb + lane;

    float r[32];
#pragma unroll
    for (int i = 0; i < 32; i++) r[i] = 0.f;
    for (int d = 0; d < DHd; d++) {
        float qd = qs[lane * 65 + d];
        const float* rp = rs + d * 128 + h * 32;
#pragma unroll
        for (int i = 0; i < 32; i++) r[i] += qd * rp[i];
    }
    float best = r[0]; int bi = 0;
#pragma unroll
    for (int i = 1; i < 32; i++) if (r[i] > best) { best = r[i]; bi = i; }
#pragma unroll
    for (int i = 0; i < 32; i++) if (-r[i] > best) { best = -r[i]; bi = 32 + i; }
    g_bucket[((size_t)bh * NHASH + h) * Nn + tok] = bi;
}

// ---------------- stable counting sort per (bh, hash) ----------------
__global__ void sort_kernel() {
    __shared__ unsigned char sb[Nn];
    __shared__ int hist[NBUCK];
    __shared__ int offs[NBUCK];
    int bh = blockIdx.x, h = blockIdx.y;
    int tid = threadIdx.x;
    if (tid < NBUCK) hist[tid] = 0;
    __syncthreads();
    const int base = (bh * NHASH + h) * Nn;
    for (int t = tid; t < Nn; t += 256) {
        int b = g_bucket[base + t];
        sb[t] = (unsigned char)b;
        atomicAdd(&hist[b], 1);
    }
    __syncthreads();
    if (tid == 0) {
        int acc = 0;
        for (int b = 0; b < NBUCK; b++) { offs[b] = acc; acc += hist[b]; }
    }
    __syncthreads();
    if (tid < NBUCK) {
        unsigned char b = (unsigned char)tid;
        int w = offs[tid];
        for (int t = 0; t < Nn; t++)
            if (sb[t] == b) g_st[base + (w++)] = t;
    }
}

// ---------------- chunked LSH attention ----------------
#define ATTN_SMEM_BYTES ((64*65 + 128*65 + 128*65 + 64 + 64) * 4 + (64 + 128) * 4)

__global__ void attn_kernel() {
    extern __shared__ float sm[];
    float* qs   = sm;
    float* ks   = qs + 64 * 65;
    float* vs   = ks + 128 * 65;
    float* rsum = vs + 128 * 65;
    float* rlse = rsum + 64;
    int*   tq   = (int*)(rlse + 64);
    int*   tkv  = tq + 64;

    int c  = blockIdx.x;
    int bh = blockIdx.y;
    int h  = c >> 6;
    int tid = threadIdx.x;
    int pc = (c + NCHUNK - 1) & (NCHUNK - 1);

    const int stbase = bh * (NHASH * Nn);
    if (tid < 64)       { int t0 = g_st[stbase + c * BS + tid]; tq[tid] = t0; tkv[tid] = t0; }
    else if (tid < 128) { tkv[tid] = g_st[stbase + pc * BS + (tid - 64)]; }
    __syncthreads();

    {
        int i = tid >> 2, seg = tid & 3;
        const float* src = g_qk + ((size_t)bh * Nn + tq[i]) * DHd + seg * 16;
#pragma unroll
        for (int k = 0; k < 16; k++) qs[i * 65 + seg * 16 + k] = src[k];
    }
    {
        int j = tid >> 1, seg = tid & 1;
        size_t off = ((size_t)bh * Nn + tkv[j]) * DHd + seg * 32;
        const float* ksrc = g_qk + off;
        const float* vsrc = g_v + off;
#pragma unroll
        for (int k = 0; k < 32; k++) {
            ks[j * 65 + seg * 32 + k] = ksrc[k];
            vs[j * 65 + seg * 32 + k] = vsrc[k];
        }
    }
    __syncthreads();

    {
        int w = tid >> 5, lane = tid & 31;
        for (int rr = 0; rr < 16; rr++) {
            int j = w * 16 + rr;
            float a = ks[j * 65 + lane], b = ks[j * 65 + 32 + lane];
            float s = a * a + b * b;
#pragma unroll
            for (int o = 16; o > 0; o >>= 1) s += __shfl_xor_sync(0xffffffffu, s, o);
            float inv = 1.0f / fmaxf(sqrtf(s), 1e-12f);
            ks[j * 65 + lane] = a * inv;
            ks[j * 65 + 32 + lane] = b * inv;
        }
    }
    __syncthreads();

    int ty = tid >> 3, tx = tid & 7;
    float acc0[16], acc1[16];
#pragma unroll
    for (int u = 0; u < 16; u++) { acc0[u] = 0.f; acc1[u] = 0.f; }
    for (int d = 0; d < DHd; d++) {
        float q0 = qs[ty * 65 + d];
        float q1 = qs[(ty + 32) * 65 + d];
#pragma unroll
        for (int u = 0; u < 16; u++) {
            float kv = ks[(tx + 8 * u) * 65 + d];
            acc0[u] += q0 * kv;
            acc1[u] += q1 * kv;
        }
    }
    __syncthreads();
    float* dots = ks;
    int tq0 = tq[ty], tq1 = tq[ty + 32];
#pragma unroll
    for (int u = 0; u < 16; u++) {
        int j = tx + 8 * u;
        int tk = tkv[j];
        dots[ty * 129 + j]        = (tq0 == tk) ? -5e4f : acc0[u] * 0.125f;
        dots[(ty + 32) * 129 + j] = (tq1 == tk) ? -5e4f : acc1[u] * 0.125f;
    }
    __syncthreads();

    {
        int w = tid >> 5, lane = tid & 31;
        for (int rr = 0; rr < 8; rr++) {
            int i = w * 8 + rr;
            float x0 = dots[i * 129 + lane];
            float x1 = dots[i * 129 + 32 + lane];
            float x2 = dots[i * 129 + 64 + lane];
            float x3 = dots[i * 129 + 96 + lane];
            float m = fmaxf(fmaxf(x0, x1), fmaxf(x2, x3));
#pragma unroll
            for (int o = 16; o > 0; o >>= 1) m = fmaxf(m, __shfl_xor_sync(0xffffffffu, m, o));
            float e0 = expf(x0 - m), e1 = expf(x1 - m), e2 = expf(x2 - m), e3 = expf(x3 - m);
            float s = e0 + e1 + e2 + e3;
#pragma unroll
            for (int o = 16; o > 0; o >>= 1) s += __shfl_xor_sync(0xffffffffu, s, o);
            dots[i * 129 + lane]      = e0;
            dots[i * 129 + 32 + lane] = e1;
            dots[i * 129 + 64 + lane] = e2;
            dots[i * 129 + 96 + lane] = e3;
            if (lane == 0) { rsum[i] = s; rlse[i] = m + logf(s); }
        }
    }
    __syncthreads();

    float o0[8], o1[8];
#pragma unroll
    for (int k = 0; k < 8; k++) { o0[k] = 0.f; o1[k] = 0.f; }
    for (int j = 0; j < 128; j++) {
        float p0 = dots[ty * 129 + j];
        float p1 = dots[(ty + 32) * 129 + j];
        const float* vr = vs + j * 65 + tx * 8;
#pragma unroll
        for (int k = 0; k < 8; k++) {
            float vv = vr[k];
            o0[k] += p0 * vv;
            o1[k] += p1 * vv;
        }
    }
    float inv0 = 1.0f / rsum[ty];
    float inv1 = 1.0f / rsum[ty + 32];
    size_t ob0 = (((size_t)(bh * NHASH + h)) * Nn + tq0) * DHd + tx * 8;
    size_t ob1 = (((size_t)(bh * NHASH + h)) * Nn + tq1) * DHd + tx * 8;
#pragma unroll
    for (int k = 0; k < 8; k++) {
        g_oph[ob0 + k] = o0[k] * inv0;
        g_oph[ob1 + k] = o1[k] * inv1;
    }
    if (tx == 0) {
        g_lse[(bh * NHASH + h) * Nn + tq0] = rlse[ty];
        g_lse[(bh * NHASH + h) * Nn + tq1] = rlse[ty + 32];
    }
}

// ---------------- combine hash rounds ----------------
__global__ void combine_kernel() {
    int gid = blockIdx.x * 256 + threadIdx.x;
    int slot = gid >> 6;
    int d = gid & 63;
    int bh = slot >> 12;
    int t = slot & 4095;
    int base = bh * NHASH * Nn + t;
    float l0 = g_lse[base + 0 * Nn];
    float l1 = g_lse[base + 1 * Nn];
    float l2 = g_lse[base + 2 * Nn];
    float l3 = g_lse[base + 3 * Nn];
    float m = fmaxf(fmaxf(l0, l1), fmaxf(l2, l3));
    float w0 = expf(l0 - m), w1 = expf(l1 - m), w2 = expf(l2 - m), w3 = expf(l3 - m);
    float s = w0 + w1 + w2 + w3;
    size_t ob = ((size_t)bh * NHASH * Nn + t) * DHd + d;
    float acc = w0 * g_oph[ob]
              + w1 * g_oph[ob + (size_t)Nn * DHd]
              + w2 * g_oph[ob + (size_t)2 * Nn * DHd]
              + w3 * g_oph[ob + (size_t)3 * Nn * DHd];
    acc /= s;
    int b = bh >> 4, head = bh & 15;
    g_ocomb[((size_t)b * Nn + t) * Cc + head * DHd + d] = acc;
}

// ---------------- launch ----------------
extern "C" void kernel_launch(void* const* d_in, const int* in_sizes, int n_in,
                              void* d_out, int out_size) {
    const float* queries = (const float*)d_in[0];
    const float* Wqk  = (const float*)d_in[4];
    const float* Wv   = (const float*)d_in[5];
    const float* Wout = (const float*)d_in[6];
    const float* bout = (const float*)d_in[7];
    const float* rot  = (const float*)d_in[8];
    float* out = (float*)d_out;

    cudaFuncSetAttribute(attn_kernel, cudaFuncAttributeMaxDynamicSharedMemorySize, ATTN_SMEM_BYTES);
    cudaFuncSetAttribute(mma_gemm, cudaFuncAttributeMaxDynamicSharedMemorySize, GEMM_SMEM);

    void *p_ocomb, *p_asp, *p_wqkv, *p_wout;
    cudaGetSymbolAddress(&p_ocomb, g_ocomb);
    cudaGetSymbolAddress(&p_asp, g_asp);
    cudaGetSymbolAddress(&p_wqkv, g_wqkv_sp);
    cudaGetSymbolAddress(&p_wout, g_wout_sp);
    __nv_bfloat16* asp  = (__nv_bfloat16*)p_asp;
    __nv_bfloat16* wqkv = (__nv_bfloat16*)p_wqkv;
    __nv_bfloat16* wout = (__nv_bfloat16*)p_wout;
    const size_t WQKV_PL = (size_t)2048 * 1024;
    const size_t WOUT_PL = (size_t)1024 * 1024;
    const int NW = 1024 * 1024;
    const int NA = Mrows * Kdim;

    // limb splits
    split3_kernel<<<NA / 1024, 256>>>(queries, asp, asp + APL, asp + 2 * APL, NA);
    split3_kernel<<<NW / 1024, 256>>>(Wqk, wqkv, wqkv + WQKV_PL, wqkv + 2 * WQKV_PL, NW);
    split3_kernel<<<NW / 1024, 256>>>(Wv, wqkv + NW, wqkv + WQKV_PL + NW, wqkv + 2 * WQKV_PL + NW, NW);
    split3_kernel<<<NW / 1024, 256>>>(Wout, wout, wout + WOUT_PL, wout + 2 * WOUT_PL, NW);

    // fused QK+V GEMM: M=8192, N=2048 -> g_qk/g_v (head layout)
    mma_gemm<<<dim3(16, 64), 256, GEMM_SMEM>>>(asp, APL, wqkv, WQKV_PL, nullptr, 0, nullptr);

    bucket_kernel<<<dim3(Nn / 32, BH), 128>>>(rot);
    sort_kernel<<<dim3(BH, NHASH), 256>>>();
    attn_kernel<<<dim3(NCHUNK, BH), 256, ATTN_SMEM_BYTES>>>();
    combine_kernel<<<(BH * Nn * DHd) / 256, 256>>>();

    // output GEMM: split combined output, then M=8192, N=1024 (+bias) -> d_out
    split3_kernel<<<NA / 1024, 256>>>((const float*)p_ocomb, asp, asp + APL, asp + 2 * APL, NA);
    mma_gemm<<<dim3(8, 64), 256, GEMM_SMEM>>>(asp, APL, wout, WOUT_PL, bout, 1, out);
}

// round 6
// speedup vs baseline: 1.3532x; 1.1358x over previous
#include <cuda_runtime.h>
#include <cuda_bf16.h>
#include <math.h>
#include <stdint.h>

// ---------------- problem constants ----------------
#define Bb      2
#define Nn      4096
#define Cc      1024
#define Hh      16
#define DHd     64
#define BH      32          // Bb*Hh
#define NHASH   4
#define NBUCK   64          // Nn / BUCKET
#define NCHUNK  256         // NHASH*NBUCK
#define BS      64          // bucket size
#define Kdim    1024
#define Mrows   8192        // Bb*Nn

// ---------------- device scratch ----------------
__device__ float g_qk  [BH * Nn * DHd];            // 32 MB  (bh, t, d)
__device__ float g_v   [BH * Nn * DHd];            // 32 MB
__device__ int   g_bucket[BH * NHASH * Nn];        // 2 MB
__device__ int   g_st  [BH * NHASH * Nn];          // 2 MB
__device__ float g_oph [BH * NHASH * Nn * DHd];    // 134 MB per-hash outputs (scattered)
__device__ float g_lse [BH * NHASH * Nn];          // 2 MB

// bf16x3 limbs
#define APL ((size_t)Mrows * Kdim)
__device__ __nv_bfloat16 g_asp[3 * APL];                      // 48 MB activations
__device__ __nv_bfloat16 g_wqkv_sp[(size_t)3 * 2048 * 1024];  // 12 MB (rows 0..1023 Wqk, 1024..2047 Wv)
__device__ __nv_bfloat16 g_wout_sp[(size_t)3 * 1024 * 1024];  // 6 MB

// ================= helpers (sm_103-safe) =================
__device__ __forceinline__ uint32_t smem_to_u32(const void* p) {
    uint32_t a;
    asm("{ .reg .u64 t; cvta.to.shared.u64 t, %1; cvt.u32.u64 %0, t; }" : "=r"(a) : "l"(p));
    return a;
}
#define CP_ASYNC16(saddr, gptr) \
    asm volatile("cp.async.cg.shared.global [%0], [%1], 16;" \
        :: "r"(saddr), "l"(__cvta_generic_to_global(gptr)))
#define CP_COMMIT() asm volatile("cp.async.commit_group;" ::: "memory")
#define CP_WAIT(n)  asm volatile("cp.async.wait_group %0;" :: "n"(n) : "memory")

__device__ __forceinline__ void ldmx4(uint32_t* r, uint32_t addr) {
    asm volatile("ldmatrix.sync.aligned.m8n8.x4.shared.b16 {%0,%1,%2,%3}, [%4];"
        : "=r"(r[0]), "=r"(r[1]), "=r"(r[2]), "=r"(r[3]) : "r"(addr));
}
__device__ __forceinline__ void mma16816(float* d, const uint32_t* a, uint32_t b0, uint32_t b1) {
    asm volatile("mma.sync.aligned.m16n8k16.row.col.f32.bf16.bf16.f32 "
        "{%0,%1,%2,%3}, {%4,%5,%6,%7}, {%8,%9}, {%0,%1,%2,%3};"
        : "+f"(d[0]), "+f"(d[1]), "+f"(d[2]), "+f"(d[3])
        : "r"(a[0]), "r"(a[1]), "r"(a[2]), "r"(a[3]), "r"(b0), "r"(b1));
}
__device__ __forceinline__ uint32_t pack_bf2(float a, float b) {
    uint16_t ua = __bfloat16_as_ushort(__float2bfloat16(a));
    uint16_t ub = __bfloat16_as_ushort(__float2bfloat16(b));
    return (uint32_t)ua | ((uint32_t)ub << 16);
}

// ================= bf16x3 limb split (vectorized: 8 elems/thread) =================
__global__ void split3_kernel(const float* __restrict__ x,
                              __nv_bfloat16* __restrict__ hi,
                              __nv_bfloat16* __restrict__ mid,
                              __nv_bfloat16* __restrict__ lo, int n) {
    int i = (blockIdx.x * 256 + threadIdx.x) * 8;
    if (i >= n) return;
    float4 v0 = *(const float4*)(x + i);
    float4 v1 = *(const float4*)(x + i + 4);
    float a[8] = {v0.x, v0.y, v0.z, v0.w, v1.x, v1.y, v1.z, v1.w};
    float hf[8], mf[8], lf[8];
#pragma unroll
    for (int j = 0; j < 8; j++) {
        float h = __bfloat162float(__float2bfloat16(a[j]));
        float r = a[j] - h;
        float m = __bfloat162float(__float2bfloat16(r));
        hf[j] = h; mf[j] = m; lf[j] = r - m;
    }
    uint4 hp = make_uint4(pack_bf2(hf[0], hf[1]), pack_bf2(hf[2], hf[3]),
                          pack_bf2(hf[4], hf[5]), pack_bf2(hf[6], hf[7]));
    uint4 mp = make_uint4(pack_bf2(mf[0], mf[1]), pack_bf2(mf[2], mf[3]),
                          pack_bf2(mf[4], mf[5]), pack_bf2(mf[6], mf[7]));
    uint4 lp = make_uint4(pack_bf2(lf[0], lf[1]), pack_bf2(lf[2], lf[3]),
                          pack_bf2(lf[4], lf[5]), pack_bf2(lf[6], lf[7]));
    *(uint4*)(hi + i) = hp;
    *(uint4*)(mid + i) = mp;
    *(uint4*)(lo + i) = lp;
}

// ================= HMMA GEMM (bf16 limbs, variable pass count, small->large) =================
#define ROWB     80
#define MATB     (128 * ROWB)
#define STAGEB   (2 * MATB)
#define GEMM_SMEM (3 * STAGEB)
// 6-pass (fp32-equivalent): (1,1)(0,2)(2,0)(0,1)(1,0)(0,0)
#define PA6 0x010201u
#define PW6 0x001021u
// 3-pass (~4e-6): (0,1)(1,0)(0,0)
#define PA3 0x010u
#define PW3 0x001u

__global__ __launch_bounds__(256, 2) void mma_gemm(
        const __nv_bfloat16* __restrict__ Asp, size_t Apl,
        const __nv_bfloat16* __restrict__ Bsp, size_t Bpl,
        const float* __restrict__ bias, float* __restrict__ outp,
        float* __restrict__ headout, int npass, uint32_t paTbl, uint32_t pwTbl) {
    extern __shared__ char smem[];
    uint32_t sbase = smem_to_u32(smem);
    int tid = threadIdx.x;
    int lane = tid & 31, warp = tid >> 5;
    int wm = warp >> 2, wn = warp & 3;
    int bn = blockIdx.x * 128, bm = blockIdx.y * 128;
    int nstage = npass * 32;

    int v0 = tid, v1 = tid + 256;
    int r0 = v0 >> 2, c0 = v0 & 3;
    int r1 = v1 >> 2, c1 = v1 & 3;
    uint32_t so0 = (uint32_t)(r0 * ROWB + c0 * 16);
    uint32_t so1 = (uint32_t)(r1 * ROWB + c1 * 16);

    uint32_t aoff = (uint32_t)((wm * 64 + (lane & 15)) * ROWB + (lane >> 4) * 16);
    uint32_t boff = (uint32_t)((wn * 32 + ((lane >> 4) & 1) * 8 + (lane & 7)) * ROWB
                               + ((lane >> 3) & 1) * 16);

    float D[4][4][4];
#pragma unroll
    for (int i = 0; i < 4; i++)
#pragma unroll
        for (int j = 0; j < 4; j++)
#pragma unroll
            for (int q = 0; q < 4; q++) D[i][j][q] = 0.f;

#pragma unroll
    for (int s = 0; s < 2; s++) {
        int k0 = s * 32;
        const __nv_bfloat16* Ap = Asp + (size_t)(paTbl & 7) * Apl;
        const __nv_bfloat16* Bp = Bsp + (size_t)(pwTbl & 7) * Bpl;
        uint32_t st = sbase + s * STAGEB;
        CP_ASYNC16(st + so0, Ap + (size_t)(bm + r0) * Kdim + k0 + c0 * 8);
        CP_ASYNC16(st + so1, Ap + (size_t)(bm + r1) * Kdim + k0 + c1 * 8);
        CP_ASYNC16(st + MATB + so0, Bp + (size_t)(bn + r0) * Kdim + k0 + c0 * 8);
        CP_ASYNC16(st + MATB + so1, Bp + (size_t)(bn + r1) * Kdim + k0 + c1 * 8);
        CP_COMMIT();
    }

    for (int s = 0; s < nstage; s++) {
        if (s == nstage - 1) { CP_WAIT(0); } else { CP_WAIT(1); }
        __syncthreads();
        if (s + 2 < nstage) {
            int sn = s + 2;
            int p = sn >> 5, k0 = (sn & 31) << 5;
            const __nv_bfloat16* Ap = Asp + (size_t)((paTbl >> (p * 4)) & 7) * Apl;
            const __nv_bfloat16* Bp = Bsp + (size_t)((pwTbl >> (p * 4)) & 7) * Bpl;
            uint32_t st = sbase + (uint32_t)(sn % 3) * STAGEB;
            CP_ASYNC16(st + so0, Ap + (size_t)(bm + r0) * Kdim + k0 + c0 * 8);
            CP_ASYNC16(st + so1, Ap + (size_t)(bm + r1) * Kdim + k0 + c1 * 8);
            CP_ASYNC16(st + MATB + so0, Bp + (size_t)(bn + r0) * Kdim + k0 + c0 * 8);
            CP_ASYNC16(st + MATB + so1, Bp + (size_t)(bn + r1) * Kdim + k0 + c1 * 8);
            CP_COMMIT();
        }
        uint32_t st = sbase + (uint32_t)(s % 3) * STAGEB;
        uint32_t ab = st + aoff;
        uint32_t bb = st + MATB + boff;
#pragma unroll
        for (int ks = 0; ks < 2; ks++) {
            uint32_t A4[4][4], B4[2][4];
#pragma unroll
            for (int i = 0; i < 4; i++) ldmx4(A4[i], ab + i * (16 * ROWB) + ks * 32);
#pragma unroll
            for (int jp = 0; jp < 2; jp++) ldmx4(B4[jp], bb + jp * (16 * ROWB) + ks * 32);
#pragma unroll
            for (int i = 0; i < 4; i++)
#pragma unroll
                for (int jn = 0; jn < 4; jn++)
                    mma16816(D[i][jn], A4[i], B4[jn >> 1][(jn & 1) * 2], B4[jn >> 1][(jn & 1) * 2 + 1]);
        }
    }

    int g = lane >> 2, t = lane & 3;
#pragma unroll
    for (int i = 0; i < 4; i++) {
#pragma unroll
        for (int jn = 0; jn < 4; jn++) {
            int m0 = bm + wm * 64 + i * 16 + g;
            int n0 = bn + wn * 32 + jn * 8 + t * 2;
            float2 va = make_float2(D[i][jn][0], D[i][jn][1]);
            float2 vb = make_float2(D[i][jn][2], D[i][jn][3]);
            if (headout) {
                int bI = m0 >> 12;
                int t0 = m0 & 4095, t1 = (m0 + 8) & 4095;
                int hd = n0 >> 6, dh = n0 & 63;
                *(float2*)(headout + (((size_t)(bI * Hh + hd)) * Nn + t0) * DHd + dh) = va;
                *(float2*)(headout + (((size_t)(bI * Hh + hd)) * Nn + t1) * DHd + dh) = vb;
            } else {
                float2 bv = *(const float2*)(bias + n0);
                va.x += bv.x; va.y += bv.y; vb.x += bv.x; vb.y += bv.y;
                *(float2*)(outp + (size_t)m0 * Cc + n0) = va;
                *(float2*)(outp + (size_t)(m0 + 8) * Cc + n0) = vb;
            }
        }
    }
}

// ---------------- LSH bucketing (2 tokens/thread: reuse rotation LDS vectors) ----------------
__global__ void bucket_kernel(const float* __restrict__ rot) {
    __shared__ float rs[DHd * 128];   // rotations (d, h*32+i)
    __shared__ float qs[64 * 65];     // 64 tokens x 64 dims (padded)
    int bh = blockIdx.y;
    int tb = blockIdx.x * 64;
    int tid = threadIdx.x;            // 128

    for (int i = tid; i < DHd * 128; i += 128) rs[i] = rot[i];
    {
        int row = tid >> 1, seg = tid & 1;
        const float* src = g_qk + ((size_t)bh * Nn + tb + row) * DHd + seg * 32;
#pragma unroll
        for (int k = 0; k < 32; k++) qs[row * 65 + seg * 32 + k] = src[k];
    }
    __syncthreads();

    int h = tid >> 5;
    int lane = tid & 31;

    float r0[32], r1[32];
#pragma unroll
    for (int i = 0; i < 32; i++) { r0[i] = 0.f; r1[i] = 0.f; }
    for (int d = 0; d < DHd; d++) {
        float q0 = qs[lane * 65 + d];
        float q1 = qs[(lane + 32) * 65 + d];
        const float* rp = rs + d * 128 + h * 32;
#pragma unroll
        for (int i = 0; i < 32; i++) {
            float rv = rp[i];
            r0[i] += q0 * rv;
            r1[i] += q1 * rv;
        }
    }
    float best0 = r0[0]; int bi0 = 0;
    float best1 = r1[0]; int bi1 = 0;
#pragma unroll
    for (int i = 1; i < 32; i++) {
        if (r0[i] > best0) { best0 = r0[i]; bi0 = i; }
        if (r1[i] > best1) { best1 = r1[i]; bi1 = i; }
    }
#pragma unroll
    for (int i = 0; i < 32; i++) {
        if (-r0[i] > best0) { best0 = -r0[i]; bi0 = 32 + i; }
        if (-r1[i] > best1) { best1 = -r1[i]; bi1 = 32 + i; }
    }
    g_bucket[((size_t)bh * NHASH + h) * Nn + tb + lane] = bi0;
    g_bucket[((size_t)bh * NHASH + h) * Nn + tb + lane + 32] = bi1;
}

// ---------------- stable counting sort per (bh, hash) ----------------
__global__ void sort_kernel() {
    __shared__ unsigned char sb[Nn];
    __shared__ int hist[NBUCK];
    __shared__ int offs[NBUCK];
    int bh = blockIdx.x, h = blockIdx.y;
    int tid = threadIdx.x;
    if (tid < NBUCK) hist[tid] = 0;
    __syncthreads();
    const int base = (bh * NHASH + h) * Nn;
    for (int t = tid; t < Nn; t += 256) {
        int b = g_bucket[base + t];
        sb[t] = (unsigned char)b;
        atomicAdd(&hist[b], 1);
    }
    __syncthreads();
    if (tid == 0) {
        int acc = 0;
        for (int b = 0; b < NBUCK; b++) { offs[b] = acc; acc += hist[b]; }
    }
    __syncthreads();
    if (tid < NBUCK) {
        unsigned char b = (unsigned char)tid;
        int w = offs[tid];
        for (int t = 0; t < Nn; t++)
            if (sb[t] == b) g_st[base + (w++)] = t;
    }
}

// ---------------- chunked LSH attention ----------------
#define ATTN_SMEM_BYTES ((64*65 + 128*65 + 128*65 + 64 + 64) * 4 + (64 + 128) * 4)

__global__ void attn_kernel() {
    extern __shared__ float sm[];
    float* qs   = sm;
    float* ks   = qs + 64 * 65;
    float* vs   = ks + 128 * 65;
    float* rsum = vs + 128 * 65;
    float* rlse = rsum + 64;
    int*   tq   = (int*)(rlse + 64);
    int*   tkv  = tq + 64;

    int c  = blockIdx.x;
    int bh = blockIdx.y;
    int h  = c >> 6;
    int tid = threadIdx.x;
    int pc = (c + NCHUNK - 1) & (NCHUNK - 1);

    const int stbase = bh * (NHASH * Nn);
    if (tid < 64)       { int t0 = g_st[stbase + c * BS + tid]; tq[tid] = t0; tkv[tid] = t0; }
    else if (tid < 128) { tkv[tid] = g_st[stbase + pc * BS + (tid - 64)]; }
    __syncthreads();

    {
        int i = tid >> 2, seg = tid & 3;
        const float* src = g_qk + ((size_t)bh * Nn + tq[i]) * DHd + seg * 16;
#pragma unroll
        for (int k = 0; k < 16; k++) qs[i * 65 + seg * 16 + k] = src[k];
    }
    {
        int j = tid >> 1, seg = tid & 1;
        size_t off = ((size_t)bh * Nn + tkv[j]) * DHd + seg * 32;
        const float* ksrc = g_qk + off;
        const float* vsrc = g_v + off;
#pragma unroll
        for (int k = 0; k < 32; k++) {
            ks[j * 65 + seg * 32 + k] = ksrc[k];
            vs[j * 65 + seg * 32 + k] = vsrc[k];
        }
    }
    __syncthreads();

    {
        int w = tid >> 5, lane = tid & 31;
        for (int rr = 0; rr < 16; rr++) {
            int j = w * 16 + rr;
            float a = ks[j * 65 + lane], b = ks[j * 65 + 32 + lane];
            float s = a * a + b * b;
#pragma unroll
            for (int o = 16; o > 0; o >>= 1) s += __shfl_xor_sync(0xffffffffu, s, o);
            float inv = 1.0f / fmaxf(sqrtf(s), 1e-12f);
            ks[j * 65 + lane] = a * inv;
            ks[j * 65 + 32 + lane] = b * inv;
        }
    }
    __syncthreads();

    int ty = tid >> 3, tx = tid & 7;
    float acc0[16], acc1[16];
#pragma unroll
    for (int u = 0; u < 16; u++) { acc0[u] = 0.f; acc1[u] = 0.f; }
    for (int d = 0; d < DHd; d++) {
        float q0 = qs[ty * 65 + d];
        float q1 = qs[(ty + 32) * 65 + d];
#pragma unroll
        for (int u = 0; u < 16; u++) {
            float kv = ks[(tx + 8 * u) * 65 + d];
            acc0[u] += q0 * kv;
            acc1[u] += q1 * kv;
        }
    }
    __syncthreads();
    float* dots = ks;
    int tq0 = tq[ty], tq1 = tq[ty + 32];
#pragma unroll
    for (int u = 0; u < 16; u++) {
        int j = tx + 8 * u;
        int tk = tkv[j];
        dots[ty * 129 + j]        = (tq0 == tk) ? -5e4f : acc0[u] * 0.125f;
        dots[(ty + 32) * 129 + j] = (tq1 == tk) ? -5e4f : acc1[u] * 0.125f;
    }
    __syncthreads();

    {
        int w = tid >> 5, lane = tid & 31;
        for (int rr = 0; rr < 8; rr++) {
            int i = w * 8 + rr;
            float x0 = dots[i * 129 + lane];
            float x1 = dots[i * 129 + 32 + lane];
            float x2 = dots[i * 129 + 64 + lane];
            float x3 = dots[i * 129 + 96 + lane];
            float m = fmaxf(fmaxf(x0, x1), fmaxf(x2, x3));
#pragma unroll
            for (int o = 16; o > 0; o >>= 1) m = fmaxf(m, __shfl_xor_sync(0xffffffffu, m, o));
            float e0 = expf(x0 - m), e1 = expf(x1 - m), e2 = expf(x2 - m), e3 = expf(x3 - m);
            float s = e0 + e1 + e2 + e3;
#pragma unroll
            for (int o = 16; o > 0; o >>= 1) s += __shfl_xor_sync(0xffffffffu, s, o);
            dots[i * 129 + lane]      = e0;
            dots[i * 129 + 32 + lane] = e1;
            dots[i * 129 + 64 + lane] = e2;
            dots[i * 129 + 96 + lane] = e3;
            if (lane == 0) { rsum[i] = s; rlse[i] = m + logf(s); }
        }
    }
    __syncthreads();

    float o0[8], o1[8];
#pragma unroll
    for (int k = 0; k < 8; k++) { o0[k] = 0.f; o1[k] = 0.f; }
    for (int j = 0; j < 128; j++) {
        float p0 = dots[ty * 129 + j];
        float p1 = dots[(ty + 32) * 129 + j];
        const float* vr = vs + j * 65 + tx * 8;
#pragma unroll
        for (int k = 0; k < 8; k++) {
            float vv = vr[k];
            o0[k] += p0 * vv;
            o1[k] += p1 * vv;
        }
    }
    float inv0 = 1.0f / rsum[ty];
    float inv1 = 1.0f / rsum[ty + 32];
    size_t ob0 = (((size_t)(bh * NHASH + h)) * Nn + tq0) * DHd + tx * 8;
    size_t ob1 = (((size_t)(bh * NHASH + h)) * Nn + tq1) * DHd + tx * 8;
#pragma unroll
    for (int k = 0; k < 8; k++) {
        g_oph[ob0 + k] = o0[k] * inv0;
        g_oph[ob1 + k] = o1[k] * inv1;
    }
    if (tx == 0) {
        g_lse[(bh * NHASH + h) * Nn + tq0] = rlse[ty];
        g_lse[(bh * NHASH + h) * Nn + tq1] = rlse[ty + 32];
    }
}

// ---------------- fused combine + limb split ----------------
// Weighted-sum the 4 hash rounds, then write bf16x3 limb planes of the combined
// activation directly (feeds the Wout GEMM) -- no fp32 round-trip buffer.
__global__ void combine_split_kernel(__nv_bfloat16* __restrict__ hi,
                                     __nv_bfloat16* __restrict__ mid,
                                     __nv_bfloat16* __restrict__ lo) {
    int u = blockIdx.x * 256 + threadIdx.x;     // 1M threads, 8 d's each
    int slot = u >> 3;
    int dseg = (u & 7) * 8;
    int bh = slot >> 12;
    int t = slot & 4095;
    int base = bh * NHASH * Nn + t;
    float l0 = g_lse[base + 0 * Nn];
    float l1 = g_lse[base + 1 * Nn];
    float l2 = g_lse[base + 2 * Nn];
    float l3 = g_lse[base + 3 * Nn];
    float m = fmaxf(fmaxf(l0, l1), fmaxf(l2, l3));
    float w[4] = {expf(l0 - m), expf(l1 - m), expf(l2 - m), expf(l3 - m)};
    float sinv = 1.0f / (w[0] + w[1] + w[2] + w[3]);

    float acc[8];
#pragma unroll
    for (int j = 0; j < 8; j++) acc[j] = 0.f;
#pragma unroll
    for (int k = 0; k < 4; k++) {
        const float4* p = (const float4*)(g_oph + (((size_t)(bh * NHASH + k)) * Nn + t) * DHd + dseg);
        float4 x0 = p[0], x1 = p[1];
        acc[0] += w[k] * x0.x; acc[1] += w[k] * x0.y; acc[2] += w[k] * x0.z; acc[3] += w[k] * x0.w;
        acc[4] += w[k] * x1.x; acc[5] += w[k] * x1.y; acc[6] += w[k] * x1.z; acc[7] += w[k] * x1.w;
    }
    float hf[8], mf[8], lf[8];
#pragma unroll
    for (int j = 0; j < 8; j++) {
        float a = acc[j] * sinv;
        float h = __bfloat162float(__float2bfloat16(a));
        float r = a - h;
        float mm = __bfloat162float(__float2bfloat16(r));
        hf[j] = h; mf[j] = mm; lf[j] = r - mm;
    }
    int b = bh >> 4, head = bh & 15;
    size_t oidx = ((size_t)b * Nn + t) * Cc + head * DHd + dseg;
    *(uint4*)(hi + oidx) = make_uint4(pack_bf2(hf[0], hf[1]), pack_bf2(hf[2], hf[3]),
                                      pack_bf2(hf[4], hf[5]), pack_bf2(hf[6], hf[7]));
    *(uint4*)(mid + oidx) = make_uint4(pack_bf2(mf[0], mf[1]), pack_bf2(mf[2], mf[3]),
                                       pack_bf2(mf[4], mf[5]), pack_bf2(mf[6], mf[7]));
    *(uint4*)(lo + oidx) = make_uint4(pack_bf2(lf[0], lf[1]), pack_bf2(lf[2], lf[3]),
                                      pack_bf2(lf[4], lf[5]), pack_bf2(lf[6], lf[7]));
}

// ---------------- launch ----------------
extern "C" void kernel_launch(void* const* d_in, const int* in_sizes, int n_in,
                              void* d_out, int out_size) {
    const float* queries = (const float*)d_in[0];
    const float* Wqk  = (const float*)d_in[4];
    const float* Wv   = (const float*)d_in[5];
    const float* Wout = (const float*)d_in[6];
    const float* bout = (const float*)d_in[7];
    const float* rot  = (const float*)d_in[8];
    float* out = (float*)d_out;

    cudaFuncSetAttribute(attn_kernel, cudaFuncAttributeMaxDynamicSharedMemorySize, ATTN_SMEM_BYTES);
    cudaFuncSetAttribute(mma_gemm, cudaFuncAttributeMaxDynamicSharedMemorySize, GEMM_SMEM);

    void *p_qk, *p_v, *p_asp, *p_wqkv, *p_wout;
    cudaGetSymbolAddress(&p_qk, g_qk);
    cudaGetSymbolAddress(&p_v, g_v);
    cudaGetSymbolAddress(&p_asp, g_asp);
    cudaGetSymbolAddress(&p_wqkv, g_wqkv_sp);
    cudaGetSymbolAddress(&p_wout, g_wout_sp);
    __nv_bfloat16* asp  = (__nv_bfloat16*)p_asp;
    __nv_bfloat16* wqkv = (__nv_bfloat16*)p_wqkv;
    __nv_bfloat16* wout = (__nv_bfloat16*)p_wout;
    const size_t WQKV_PL = (size_t)2048 * 1024;
    const size_t WOUT_PL = (size_t)1024 * 1024;
    const int NW = 1024 * 1024;
    const int NA = Mrows * Kdim;

    // limb splits (vectorized)
    split3_kernel<<<NA / 2048, 256>>>(queries, asp, asp + APL, asp + 2 * APL, NA);
    split3_kernel<<<NW / 2048, 256>>>(Wqk, wqkv, wqkv + WQKV_PL, wqkv + 2 * WQKV_PL, NW);
    split3_kernel<<<NW / 2048, 256>>>(Wv, wqkv + NW, wqkv + WQKV_PL + NW, wqkv + 2 * WQKV_PL + NW, NW);
    split3_kernel<<<NW / 2048, 256>>>(Wout, wout, wout + WOUT_PL, wout + 2 * WOUT_PL, NW);

    // qk GEMM: 6-pass fp32-equivalent (feeds LSH argmax)
    mma_gemm<<<dim3(8, 64), 256, GEMM_SMEM>>>(asp, APL, wqkv, WQKV_PL,
                                              nullptr, nullptr, (float*)p_qk, 6, PA6, PW6);
    // v GEMM: 3-pass (continuous path)
    mma_gemm<<<dim3(8, 64), 256, GEMM_SMEM>>>(asp, APL, wqkv + NW, WQKV_PL,
                                              nullptr, nullptr, (float*)p_v, 3, PA3, PW3);

    bucket_kernel<<<dim3(Nn / 64, BH), 128>>>(rot);
    sort_kernel<<<dim3(BH, NHASH), 256>>>();
    attn_kernel<<<dim3(NCHUNK, BH), 256, ATTN_SMEM_BYTES>>>();

    // fused combine + split -> limb planes for Wout GEMM
    combine_split_kernel<<<(BH * Nn * DHd / 8) / 256, 256>>>(asp, asp + APL, asp + 2 * APL);

    // Wout GEMM: 3-pass, +bias -> d_out
    mma_gemm<<<dim3(8, 64), 256, GEMM_SMEM>>>(asp, APL, wout, WOUT_PL,
                                              bout, out, nullptr, 3, PA3, PW3);
}

// round 7
// speedup vs baseline: 2.4325x; 1.7976x over previous
#include <cuda_runtime.h>
#include <cuda_bf16.h>
#include <math.h>
#include <stdint.h>

// ---------------- problem constants ----------------
#define Bb      2
#define Nn      4096
#define Cc      1024
#define Hh      16
#define DHd     64
#define BH      32          // Bb*Hh
#define NHASH   4
#define NBUCK   64          // Nn / BUCKET
#define NCHUNK  256         // NHASH*NBUCK
#define BS      64          // bucket size
#define Kdim    1024
#define Mrows   8192        // Bb*Nn

// ---------------- device scratch ----------------
__device__ float g_qk  [BH * Nn * DHd];            // (bh, t, d)
__device__ float g_v   [BH * Nn * DHd];
__device__ int   g_bucket[BH * NHASH * Nn];
__device__ int   g_st  [BH * NHASH * Nn];
__device__ float g_oph [BH * NHASH * Nn * DHd];    // per-hash outputs (scattered)
__device__ float g_lse [BH * NHASH * Nn];

// bf16x3 limbs
#define APL ((size_t)Mrows * Kdim)
__device__ __nv_bfloat16 g_asp[3 * APL];
__device__ __nv_bfloat16 g_wqkv_sp[(size_t)3 * 2048 * 1024];
__device__ __nv_bfloat16 g_wout_sp[(size_t)3 * 1024 * 1024];

// ================= helpers (sm_103-safe) =================
__device__ __forceinline__ uint32_t smem_to_u32(const void* p) {
    uint32_t a;
    asm("{ .reg .u64 t; cvta.to.shared.u64 t, %1; cvt.u32.u64 %0, t; }" : "=r"(a) : "l"(p));
    return a;
}
#define CP_ASYNC16(saddr, gptr) \
    asm volatile("cp.async.cg.shared.global [%0], [%1], 16;" \
        :: "r"(saddr), "l"(__cvta_generic_to_global(gptr)))
#define CP_COMMIT() asm volatile("cp.async.commit_group;" ::: "memory")
#define CP_WAIT(n)  asm volatile("cp.async.wait_group %0;" :: "n"(n) : "memory")

__device__ __forceinline__ void ldmx4(uint32_t* r, uint32_t addr) {
    asm volatile("ldmatrix.sync.aligned.m8n8.x4.shared.b16 {%0,%1,%2,%3}, [%4];"
        : "=r"(r[0]), "=r"(r[1]), "=r"(r[2]), "=r"(r[3]) : "r"(addr));
}
__device__ __forceinline__ void ldmx4t(uint32_t* r, uint32_t addr) {
    asm volatile("ldmatrix.sync.aligned.m8n8.x4.trans.shared.b16 {%0,%1,%2,%3}, [%4];"
        : "=r"(r[0]), "=r"(r[1]), "=r"(r[2]), "=r"(r[3]) : "r"(addr));
}
__device__ __forceinline__ void mma16816(float* d, const uint32_t* a, uint32_t b0, uint32_t b1) {
    asm volatile("mma.sync.aligned.m16n8k16.row.col.f32.bf16.bf16.f32 "
        "{%0,%1,%2,%3}, {%4,%5,%6,%7}, {%8,%9}, {%0,%1,%2,%3};"
        : "+f"(d[0]), "+f"(d[1]), "+f"(d[2]), "+f"(d[3])
        : "r"(a[0]), "r"(a[1]), "r"(a[2]), "r"(a[3]), "r"(b0), "r"(b1));
}
__device__ __forceinline__ uint32_t pack_bf2(float a, float b) {
    uint16_t ua = __bfloat16_as_ushort(__float2bfloat16(a));
    uint16_t ub = __bfloat16_as_ushort(__float2bfloat16(b));
    return (uint32_t)ua | ((uint32_t)ub << 16);
}
// split (a,b) into hi/mid bf16 pairs packed as u32
__device__ __forceinline__ void split2u(float a, float b, uint32_t& hp, uint32_t& mp) {
    float ha = __bfloat162float(__float2bfloat16(a));
    float hb = __bfloat162float(__float2bfloat16(b));
    hp = pack_bf2(ha, hb);
    mp = pack_bf2(a - ha, b - hb);
}

// ================= bf16x3 limb split (vectorized) =================
__global__ void split3_kernel(const float* __restrict__ x,
                              __nv_bfloat16* __restrict__ hi,
                              __nv_bfloat16* __restrict__ mid,
                              __nv_bfloat16* __restrict__ lo, int n) {
    int i = (blockIdx.x * 256 + threadIdx.x) * 8;
    if (i >= n) return;
    float4 v0 = *(const float4*)(x + i);
    float4 v1 = *(const float4*)(x + i + 4);
    float a[8] = {v0.x, v0.y, v0.z, v0.w, v1.x, v1.y, v1.z, v1.w};
    float hf[8], mf[8], lf[8];
#pragma unroll
    for (int j = 0; j < 8; j++) {
        float h = __bfloat162float(__float2bfloat16(a[j]));
        float r = a[j] - h;
        float m = __bfloat162float(__float2bfloat16(r));
        hf[j] = h; mf[j] = m; lf[j] = r - m;
    }
    *(uint4*)(hi + i) = make_uint4(pack_bf2(hf[0], hf[1]), pack_bf2(hf[2], hf[3]),
                                   pack_bf2(hf[4], hf[5]), pack_bf2(hf[6], hf[7]));
    *(uint4*)(mid + i) = make_uint4(pack_bf2(mf[0], mf[1]), pack_bf2(mf[2], mf[3]),
                                    pack_bf2(mf[4], mf[5]), pack_bf2(mf[6], mf[7]));
    *(uint4*)(lo + i) = make_uint4(pack_bf2(lf[0], lf[1]), pack_bf2(lf[2], lf[3]),
                                   pack_bf2(lf[4], lf[5]), pack_bf2(lf[6], lf[7]));
}

// ================= HMMA GEMM (bf16 limbs, variable pass count, small->large) =================
#define ROWB     80
#define MATB     (128 * ROWB)
#define STAGEB   (2 * MATB)
#define GEMM_SMEM (3 * STAGEB)
#define PA6 0x010201u
#define PW6 0x001021u
#define PA3 0x010u
#define PW3 0x001u

__global__ __launch_bounds__(256, 2) void mma_gemm(
        const __nv_bfloat16* __restrict__ Asp, size_t Apl,
        const __nv_bfloat16* __restrict__ Bsp, size_t Bpl,
        const float* __restrict__ bias, float* __restrict__ outp,
        float* __restrict__ headout, int npass, uint32_t paTbl, uint32_t pwTbl) {
    extern __shared__ char smem[];
    uint32_t sbase = smem_to_u32(smem);
    int tid = threadIdx.x;
    int lane = tid & 31, warp = tid >> 5;
    int wm = warp >> 2, wn = warp & 3;
    int bn = blockIdx.x * 128, bm = blockIdx.y * 128;
    int nstage = npass * 32;

    int v0 = tid, v1 = tid + 256;
    int r0 = v0 >> 2, c0 = v0 & 3;
    int r1 = v1 >> 2, c1 = v1 & 3;
    uint32_t so0 = (uint32_t)(r0 * ROWB + c0 * 16);
    uint32_t so1 = (uint32_t)(r1 * ROWB + c1 * 16);

    uint32_t aoff = (uint32_t)((wm * 64 + (lane & 15)) * ROWB + (lane >> 4) * 16);
    uint32_t boff = (uint32_t)((wn * 32 + ((lane >> 4) & 1) * 8 + (lane & 7)) * ROWB
                               + ((lane >> 3) & 1) * 16);

    float D[4][4][4];
#pragma unroll
    for (int i = 0; i < 4; i++)
#pragma unroll
        for (int j = 0; j < 4; j++)
#pragma unroll
            for (int q = 0; q < 4; q++) D[i][j][q] = 0.f;

#pragma unroll
    for (int s = 0; s < 2; s++) {
        int k0 = s * 32;
        const __nv_bfloat16* Ap = Asp + (size_t)(paTbl & 7) * Apl;
        const __nv_bfloat16* Bp = Bsp + (size_t)(pwTbl & 7) * Bpl;
        uint32_t st = sbase + s * STAGEB;
        CP_ASYNC16(st + so0, Ap + (size_t)(bm + r0) * Kdim + k0 + c0 * 8);
        CP_ASYNC16(st + so1, Ap + (size_t)(bm + r1) * Kdim + k0 + c1 * 8);
        CP_ASYNC16(st + MATB + so0, Bp + (size_t)(bn + r0) * Kdim + k0 + c0 * 8);
        CP_ASYNC16(st + MATB + so1, Bp + (size_t)(bn + r1) * Kdim + k0 + c1 * 8);
        CP_COMMIT();
    }

    for (int s = 0; s < nstage; s++) {
        if (s == nstage - 1) { CP_WAIT(0); } else { CP_WAIT(1); }
        __syncthreads();
        if (s + 2 < nstage) {
            int sn = s + 2;
            int p = sn >> 5, k0 = (sn & 31) << 5;
            const __nv_bfloat16* Ap = Asp + (size_t)((paTbl >> (p * 4)) & 7) * Apl;
            const __nv_bfloat16* Bp = Bsp + (size_t)((pwTbl >> (p * 4)) & 7) * Bpl;
            uint32_t st = sbase + (uint32_t)(sn % 3) * STAGEB;
            CP_ASYNC16(st + so0, Ap + (size_t)(bm + r0) * Kdim + k0 + c0 * 8);
            CP_ASYNC16(st + so1, Ap + (size_t)(bm + r1) * Kdim + k0 + c1 * 8);
            CP_ASYNC16(st + MATB + so0, Bp + (size_t)(bn + r0) * Kdim + k0 + c0 * 8);
            CP_ASYNC16(st + MATB + so1, Bp + (size_t)(bn + r1) * Kdim + k0 + c1 * 8);
            CP_COMMIT();
        }
        uint32_t st = sbase + (uint32_t)(s % 3) * STAGEB;
        uint32_t ab = st + aoff;
        uint32_t bb = st + MATB + boff;
#pragma unroll
        for (int ks = 0; ks < 2; ks++) {
            uint32_t A4[4][4], B4[2][4];
#pragma unroll
            for (int i = 0; i < 4; i++) ldmx4(A4[i], ab + i * (16 * ROWB) + ks * 32);
#pragma unroll
            for (int jp = 0; jp < 2; jp++) ldmx4(B4[jp], bb + jp * (16 * ROWB) + ks * 32);
#pragma unroll
            for (int i = 0; i < 4; i++)
#pragma unroll
                for (int jn = 0; jn < 4; jn++)
                    mma16816(D[i][jn], A4[i], B4[jn >> 1][(jn & 1) * 2], B4[jn >> 1][(jn & 1) * 2 + 1]);
        }
    }

    int g = lane >> 2, t = lane & 3;
#pragma unroll
    for (int i = 0; i < 4; i++) {
#pragma unroll
        for (int jn = 0; jn < 4; jn++) {
            int m0 = bm + wm * 64 + i * 16 + g;
            int n0 = bn + wn * 32 + jn * 8 + t * 2;
            float2 va = make_float2(D[i][jn][0], D[i][jn][1]);
            float2 vb = make_float2(D[i][jn][2], D[i][jn][3]);
            if (headout) {
                int bI = m0 >> 12;
                int t0 = m0 & 4095, t1 = (m0 + 8) & 4095;
                int hd = n0 >> 6, dh = n0 & 63;
                *(float2*)(headout + (((size_t)(bI * Hh + hd)) * Nn + t0) * DHd + dh) = va;
                *(float2*)(headout + (((size_t)(bI * Hh + hd)) * Nn + t1) * DHd + dh) = vb;
            } else {
                float2 bv = *(const float2*)(bias + n0);
                va.x += bv.x; va.y += bv.y; vb.x += bv.x; vb.y += bv.y;
                *(float2*)(outp + (size_t)m0 * Cc + n0) = va;
                *(float2*)(outp + (size_t)(m0 + 8) * Cc + n0) = vb;
            }
        }
    }
}

// ---------------- LSH bucketing (2 tokens/thread) ----------------
__global__ void bucket_kernel(const float* __restrict__ rot) {
    __shared__ float rs[DHd * 128];
    __shared__ float qs[64 * 65];
    int bh = blockIdx.y;
    int tb = blockIdx.x * 64;
    int tid = threadIdx.x;

    for (int i = tid; i < DHd * 128; i += 128) rs[i] = rot[i];
    {
        int row = tid >> 1, seg = tid & 1;
        const float* src = g_qk + ((size_t)bh * Nn + tb + row) * DHd + seg * 32;
#pragma unroll
        for (int k = 0; k < 32; k++) qs[row * 65 + seg * 32 + k] = src[k];
    }
    __syncthreads();

    int h = tid >> 5;
    int lane = tid & 31;

    float r0[32], r1[32];
#pragma unroll
    for (int i = 0; i < 32; i++) { r0[i] = 0.f; r1[i] = 0.f; }
    for (int d = 0; d < DHd; d++) {
        float q0 = qs[lane * 65 + d];
        float q1 = qs[(lane + 32) * 65 + d];
        const float* rp = rs + d * 128 + h * 32;
#pragma unroll
        for (int i = 0; i < 32; i++) {
            float rv = rp[i];
            r0[i] += q0 * rv;
            r1[i] += q1 * rv;
        }
    }
    float best0 = r0[0]; int bi0 = 0;
    float best1 = r1[0]; int bi1 = 0;
#pragma unroll
    for (int i = 1; i < 32; i++) {
        if (r0[i] > best0) { best0 = r0[i]; bi0 = i; }
        if (r1[i] > best1) { best1 = r1[i]; bi1 = i; }
    }
#pragma unroll
    for (int i = 0; i < 32; i++) {
        if (-r0[i] > best0) { best0 = -r0[i]; bi0 = 32 + i; }
        if (-r1[i] > best1) { best1 = -r1[i]; bi1 = 32 + i; }
    }
    g_bucket[((size_t)bh * NHASH + h) * Nn + tb + lane] = bi0;
    g_bucket[((size_t)bh * NHASH + h) * Nn + tb + lane + 32] = bi1;
}

// ---------------- stable counting sort per (bh, hash) ----------------
__global__ void sort_kernel() {
    __shared__ unsigned char sb[Nn];
    __shared__ int hist[NBUCK];
    __shared__ int offs[NBUCK];
    int bh = blockIdx.x, h = blockIdx.y;
    int tid = threadIdx.x;
    if (tid < NBUCK) hist[tid] = 0;
    __syncthreads();
    const int base = (bh * NHASH + h) * Nn;
    for (int t = tid; t < Nn; t += 256) {
        int b = g_bucket[base + t];
        sb[t] = (unsigned char)b;
        atomicAdd(&hist[b], 1);
    }
    __syncthreads();
    if (tid == 0) {
        int acc = 0;
        for (int b = 0; b < NBUCK; b++) { offs[b] = acc; acc += hist[b]; }
    }
    __syncthreads();
    if (tid < NBUCK) {
        unsigned char b = (unsigned char)tid;
        int w = offs[tid];
        for (int t = 0; t < Nn; t++)
            if (sb[t] == b) g_st[base + (w++)] = t;
    }
}

// ---------------- chunked LSH attention: HMMA 2-limb ----------------
// smem layout (bytes):
//   0     tkv[128] int
//   512   rmaxp[64][4] f32
//   1536  rsump[64][4] f32
//   2560  rsuminv[64] f32
//   3072  k_hi  128x72 bf16 (18432)
//   21504 k_mid (18432)
//   39936 v_hi  128x72 bf16 (18432)
//   58368 v_mid (18432)
//   76800 region: q_hi 64x72 (9216) @76800, q_mid @86016  [dead after dots]
//                 p_hi 64x136 (17408) @76800, p_mid @94208
//   total 111616
#define AT_KHI   3072
#define AT_KMID  21504
#define AT_VHI   39936
#define AT_VMID  58368
#define AT_QHI   76800
#define AT_QMID  86016
#define AT_PHI   76800
#define AT_PMID  94208
#define ATTN_SMEM_BYTES 111616

__global__ __launch_bounds__(256, 2) void attn_kernel() {
    extern __shared__ char sm[];
    int*   tkv     = (int*)sm;
    float* rmaxp   = (float*)(sm + 512);
    float* rsump   = (float*)(sm + 1536);
    float* rsuminv = (float*)(sm + 2560);
    uint32_t sb = smem_to_u32(sm);

    int c = blockIdx.x, bh = blockIdx.y;
    int h = c >> 6;
    int tid = threadIdx.x, lane = tid & 31, warp = tid >> 5;
    int g = lane >> 2, t = lane & 3;
    int wm = warp >> 2, wn = warp & 3;
    int pc = (c + NCHUNK - 1) & (NCHUNK - 1);
    const int stb = bh * (NHASH * Nn);

    if (tid < 64)       tkv[tid] = g_st[stb + c * BS + tid];
    else if (tid < 128) tkv[tid] = g_st[stb + pc * BS + (tid - 64)];
    __syncthreads();

    // ---- gather q -> limbs (pre-scaled by 0.125, exact) ----
    {
        int i = tid >> 2, seg = tid & 3;
        const float* src = g_qk + ((size_t)bh * Nn + tkv[i]) * DHd + seg * 16;
        char* dh_ = sm + AT_QHI + i * 144 + seg * 32;
        char* dm_ = sm + AT_QMID + i * 144 + seg * 32;
#pragma unroll
        for (int k4 = 0; k4 < 4; k4++) {
            float4 v = *(const float4*)(src + k4 * 4);
            uint32_t h0, m0, h1, m1;
            split2u(v.x * 0.125f, v.y * 0.125f, h0, m0);
            split2u(v.z * 0.125f, v.w * 0.125f, h1, m1);
            *(uint32_t*)(dh_ + k4 * 8)     = h0;
            *(uint32_t*)(dh_ + k4 * 8 + 4) = h1;
            *(uint32_t*)(dm_ + k4 * 8)     = m0;
            *(uint32_t*)(dm_ + k4 * 8 + 4) = m1;
        }
    }
    // ---- gather v -> limbs ----
    {
        int j = tid >> 1, seg = tid & 1;
        const float* src = g_v + ((size_t)bh * Nn + tkv[j]) * DHd + seg * 32;
        char* dh_ = sm + AT_VHI + j * 144 + seg * 64;
        char* dm_ = sm + AT_VMID + j * 144 + seg * 64;
#pragma unroll
        for (int k4 = 0; k4 < 8; k4++) {
            float4 v = *(const float4*)(src + k4 * 4);
            uint32_t h0, m0, h1, m1;
            split2u(v.x, v.y, h0, m0);
            split2u(v.z, v.w, h1, m1);
            *(uint32_t*)(dh_ + k4 * 8)     = h0;
            *(uint32_t*)(dh_ + k4 * 8 + 4) = h1;
            *(uint32_t*)(dm_ + k4 * 8)     = m0;
            *(uint32_t*)(dm_ + k4 * 8 + 4) = m1;
        }
    }
    // ---- gather k: rows normalized (same formula as fp32 baseline), -> limbs ----
    for (int rr = 0; rr < 16; rr++) {
        int j = warp * 16 + rr;
        const float* src = g_qk + ((size_t)bh * Nn + tkv[j]) * DHd;
        float a = src[lane], b = src[lane + 32];
        float s = a * a + b * b;
#pragma unroll
        for (int o = 16; o > 0; o >>= 1) s += __shfl_xor_sync(0xffffffffu, s, o);
        float inv = 1.0f / fmaxf(sqrtf(s), 1e-12f);
        float ka = a * inv, kb = b * inv;
        float kah = __bfloat162float(__float2bfloat16(ka));
        float kbh = __bfloat162float(__float2bfloat16(kb));
        *(__nv_bfloat16*)(sm + AT_KHI + j * 144 + lane * 2)       = __float2bfloat16(kah);
        *(__nv_bfloat16*)(sm + AT_KHI + j * 144 + 64 + lane * 2)  = __float2bfloat16(kbh);
        *(__nv_bfloat16*)(sm + AT_KMID + j * 144 + lane * 2)      = __float2bfloat16(ka - kah);
        *(__nv_bfloat16*)(sm + AT_KMID + j * 144 + 64 + lane * 2) = __float2bfloat16(kb - kbh);
    }
    __syncthreads();

    // ---- dots MMA: D[i][j] = q'[i][:] . k[j][:], 3 products small->large ----
    float Dd[2][4][4];
#pragma unroll
    for (int i = 0; i < 2; i++)
#pragma unroll
        for (int jn = 0; jn < 4; jn++)
#pragma unroll
            for (int q = 0; q < 4; q++) Dd[i][jn][q] = 0.f;

    uint32_t arow = (uint32_t)((wm * 32 + (lane & 15)) * 144 + (lane >> 4) * 16);
    uint32_t brow = (uint32_t)((wn * 32 + ((lane >> 4) & 1) * 8 + (lane & 7)) * 144
                               + ((lane >> 3) & 1) * 16);
    const uint32_t QL[3] = {sb + AT_QMID, sb + AT_QHI, sb + AT_QHI};
    const uint32_t KL[3] = {sb + AT_KHI, sb + AT_KMID, sb + AT_KHI};
#pragma unroll
    for (int p = 0; p < 3; p++) {
#pragma unroll
        for (int ks = 0; ks < 4; ks++) {
            uint32_t A4[2][4], B4[2][4];
#pragma unroll
            for (int i = 0; i < 2; i++) ldmx4(A4[i], QL[p] + arow + i * (16 * 144) + ks * 32);
#pragma unroll
            for (int jp = 0; jp < 2; jp++) ldmx4(B4[jp], KL[p] + brow + jp * (16 * 144) + ks * 32);
#pragma unroll
            for (int i = 0; i < 2; i++)
#pragma unroll
                for (int jn = 0; jn < 4; jn++)
                    mma16816(Dd[i][jn], A4[i], B4[jn >> 1][(jn & 1) * 2], B4[jn >> 1][(jn & 1) * 2 + 1]);
        }
    }

    // ---- mask + row max (fragments) ----
    int trow[4] = { tkv[wm * 32 + g], tkv[wm * 32 + g + 8],
                    tkv[wm * 32 + 16 + g], tkv[wm * 32 + 16 + g + 8] };
    int tcol[8];
#pragma unroll
    for (int jn = 0; jn < 4; jn++) {
        int c0 = wn * 32 + jn * 8 + t * 2;
        tcol[jn * 2] = tkv[c0]; tcol[jn * 2 + 1] = tkv[c0 + 1];
    }
#pragma unroll
    for (int i = 0; i < 2; i++)
#pragma unroll
        for (int jn = 0; jn < 4; jn++)
#pragma unroll
            for (int q = 0; q < 4; q++)
                if (trow[i * 2 + (q >> 1)] == tcol[jn * 2 + (q & 1)]) Dd[i][jn][q] = -5e4f;

    float pm[4] = {-3.0e38f, -3.0e38f, -3.0e38f, -3.0e38f};
#pragma unroll
    for (int i = 0; i < 2; i++)
#pragma unroll
        for (int jn = 0; jn < 4; jn++)
#pragma unroll
            for (int q = 0; q < 4; q++) {
                int k = i * 2 + (q >> 1);
                pm[k] = fmaxf(pm[k], Dd[i][jn][q]);
            }
#pragma unroll
    for (int k = 0; k < 4; k++) {
        pm[k] = fmaxf(pm[k], __shfl_xor_sync(0xffffffffu, pm[k], 1));
        pm[k] = fmaxf(pm[k], __shfl_xor_sync(0xffffffffu, pm[k], 2));
    }
    if (t == 0) {
#pragma unroll
        for (int k = 0; k < 4; k++)
            rmaxp[(wm * 32 + (k >> 1) * 16 + g + (k & 1) * 8) * 4 + wn] = pm[k];
    }
    __syncthreads();

    // ---- exp -> P limbs + partial sums ----
    float rowm[4];
#pragma unroll
    for (int k = 0; k < 4; k++) {
        const float* p = rmaxp + (wm * 32 + (k >> 1) * 16 + g + (k & 1) * 8) * 4;
        rowm[k] = fmaxf(fmaxf(p[0], p[1]), fmaxf(p[2], p[3]));
    }
    float ps[4] = {0.f, 0.f, 0.f, 0.f};
#pragma unroll
    for (int i = 0; i < 2; i++) {
        int r0 = wm * 32 + i * 16 + g;
#pragma unroll
        for (int jn = 0; jn < 4; jn++) {
            float e0 = __expf(Dd[i][jn][0] - rowm[i * 2]);
            float e1 = __expf(Dd[i][jn][1] - rowm[i * 2]);
            float e2 = __expf(Dd[i][jn][2] - rowm[i * 2 + 1]);
            float e3 = __expf(Dd[i][jn][3] - rowm[i * 2 + 1]);
            ps[i * 2] += e0 + e1;
            ps[i * 2 + 1] += e2 + e3;
            int c0 = wn * 32 + jn * 8 + t * 2;
            uint32_t h0, m0, h1, m1;
            split2u(e0, e1, h0, m0);
            split2u(e2, e3, h1, m1);
            *(uint32_t*)(sm + AT_PHI  + r0 * 272 + c0 * 2)       = h0;
            *(uint32_t*)(sm + AT_PMID + r0 * 272 + c0 * 2)       = m0;
            *(uint32_t*)(sm + AT_PHI  + (r0 + 8) * 272 + c0 * 2) = h1;
            *(uint32_t*)(sm + AT_PMID + (r0 + 8) * 272 + c0 * 2) = m1;
        }
    }
#pragma unroll
    for (int k = 0; k < 4; k++) {
        ps[k] += __shfl_xor_sync(0xffffffffu, ps[k], 1);
        ps[k] += __shfl_xor_sync(0xffffffffu, ps[k], 2);
    }
    if (t == 0) {
#pragma unroll
        for (int k = 0; k < 4; k++)
            rsump[(wm * 32 + (k >> 1) * 16 + g + (k & 1) * 8) * 4 + wn] = ps[k];
    }
    __syncthreads();

    if (tid < 64) {
        const float* p = rsump + tid * 4;
        float s = p[0] + p[1] + p[2] + p[3];
        const float* q = rmaxp + tid * 4;
        float m = fmaxf(fmaxf(q[0], q[1]), fmaxf(q[2], q[3]));
        rsuminv[tid] = 1.0f / s;
        g_lse[(bh * NHASH + h) * Nn + tkv[tid]] = m + logf(s);
    }
    __syncthreads();

    // ---- PV MMA: O[i][dh] = P[i][:] . V[:][dh] via ldmatrix.trans on V ----
    float Dp[2][2][4];
#pragma unroll
    for (int i = 0; i < 2; i++)
#pragma unroll
        for (int jn = 0; jn < 2; jn++)
#pragma unroll
            for (int q = 0; q < 4; q++) Dp[i][jn][q] = 0.f;

    uint32_t parow = (uint32_t)((wm * 32 + (lane & 15)) * 272 + (lane >> 4) * 16);
    uint32_t vbrow = (uint32_t)((lane & 15) * 144 + (lane >> 4) * 16 + wn * 32);
    const uint32_t PL[3] = {sb + AT_PMID, sb + AT_PHI, sb + AT_PHI};
    const uint32_t VL[3] = {sb + AT_VHI, sb + AT_VMID, sb + AT_VHI};
#pragma unroll
    for (int p = 0; p < 3; p++) {
#pragma unroll
        for (int ks = 0; ks < 8; ks++) {
            uint32_t A4[2][4], B4[4];
#pragma unroll
            for (int i = 0; i < 2; i++) ldmx4(A4[i], PL[p] + parow + i * (16 * 272) + ks * 32);
            ldmx4t(B4, VL[p] + vbrow + ks * (16 * 144));
#pragma unroll
            for (int i = 0; i < 2; i++)
#pragma unroll
                for (int jn = 0; jn < 2; jn++)
                    mma16816(Dp[i][jn], A4[i], B4[jn * 2], B4[jn * 2 + 1]);
        }
    }

    // ---- epilogue: normalize + scatter ----
#pragma unroll
    for (int i = 0; i < 2; i++) {
        int r0 = wm * 32 + i * 16 + g;
        float inv0 = rsuminv[r0], inv1 = rsuminv[r0 + 8];
        size_t b0 = ((size_t)(bh * NHASH + h) * Nn + trow[i * 2]) * DHd;
        size_t b1 = ((size_t)(bh * NHASH + h) * Nn + trow[i * 2 + 1]) * DHd;
#pragma unroll
        for (int jn = 0; jn < 2; jn++) {
            int dh = wn * 16 + jn * 8 + t * 2;
            *(float2*)(g_oph + b0 + dh) = make_float2(Dp[i][jn][0] * inv0, Dp[i][jn][1] * inv0);
            *(float2*)(g_oph + b1 + dh) = make_float2(Dp[i][jn][2] * inv1, Dp[i][jn][3] * inv1);
        }
    }
}

// ---------------- fused combine + limb split ----------------
__global__ void combine_split_kernel(__nv_bfloat16* __restrict__ hi,
                                     __nv_bfloat16* __restrict__ mid,
                                     __nv_bfloat16* __restrict__ lo) {
    int u = blockIdx.x * 256 + threadIdx.x;
    int slot = u >> 3;
    int dseg = (u & 7) * 8;
    int bh = slot >> 12;
    int t = slot & 4095;
    int base = bh * NHASH * Nn + t;
    float l0 = g_lse[base + 0 * Nn];
    float l1 = g_lse[base + 1 * Nn];
    float l2 = g_lse[base + 2 * Nn];
    float l3 = g_lse[base + 3 * Nn];
    float m = fmaxf(fmaxf(l0, l1), fmaxf(l2, l3));
    float w[4] = {expf(l0 - m), expf(l1 - m), expf(l2 - m), expf(l3 - m)};
    float sinv = 1.0f / (w[0] + w[1] + w[2] + w[3]);

    float acc[8];
#pragma unroll
    for (int j = 0; j < 8; j++) acc[j] = 0.f;
#pragma unroll
    for (int k = 0; k < 4; k++) {
        const float4* p = (const float4*)(g_oph + (((size_t)(bh * NHASH + k)) * Nn + t) * DHd + dseg);
        float4 x0 = p[0], x1 = p[1];
        acc[0] += w[k] * x0.x; acc[1] += w[k] * x0.y; acc[2] += w[k] * x0.z; acc[3] += w[k] * x0.w;
        acc[4] += w[k] * x1.x; acc[5] += w[k] * x1.y; acc[6] += w[k] * x1.z; acc[7] += w[k] * x1.w;
    }
    float hf[8], mf[8], lf[8];
#pragma unroll
    for (int j = 0; j < 8; j++) {
        float a = acc[j] * sinv;
        float h = __bfloat162float(__float2bfloat16(a));
        float r = a - h;
        float mm = __bfloat162float(__float2bfloat16(r));
        hf[j] = h; mf[j] = mm; lf[j] = r - mm;
    }
    int b = bh >> 4, head = bh & 15;
    size_t oidx = ((size_t)b * Nn + t) * Cc + head * DHd + dseg;
    *(uint4*)(hi + oidx) = make_uint4(pack_bf2(hf[0], hf[1]), pack_bf2(hf[2], hf[3]),
                                      pack_bf2(hf[4], hf[5]), pack_bf2(hf[6], hf[7]));
    *(uint4*)(mid + oidx) = make_uint4(pack_bf2(mf[0], mf[1]), pack_bf2(mf[2], mf[3]),
                                       pack_bf2(mf[4], mf[5]), pack_bf2(mf[6], mf[7]));
    *(uint4*)(lo + oidx) = make_uint4(pack_bf2(lf[0], lf[1]), pack_bf2(lf[2], lf[3]),
                                      pack_bf2(lf[4], lf[5]), pack_bf2(lf[6], lf[7]));
}

// ---------------- launch ----------------
extern "C" void kernel_launch(void* const* d_in, const int* in_sizes, int n_in,
                              void* d_out, int out_size) {
    const float* queries = (const float*)d_in[0];
    const float* Wqk  = (const float*)d_in[4];
    const float* Wv   = (const float*)d_in[5];
    const float* Wout = (const float*)d_in[6];
    const float* bout = (const float*)d_in[7];
    const float* rot  = (const float*)d_in[8];
    float* out = (float*)d_out;

    cudaFuncSetAttribute(attn_kernel, cudaFuncAttributeMaxDynamicSharedMemorySize, ATTN_SMEM_BYTES);
    cudaFuncSetAttribute(mma_gemm, cudaFuncAttributeMaxDynamicSharedMemorySize, GEMM_SMEM);

    void *p_qk, *p_v, *p_asp, *p_wqkv, *p_wout;
    cudaGetSymbolAddress(&p_qk, g_qk);
    cudaGetSymbolAddress(&p_v, g_v);
    cudaGetSymbolAddress(&p_asp, g_asp);
    cudaGetSymbolAddress(&p_wqkv, g_wqkv_sp);
    cudaGetSymbolAddress(&p_wout, g_wout_sp);
    __nv_bfloat16* asp  = (__nv_bfloat16*)p_asp;
    __nv_bfloat16* wqkv = (__nv_bfloat16*)p_wqkv;
    __nv_bfloat16* wout = (__nv_bfloat16*)p_wout;
    const size_t WQKV_PL = (size_t)2048 * 1024;
    const size_t WOUT_PL = (size_t)1024 * 1024;
    const int NW = 1024 * 1024;
    const int NA = Mrows * Kdim;

    split3_kernel<<<NA / 2048, 256>>>(queries, asp, asp + APL, asp + 2 * APL, NA);
    split3_kernel<<<NW / 2048, 256>>>(Wqk, wqkv, wqkv + WQKV_PL, wqkv + 2 * WQKV_PL, NW);
    split3_kernel<<<NW / 2048, 256>>>(Wv, wqkv + NW, wqkv + WQKV_PL + NW, wqkv + 2 * WQKV_PL + NW, NW);
    split3_kernel<<<NW / 2048, 256>>>(Wout, wout, wout + WOUT_PL, wout + 2 * WOUT_PL, NW);

    // qk GEMM: 6-pass fp32-equivalent (feeds LSH argmax)
    mma_gemm<<<dim3(8, 64), 256, GEMM_SMEM>>>(asp, APL, wqkv, WQKV_PL,
                                              nullptr, nullptr, (float*)p_qk, 6, PA6, PW6);
    // v GEMM: 3-pass (continuous path)
    mma_gemm<<<dim3(8, 64), 256, GEMM_SMEM>>>(asp, APL, wqkv + NW, WQKV_PL,
                                              nullptr, nullptr, (float*)p_v, 3, PA3, PW3);

    bucket_kernel<<<dim3(Nn / 64, BH), 128>>>(rot);
    sort_kernel<<<dim3(BH, NHASH), 256>>>();
    attn_kernel<<<dim3(NCHUNK, BH), 256, ATTN_SMEM_BYTES>>>();

    combine_split_kernel<<<(BH * Nn * DHd / 8) / 256, 256>>>(asp, asp + APL, asp + 2 * APL);

    mma_gemm<<<dim3(8, 64), 256, GEMM_SMEM>>>(asp, APL, wout, WOUT_PL,
                                              bout, out, nullptr, 3, PA3, PW3);
}

// round 8
// speedup vs baseline: 2.4536x; 1.0087x over previous
#include <cuda_runtime.h>
#include <cuda_bf16.h>
#include <math.h>
#include <stdint.h>

// ---------------- problem constants ----------------
#define Bb      2
#define Nn      4096
#define Cc      1024
#define Hh      16
#define DHd     64
#define BH      32          // Bb*Hh
#define NHASH   4
#define NBUCK   64          // Nn / BUCKET
#define NCHUNK  256         // NHASH*NBUCK
#define BS      64          // bucket size
#define Kdim    1024
#define Mrows   8192        // Bb*Nn

// ---------------- device scratch ----------------
__device__ float g_qk  [BH * Nn * DHd];            // (bh, t, d)
__device__ float g_v   [BH * Nn * DHd];
__device__ int   g_bucket[BH * NHASH * Nn];
__device__ int   g_st  [BH * NHASH * Nn];
__device__ float g_oph [BH * NHASH * Nn * DHd];    // per-hash outputs (scattered)
__device__ float g_lse [BH * NHASH * Nn];

// bf16x3 limbs
#define APL ((size_t)Mrows * Kdim)
__device__ __nv_bfloat16 g_asp[3 * APL];
__device__ __nv_bfloat16 g_wqkv_sp[(size_t)3 * 2048 * 1024];
__device__ __nv_bfloat16 g_wout_sp[(size_t)3 * 1024 * 1024];

// ================= helpers (sm_103-safe) =================
__device__ __forceinline__ uint32_t smem_to_u32(const void* p) {
    uint32_t a;
    asm("{ .reg .u64 t; cvta.to.shared.u64 t, %1; cvt.u32.u64 %0, t; }" : "=r"(a) : "l"(p));
    return a;
}
#define CP_ASYNC16(saddr, gptr) \
    asm volatile("cp.async.cg.shared.global [%0], [%1], 16;" \
        :: "r"(saddr), "l"(__cvta_generic_to_global(gptr)))
#define CP_COMMIT() asm volatile("cp.async.commit_group;" ::: "memory")
#define CP_WAIT(n)  asm volatile("cp.async.wait_group %0;" :: "n"(n) : "memory")

__device__ __forceinline__ void ldmx4(uint32_t* r, uint32_t addr) {
    asm volatile("ldmatrix.sync.aligned.m8n8.x4.shared.b16 {%0,%1,%2,%3}, [%4];"
        : "=r"(r[0]), "=r"(r[1]), "=r"(r[2]), "=r"(r[3]) : "r"(addr));
}
__device__ __forceinline__ void ldmx4t(uint32_t* r, uint32_t addr) {
    asm volatile("ldmatrix.sync.aligned.m8n8.x4.trans.shared.b16 {%0,%1,%2,%3}, [%4];"
        : "=r"(r[0]), "=r"(r[1]), "=r"(r[2]), "=r"(r[3]) : "r"(addr));
}
__device__ __forceinline__ void mma16816(float* d, const uint32_t* a, uint32_t b0, uint32_t b1) {
    asm volatile("mma.sync.aligned.m16n8k16.row.col.f32.bf16.bf16.f32 "
        "{%0,%1,%2,%3}, {%4,%5,%6,%7}, {%8,%9}, {%0,%1,%2,%3};"
        : "+f"(d[0]), "+f"(d[1]), "+f"(d[2]), "+f"(d[3])
        : "r"(a[0]), "r"(a[1]), "r"(a[2]), "r"(a[3]), "r"(b0), "r"(b1));
}
__device__ __forceinline__ uint32_t pack_bf2(float a, float b) {
    uint16_t ua = __bfloat16_as_ushort(__float2bfloat16(a));
    uint16_t ub = __bfloat16_as_ushort(__float2bfloat16(b));
    return (uint32_t)ua | ((uint32_t)ub << 16);
}
__device__ __forceinline__ void split2u(float a, float b, uint32_t& hp, uint32_t& mp) {
    float ha = __bfloat162float(__float2bfloat16(a));
    float hb = __bfloat162float(__float2bfloat16(b));
    hp = pack_bf2(ha, hb);
    mp = pack_bf2(a - ha, b - hb);
}

// ================= bf16x3 limb split (vectorized) =================
__global__ void split3_kernel(const float* __restrict__ x,
                              __nv_bfloat16* __restrict__ hi,
                              __nv_bfloat16* __restrict__ mid,
                              __nv_bfloat16* __restrict__ lo, int n) {
    int i = (blockIdx.x * 256 + threadIdx.x) * 8;
    if (i >= n) return;
    float4 v0 = *(const float4*)(x + i);
    float4 v1 = *(const float4*)(x + i + 4);
    float a[8] = {v0.x, v0.y, v0.z, v0.w, v1.x, v1.y, v1.z, v1.w};
    float hf[8], mf[8], lf[8];
#pragma unroll
    for (int j = 0; j < 8; j++) {
        float h = __bfloat162float(__float2bfloat16(a[j]));
        float r = a[j] - h;
        float m = __bfloat162float(__float2bfloat16(r));
        hf[j] = h; mf[j] = m; lf[j] = r - m;
    }
    *(uint4*)(hi + i) = make_uint4(pack_bf2(hf[0], hf[1]), pack_bf2(hf[2], hf[3]),
                                   pack_bf2(hf[4], hf[5]), pack_bf2(hf[6], hf[7]));
    *(uint4*)(mid + i) = make_uint4(pack_bf2(mf[0], mf[1]), pack_bf2(mf[2], mf[3]),
                                    pack_bf2(mf[4], mf[5]), pack_bf2(mf[6], mf[7]));
    *(uint4*)(lo + i) = make_uint4(pack_bf2(lf[0], lf[1]), pack_bf2(lf[2], lf[3]),
                                   pack_bf2(lf[4], lf[5]), pack_bf2(lf[6], lf[7]));
}

// ================= HMMA GEMM body (bf16 limbs, 4-stage cp.async pipeline) =================
#define ROWB     80
#define MATB     (128 * ROWB)
#define STAGEB   (2 * MATB)
#define GEMM_SMEM (4 * STAGEB)   // 81920
#define PA6 0x010201u
#define PW6 0x001021u
#define PA3 0x010u
#define PW3 0x001u

__device__ __forceinline__ void gemm_issue(uint32_t st,
        const __nv_bfloat16* Ap, const __nv_bfloat16* Bp, int bm, int bn, int k0,
        uint32_t so0, uint32_t so1, int r0, int c0, int r1, int c1) {
    CP_ASYNC16(st + so0, Ap + (size_t)(bm + r0) * Kdim + k0 + c0 * 8);
    CP_ASYNC16(st + so1, Ap + (size_t)(bm + r1) * Kdim + k0 + c1 * 8);
    CP_ASYNC16(st + MATB + so0, Bp + (size_t)(bn + r0) * Kdim + k0 + c0 * 8);
    CP_ASYNC16(st + MATB + so1, Bp + (size_t)(bn + r1) * Kdim + k0 + c1 * 8);
    CP_COMMIT();
}

__device__ __forceinline__ void gemm_body(char* smem,
        const __nv_bfloat16* __restrict__ Asp, size_t Apl,
        const __nv_bfloat16* __restrict__ Bsp, size_t Bpl,
        const float* __restrict__ bias, float* __restrict__ outp,
        float* __restrict__ headout, int npass, uint32_t paTbl, uint32_t pwTbl,
        int bn, int bm) {
    uint32_t sbase = smem_to_u32(smem);
    int tid = threadIdx.x;
    int lane = tid & 31, warp = tid >> 5;
    int wm = warp >> 2, wn = warp & 3;
    int nstage = npass * 32;

    int v0 = tid, v1 = tid + 256;
    int r0 = v0 >> 2, c0 = v0 & 3;
    int r1 = v1 >> 2, c1 = v1 & 3;
    uint32_t so0 = (uint32_t)(r0 * ROWB + c0 * 16);
    uint32_t so1 = (uint32_t)(r1 * ROWB + c1 * 16);

    uint32_t aoff = (uint32_t)((wm * 64 + (lane & 15)) * ROWB + (lane >> 4) * 16);
    uint32_t boff = (uint32_t)((wn * 32 + ((lane >> 4) & 1) * 8 + (lane & 7)) * ROWB
                               + ((lane >> 3) & 1) * 16);

    float D[4][4][4];
#pragma unroll
    for (int i = 0; i < 4; i++)
#pragma unroll
        for (int j = 0; j < 4; j++)
#pragma unroll
            for (int q = 0; q < 4; q++) D[i][j][q] = 0.f;

    // prologue: stages 0,1,2 (all pass 0)
#pragma unroll
    for (int s = 0; s < 3; s++) {
        const __nv_bfloat16* Ap = Asp + (size_t)(paTbl & 7) * Apl;
        const __nv_bfloat16* Bp = Bsp + (size_t)(pwTbl & 7) * Bpl;
        gemm_issue(sbase + s * STAGEB, Ap, Bp, bm, bn, s * 32, so0, so1, r0, c0, r1, c1);
    }

    for (int s = 0; s < nstage; s++) {
        if (s <= nstage - 3)      { CP_WAIT(2); }
        else if (s == nstage - 2) { CP_WAIT(1); }
        else                      { CP_WAIT(0); }
        __syncthreads();
        if (s + 3 < nstage) {
            int sn = s + 3;
            int p = sn >> 5, k0 = (sn & 31) << 5;
            const __nv_bfloat16* Ap = Asp + (size_t)((paTbl >> (p * 4)) & 7) * Apl;
            const __nv_bfloat16* Bp = Bsp + (size_t)((pwTbl >> (p * 4)) & 7) * Bpl;
            gemm_issue(sbase + (uint32_t)(sn & 3) * STAGEB, Ap, Bp, bm, bn, k0,
                       so0, so1, r0, c0, r1, c1);
        }
        uint32_t st = sbase + (uint32_t)(s & 3) * STAGEB;
        uint32_t ab = st + aoff;
        uint32_t bb = st + MATB + boff;
#pragma unroll
        for (int ks = 0; ks < 2; ks++) {
            uint32_t A4[4][4], B4[2][4];
#pragma unroll
            for (int i = 0; i < 4; i++) ldmx4(A4[i], ab + i * (16 * ROWB) + ks * 32);
#pragma unroll
            for (int jp = 0; jp < 2; jp++) ldmx4(B4[jp], bb + jp * (16 * ROWB) + ks * 32);
#pragma unroll
            for (int i = 0; i < 4; i++)
#pragma unroll
                for (int jn = 0; jn < 4; jn++)
                    mma16816(D[i][jn], A4[i], B4[jn >> 1][(jn & 1) * 2], B4[jn >> 1][(jn & 1) * 2 + 1]);
        }
    }

    int g = lane >> 2, t = lane & 3;
#pragma unroll
    for (int i = 0; i < 4; i++) {
#pragma unroll
        for (int jn = 0; jn < 4; jn++) {
            int m0 = bm + wm * 64 + i * 16 + g;
            int n0 = bn + wn * 32 + jn * 8 + t * 2;
            float2 va = make_float2(D[i][jn][0], D[i][jn][1]);
            float2 vb = make_float2(D[i][jn][2], D[i][jn][3]);
            if (headout) {
                int bI = m0 >> 12;
                int t0 = m0 & 4095, t1 = (m0 + 8) & 4095;
                int hd = n0 >> 6, dh = n0 & 63;
                *(float2*)(headout + (((size_t)(bI * Hh + hd)) * Nn + t0) * DHd + dh) = va;
                *(float2*)(headout + (((size_t)(bI * Hh + hd)) * Nn + t1) * DHd + dh) = vb;
            } else {
                float2 bv = *(const float2*)(bias + n0);
                va.x += bv.x; va.y += bv.y; vb.x += bv.x; vb.y += bv.y;
                *(float2*)(outp + (size_t)m0 * Cc + n0) = va;
                *(float2*)(outp + (size_t)(m0 + 8) * Cc + n0) = vb;
            }
        }
    }
}

__global__ __launch_bounds__(256, 2) void mma_gemm(
        const __nv_bfloat16* __restrict__ Asp, size_t Apl,
        const __nv_bfloat16* __restrict__ Bsp, size_t Bpl,
        const float* __restrict__ bias, float* __restrict__ outp,
        float* __restrict__ headout, int npass, uint32_t paTbl, uint32_t pwTbl) {
    extern __shared__ char smem[];
    gemm_body(smem, Asp, Apl, Bsp, Bpl, bias, outp, headout, npass, paTbl, pwTbl,
              blockIdx.x * 128, blockIdx.y * 128);
}

// ---------------- LSH bucketing body (256 threads; same arithmetic as passing version) ----------------
__device__ __forceinline__ void bucket_body(char* smemc, const float* __restrict__ rot,
                                            int bh, int tb) {
    float* rs = (float*)smemc;          // 128x64 rotations (d, h*32+i): 32 KB
    float* qs = rs + DHd * 128;         // 64x65 tokens: 16.25 KB
    int tid = threadIdx.x;              // 256

    for (int i = tid; i < DHd * 128; i += 256) rs[i] = rot[i];
    {
        int row = tid >> 2, seg = tid & 3;
        const float* src = g_qk + ((size_t)bh * Nn + tb + row) * DHd + seg * 16;
#pragma unroll
        for (int k = 0; k < 16; k++) qs[row * 65 + seg * 16 + k] = src[k];
    }
    __syncthreads();

    int warp = tid >> 5, lane = tid & 31;
    int h = warp & 3;
    int tok = (warp >> 2) * 32 + lane;   // 0..63 within block

    float r[32];
#pragma unroll
    for (int i = 0; i < 32; i++) r[i] = 0.f;
    for (int d = 0; d < DHd; d++) {
        float qd = qs[tok * 65 + d];
        const float* rp = rs + d * 128 + h * 32;
#pragma unroll
        for (int i = 0; i < 32; i++) r[i] += qd * rp[i];
    }
    float best = r[0]; int bi = 0;
#pragma unroll
    for (int i = 1; i < 32; i++) if (r[i] > best) { best = r[i]; bi = i; }
#pragma unroll
    for (int i = 0; i < 32; i++) if (-r[i] > best) { best = -r[i]; bi = 32 + i; }
    g_bucket[((size_t)bh * NHASH + h) * Nn + tb + tok] = bi;
}

// ---------------- fused: v GEMM (blocks x<8) + bucketing (x>=8, y<32) ----------------
__global__ __launch_bounds__(256, 2) void vgemm_bucket(
        const __nv_bfloat16* __restrict__ Asp, size_t Apl,
        const __nv_bfloat16* __restrict__ Bsp, size_t Bpl,
        float* __restrict__ headout, const float* __restrict__ rot) {
    extern __shared__ char smem[];
    if (blockIdx.x < 8) {
        gemm_body(smem, Asp, Apl, Bsp, Bpl, nullptr, nullptr, headout, 3, PA3, PW3,
                  blockIdx.x * 128, blockIdx.y * 128);
    } else if (blockIdx.y < 32) {
        bucket_body(smem, rot, blockIdx.y, (blockIdx.x - 8) * 64);
    }
}

// ---------------- stable counting sort per (bh, hash) ----------------
__global__ void sort_kernel() {
    __shared__ unsigned char sb[Nn];
    __shared__ int hist[NBUCK];
    __shared__ int offs[NBUCK];
    int bh = blockIdx.x, h = blockIdx.y;
    int tid = threadIdx.x;
    if (tid < NBUCK) hist[tid] = 0;
    __syncthreads();
    const int base = (bh * NHASH + h) * Nn;
    for (int t = tid; t < Nn; t += 256) {
        int b = g_bucket[base + t];
        sb[t] = (unsigned char)b;
        atomicAdd(&hist[b], 1);
    }
    __syncthreads();
    if (tid == 0) {
        int acc = 0;
        for (int b = 0; b < NBUCK; b++) { offs[b] = acc; acc += hist[b]; }
    }
    __syncthreads();
    if (tid < NBUCK) {
        unsigned char b = (unsigned char)tid;
        int w = offs[tid];
        for (int t = 0; t < Nn; t++)
            if (sb[t] == b) g_st[base + (w++)] = t;
    }
}

// ---------------- chunked LSH attention: HMMA 2-limb ----------------
#define AT_KHI   3072
#define AT_KMID  21504
#define AT_VHI   39936
#define AT_VMID  58368
#define AT_QHI   76800
#define AT_QMID  86016
#define AT_PHI   76800
#define AT_PMID  94208
#define ATTN_SMEM_BYTES 111616

__global__ __launch_bounds__(256, 2) void attn_kernel() {
    extern __shared__ char sm[];
    int*   tkv     = (int*)sm;
    float* rmaxp   = (float*)(sm + 512);
    float* rsump   = (float*)(sm + 1536);
    float* rsuminv = (float*)(sm + 2560);
    uint32_t sb = smem_to_u32(sm);

    int c = blockIdx.x, bh = blockIdx.y;
    int h = c >> 6;
    int tid = threadIdx.x, lane = tid & 31, warp = tid >> 5;
    int g = lane >> 2, t = lane & 3;
    int wm = warp >> 2, wn = warp & 3;
    int pc = (c + NCHUNK - 1) & (NCHUNK - 1);
    const int stb = bh * (NHASH * Nn);

    if (tid < 64)       tkv[tid] = g_st[stb + c * BS + tid];
    else if (tid < 128) tkv[tid] = g_st[stb + pc * BS + (tid - 64)];
    __syncthreads();

    // gather q -> limbs (pre-scaled by 0.125)
    {
        int i = tid >> 2, seg = tid & 3;
        const float* src = g_qk + ((size_t)bh * Nn + tkv[i]) * DHd + seg * 16;
        char* dh_ = sm + AT_QHI + i * 144 + seg * 32;
        char* dm_ = sm + AT_QMID + i * 144 + seg * 32;
#pragma unroll
        for (int k4 = 0; k4 < 4; k4++) {
            float4 v = *(const float4*)(src + k4 * 4);
            uint32_t h0, m0, h1, m1;
            split2u(v.x * 0.125f, v.y * 0.125f, h0, m0);
            split2u(v.z * 0.125f, v.w * 0.125f, h1, m1);
            *(uint32_t*)(dh_ + k4 * 8)     = h0;
            *(uint32_t*)(dh_ + k4 * 8 + 4) = h1;
            *(uint32_t*)(dm_ + k4 * 8)     = m0;
            *(uint32_t*)(dm_ + k4 * 8 + 4) = m1;
        }
    }
    // gather v -> limbs
    {
        int j = tid >> 1, seg = tid & 1;
        const float* src = g_v + ((size_t)bh * Nn + tkv[j]) * DHd + seg * 32;
        char* dh_ = sm + AT_VHI + j * 144 + seg * 64;
        char* dm_ = sm + AT_VMID + j * 144 + seg * 64;
#pragma unroll
        for (int k4 = 0; k4 < 8; k4++) {
            float4 v = *(const float4*)(src + k4 * 4);
            uint32_t h0, m0, h1, m1;
            split2u(v.x, v.y, h0, m0);
            split2u(v.z, v.w, h1, m1);
            *(uint32_t*)(dh_ + k4 * 8)     = h0;
            *(uint32_t*)(dh_ + k4 * 8 + 4) = h1;
            *(uint32_t*)(dm_ + k4 * 8)     = m0;
            *(uint32_t*)(dm_ + k4 * 8 + 4) = m1;
        }
    }
    // gather k: normalized rows -> limbs
    for (int rr = 0; rr < 16; rr++) {
        int j = warp * 16 + rr;
        const float* src = g_qk + ((size_t)bh * Nn + tkv[j]) * DHd;
        float a = src[lane], b = src[lane + 32];
        float s = a * a + b * b;
#pragma unroll
        for (int o = 16; o > 0; o >>= 1) s += __shfl_xor_sync(0xffffffffu, s, o);
        float inv = 1.0f / fmaxf(sqrtf(s), 1e-12f);
        float ka = a * inv, kb = b * inv;
        float kah = __bfloat162float(__float2bfloat16(ka));
        float kbh = __bfloat162float(__float2bfloat16(kb));
        *(__nv_bfloat16*)(sm + AT_KHI + j * 144 + lane * 2)       = __float2bfloat16(kah);
        *(__nv_bfloat16*)(sm + AT_KHI + j * 144 + 64 + lane * 2)  = __float2bfloat16(kbh);
        *(__nv_bfloat16*)(sm + AT_KMID + j * 144 + lane * 2)      = __float2bfloat16(ka - kah);
        *(__nv_bfloat16*)(sm + AT_KMID + j * 144 + 64 + lane * 2) = __float2bfloat16(kb - kbh);
    }
    __syncthreads();

    // dots MMA
    float Dd[2][4][4];
#pragma unroll
    for (int i = 0; i < 2; i++)
#pragma unroll
        for (int jn = 0; jn < 4; jn++)
#pragma unroll
            for (int q = 0; q < 4; q++) Dd[i][jn][q] = 0.f;

    uint32_t arow = (uint32_t)((wm * 32 + (lane & 15)) * 144 + (lane >> 4) * 16);
    uint32_t brow = (uint32_t)((wn * 32 + ((lane >> 4) & 1) * 8 + (lane & 7)) * 144
                               + ((lane >> 3) & 1) * 16);
    const uint32_t QL[3] = {sb + AT_QMID, sb + AT_QHI, sb + AT_QHI};
    const uint32_t KL[3] = {sb + AT_KHI, sb + AT_KMID, sb + AT_KHI};
#pragma unroll
    for (int p = 0; p < 3; p++) {
#pragma unroll
        for (int ks = 0; ks < 4; ks++) {
            uint32_t A4[2][4], B4[2][4];
#pragma unroll
            for (int i = 0; i < 2; i++) ldmx4(A4[i], QL[p] + arow + i * (16 * 144) + ks * 32);
#pragma unroll
            for (int jp = 0; jp < 2; jp++) ldmx4(B4[jp], KL[p] + brow + jp * (16 * 144) + ks * 32);
#pragma unroll
            for (int i = 0; i < 2; i++)
#pragma unroll
                for (int jn = 0; jn < 4; jn++)
                    mma16816(Dd[i][jn], A4[i], B4[jn >> 1][(jn & 1) * 2], B4[jn >> 1][(jn & 1) * 2 + 1]);
        }
    }

    // mask + row max
    int trow[4] = { tkv[wm * 32 + g], tkv[wm * 32 + g + 8],
                    tkv[wm * 32 + 16 + g], tkv[wm * 32 + 16 + g + 8] };
    int tcol[8];
#pragma unroll
    for (int jn = 0; jn < 4; jn++) {
        int c0 = wn * 32 + jn * 8 + t * 2;
        tcol[jn * 2] = tkv[c0]; tcol[jn * 2 + 1] = tkv[c0 + 1];
    }
#pragma unroll
    for (int i = 0; i < 2; i++)
#pragma unroll
        for (int jn = 0; jn < 4; jn++)
#pragma unroll
            for (int q = 0; q < 4; q++)
                if (trow[i * 2 + (q >> 1)] == tcol[jn * 2 + (q & 1)]) Dd[i][jn][q] = -5e4f;

    float pm[4] = {-3.0e38f, -3.0e38f, -3.0e38f, -3.0e38f};
#pragma unroll
    for (int i = 0; i < 2; i++)
#pragma unroll
        for (int jn = 0; jn < 4; jn++)
#pragma unroll
            for (int q = 0; q < 4; q++) {
                int k = i * 2 + (q >> 1);
                pm[k] = fmaxf(pm[k], Dd[i][jn][q]);
            }
#pragma unroll
    for (int k = 0; k < 4; k++) {
        pm[k] = fmaxf(pm[k], __shfl_xor_sync(0xffffffffu, pm[k], 1));
        pm[k] = fmaxf(pm[k], __shfl_xor_sync(0xffffffffu, pm[k], 2));
    }
    if (t == 0) {
#pragma unroll
        for (int k = 0; k < 4; k++)
            rmaxp[(wm * 32 + (k >> 1) * 16 + g + (k & 1) * 8) * 4 + wn] = pm[k];
    }
    __syncthreads();

    // exp -> P limbs + partial sums
    float rowm[4];
#pragma unroll
    for (int k = 0; k < 4; k++) {
        const float* p = rmaxp + (wm * 32 + (k >> 1) * 16 + g + (k & 1) * 8) * 4;
        rowm[k] = fmaxf(fmaxf(p[0], p[1]), fmaxf(p[2], p[3]));
    }
    float ps[4] = {0.f, 0.f, 0.f, 0.f};
#pragma unroll
    for (int i = 0; i < 2; i++) {
        int r0 = wm * 32 + i * 16 + g;
#pragma unroll
        for (int jn = 0; jn < 4; jn++) {
            float e0 = __expf(Dd[i][jn][0] - rowm[i * 2]);
            float e1 = __expf(Dd[i][jn][1] - rowm[i * 2]);
            float e2 = __expf(Dd[i][jn][2] - rowm[i * 2 + 1]);
            float e3 = __expf(Dd[i][jn][3] - rowm[i * 2 + 1]);
            ps[i * 2] += e0 + e1;
            ps[i * 2 + 1] += e2 + e3;
            int c0 = wn * 32 + jn * 8 + t * 2;
            uint32_t h0, m0, h1, m1;
            split2u(e0, e1, h0, m0);
            split2u(e2, e3, h1, m1);
            *(uint32_t*)(sm + AT_PHI  + r0 * 272 + c0 * 2)       = h0;
            *(uint32_t*)(sm + AT_PMID + r0 * 272 + c0 * 2)       = m0;
            *(uint32_t*)(sm + AT_PHI  + (r0 + 8) * 272 + c0 * 2) = h1;
            *(uint32_t*)(sm + AT_PMID + (r0 + 8) * 272 + c0 * 2) = m1;
        }
    }
#pragma unroll
    for (int k = 0; k < 4; k++) {
        ps[k] += __shfl_xor_sync(0xffffffffu, ps[k], 1);
        ps[k] += __shfl_xor_sync(0xffffffffu, ps[k], 2);
    }
    if (t == 0) {
#pragma unroll
        for (int k = 0; k < 4; k++)
            rsump[(wm * 32 + (k >> 1) * 16 + g + (k & 1) * 8) * 4 + wn] = ps[k];
    }
    __syncthreads();

    if (tid < 64) {
        const float* p = rsump + tid * 4;
        float s = p[0] + p[1] + p[2] + p[3];
        const float* q = rmaxp + tid * 4;
        float m = fmaxf(fmaxf(q[0], q[1]), fmaxf(q[2], q[3]));
        rsuminv[tid] = 1.0f / s;
        g_lse[(bh * NHASH + h) * Nn + tkv[tid]] = m + logf(s);
    }
    __syncthreads();

    // PV MMA
    float Dp[2][2][4];
#pragma unroll
    for (int i = 0; i < 2; i++)
#pragma unroll
        for (int jn = 0; jn < 2; jn++)
#pragma unroll
            for (int q = 0; q < 4; q++) Dp[i][jn][q] = 0.f;

    uint32_t parow = (uint32_t)((wm * 32 + (lane & 15)) * 272 + (lane >> 4) * 16);
    uint32_t vbrow = (uint32_t)((lane & 15) * 144 + (lane >> 4) * 16 + wn * 32);
    const uint32_t PL[3] = {sb + AT_PMID, sb + AT_PHI, sb + AT_PHI};
    const uint32_t VL[3] = {sb + AT_VHI, sb + AT_VMID, sb + AT_VHI};
#pragma unroll
    for (int p = 0; p < 3; p++) {
#pragma unroll
        for (int ks = 0; ks < 8; ks++) {
            uint32_t A4[2][4], B4[4];
#pragma unroll
            for (int i = 0; i < 2; i++) ldmx4(A4[i], PL[p] + parow + i * (16 * 272) + ks * 32);
            ldmx4t(B4, VL[p] + vbrow + ks * (16 * 144));
#pragma unroll
            for (int i = 0; i < 2; i++)
#pragma unroll
                for (int jn = 0; jn < 2; jn++)
                    mma16816(Dp[i][jn], A4[i], B4[jn * 2], B4[jn * 2 + 1]);
        }
    }

    // epilogue: normalize + scatter
#pragma unroll
    for (int i = 0; i < 2; i++) {
        int r0 = wm * 32 + i * 16 + g;
        float inv0 = rsuminv[r0], inv1 = rsuminv[r0 + 8];
        size_t b0 = ((size_t)(bh * NHASH + h) * Nn + trow[i * 2]) * DHd;
        size_t b1 = ((size_t)(bh * NHASH + h) * Nn + trow[i * 2 + 1]) * DHd;
#pragma unroll
        for (int jn = 0; jn < 2; jn++) {
            int dh = wn * 16 + jn * 8 + t * 2;
            *(float2*)(g_oph + b0 + dh) = make_float2(Dp[i][jn][0] * inv0, Dp[i][jn][1] * inv0);
            *(float2*)(g_oph + b1 + dh) = make_float2(Dp[i][jn][2] * inv1, Dp[i][jn][3] * inv1);
        }
    }
}

// ---------------- fused combine + limb split ----------------
__global__ void combine_split_kernel(__nv_bfloat16* __restrict__ hi,
                                     __nv_bfloat16* __restrict__ mid,
                                     __nv_bfloat16* __restrict__ lo) {
    int u = blockIdx.x * 256 + threadIdx.x;
    int slot = u >> 3;
    int dseg = (u & 7) * 8;
    int bh = slot >> 12;
    int t = slot & 4095;
    int base = bh * NHASH * Nn + t;
    float l0 = g_lse[base + 0 * Nn];
    float l1 = g_lse[base + 1 * Nn];
    float l2 = g_lse[base + 2 * Nn];
    float l3 = g_lse[base + 3 * Nn];
    float m = fmaxf(fmaxf(l0, l1), fmaxf(l2, l3));
    float w[4] = {expf(l0 - m), expf(l1 - m), expf(l2 - m), expf(l3 - m)};
    float sinv = 1.0f / (w[0] + w[1] + w[2] + w[3]);

    float acc[8];
#pragma unroll
    for (int j = 0; j < 8; j++) acc[j] = 0.f;
#pragma unroll
    for (int k = 0; k < 4; k++) {
        const float4* p = (const float4*)(g_oph + (((size_t)(bh * NHASH + k)) * Nn + t) * DHd + dseg);
        float4 x0 = p[0], x1 = p[1];
        acc[0] += w[k] * x0.x; acc[1] += w[k] * x0.y; acc[2] += w[k] * x0.z; acc[3] += w[k] * x0.w;
        acc[4] += w[k] * x1.x; acc[5] += w[k] * x1.y; acc[6] += w[k] * x1.z; acc[7] += w[k] * x1.w;
    }
    float hf[8], mf[8], lf[8];
#pragma unroll
    for (int j = 0; j < 8; j++) {
        float a = acc[j] * sinv;
        float h = __bfloat162float(__float2bfloat16(a));
        float r = a - h;
        float mm = __bfloat162float(__float2bfloat16(r));
        hf[j] = h; mf[j] = mm; lf[j] = r - mm;
    }
    int b = bh >> 4, head = bh & 15;
    size_t oidx = ((size_t)b * Nn + t) * Cc + head * DHd + dseg;
    *(uint4*)(hi + oidx) = make_uint4(pack_bf2(hf[0], hf[1]), pack_bf2(hf[2], hf[3]),
                                      pack_bf2(hf[4], hf[5]), pack_bf2(hf[6], hf[7]));
    *(uint4*)(mid + oidx) = make_uint4(pack_bf2(mf[0], mf[1]), pack_bf2(mf[2], mf[3]),
                                       pack_bf2(mf[4], mf[5]), pack_bf2(mf[6], mf[7]));
    *(uint4*)(lo + oidx) = make_uint4(pack_bf2(lf[0], lf[1]), pack_bf2(lf[2], lf[3]),
                                      pack_bf2(lf[4], lf[5]), pack_bf2(lf[6], lf[7]));
}

// ---------------- launch ----------------
extern "C" void kernel_launch(void* const* d_in, const int* in_sizes, int n_in,
                              void* d_out, int out_size) {
    const float* queries = (const float*)d_in[0];
    const float* Wqk  = (const float*)d_in[4];
    const float* Wv   = (const float*)d_in[5];
    const float* Wout = (const float*)d_in[6];
    const float* bout = (const float*)d_in[7];
    const float* rot  = (const float*)d_in[8];
    float* out = (float*)d_out;

    cudaFuncSetAttribute(attn_kernel, cudaFuncAttributeMaxDynamicSharedMemorySize, ATTN_SMEM_BYTES);
    cudaFuncSetAttribute(mma_gemm, cudaFuncAttributeMaxDynamicSharedMemorySize, GEMM_SMEM);
    cudaFuncSetAttribute(vgemm_bucket, cudaFuncAttributeMaxDynamicSharedMemorySize, GEMM_SMEM);

    void *p_qk, *p_v, *p_asp, *p_wqkv, *p_wout;
    cudaGetSymbolAddress(&p_qk, g_qk);
    cudaGetSymbolAddress(&p_v, g_v);
    cudaGetSymbolAddress(&p_asp, g_asp);
    cudaGetSymbolAddress(&p_wqkv, g_wqkv_sp);
    cudaGetSymbolAddress(&p_wout, g_wout_sp);
    __nv_bfloat16* asp  = (__nv_bfloat16*)p_asp;
    __nv_bfloat16* wqkv = (__nv_bfloat16*)p_wqkv;
    __nv_bfloat16* wout = (__nv_bfloat16*)p_wout;
    const size_t WQKV_PL = (size_t)2048 * 1024;
    const size_t WOUT_PL = (size_t)1024 * 1024;
    const int NW = 1024 * 1024;
    const int NA = Mrows * Kdim;

    split3_kernel<<<NA / 2048, 256>>>(queries, asp, asp + APL, asp + 2 * APL, NA);
    split3_kernel<<<NW / 2048, 256>>>(Wqk, wqkv, wqkv + WQKV_PL, wqkv + 2 * WQKV_PL, NW);
    split3_kernel<<<NW / 2048, 256>>>(Wv, wqkv + NW, wqkv + WQKV_PL + NW, wqkv + 2 * WQKV_PL + NW, NW);
    split3_kernel<<<NW / 2048, 256>>>(Wout, wout, wout + WOUT_PL, wout + 2 * WOUT_PL, NW);

    // qk GEMM: 6-pass fp32-equivalent (feeds LSH argmax)
    mma_gemm<<<dim3(8, 64), 256, GEMM_SMEM>>>(asp, APL, wqkv, WQKV_PL,
                                              nullptr, nullptr, (float*)p_qk, 6, PA6, PW6);

    // fused: v GEMM (3-pass) overlapped with bucketing (both depend only on qk/asp)
    vgemm_bucket<<<dim3(72, 64), 256, GEMM_SMEM>>>(asp, APL, wqkv + NW, WQKV_PL,
                                                   (float*)p_v, rot);

    sort_kernel<<<dim3(BH, NHASH), 256>>>();
    attn_kernel<<<dim3(NCHUNK, BH), 256, ATTN_SMEM_BYTES>>>();

    combine_split_kernel<<<(BH * Nn * DHd / 8) / 256, 256>>>(asp, asp + APL, asp + 2 * APL);

    mma_gemm<<<dim3(8, 64), 256, GEMM_SMEM>>>(asp, APL, wout, WOUT_PL,
                                              bout, out, nullptr, 3, PA3, PW3);
}

// round 9
// speedup vs baseline: 2.6891x; 1.0960x over previous
#include <cuda_runtime.h>
#include <cuda_fp16.h>
#include <cuda_bf16.h>
#include <math.h>
#include <stdint.h>

// ---------------- problem constants ----------------
#define Bb      2
#define Nn      4096
#define Cc      1024
#define Hh      16
#define DHd     64
#define BH      32          // Bb*Hh
#define NHASH   4
#define NBUCK   64          // Nn / BUCKET
#define NCHUNK  256         // NHASH*NBUCK
#define BS      64          // bucket size
#define Kdim    1024
#define Mrows   8192        // Bb*Nn

// ---------------- device scratch ----------------
__device__ float g_qk  [BH * Nn * DHd];            // (bh, t, d)
__device__ float g_v   [BH * Nn * DHd];
__device__ int   g_bucket[BH * NHASH * Nn];
__device__ int   g_st  [BH * NHASH * Nn];
__device__ float g_oph [BH * NHASH * Nn * DHd];    // per-hash outputs (scattered)
__device__ float g_lse [BH * NHASH * Nn];

// fp16 2-limb planes (hi, mid). W-side limbs pre-scaled by 64 (epilogue x 1/64).
#define APL ((size_t)Mrows * Kdim)
__device__ __half g_asp[2 * APL];                       // 32 MB activations
__device__ __half g_wqkv_sp[(size_t)2 * 2048 * 1024];   // 8 MB (rows 0..1023 Wqk, 1024..2047 Wv)
__device__ __half g_wout_sp[(size_t)2 * 1024 * 1024];   // 4 MB
#define WSCALE 64.0f
#define OSCALE (1.0f / 64.0f)

// ================= helpers (sm_103-safe) =================
__device__ __forceinline__ uint32_t smem_to_u32(const void* p) {
    uint32_t a;
    asm("{ .reg .u64 t; cvta.to.shared.u64 t, %1; cvt.u32.u64 %0, t; }" : "=r"(a) : "l"(p));
    return a;
}
#define CP_ASYNC16(saddr, gptr) \
    asm volatile("cp.async.cg.shared.global [%0], [%1], 16;" \
        :: "r"(saddr), "l"(__cvta_generic_to_global(gptr)))
#define CP_COMMIT() asm volatile("cp.async.commit_group;" ::: "memory")
#define CP_WAIT(n)  asm volatile("cp.async.wait_group %0;" :: "n"(n) : "memory")

__device__ __forceinline__ void ldmx4(uint32_t* r, uint32_t addr) {
    asm volatile("ldmatrix.sync.aligned.m8n8.x4.shared.b16 {%0,%1,%2,%3}, [%4];"
        : "=r"(r[0]), "=r"(r[1]), "=r"(r[2]), "=r"(r[3]) : "r"(addr));
}
__device__ __forceinline__ void ldmx4t(uint32_t* r, uint32_t addr) {
    asm volatile("ldmatrix.sync.aligned.m8n8.x4.trans.shared.b16 {%0,%1,%2,%3}, [%4];"
        : "=r"(r[0]), "=r"(r[1]), "=r"(r[2]), "=r"(r[3]) : "r"(addr));
}
// fp16 in, fp32 accum
__device__ __forceinline__ void mma16816h(float* d, const uint32_t* a, uint32_t b0, uint32_t b1) {
    asm volatile("mma.sync.aligned.m16n8k16.row.col.f32.f16.f16.f32 "
        "{%0,%1,%2,%3}, {%4,%5,%6,%7}, {%8,%9}, {%0,%1,%2,%3};"
        : "+f"(d[0]), "+f"(d[1]), "+f"(d[2]), "+f"(d[3])
        : "r"(a[0]), "r"(a[1]), "r"(a[2]), "r"(a[3]), "r"(b0), "r"(b1));
}
// bf16 in, fp32 accum (attention kernel)
__device__ __forceinline__ void mma16816(float* d, const uint32_t* a, uint32_t b0, uint32_t b1) {
    asm volatile("mma.sync.aligned.m16n8k16.row.col.f32.bf16.bf16.f32 "
        "{%0,%1,%2,%3}, {%4,%5,%6,%7}, {%8,%9}, {%0,%1,%2,%3};"
        : "+f"(d[0]), "+f"(d[1]), "+f"(d[2]), "+f"(d[3])
        : "r"(a[0]), "r"(a[1]), "r"(a[2]), "r"(a[3]), "r"(b0), "r"(b1));
}
__device__ __forceinline__ uint32_t pack_bf2(float a, float b) {
    uint16_t ua = __bfloat16_as_ushort(__float2bfloat16(a));
    uint16_t ub = __bfloat16_as_ushort(__float2bfloat16(b));
    return (uint32_t)ua | ((uint32_t)ub << 16);
}
__device__ __forceinline__ uint32_t pack_h2(float a, float b) {
    uint16_t ua = __half_as_ushort(__float2half_rn(a));
    uint16_t ub = __half_as_ushort(__float2half_rn(b));
    return (uint32_t)ua | ((uint32_t)ub << 16);
}
// bf16 split (attention)
__device__ __forceinline__ void split2u(float a, float b, uint32_t& hp, uint32_t& mp) {
    float ha = __bfloat162float(__float2bfloat16(a));
    float hb = __bfloat162float(__float2bfloat16(b));
    hp = pack_bf2(ha, hb);
    mp = pack_bf2(a - ha, b - hb);
}

// ================= fp16 2-limb split (vectorized, with pre-scale) =================
__global__ void split2_kernel(const float* __restrict__ x,
                              __half* __restrict__ hi,
                              __half* __restrict__ mid, int n, float scale) {
    int i = (blockIdx.x * 256 + threadIdx.x) * 8;
    if (i >= n) return;
    float4 v0 = *(const float4*)(x + i);
    float4 v1 = *(const float4*)(x + i + 4);
    float a[8] = {v0.x, v0.y, v0.z, v0.w, v1.x, v1.y, v1.z, v1.w};
    float hf[8], mf[8];
#pragma unroll
    for (int j = 0; j < 8; j++) {
        float s = a[j] * scale;
        float h = __half2float(__float2half_rn(s));
        hf[j] = h; mf[j] = s - h;
    }
    *(uint4*)(hi + i) = make_uint4(pack_h2(hf[0], hf[1]), pack_h2(hf[2], hf[3]),
                                   pack_h2(hf[4], hf[5]), pack_h2(hf[6], hf[7]));
    *(uint4*)(mid + i) = make_uint4(pack_h2(mf[0], mf[1]), pack_h2(mf[2], mf[3]),
                                    pack_h2(mf[4], mf[5]), pack_h2(mf[6], mf[7]));
}

// ================= HMMA GEMM body (fp16 limbs, small->large pass order) =================
#define ROWB     80
#define MATB     (128 * ROWB)
#define STAGEB   (2 * MATB)
#define GEMM_SMEM (4 * STAGEB)   // 81920
// 4-pass (qk, ~2^-24): (1,1)(0,1)(1,0)(0,0)
#define PA4 0x0101u
#define PW4 0x0011u
// 3-pass (v/wout, ~2^-24): (0,1)(1,0)(0,0)
#define PA3 0x010u
#define PW3 0x001u

__device__ __forceinline__ void gemm_issue(uint32_t st,
        const __half* Ap, const __half* Bp, int bm, int bn, int k0,
        uint32_t so0, uint32_t so1, int r0, int c0, int r1, int c1) {
    CP_ASYNC16(st + so0, Ap + (size_t)(bm + r0) * Kdim + k0 + c0 * 8);
    CP_ASYNC16(st + so1, Ap + (size_t)(bm + r1) * Kdim + k0 + c1 * 8);
    CP_ASYNC16(st + MATB + so0, Bp + (size_t)(bn + r0) * Kdim + k0 + c0 * 8);
    CP_ASYNC16(st + MATB + so1, Bp + (size_t)(bn + r1) * Kdim + k0 + c1 * 8);
    CP_COMMIT();
}

__device__ __forceinline__ void gemm_body(char* smem,
        const __half* __restrict__ Asp, size_t Apl,
        const __half* __restrict__ Bsp, size_t Bpl,
        const float* __restrict__ bias, float* __restrict__ outp,
        float* __restrict__ headout, int npass, uint32_t paTbl, uint32_t pwTbl,
        int bn, int bm) {
    uint32_t sbase = smem_to_u32(smem);
    int tid = threadIdx.x;
    int lane = tid & 31, warp = tid >> 5;
    int wm = warp >> 2, wn = warp & 3;
    int nstage = npass * 32;

    int v0 = tid, v1 = tid + 256;
    int r0 = v0 >> 2, c0 = v0 & 3;
    int r1 = v1 >> 2, c1 = v1 & 3;
    uint32_t so0 = (uint32_t)(r0 * ROWB + c0 * 16);
    uint32_t so1 = (uint32_t)(r1 * ROWB + c1 * 16);

    uint32_t aoff = (uint32_t)((wm * 64 + (lane & 15)) * ROWB + (lane >> 4) * 16);
    uint32_t boff = (uint32_t)((wn * 32 + ((lane >> 4) & 1) * 8 + (lane & 7)) * ROWB
                               + ((lane >> 3) & 1) * 16);

    float D[4][4][4];
#pragma unroll
    for (int i = 0; i < 4; i++)
#pragma unroll
        for (int j = 0; j < 4; j++)
#pragma unroll
            for (int q = 0; q < 4; q++) D[i][j][q] = 0.f;

    // prologue: stages 0,1,2 (all pass 0)
#pragma unroll
    for (int s = 0; s < 3; s++) {
        const __half* Ap = Asp + (size_t)(paTbl & 7) * Apl;
        const __half* Bp = Bsp + (size_t)(pwTbl & 7) * Bpl;
        gemm_issue(sbase + s * STAGEB, Ap, Bp, bm, bn, s * 32, so0, so1, r0, c0, r1, c1);
    }

    for (int s = 0; s < nstage; s++) {
        if (s <= nstage - 3)      { CP_WAIT(2); }
        else if (s == nstage - 2) { CP_WAIT(1); }
        else                      { CP_WAIT(0); }
        __syncthreads();
        if (s + 3 < nstage) {
            int sn = s + 3;
            int p = sn >> 5, k0 = (sn & 31) << 5;
            const __half* Ap = Asp + (size_t)((paTbl >> (p * 4)) & 7) * Apl;
            const __half* Bp = Bsp + (size_t)((pwTbl >> (p * 4)) & 7) * Bpl;
            gemm_issue(sbase + (uint32_t)(sn & 3) * STAGEB, Ap, Bp, bm, bn, k0,
                       so0, so1, r0, c0, r1, c1);
        }
        uint32_t st = sbase + (uint32_t)(s & 3) * STAGEB;
        uint32_t ab = st + aoff;
        uint32_t bb = st + MATB + boff;
#pragma unroll
        for (int ks = 0; ks < 2; ks++) {
            uint32_t A4[4][4], B4[2][4];
#pragma unroll
            for (int i = 0; i < 4; i++) ldmx4(A4[i], ab + i * (16 * ROWB) + ks * 32);
#pragma unroll
            for (int jp = 0; jp < 2; jp++) ldmx4(B4[jp], bb + jp * (16 * ROWB) + ks * 32);
#pragma unroll
            for (int i = 0; i < 4; i++)
#pragma unroll
                for (int jn = 0; jn < 4; jn++)
                    mma16816h(D[i][jn], A4[i], B4[jn >> 1][(jn & 1) * 2], B4[jn >> 1][(jn & 1) * 2 + 1]);
        }
    }

    int g = lane >> 2, t = lane & 3;
#pragma unroll
    for (int i = 0; i < 4; i++) {
#pragma unroll
        for (int jn = 0; jn < 4; jn++) {
            int m0 = bm + wm * 64 + i * 16 + g;
            int n0 = bn + wn * 32 + jn * 8 + t * 2;
            float2 va = make_float2(D[i][jn][0] * OSCALE, D[i][jn][1] * OSCALE);
            float2 vb = make_float2(D[i][jn][2] * OSCALE, D[i][jn][3] * OSCALE);
            if (headout) {
                int bI = m0 >> 12;
                int t0 = m0 & 4095, t1 = (m0 + 8) & 4095;
                int hd = n0 >> 6, dh = n0 & 63;
                *(float2*)(headout + (((size_t)(bI * Hh + hd)) * Nn + t0) * DHd + dh) = va;
                *(float2*)(headout + (((size_t)(bI * Hh + hd)) * Nn + t1) * DHd + dh) = vb;
            } else {
                float2 bv = *(const float2*)(bias + n0);
                va.x += bv.x; va.y += bv.y; vb.x += bv.x; vb.y += bv.y;
                *(float2*)(outp + (size_t)m0 * Cc + n0) = va;
                *(float2*)(outp + (size_t)(m0 + 8) * Cc + n0) = vb;
            }
        }
    }
}

__global__ __launch_bounds__(256, 2) void mma_gemm(
        const __half* __restrict__ Asp, size_t Apl,
        const __half* __restrict__ Bsp, size_t Bpl,
        const float* __restrict__ bias, float* __restrict__ outp,
        float* __restrict__ headout, int npass, uint32_t paTbl, uint32_t pwTbl) {
    extern __shared__ char smem[];
    gemm_body(smem, Asp, Apl, Bsp, Bpl, bias, outp, headout, npass, paTbl, pwTbl,
              blockIdx.x * 128, blockIdx.y * 128);
}

// ---------------- LSH bucketing body (256 threads) ----------------
__device__ __forceinline__ void bucket_body(char* smemc, const float* __restrict__ rot,
                                            int bh, int tb) {
    float* rs = (float*)smemc;
    float* qs = rs + DHd * 128;
    int tid = threadIdx.x;

    for (int i = tid; i < DHd * 128; i += 256) rs[i] = rot[i];
    {
        int row = tid >> 2, seg = tid & 3;
        const float* src = g_qk + ((size_t)bh * Nn + tb + row) * DHd + seg * 16;
#pragma unroll
        for (int k = 0; k < 16; k++) qs[row * 65 + seg * 16 + k] = src[k];
    }
    __syncthreads();

    int warp = tid >> 5, lane = tid & 31;
    int h = warp & 3;
    int tok = (warp >> 2) * 32 + lane;

    float r[32];
#pragma unroll
    for (int i = 0; i < 32; i++) r[i] = 0.f;
    for (int d = 0; d < DHd; d++) {
        float qd = qs[tok * 65 + d];
        const float* rp = rs + d * 128 + h * 32;
#pragma unroll
        for (int i = 0; i < 32; i++) r[i] += qd * rp[i];
    }
    float best = r[0]; int bi = 0;
#pragma unroll
    for (int i = 1; i < 32; i++) if (r[i] > best) { best = r[i]; bi = i; }
#pragma unroll
    for (int i = 0; i < 32; i++) if (-r[i] > best) { best = -r[i]; bi = 32 + i; }
    g_bucket[((size_t)bh * NHASH + h) * Nn + tb + tok] = bi;
}

// ---------------- fused: v GEMM (blocks x<8) + bucketing (x>=8, y<32) ----------------
__global__ __launch_bounds__(256, 2) void vgemm_bucket(
        const __half* __restrict__ Asp, size_t Apl,
        const __half* __restrict__ Bsp, size_t Bpl,
        float* __restrict__ headout, const float* __restrict__ rot) {
    extern __shared__ char smem[];
    if (blockIdx.x < 8) {
        gemm_body(smem, Asp, Apl, Bsp, Bpl, nullptr, nullptr, headout, 3, PA3, PW3,
                  blockIdx.x * 128, blockIdx.y * 128);
    } else if (blockIdx.y < 32) {
        bucket_body(smem, rot, blockIdx.y, (blockIdx.x - 8) * 64);
    }
}

// ---------------- stable counting sort per (bh, hash) ----------------
__global__ void sort_kernel() {
    __shared__ unsigned char sb[Nn];
    __shared__ int hist[NBUCK];
    __shared__ int offs[NBUCK];
    int bh = blockIdx.x, h = blockIdx.y;
    int tid = threadIdx.x;
    if (tid < NBUCK) hist[tid] = 0;
    __syncthreads();
    const int base = (bh * NHASH + h) * Nn;
    for (int t = tid; t < Nn; t += 256) {
        int b = g_bucket[base + t];
        sb[t] = (unsigned char)b;
        atomicAdd(&hist[b], 1);
    }
    __syncthreads();
    if (tid == 0) {
        int acc = 0;
        for (int b = 0; b < NBUCK; b++) { offs[b] = acc; acc += hist[b]; }
    }
    __syncthreads();
    if (tid < NBUCK) {
        unsigned char b = (unsigned char)tid;
        int w = offs[tid];
        for (int t = 0; t < Nn; t++)
            if (sb[t] == b) g_st[base + (w++)] = t;
    }
}

// ---------------- chunked LSH attention: HMMA 2-limb bf16 (unchanged) ----------------
#define AT_KHI   3072
#define AT_KMID  21504
#define AT_VHI   39936
#define AT_VMID  58368
#define AT_QHI   76800
#define AT_QMID  86016
#define AT_PHI   76800
#define AT_PMID  94208
#define ATTN_SMEM_BYTES 111616

__global__ __launch_bounds__(256, 2) void attn_kernel() {
    extern __shared__ char sm[];
    int*   tkv     = (int*)sm;
    float* rmaxp   = (float*)(sm + 512);
    float* rsump   = (float*)(sm + 1536);
    float* rsuminv = (float*)(sm + 2560);
    uint32_t sb = smem_to_u32(sm);

    int c = blockIdx.x, bh = blockIdx.y;
    int h = c >> 6;
    int tid = threadIdx.x, lane = tid & 31, warp = tid >> 5;
    int g = lane >> 2, t = lane & 3;
    int wm = warp >> 2, wn = warp & 3;
    int pc = (c + NCHUNK - 1) & (NCHUNK - 1);
    const int stb = bh * (NHASH * Nn);

    if (tid < 64)       tkv[tid] = g_st[stb + c * BS + tid];
    else if (tid < 128) tkv[tid] = g_st[stb + pc * BS + (tid - 64)];
    __syncthreads();

    // gather q -> limbs (pre-scaled by 0.125)
    {
        int i = tid >> 2, seg = tid & 3;
        const float* src = g_qk + ((size_t)bh * Nn + tkv[i]) * DHd + seg * 16;
        char* dh_ = sm + AT_QHI + i * 144 + seg * 32;
        char* dm_ = sm + AT_QMID + i * 144 + seg * 32;
#pragma unroll
        for (int k4 = 0; k4 < 4; k4++) {
            float4 v = *(const float4*)(src + k4 * 4);
            uint32_t h0, m0, h1, m1;
            split2u(v.x * 0.125f, v.y * 0.125f, h0, m0);
            split2u(v.z * 0.125f, v.w * 0.125f, h1, m1);
            *(uint32_t*)(dh_ + k4 * 8)     = h0;
            *(uint32_t*)(dh_ + k4 * 8 + 4) = h1;
            *(uint32_t*)(dm_ + k4 * 8)     = m0;
            *(uint32_t*)(dm_ + k4 * 8 + 4) = m1;
        }
    }
    // gather v -> limbs
    {
        int j = tid >> 1, seg = tid & 1;
        const float* src = g_v + ((size_t)bh * Nn + tkv[j]) * DHd + seg * 32;
        char* dh_ = sm + AT_VHI + j * 144 + seg * 64;
        char* dm_ = sm + AT_VMID + j * 144 + seg * 64;
#pragma unroll
        for (int k4 = 0; k4 < 8; k4++) {
            float4 v = *(const float4*)(src + k4 * 4);
            uint32_t h0, m0, h1, m1;
            split2u(v.x, v.y, h0, m0);
            split2u(v.z, v.w, h1, m1);
            *(uint32_t*)(dh_ + k4 * 8)     = h0;
            *(uint32_t*)(dh_ + k4 * 8 + 4) = h1;
            *(uint32_t*)(dm_ + k4 * 8)     = m0;
            *(uint32_t*)(dm_ + k4 * 8 + 4) = m1;
        }
    }
    // gather k: normalized rows -> limbs
    for (int rr = 0; rr < 16; rr++) {
        int j = warp * 16 + rr;
        const float* src = g_qk + ((size_t)bh * Nn + tkv[j]) * DHd;
        float a = src[lane], b = src[lane + 32];
        float s = a * a + b * b;
#pragma unroll
        for (int o = 16; o > 0; o >>= 1) s += __shfl_xor_sync(0xffffffffu, s, o);
        float inv = 1.0f / fmaxf(sqrtf(s), 1e-12f);
        float ka = a * inv, kb = b * inv;
        float kah = __bfloat162float(__float2bfloat16(ka));
        float kbh = __bfloat162float(__float2bfloat16(kb));
        *(__nv_bfloat16*)(sm + AT_KHI + j * 144 + lane * 2)       = __float2bfloat16(kah);
        *(__nv_bfloat16*)(sm + AT_KHI + j * 144 + 64 + lane * 2)  = __float2bfloat16(kbh);
        *(__nv_bfloat16*)(sm + AT_KMID + j * 144 + lane * 2)      = __float2bfloat16(ka - kah);
        *(__nv_bfloat16*)(sm + AT_KMID + j * 144 + 64 + lane * 2) = __float2bfloat16(kb - kbh);
    }
    __syncthreads();

    // dots MMA
    float Dd[2][4][4];
#pragma unroll
    for (int i = 0; i < 2; i++)
#pragma unroll
        for (int jn = 0; jn < 4; jn++)
#pragma unroll
            for (int q = 0; q < 4; q++) Dd[i][jn][q] = 0.f;

    uint32_t arow = (uint32_t)((wm * 32 + (lane & 15)) * 144 + (lane >> 4) * 16);
    uint32_t brow = (uint32_t)((wn * 32 + ((lane >> 4) & 1) * 8 + (lane & 7)) * 144
                               + ((lane >> 3) & 1) * 16);
    const uint32_t QL[3] = {sb + AT_QMID, sb + AT_QHI, sb + AT_QHI};
    const uint32_t KL[3] = {sb + AT_KHI, sb + AT_KMID, sb + AT_KHI};
#pragma unroll
    for (int p = 0; p < 3; p++) {
#pragma unroll
        for (int ks = 0; ks < 4; ks++) {
            uint32_t A4[2][4], B4[2][4];
#pragma unroll
            for (int i = 0; i < 2; i++) ldmx4(A4[i], QL[p] + arow + i * (16 * 144) + ks * 32);
#pragma unroll
            for (int jp = 0; jp < 2; jp++) ldmx4(B4[jp], KL[p] + brow + jp * (16 * 144) + ks * 32);
#pragma unroll
            for (int i = 0; i < 2; i++)
#pragma unroll
                for (int jn = 0; jn < 4; jn++)
                    mma16816(Dd[i][jn], A4[i], B4[jn >> 1][(jn & 1) * 2], B4[jn >> 1][(jn & 1) * 2 + 1]);
        }
    }

    // mask + row max
    int trow[4] = { tkv[wm * 32 + g], tkv[wm * 32 + g + 8],
                    tkv[wm * 32 + 16 + g], tkv[wm * 32 + 16 + g + 8] };
    int tcol[8];
#pragma unroll
    for (int jn = 0; jn < 4; jn++) {
        int c0 = wn * 32 + jn * 8 + t * 2;
        tcol[jn * 2] = tkv[c0]; tcol[jn * 2 + 1] = tkv[c0 + 1];
    }
#pragma unroll
    for (int i = 0; i < 2; i++)
#pragma unroll
        for (int jn = 0; jn < 4; jn++)
#pragma unroll
            for (int q = 0; q < 4; q++)
                if (trow[i * 2 + (q >> 1)] == tcol[jn * 2 + (q & 1)]) Dd[i][jn][q] = -5e4f;

    float pm[4] = {-3.0e38f, -3.0e38f, -3.0e38f, -3.0e38f};
#pragma unroll
    for (int i = 0; i < 2; i++)
#pragma unroll
        for (int jn = 0; jn < 4; jn++)
#pragma unroll
            for (int q = 0; q < 4; q++) {
                int k = i * 2 + (q >> 1);
                pm[k] = fmaxf(pm[k], Dd[i][jn][q]);
            }
#pragma unroll
    for (int k = 0; k < 4; k++) {
        pm[k] = fmaxf(pm[k], __shfl_xor_sync(0xffffffffu, pm[k], 1));
        pm[k] = fmaxf(pm[k], __shfl_xor_sync(0xffffffffu, pm[k], 2));
    }
    if (t == 0) {
#pragma unroll
        for (int k = 0; k < 4; k++)
            rmaxp[(wm * 32 + (k >> 1) * 16 + g + (k & 1) * 8) * 4 + wn] = pm[k];
    }
    __syncthreads();

    // exp -> P limbs + partial sums
    float rowm[4];
#pragma unroll
    for (int k = 0; k < 4; k++) {
        const float* p = rmaxp + (wm * 32 + (k >> 1) * 16 + g + (k & 1) * 8) * 4;
        rowm[k] = fmaxf(fmaxf(p[0], p[1]), fmaxf(p[2], p[3]));
    }
    float ps[4] = {0.f, 0.f, 0.f, 0.f};
#pragma unroll
    for (int i = 0; i < 2; i++) {
        int r0 = wm * 32 + i * 16 + g;
#pragma unroll
        for (int jn = 0; jn < 4; jn++) {
            float e0 = __expf(Dd[i][jn][0] - rowm[i * 2]);
            float e1 = __expf(Dd[i][jn][1] - rowm[i * 2]);
            float e2 = __expf(Dd[i][jn][2] - rowm[i * 2 + 1]);
            float e3 = __expf(Dd[i][jn][3] - rowm[i * 2 + 1]);
            ps[i * 2] += e0 + e1;
            ps[i * 2 + 1] += e2 + e3;
            int c0 = wn * 32 + jn * 8 + t * 2;
            uint32_t h0, m0, h1, m1;
            split2u(e0, e1, h0, m0);
            split2u(e2, e3, h1, m1);
            *(uint32_t*)(sm + AT_PHI  + r0 * 272 + c0 * 2)       = h0;
            *(uint32_t*)(sm + AT_PMID + r0 * 272 + c0 * 2)       = m0;
            *(uint32_t*)(sm + AT_PHI  + (r0 + 8) * 272 + c0 * 2) = h1;
            *(uint32_t*)(sm + AT_PMID + (r0 + 8) * 272 + c0 * 2) = m1;
        }
    }
#pragma unroll
    for (int k = 0; k < 4; k++) {
        ps[k] += __shfl_xor_sync(0xffffffffu, ps[k], 1);
        ps[k] += __shfl_xor_sync(0xffffffffu, ps[k], 2);
    }
    if (t == 0) {
#pragma unroll
        for (int k = 0; k < 4; k++)
            rsump[(wm * 32 + (k >> 1) * 16 + g + (k & 1) * 8) * 4 + wn] = ps[k];
    }
    __syncthreads();

    if (tid < 64) {
        const float* p = rsump + tid * 4;
        float s = p[0] + p[1] + p[2] + p[3];
        const float* q = rmaxp + tid * 4;
        float m = fmaxf(fmaxf(q[0], q[1]), fmaxf(q[2], q[3]));
        rsuminv[tid] = 1.0f / s;
        g_lse[(bh * NHASH + h) * Nn + tkv[tid]] = m + logf(s);
    }
    __syncthreads();

    // PV MMA
    float Dp[2][2][4];
#pragma unroll
    for (int i = 0; i < 2; i++)
#pragma unroll
        for (int jn = 0; jn < 2; jn++)
#pragma unroll
            for (int q = 0; q < 4; q++) Dp[i][jn][q] = 0.f;

    uint32_t parow = (uint32_t)((wm * 32 + (lane & 15)) * 272 + (lane >> 4) * 16);
    uint32_t vbrow = (uint32_t)((lane & 15) * 144 + (lane >> 4) * 16 + wn * 32);
    const uint32_t PL[3] = {sb + AT_PMID, sb + AT_PHI, sb + AT_PHI};
    const uint32_t VL[3] = {sb + AT_VHI, sb + AT_VMID, sb + AT_VHI};
#pragma unroll
    for (int p = 0; p < 3; p++) {
#pragma unroll
        for (int ks = 0; ks < 8; ks++) {
            uint32_t A4[2][4], B4[4];
#pragma unroll
            for (int i = 0; i < 2; i++) ldmx4(A4[i], PL[p] + parow + i * (16 * 272) + ks * 32);
            ldmx4t(B4, VL[p] + vbrow + ks * (16 * 144));
#pragma unroll
            for (int i = 0; i < 2; i++)
#pragma unroll
                for (int jn = 0; jn < 2; jn++)
                    mma16816(Dp[i][jn], A4[i], B4[jn * 2], B4[jn * 2 + 1]);
        }
    }

    // epilogue: normalize + scatter
#pragma unroll
    for (int i = 0; i < 2; i++) {
        int r0 = wm * 32 + i * 16 + g;
        float inv0 = rsuminv[r0], inv1 = rsuminv[r0 + 8];
        size_t b0 = ((size_t)(bh * NHASH + h) * Nn + trow[i * 2]) * DHd;
        size_t b1 = ((size_t)(bh * NHASH + h) * Nn + trow[i * 2 + 1]) * DHd;
#pragma unroll
        for (int jn = 0; jn < 2; jn++) {
            int dh = wn * 16 + jn * 8 + t * 2;
            *(float2*)(g_oph + b0 + dh) = make_float2(Dp[i][jn][0] * inv0, Dp[i][jn][1] * inv0);
            *(float2*)(g_oph + b1 + dh) = make_float2(Dp[i][jn][2] * inv1, Dp[i][jn][3] * inv1);
        }
    }
}

// ---------------- fused combine + fp16 2-limb split ----------------
__global__ void combine_split_kernel(__half* __restrict__ hi, __half* __restrict__ mid) {
    int u = blockIdx.x * 256 + threadIdx.x;
    int slot = u >> 3;
    int dseg = (u & 7) * 8;
    int bh = slot >> 12;
    int t = slot & 4095;
    int base = bh * NHASH * Nn + t;
    float l0 = g_lse[base + 0 * Nn];
    float l1 = g_lse[base + 1 * Nn];
    float l2 = g_lse[base + 2 * Nn];
    float l3 = g_lse[base + 3 * Nn];
    float m = fmaxf(fmaxf(l0, l1), fmaxf(l2, l3));
    float w[4] = {expf(l0 - m), expf(l1 - m), expf(l2 - m), expf(l3 - m)};
    float sinv = 1.0f / (w[0] + w[1] + w[2] + w[3]);

    float acc[8];
#pragma unroll
    for (int j = 0; j < 8; j++) acc[j] = 0.f;
#pragma unroll
    for (int k = 0; k < 4; k++) {
        const float4* p = (const float4*)(g_oph + (((size_t)(bh * NHASH + k)) * Nn + t) * DHd + dseg);
        float4 x0 = p[0], x1 = p[1];
        acc[0] += w[k] * x0.x; acc[1] += w[k] * x0.y; acc[2] += w[k] * x0.z; acc[3] += w[k] * x0.w;
        acc[4] += w[k] * x1.x; acc[5] += w[k] * x1.y; acc[6] += w[k] * x1.z; acc[7] += w[k] * x1.w;
    }
    float hf[8], mf[8];
#pragma unroll
    for (int j = 0; j < 8; j++) {
        float a = acc[j] * sinv;
        float h = __half2float(__float2half_rn(a));
        hf[j] = h; mf[j] = a - h;
    }
    int b = bh >> 4, head = bh & 15;
    size_t oidx = ((size_t)b * Nn + t) * Cc + head * DHd + dseg;
    *(uint4*)(hi + oidx) = make_uint4(pack_h2(hf[0], hf[1]), pack_h2(hf[2], hf[3]),
                                      pack_h2(hf[4], hf[5]), pack_h2(hf[6], hf[7]));
    *(uint4*)(mid + oidx) = make_uint4(pack_h2(mf[0], mf[1]), pack_h2(mf[2], mf[3]),
                                       pack_h2(mf[4], mf[5]), pack_h2(mf[6], mf[7]));
}

// ---------------- launch ----------------
extern "C" void kernel_launch(void* const* d_in, const int* in_sizes, int n_in,
                              void* d_out, int out_size) {
    const float* queries = (const float*)d_in[0];
    const float* Wqk  = (const float*)d_in[4];
    const float* Wv   = (const float*)d_in[5];
    const float* Wout = (const float*)d_in[6];
    const float* bout = (const float*)d_in[7];
    const float* rot  = (const float*)d_in[8];
    float* out = (float*)d_out;

    cudaFuncSetAttribute(attn_kernel, cudaFuncAttributeMaxDynamicSharedMemorySize, ATTN_SMEM_BYTES);
    cudaFuncSetAttribute(mma_gemm, cudaFuncAttributeMaxDynamicSharedMemorySize, GEMM_SMEM);
    cudaFuncSetAttribute(vgemm_bucket, cudaFuncAttributeMaxDynamicSharedMemorySize, GEMM_SMEM);

    void *p_qk, *p_v, *p_asp, *p_wqkv, *p_wout;
    cudaGetSymbolAddress(&p_qk, g_qk);
    cudaGetSymbolAddress(&p_v, g_v);
    cudaGetSymbolAddress(&p_asp, g_asp);
    cudaGetSymbolAddress(&p_wqkv, g_wqkv_sp);
    cudaGetSymbolAddress(&p_wout, g_wout_sp);
    __half* asp  = (__half*)p_asp;
    __half* wqkv = (__half*)p_wqkv;
    __half* wout = (__half*)p_wout;
    const size_t WQKV_PL = (size_t)2048 * 1024;
    const size_t WOUT_PL = (size_t)1024 * 1024;
    const int NW = 1024 * 1024;
    const int NA = Mrows * Kdim;

    // limb splits: activations unscaled, weights pre-scaled x64
    split2_kernel<<<NA / 2048, 256>>>(queries, asp, asp + APL, NA, 1.0f);
    split2_kernel<<<NW / 2048, 256>>>(Wqk, wqkv, wqkv + WQKV_PL, NW, WSCALE);
    split2_kernel<<<NW / 2048, 256>>>(Wv, wqkv + NW, wqkv + WQKV_PL + NW, NW, WSCALE);
    split2_kernel<<<NW / 2048, 256>>>(Wout, wout, wout + WOUT_PL, NW, WSCALE);

    // qk GEMM: 4-pass fp16 (~2^-24, feeds LSH argmax)
    mma_gemm<<<dim3(8, 64), 256, GEMM_SMEM>>>(asp, APL, wqkv, WQKV_PL,
                                              nullptr, nullptr, (float*)p_qk, 4, PA4, PW4);

    // fused: v GEMM (3-pass fp16) overlapped with bucketing
    vgemm_bucket<<<dim3(72, 64), 256, GEMM_SMEM>>>(asp, APL, wqkv + NW, WQKV_PL,
                                                   (float*)p_v, rot);

    sort_kernel<<<dim3(BH, NHASH), 256>>>();
    attn_kernel<<<dim3(NCHUNK, BH), 256, ATTN_SMEM_BYTES>>>();

    combine_split_kernel<<<(BH * Nn * DHd / 8) / 256, 256>>>(asp, asp + APL);

    // Wout GEMM: 3-pass fp16, +bias -> d_out
    mma_gemm<<<dim3(8, 64), 256, GEMM_SMEM>>>(asp, APL, wout, WOUT_PL,
                                              bout, out, nullptr, 3, PA3, PW3);
}

// round 10
// speedup vs baseline: 2.7031x; 1.0052x over previous
#include <cuda_runtime.h>
#include <cuda_fp16.h>
#include <cuda_bf16.h>
#include <math.h>
#include <stdint.h>

// ---------------- problem constants ----------------
#define Bb      2
#define Nn      4096
#define Cc      1024
#define Hh      16
#define DHd     64
#define BH      32          // Bb*Hh
#define NHASH   4
#define NBUCK   64          // Nn / BUCKET
#define NCHUNK  256         // NHASH*NBUCK
#define BS      64          // bucket size
#define Kdim    1024
#define Mrows   8192        // Bb*Nn

// ---------------- device scratch ----------------
__device__ float g_qk  [BH * Nn * DHd];            // (bh, t, d)
__device__ float g_v   [BH * Nn * DHd];
__device__ int   g_bucket[BH * NHASH * Nn];
__device__ int   g_st  [BH * NHASH * Nn];
__device__ float g_oph [BH * NHASH * Nn * DHd];    // per-hash outputs (scattered)
__device__ float g_lse [BH * NHASH * Nn];

// fp16 2-limb planes (hi, mid). W-side limbs pre-scaled by 64 (epilogue x 1/64).
#define APL ((size_t)Mrows * Kdim)
#define WQKV_PL ((size_t)2048 * 1024)
#define WOUT_PL ((size_t)1024 * 1024)
__device__ __half g_asp[2 * APL];
__device__ __half g_wqkv_sp[2 * WQKV_PL];
__device__ __half g_wout_sp[2 * WOUT_PL];
#define WSCALE 64.0f
#define OSCALE (1.0f / 64.0f)

// ================= helpers (sm_103-safe) =================
__device__ __forceinline__ uint32_t smem_to_u32(const void* p) {
    uint32_t a;
    asm("{ .reg .u64 t; cvta.to.shared.u64 t, %1; cvt.u32.u64 %0, t; }" : "=r"(a) : "l"(p));
    return a;
}
#define CP_ASYNC16(saddr, gptr) \
    asm volatile("cp.async.cg.shared.global [%0], [%1], 16;" \
        :: "r"(saddr), "l"(__cvta_generic_to_global(gptr)))
#define CP_COMMIT() asm volatile("cp.async.commit_group;" ::: "memory")
#define CP_WAIT(n)  asm volatile("cp.async.wait_group %0;" :: "n"(n) : "memory")

__device__ __forceinline__ void ldmx4(uint32_t* r, uint32_t addr) {
    asm volatile("ldmatrix.sync.aligned.m8n8.x4.shared.b16 {%0,%1,%2,%3}, [%4];"
        : "=r"(r[0]), "=r"(r[1]), "=r"(r[2]), "=r"(r[3]) : "r"(addr));
}
__device__ __forceinline__ void ldmx4t(uint32_t* r, uint32_t addr) {
    asm volatile("ldmatrix.sync.aligned.m8n8.x4.trans.shared.b16 {%0,%1,%2,%3}, [%4];"
        : "=r"(r[0]), "=r"(r[1]), "=r"(r[2]), "=r"(r[3]) : "r"(addr));
}
__device__ __forceinline__ void mma16816h(float* d, const uint32_t* a, uint32_t b0, uint32_t b1) {
    asm volatile("mma.sync.aligned.m16n8k16.row.col.f32.f16.f16.f32 "
        "{%0,%1,%2,%3}, {%4,%5,%6,%7}, {%8,%9}, {%0,%1,%2,%3};"
        : "+f"(d[0]), "+f"(d[1]), "+f"(d[2]), "+f"(d[3])
        : "r"(a[0]), "r"(a[1]), "r"(a[2]), "r"(a[3]), "r"(b0), "r"(b1));
}
__device__ __forceinline__ void mma16816(float* d, const uint32_t* a, uint32_t b0, uint32_t b1) {
    asm volatile("mma.sync.aligned.m16n8k16.row.col.f32.bf16.bf16.f32 "
        "{%0,%1,%2,%3}, {%4,%5,%6,%7}, {%8,%9}, {%0,%1,%2,%3};"
        : "+f"(d[0]), "+f"(d[1]), "+f"(d[2]), "+f"(d[3])
        : "r"(a[0]), "r"(a[1]), "r"(a[2]), "r"(a[3]), "r"(b0), "r"(b1));
}
__device__ __forceinline__ uint32_t pack_bf2(float a, float b) {
    uint16_t ua = __bfloat16_as_ushort(__float2bfloat16(a));
    uint16_t ub = __bfloat16_as_ushort(__float2bfloat16(b));
    return (uint32_t)ua | ((uint32_t)ub << 16);
}
__device__ __forceinline__ uint32_t pack_h2(float a, float b) {
    uint16_t ua = __half_as_ushort(__float2half_rn(a));
    uint16_t ub = __half_as_ushort(__float2half_rn(b));
    return (uint32_t)ua | ((uint32_t)ub << 16);
}
__device__ __forceinline__ void split2u(float a, float b, uint32_t& hp, uint32_t& mp) {
    float ha = __bfloat162float(__float2bfloat16(a));
    float hb = __bfloat162float(__float2bfloat16(b));
    hp = pack_bf2(ha, hb);
    mp = pack_bf2(a - ha, b - hb);
}

// ================= merged fp16 2-limb split (all 4 tensors, one launch) =================
__device__ __forceinline__ void split8(const float* __restrict__ x,
                                       __half* __restrict__ hi, __half* __restrict__ mid,
                                       int i, float scale) {
    float4 v0 = *(const float4*)(x + i);
    float4 v1 = *(const float4*)(x + i + 4);
    float a[8] = {v0.x, v0.y, v0.z, v0.w, v1.x, v1.y, v1.z, v1.w};
    float hf[8], mf[8];
#pragma unroll
    for (int j = 0; j < 8; j++) {
        float s = a[j] * scale;
        float h = __half2float(__float2half_rn(s));
        hf[j] = h; mf[j] = s - h;
    }
    *(uint4*)(hi + i) = make_uint4(pack_h2(hf[0], hf[1]), pack_h2(hf[2], hf[3]),
                                   pack_h2(hf[4], hf[5]), pack_h2(hf[6], hf[7]));
    *(uint4*)(mid + i) = make_uint4(pack_h2(mf[0], mf[1]), pack_h2(mf[2], mf[3]),
                                    pack_h2(mf[4], mf[5]), pack_h2(mf[6], mf[7]));
}

__global__ void split_all_kernel(const float* __restrict__ q,
                                 const float* __restrict__ wqk,
                                 const float* __restrict__ wv,
                                 const float* __restrict__ wo,
                                 __half* __restrict__ asp,
                                 __half* __restrict__ wqkv,
                                 __half* __restrict__ wout) {
    int bid = blockIdx.x;
    int li = threadIdx.x * 8;
    const int NW = 1024 * 1024;
    if (bid < 4096) {                      // activations (8192x1024), scale 1
        int i = bid * 2048 + li;
        split8(q, asp, asp + APL, i, 1.0f);
    } else if (bid < 4608) {               // Wqk rows [0,1024)
        int i = (bid - 4096) * 2048 + li;
        split8(wqk, wqkv, wqkv + WQKV_PL, i, WSCALE);
    } else if (bid < 5120) {               // Wv rows [1024,2048)
        int i = (bid - 4608) * 2048 + li;
        split8(wv, wqkv + NW, wqkv + WQKV_PL + NW, i, WSCALE);
    } else {                               // Wout
        int i = (bid - 5120) * 2048 + li;
        split8(wo, wout, wout + WOUT_PL, i, WSCALE);
    }
}

// ================= HMMA GEMM body (fp16 limbs, small->large pass order) =================
#define ROWB     80
#define MATB     (128 * ROWB)
#define STAGEB   (2 * MATB)
#define GEMM_SMEM (4 * STAGEB)   // 81920
#define PA4 0x0101u
#define PW4 0x0011u
#define PA3 0x010u
#define PW3 0x001u

__device__ __forceinline__ void gemm_issue(uint32_t st,
        const __half* Ap, const __half* Bp, int bm, int bn, int k0,
        uint32_t so0, uint32_t so1, int r0, int c0, int r1, int c1) {
    CP_ASYNC16(st + so0, Ap + (size_t)(bm + r0) * Kdim + k0 + c0 * 8);
    CP_ASYNC16(st + so1, Ap + (size_t)(bm + r1) * Kdim + k0 + c1 * 8);
    CP_ASYNC16(st + MATB + so0, Bp + (size_t)(bn + r0) * Kdim + k0 + c0 * 8);
    CP_ASYNC16(st + MATB + so1, Bp + (size_t)(bn + r1) * Kdim + k0 + c1 * 8);
    CP_COMMIT();
}

__device__ __forceinline__ void gemm_body(char* smem,
        const __half* __restrict__ Asp, size_t Apl,
        const __half* __restrict__ Bsp, size_t Bpl,
        const float* __restrict__ bias, float* __restrict__ outp,
        float* __restrict__ headout, int npass, uint32_t paTbl, uint32_t pwTbl,
        int bn, int bm) {
    uint32_t sbase = smem_to_u32(smem);
    int tid = threadIdx.x;
    int lane = tid & 31, warp = tid >> 5;
    int wm = warp >> 2, wn = warp & 3;
    int nstage = npass * 32;

    int v0 = tid, v1 = tid + 256;
    int r0 = v0 >> 2, c0 = v0 & 3;
    int r1 = v1 >> 2, c1 = v1 & 3;
    uint32_t so0 = (uint32_t)(r0 * ROWB + c0 * 16);
    uint32_t so1 = (uint32_t)(r1 * ROWB + c1 * 16);

    uint32_t aoff = (uint32_t)((wm * 64 + (lane & 15)) * ROWB + (lane >> 4) * 16);
    uint32_t boff = (uint32_t)((wn * 32 + ((lane >> 4) & 1) * 8 + (lane & 7)) * ROWB
                               + ((lane >> 3) & 1) * 16);

    float D[4][4][4];
#pragma unroll
    for (int i = 0; i < 4; i++)
#pragma unroll
        for (int j = 0; j < 4; j++)
#pragma unroll
            for (int q = 0; q < 4; q++) D[i][j][q] = 0.f;

#pragma unroll
    for (int s = 0; s < 3; s++) {
        const __half* Ap = Asp + (size_t)(paTbl & 7) * Apl;
        const __half* Bp = Bsp + (size_t)(pwTbl & 7) * Bpl;
        gemm_issue(sbase + s * STAGEB, Ap, Bp, bm, bn, s * 32, so0, so1, r0, c0, r1, c1);
    }

    for (int s = 0; s < nstage; s++) {
        if (s <= nstage - 3)      { CP_WAIT(2); }
        else if (s == nstage - 2) { CP_WAIT(1); }
        else                      { CP_WAIT(0); }
        __syncthreads();
        if (s + 3 < nstage) {
            int sn = s + 3;
            int p = sn >> 5, k0 = (sn & 31) << 5;
            const __half* Ap = Asp + (size_t)((paTbl >> (p * 4)) & 7) * Apl;
            const __half* Bp = Bsp + (size_t)((pwTbl >> (p * 4)) & 7) * Bpl;
            gemm_issue(sbase + (uint32_t)(sn & 3) * STAGEB, Ap, Bp, bm, bn, k0,
                       so0, so1, r0, c0, r1, c1);
        }
        uint32_t st = sbase + (uint32_t)(s & 3) * STAGEB;
        uint32_t ab = st + aoff;
        uint32_t bb = st + MATB + boff;
#pragma unroll
        for (int ks = 0; ks < 2; ks++) {
            uint32_t A4[4][4], B4[2][4];
#pragma unroll
            for (int i = 0; i < 4; i++) ldmx4(A4[i], ab + i * (16 * ROWB) + ks * 32);
#pragma unroll
            for (int jp = 0; jp < 2; jp++) ldmx4(B4[jp], bb + jp * (16 * ROWB) + ks * 32);
#pragma unroll
            for (int i = 0; i < 4; i++)
#pragma unroll
                for (int jn = 0; jn < 4; jn++)
                    mma16816h(D[i][jn], A4[i], B4[jn >> 1][(jn & 1) * 2], B4[jn >> 1][(jn & 1) * 2 + 1]);
        }
    }

    int g = lane >> 2, t = lane & 3;
#pragma unroll
    for (int i = 0; i < 4; i++) {
#pragma unroll
        for (int jn = 0; jn < 4; jn++) {
            int m0 = bm + wm * 64 + i * 16 + g;
            int n0 = bn + wn * 32 + jn * 8 + t * 2;
            float2 va = make_float2(D[i][jn][0] * OSCALE, D[i][jn][1] * OSCALE);
            float2 vb = make_float2(D[i][jn][2] * OSCALE, D[i][jn][3] * OSCALE);
            if (headout) {
                int bI = m0 >> 12;
                int t0 = m0 & 4095, t1 = (m0 + 8) & 4095;
                int hd = n0 >> 6, dh = n0 & 63;
                *(float2*)(headout + (((size_t)(bI * Hh + hd)) * Nn + t0) * DHd + dh) = va;
                *(float2*)(headout + (((size_t)(bI * Hh + hd)) * Nn + t1) * DHd + dh) = vb;
            } else {
                float2 bv = *(const float2*)(bias + n0);
                va.x += bv.x; va.y += bv.y; vb.x += bv.x; vb.y += bv.y;
                *(float2*)(outp + (size_t)m0 * Cc + n0) = va;
                *(float2*)(outp + (size_t)(m0 + 8) * Cc + n0) = vb;
            }
        }
    }
}

__global__ __launch_bounds__(256, 2) void mma_gemm(
        const __half* __restrict__ Asp, size_t Apl,
        const __half* __restrict__ Bsp, size_t Bpl,
        const float* __restrict__ bias, float* __restrict__ outp,
        float* __restrict__ headout, int npass, uint32_t paTbl, uint32_t pwTbl) {
    extern __shared__ char smem[];
    gemm_body(smem, Asp, Apl, Bsp, Bpl, bias, outp, headout, npass, paTbl, pwTbl,
              blockIdx.x * 128, blockIdx.y * 128);
}

// ---------------- LSH bucketing body (256 threads) ----------------
__device__ __forceinline__ void bucket_body(char* smemc, const float* __restrict__ rot,
                                            int bh, int tb) {
    float* rs = (float*)smemc;
    float* qs = rs + DHd * 128;
    int tid = threadIdx.x;

    for (int i = tid; i < DHd * 128; i += 256) rs[i] = rot[i];
    {
        int row = tid >> 2, seg = tid & 3;
        const float* src = g_qk + ((size_t)bh * Nn + tb + row) * DHd + seg * 16;
#pragma unroll
        for (int k = 0; k < 16; k++) qs[row * 65 + seg * 16 + k] = src[k];
    }
    __syncthreads();

    int warp = tid >> 5, lane = tid & 31;
    int h = warp & 3;
    int tok = (warp >> 2) * 32 + lane;

    float r[32];
#pragma unroll
    for (int i = 0; i < 32; i++) r[i] = 0.f;
    for (int d = 0; d < DHd; d++) {
        float qd = qs[tok * 65 + d];
        const float* rp = rs + d * 128 + h * 32;
#pragma unroll
        for (int i = 0; i < 32; i++) r[i] += qd * rp[i];
    }
    float best = r[0]; int bi = 0;
#pragma unroll
    for (int i = 1; i < 32; i++) if (r[i] > best) { best = r[i]; bi = i; }
#pragma unroll
    for (int i = 0; i < 32; i++) if (-r[i] > best) { best = -r[i]; bi = 32 + i; }
    g_bucket[((size_t)bh * NHASH + h) * Nn + tb + tok] = bi;
}

// ---------------- fused: v GEMM (blocks x<8) + bucketing (x>=8, y<32) ----------------
__global__ __launch_bounds__(256, 2) void vgemm_bucket(
        const __half* __restrict__ Asp, size_t Apl,
        const __half* __restrict__ Bsp, size_t Bpl,
        float* __restrict__ headout, const float* __restrict__ rot) {
    extern __shared__ char smem[];
    if (blockIdx.x < 8) {
        gemm_body(smem, Asp, Apl, Bsp, Bpl, nullptr, nullptr, headout, 3, PA3, PW3,
                  blockIdx.x * 128, blockIdx.y * 128);
    } else if (blockIdx.y < 32) {
        bucket_body(smem, rot, blockIdx.y, (blockIdx.x - 8) * 64);
    }
}

// ---------------- parallel stable counting sort per (bh, hash) ----------------
// 256 threads; thread = 16-token segment. Per-seg histograms -> per-bucket
// prefix over segs -> exact stable scatter.
#define SORT_SMEM 49152   // cnt u8[256][64] + segoff u16[256][64]
__global__ void sort_kernel() {
    extern __shared__ char ss[];
    unsigned char*  cnt    = (unsigned char*)ss;              // [seg][bucket]
    unsigned short* segoff = (unsigned short*)(ss + 16384);   // [seg][bucket]
    __shared__ int bbase[NBUCK];
    int bh = blockIdx.x, h = blockIdx.y;
    int tid = threadIdx.x;
    const int gb = (bh * NHASH + h) * Nn;

    uint32_t* ci = (uint32_t*)cnt;
    for (int i = tid; i < 4096; i += 256) ci[i] = 0;
    __syncthreads();

    int bb[16];
#pragma unroll
    for (int k = 0; k < 16; k++) {
        int b = g_bucket[gb + tid * 16 + k];
        bb[k] = b;
        cnt[tid * 64 + b]++;
    }
    __syncthreads();

    if (tid < NBUCK) {
        int run = 0;
        for (int seg = 0; seg < 256; seg++) {
            segoff[seg * 64 + tid] = (unsigned short)run;
            run += cnt[seg * 64 + tid];
        }
        bbase[tid] = run;
    }
    __syncthreads();
    if (tid == 0) {
        int acc = 0;
        for (int b = 0; b < NBUCK; b++) { int c = bbase[b]; bbase[b] = acc; acc += c; }
    }
    __syncthreads();

#pragma unroll
    for (int k = 0; k < 16; k++) {
        int b = bb[k];
        int pos = bbase[b] + segoff[tid * 64 + b];
        segoff[tid * 64 + b]++;
        g_st[gb + pos] = tid * 16 + k;
    }
}

// ---------------- chunked LSH attention: HMMA 2-limb, no-max softmax ----------------
#define AT_KHI   3072
#define AT_KMID  21504
#define AT_VHI   39936
#define AT_VMID  58368
#define AT_QHI   76800
#define AT_QMID  86016
#define AT_PHI   76800
#define AT_PMID  94208
#define ATTN_SMEM_BYTES 111616

__global__ __launch_bounds__(256, 2) void attn_kernel() {
    extern __shared__ char sm[];
    int*   tkv     = (int*)sm;
    float* rsump   = (float*)(sm + 1536);
    float* rsuminv = (float*)(sm + 2560);
    uint32_t sb = smem_to_u32(sm);

    int c = blockIdx.x, bh = blockIdx.y;
    int h = c >> 6;
    int tid = threadIdx.x, lane = tid & 31, warp = tid >> 5;
    int g = lane >> 2, t = lane & 3;
    int wm = warp >> 2, wn = warp & 3;
    int pc = (c + NCHUNK - 1) & (NCHUNK - 1);
    const int stb = bh * (NHASH * Nn);

    if (tid < 64)       tkv[tid] = g_st[stb + c * BS + tid];
    else if (tid < 128) tkv[tid] = g_st[stb + pc * BS + (tid - 64)];
    __syncthreads();

    // gather v -> limbs
    {
        int j = tid >> 1, seg = tid & 1;
        const float* src = g_v + ((size_t)bh * Nn + tkv[j]) * DHd + seg * 32;
        char* dh_ = sm + AT_VHI + j * 144 + seg * 64;
        char* dm_ = sm + AT_VMID + j * 144 + seg * 64;
#pragma unroll
        for (int k4 = 0; k4 < 8; k4++) {
            float4 v = *(const float4*)(src + k4 * 4);
            uint32_t h0, m0, h1, m1;
            split2u(v.x, v.y, h0, m0);
            split2u(v.z, v.w, h1, m1);
            *(uint32_t*)(dh_ + k4 * 8)     = h0;
            *(uint32_t*)(dh_ + k4 * 8 + 4) = h1;
            *(uint32_t*)(dm_ + k4 * 8)     = m0;
            *(uint32_t*)(dm_ + k4 * 8 + 4) = m1;
        }
    }
    // gather k rows (q rows 0-63 derived here too: q = raw * 0.125, k = normalized)
    for (int rr = 0; rr < 16; rr++) {
        int j = warp * 16 + rr;
        const float* src = g_qk + ((size_t)bh * Nn + tkv[j]) * DHd;
        float a = src[lane], b = src[lane + 32];
        if (warp < 4) {   // j < 64: also emit q limbs (pre-scaled by 0.125, pre-norm)
            float qa = a * 0.125f, qb = b * 0.125f;
            float qah = __bfloat162float(__float2bfloat16(qa));
            float qbh = __bfloat162float(__float2bfloat16(qb));
            *(__nv_bfloat16*)(sm + AT_QHI + j * 144 + lane * 2)       = __float2bfloat16(qah);
            *(__nv_bfloat16*)(sm + AT_QHI + j * 144 + 64 + lane * 2)  = __float2bfloat16(qbh);
            *(__nv_bfloat16*)(sm + AT_QMID + j * 144 + lane * 2)      = __float2bfloat16(qa - qah);
            *(__nv_bfloat16*)(sm + AT_QMID + j * 144 + 64 + lane * 2) = __float2bfloat16(qb - qbh);
        }
        float s = a * a + b * b;
#pragma unroll
        for (int o = 16; o > 0; o >>= 1) s += __shfl_xor_sync(0xffffffffu, s, o);
        float inv = 1.0f / fmaxf(sqrtf(s), 1e-12f);
        float ka = a * inv, kb = b * inv;
        float kah = __bfloat162float(__float2bfloat16(ka));
        float kbh = __bfloat162float(__float2bfloat16(kb));
        *(__nv_bfloat16*)(sm + AT_KHI + j * 144 + lane * 2)       = __float2bfloat16(kah);
        *(__nv_bfloat16*)(sm + AT_KHI + j * 144 + 64 + lane * 2)  = __float2bfloat16(kbh);
        *(__nv_bfloat16*)(sm + AT_KMID + j * 144 + lane * 2)      = __float2bfloat16(ka - kah);
        *(__nv_bfloat16*)(sm + AT_KMID + j * 144 + 64 + lane * 2) = __float2bfloat16(kb - kbh);
    }
    __syncthreads();

    // dots MMA
    float Dd[2][4][4];
#pragma unroll
    for (int i = 0; i < 2; i++)
#pragma unroll
        for (int jn = 0; jn < 4; jn++)
#pragma unroll
            for (int q = 0; q < 4; q++) Dd[i][jn][q] = 0.f;

    uint32_t arow = (uint32_t)((wm * 32 + (lane & 15)) * 144 + (lane >> 4) * 16);
    uint32_t brow = (uint32_t)((wn * 32 + ((lane >> 4) & 1) * 8 + (lane & 7)) * 144
                               + ((lane >> 3) & 1) * 16);
    const uint32_t QL[3] = {sb + AT_QMID, sb + AT_QHI, sb + AT_QHI};
    const uint32_t KL[3] = {sb + AT_KHI, sb + AT_KMID, sb + AT_KHI};
#pragma unroll
    for (int p = 0; p < 3; p++) {
#pragma unroll
        for (int ks = 0; ks < 4; ks++) {
            uint32_t A4[2][4], B4[2][4];
#pragma unroll
            for (int i = 0; i < 2; i++) ldmx4(A4[i], QL[p] + arow + i * (16 * 144) + ks * 32);
#pragma unroll
            for (int jp = 0; jp < 2; jp++) ldmx4(B4[jp], KL[p] + brow + jp * (16 * 144) + ks * 32);
#pragma unroll
            for (int i = 0; i < 2; i++)
#pragma unroll
                for (int jn = 0; jn < 4; jn++)
                    mma16816(Dd[i][jn], A4[i], B4[jn >> 1][(jn & 1) * 2], B4[jn >> 1][(jn & 1) * 2 + 1]);
        }
    }

    // mask
    int trow[4] = { tkv[wm * 32 + g], tkv[wm * 32 + g + 8],
                    tkv[wm * 32 + 16 + g], tkv[wm * 32 + 16 + g + 8] };
    int tcol[8];
#pragma unroll
    for (int jn = 0; jn < 4; jn++) {
        int c0 = wn * 32 + jn * 8 + t * 2;
        tcol[jn * 2] = tkv[c0]; tcol[jn * 2 + 1] = tkv[c0 + 1];
    }
#pragma unroll
    for (int i = 0; i < 2; i++)
#pragma unroll
        for (int jn = 0; jn < 4; jn++)
#pragma unroll
            for (int q = 0; q < 4; q++)
                if (trow[i * 2 + (q >> 1)] == tcol[jn * 2 + (q & 1)]) Dd[i][jn][q] = -5e4f;

    // barrier: all warps done reading Q region before P stores overwrite it
    __syncthreads();

    // exp (unshifted; dots bounded, masked underflows to 0) -> P limbs + partial sums
    float ps[4] = {0.f, 0.f, 0.f, 0.f};
#pragma unroll
    for (int i = 0; i < 2; i++) {
        int r0 = wm * 32 + i * 16 + g;
#pragma unroll
        for (int jn = 0; jn < 4; jn++) {
            float e0 = __expf(Dd[i][jn][0]);
            float e1 = __expf(Dd[i][jn][1]);
            float e2 = __expf(Dd[i][jn][2]);
            float e3 = __expf(Dd[i][jn][3]);
            ps[i * 2] += e0 + e1;
            ps[i * 2 + 1] += e2 + e3;
            int c0 = wn * 32 + jn * 8 + t * 2;
            uint32_t h0, m0, h1, m1;
            split2u(e0, e1, h0, m0);
            split2u(e2, e3, h1, m1);
            *(uint32_t*)(sm + AT_PHI  + r0 * 272 + c0 * 2)       = h0;
            *(uint32_t*)(sm + AT_PMID + r0 * 272 + c0 * 2)       = m0;
            *(uint32_t*)(sm + AT_PHI  + (r0 + 8) * 272 + c0 * 2) = h1;
            *(uint32_t*)(sm + AT_PMID + (r0 + 8) * 272 + c0 * 2) = m1;
        }
    }
#pragma unroll
    for (int k = 0; k < 4; k++) {
        ps[k] += __shfl_xor_sync(0xffffffffu, ps[k], 1);
        ps[k] += __shfl_xor_sync(0xffffffffu, ps[k], 2);
    }
    if (t == 0) {
#pragma unroll
        for (int k = 0; k < 4; k++)
            rsump[(wm * 32 + (k >> 1) * 16 + g + (k & 1) * 8) * 4 + wn] = ps[k];
    }
    __syncthreads();

    if (tid < 64) {
        const float* p = rsump + tid * 4;
        float s = p[0] + p[1] + p[2] + p[3];
        rsuminv[tid] = 1.0f / s;
        g_lse[(bh * NHASH + h) * Nn + tkv[tid]] = logf(s);
    }
    __syncthreads();

    // PV MMA
    float Dp[2][2][4];
#pragma unroll
    for (int i = 0; i < 2; i++)
#pragma unroll
        for (int jn = 0; jn < 2; jn++)
#pragma unroll
            for (int q = 0; q < 4; q++) Dp[i][jn][q] = 0.f;

    uint32_t parow = (uint32_t)((wm * 32 + (lane & 15)) * 272 + (lane >> 4) * 16);
    uint32_t vbrow = (uint32_t)((lane & 15) * 144 + (lane >> 4) * 16 + wn * 32);
    const uint32_t PL[3] = {sb + AT_PMID, sb + AT_PHI, sb + AT_PHI};
    const uint32_t VL[3] = {sb + AT_VHI, sb + AT_VMID, sb + AT_VHI};
#pragma unroll
    for (int p = 0; p < 3; p++) {
#pragma unroll
        for (int ks = 0; ks < 8; ks++) {
            uint32_t A4[2][4], B4[4];
#pragma unroll
            for (int i = 0; i < 2; i++) ldmx4(A4[i], PL[p] + parow + i * (16 * 272) + ks * 32);
            ldmx4t(B4, VL[p] + vbrow + ks * (16 * 144));
#pragma unroll
            for (int i = 0; i < 2; i++)
#pragma unroll
                for (int jn = 0; jn < 2; jn++)
                    mma16816(Dp[i][jn], A4[i], B4[jn * 2], B4[jn * 2 + 1]);
        }
    }

    // epilogue: normalize + scatter
#pragma unroll
    for (int i = 0; i < 2; i++) {
        int r0 = wm * 32 + i * 16 + g;
        float inv0 = rsuminv[r0], inv1 = rsuminv[r0 + 8];
        size_t b0 = ((size_t)(bh * NHASH + h) * Nn + trow[i * 2]) * DHd;
        size_t b1 = ((size_t)(bh * NHASH + h) * Nn + trow[i * 2 + 1]) * DHd;
#pragma unroll
        for (int jn = 0; jn < 2; jn++) {
            int dh = wn * 16 + jn * 8 + t * 2;
            *(float2*)(g_oph + b0 + dh) = make_float2(Dp[i][jn][0] * inv0, Dp[i][jn][1] * inv0);
            *(float2*)(g_oph + b1 + dh) = make_float2(Dp[i][jn][2] * inv1, Dp[i][jn][3] * inv1);
        }
    }
}

// ---------------- fused combine + fp16 2-limb split ----------------
__global__ void combine_split_kernel(__half* __restrict__ hi, __half* __restrict__ mid) {
    int u = blockIdx.x * 256 + threadIdx.x;
    int slot = u >> 3;
    int dseg = (u & 7) * 8;
    int bh = slot >> 12;
    int t = slot & 4095;
    int base = bh * NHASH * Nn + t;
    float l0 = g_lse[base + 0 * Nn];
    float l1 = g_lse[base + 1 * Nn];
    float l2 = g_lse[base + 2 * Nn];
    float l3 = g_lse[base + 3 * Nn];
    float m = fmaxf(fmaxf(l0, l1), fmaxf(l2, l3));
    float w[4] = {expf(l0 - m), expf(l1 - m), expf(l2 - m), expf(l3 - m)};
    float sinv = 1.0f / (w[0] + w[1] + w[2] + w[3]);

    float acc[8];
#pragma unroll
    for (int j = 0; j < 8; j++) acc[j] = 0.f;
#pragma unroll
    for (int k = 0; k < 4; k++) {
        const float4* p = (const float4*)(g_oph + (((size_t)(bh * NHASH + k)) * Nn + t) * DHd + dseg);
        float4 x0 = p[0], x1 = p[1];
        acc[0] += w[k] * x0.x; acc[1] += w[k] * x0.y; acc[2] += w[k] * x0.z; acc[3] += w[k] * x0.w;
        acc[4] += w[k] * x1.x; acc[5] += w[k] * x1.y; acc[6] += w[k] * x1.z; acc[7] += w[k] * x1.w;
    }
    float hf[8], mf[8];
#pragma unroll
    for (int j = 0; j < 8; j++) {
        float a = acc[j] * sinv;
        float h = __half2float(__float2half_rn(a));
        hf[j] = h; mf[j] = a - h;
    }
    int b = bh >> 4, head = bh & 15;
    size_t oidx = ((size_t)b * Nn + t) * Cc + head * DHd + dseg;
    *(uint4*)(hi + oidx) = make_uint4(pack_h2(hf[0], hf[1]), pack_h2(hf[2], hf[3]),
                                      pack_h2(hf[4], hf[5]), pack_h2(hf[6], hf[7]));
    *(uint4*)(mid + oidx) = make_uint4(pack_h2(mf[0], mf[1]), pack_h2(mf[2], mf[3]),
                                       pack_h2(mf[4], mf[5]), pack_h2(mf[6], mf[7]));
}

// ---------------- launch ----------------
extern "C" void kernel_launch(void* const* d_in, const int* in_sizes, int n_in,
                              void* d_out, int out_size) {
    const float* queries = (const float*)d_in[0];
    const float* Wqk  = (const float*)d_in[4];
    const float* Wv   = (const float*)d_in[5];
    const float* Wout = (const float*)d_in[6];
    const float* bout = (const float*)d_in[7];
    const float* rot  = (const float*)d_in[8];
    float* out = (float*)d_out;

    cudaFuncSetAttribute(attn_kernel, cudaFuncAttributeMaxDynamicSharedMemorySize, ATTN_SMEM_BYTES);
    cudaFuncSetAttribute(mma_gemm, cudaFuncAttributeMaxDynamicSharedMemorySize, GEMM_SMEM);
    cudaFuncSetAttribute(vgemm_bucket, cudaFuncAttributeMaxDynamicSharedMemorySize, GEMM_SMEM);
    cudaFuncSetAttribute(sort_kernel, cudaFuncAttributeMaxDynamicSharedMemorySize, SORT_SMEM);

    void *p_qk, *p_v, *p_asp, *p_wqkv, *p_wout;
    cudaGetSymbolAddress(&p_qk, g_qk);
    cudaGetSymbolAddress(&p_v, g_v);
    cudaGetSymbolAddress(&p_asp, g_asp);
    cudaGetSymbolAddress(&p_wqkv, g_wqkv_sp);
    cudaGetSymbolAddress(&p_wout, g_wout_sp);
    __half* asp  = (__half*)p_asp;
    __half* wqkv = (__half*)p_wqkv;
    __half* wout = (__half*)p_wout;
    const int NW = 1024 * 1024;

    // all 4 limb splits in one launch
    split_all_kernel<<<5632, 256>>>(queries, Wqk, Wv, Wout, asp, wqkv, wout);

    // qk GEMM: 4-pass fp16 (~2^-24, feeds LSH argmax)
    mma_gemm<<<dim3(8, 64), 256, GEMM_SMEM>>>(asp, APL, wqkv, WQKV_PL,
                                              nullptr, nullptr, (float*)p_qk, 4, PA4, PW4);

    // fused: v GEMM (3-pass fp16) overlapped with bucketing
    vgemm_bucket<<<dim3(72, 64), 256, GEMM_SMEM>>>(asp, APL, wqkv + NW, WQKV_PL,
                                                   (float*)p_v, rot);

    sort_kernel<<<dim3(BH, NHASH), 256, SORT_SMEM>>>();
    attn_kernel<<<dim3(NCHUNK, BH), 256, ATTN_SMEM_BYTES>>>();

    combine_split_kernel<<<(BH * Nn * DHd / 8) / 256, 256>>>(asp, asp + APL);

    // Wout GEMM: 3-pass fp16, +bias -> d_out
    mma_gemm<<<dim3(8, 64), 256, GEMM_SMEM>>>(asp, APL, wout, WOUT_PL,
                                              bout, out, nullptr, 3, PA3, PW3);
}

// round 11
// speedup vs baseline: 3.2231x; 1.1924x over previous
#include <cuda_runtime.h>
#include <cuda_fp16.h>
#include <cuda_bf16.h>
#include <math.h>
#include <stdint.h>

// ---------------- problem constants ----------------
#define Bb      2
#define Nn      4096
#define Cc      1024
#define Hh      16
#define DHd     64
#define BH      32          // Bb*Hh
#define NHASH   4
#define NBUCK   64          // Nn / BUCKET
#define NCHUNK  256         // NHASH*NBUCK
#define BS      64          // bucket size
#define Kdim    1024
#define Mrows   8192        // Bb*Nn

// ---------------- device scratch ----------------
__device__ float g_qk  [BH * Nn * DHd];            // (bh, t, d)
__device__ float g_v   [BH * Nn * DHd];
__device__ int   g_bucket[BH * NHASH * Nn];
__device__ int   g_st  [BH * NHASH * Nn];
__device__ __half g_oph2[BH * NHASH * Nn * DHd];   // per-hash outputs, fp16 (67 MB)
__device__ float g_lse [BH * NHASH * Nn];

// attention limb planes (bf16), prepared once per token
#define PLN ((size_t)BH * Nn * DHd)
__device__ __nv_bfloat16 g_qh[PLN], g_qm[PLN];     // q * 0.125 limbs
__device__ __nv_bfloat16 g_kh[PLN], g_km[PLN];     // normalized k limbs
__device__ __nv_bfloat16 g_vh[PLN], g_vm[PLN];     // v limbs

// fp16 2-limb planes for GEMMs (W-side pre-scaled by 64; epilogue x 1/64)
#define APL ((size_t)Mrows * Kdim)
#define WQKV_PL ((size_t)2048 * 1024)
#define WOUT_PL ((size_t)1024 * 1024)
__device__ __half g_asp[2 * APL];
__device__ __half g_wqkv_sp[2 * WQKV_PL];
__device__ __half g_wout_sp[2 * WOUT_PL];
#define WSCALE 64.0f
#define OSCALE (1.0f / 64.0f)

// ================= helpers (sm_103-safe) =================
__device__ __forceinline__ uint32_t smem_to_u32(const void* p) {
    uint32_t a;
    asm("{ .reg .u64 t; cvta.to.shared.u64 t, %1; cvt.u32.u64 %0, t; }" : "=r"(a) : "l"(p));
    return a;
}
#define CP_ASYNC16(saddr, gptr) \
    asm volatile("cp.async.cg.shared.global [%0], [%1], 16;" \
        :: "r"(saddr), "l"(__cvta_generic_to_global(gptr)))
#define CP_COMMIT() asm volatile("cp.async.commit_group;" ::: "memory")
#define CP_WAIT(n)  asm volatile("cp.async.wait_group %0;" :: "n"(n) : "memory")

__device__ __forceinline__ void ldmx4(uint32_t* r, uint32_t addr) {
    asm volatile("ldmatrix.sync.aligned.m8n8.x4.shared.b16 {%0,%1,%2,%3}, [%4];"
        : "=r"(r[0]), "=r"(r[1]), "=r"(r[2]), "=r"(r[3]) : "r"(addr));
}
__device__ __forceinline__ void ldmx4t(uint32_t* r, uint32_t addr) {
    asm volatile("ldmatrix.sync.aligned.m8n8.x4.trans.shared.b16 {%0,%1,%2,%3}, [%4];"
        : "=r"(r[0]), "=r"(r[1]), "=r"(r[2]), "=r"(r[3]) : "r"(addr));
}
__device__ __forceinline__ void mma16816h(float* d, const uint32_t* a, uint32_t b0, uint32_t b1) {
    asm volatile("mma.sync.aligned.m16n8k16.row.col.f32.f16.f16.f32 "
        "{%0,%1,%2,%3}, {%4,%5,%6,%7}, {%8,%9}, {%0,%1,%2,%3};"
        : "+f"(d[0]), "+f"(d[1]), "+f"(d[2]), "+f"(d[3])
        : "r"(a[0]), "r"(a[1]), "r"(a[2]), "r"(a[3]), "r"(b0), "r"(b1));
}
__device__ __forceinline__ void mma16816(float* d, const uint32_t* a, uint32_t b0, uint32_t b1) {
    asm volatile("mma.sync.aligned.m16n8k16.row.col.f32.bf16.bf16.f32 "
        "{%0,%1,%2,%3}, {%4,%5,%6,%7}, {%8,%9}, {%0,%1,%2,%3};"
        : "+f"(d[0]), "+f"(d[1]), "+f"(d[2]), "+f"(d[3])
        : "r"(a[0]), "r"(a[1]), "r"(a[2]), "r"(a[3]), "r"(b0), "r"(b1));
}
__device__ __forceinline__ uint32_t pack_bf2(float a, float b) {
    uint16_t ua = __bfloat16_as_ushort(__float2bfloat16(a));
    uint16_t ub = __bfloat16_as_ushort(__float2bfloat16(b));
    return (uint32_t)ua | ((uint32_t)ub << 16);
}
__device__ __forceinline__ uint32_t pack_h2(float a, float b) {
    uint16_t ua = __half_as_ushort(__float2half_rn(a));
    uint16_t ub = __half_as_ushort(__float2half_rn(b));
    return (uint32_t)ua | ((uint32_t)ub << 16);
}
__device__ __forceinline__ void split2u(float a, float b, uint32_t& hp, uint32_t& mp) {
    float ha = __bfloat162float(__float2bfloat16(a));
    float hb = __bfloat162float(__float2bfloat16(b));
    hp = pack_bf2(ha, hb);
    mp = pack_bf2(a - ha, b - hb);
}

// ================= merged fp16 2-limb split (all 4 GEMM tensors) =================
__device__ __forceinline__ void split8(const float* __restrict__ x,
                                       __half* __restrict__ hi, __half* __restrict__ mid,
                                       int i, float scale) {
    float4 v0 = *(const float4*)(x + i);
    float4 v1 = *(const float4*)(x + i + 4);
    float a[8] = {v0.x, v0.y, v0.z, v0.w, v1.x, v1.y, v1.z, v1.w};
    float hf[8], mf[8];
#pragma unroll
    for (int j = 0; j < 8; j++) {
        float s = a[j] * scale;
        float h = __half2float(__float2half_rn(s));
        hf[j] = h; mf[j] = s - h;
    }
    *(uint4*)(hi + i) = make_uint4(pack_h2(hf[0], hf[1]), pack_h2(hf[2], hf[3]),
                                   pack_h2(hf[4], hf[5]), pack_h2(hf[6], hf[7]));
    *(uint4*)(mid + i) = make_uint4(pack_h2(mf[0], mf[1]), pack_h2(mf[2], mf[3]),
                                    pack_h2(mf[4], mf[5]), pack_h2(mf[6], mf[7]));
}

__global__ void split_all_kernel(const float* __restrict__ q,
                                 const float* __restrict__ wqk,
                                 const float* __restrict__ wv,
                                 const float* __restrict__ wo,
                                 __half* __restrict__ asp,
                                 __half* __restrict__ wqkv,
                                 __half* __restrict__ wout) {
    int bid = blockIdx.x;
    int li = threadIdx.x * 8;
    const int NW = 1024 * 1024;
    if (bid < 4096) {
        int i = bid * 2048 + li;
        split8(q, asp, asp + APL, i, 1.0f);
    } else if (bid < 4608) {
        int i = (bid - 4096) * 2048 + li;
        split8(wqk, wqkv, wqkv + WQKV_PL, i, WSCALE);
    } else if (bid < 5120) {
        int i = (bid - 4608) * 2048 + li;
        split8(wv, wqkv + NW, wqkv + WQKV_PL + NW, i, WSCALE);
    } else {
        int i = (bid - 5120) * 2048 + li;
        split8(wo, wout, wout + WOUT_PL, i, WSCALE);
    }
}

// ================= HMMA GEMM body (fp16 limbs) =================
#define ROWB     80
#define MATB     (128 * ROWB)
#define STAGEB   (2 * MATB)
#define GEMM_SMEM (4 * STAGEB)   // 81920
#define PA4 0x0101u
#define PW4 0x0011u
#define PA3 0x010u
#define PW3 0x001u

__device__ __forceinline__ void gemm_issue(uint32_t st,
        const __half* Ap, const __half* Bp, int bm, int bn, int k0,
        uint32_t so0, uint32_t so1, int r0, int c0, int r1, int c1) {
    CP_ASYNC16(st + so0, Ap + (size_t)(bm + r0) * Kdim + k0 + c0 * 8);
    CP_ASYNC16(st + so1, Ap + (size_t)(bm + r1) * Kdim + k0 + c1 * 8);
    CP_ASYNC16(st + MATB + so0, Bp + (size_t)(bn + r0) * Kdim + k0 + c0 * 8);
    CP_ASYNC16(st + MATB + so1, Bp + (size_t)(bn + r1) * Kdim + k0 + c1 * 8);
    CP_COMMIT();
}

__device__ __forceinline__ void gemm_body(char* smem,
        const __half* __restrict__ Asp, size_t Apl,
        const __half* __restrict__ Bsp, size_t Bpl,
        const float* __restrict__ bias, float* __restrict__ outp,
        float* __restrict__ headout, int npass, uint32_t paTbl, uint32_t pwTbl,
        int bn, int bm) {
    uint32_t sbase = smem_to_u32(smem);
    int tid = threadIdx.x;
    int lane = tid & 31, warp = tid >> 5;
    int wm = warp >> 2, wn = warp & 3;
    int nstage = npass * 32;

    int v0 = tid, v1 = tid + 256;
    int r0 = v0 >> 2, c0 = v0 & 3;
    int r1 = v1 >> 2, c1 = v1 & 3;
    uint32_t so0 = (uint32_t)(r0 * ROWB + c0 * 16);
    uint32_t so1 = (uint32_t)(r1 * ROWB + c1 * 16);

    uint32_t aoff = (uint32_t)((wm * 64 + (lane & 15)) * ROWB + (lane >> 4) * 16);
    uint32_t boff = (uint32_t)((wn * 32 + ((lane >> 4) & 1) * 8 + (lane & 7)) * ROWB
                               + ((lane >> 3) & 1) * 16);

    float D[4][4][4];
#pragma unroll
    for (int i = 0; i < 4; i++)
#pragma unroll
        for (int j = 0; j < 4; j++)
#pragma unroll
            for (int q = 0; q < 4; q++) D[i][j][q] = 0.f;

#pragma unroll
    for (int s = 0; s < 3; s++) {
        const __half* Ap = Asp + (size_t)(paTbl & 7) * Apl;
        const __half* Bp = Bsp + (size_t)(pwTbl & 7) * Bpl;
        gemm_issue(sbase + s * STAGEB, Ap, Bp, bm, bn, s * 32, so0, so1, r0, c0, r1, c1);
    }

    for (int s = 0; s < nstage; s++) {
        if (s <= nstage - 3)      { CP_WAIT(2); }
        else if (s == nstage - 2) { CP_WAIT(1); }
        else                      { CP_WAIT(0); }
        __syncthreads();
        if (s + 3 < nstage) {
            int sn = s + 3;
            int p = sn >> 5, k0 = (sn & 31) << 5;
            const __half* Ap = Asp + (size_t)((paTbl >> (p * 4)) & 7) * Apl;
            const __half* Bp = Bsp + (size_t)((pwTbl >> (p * 4)) & 7) * Bpl;
            gemm_issue(sbase + (uint32_t)(sn & 3) * STAGEB, Ap, Bp, bm, bn, k0,
                       so0, so1, r0, c0, r1, c1);
        }
        uint32_t st = sbase + (uint32_t)(s & 3) * STAGEB;
        uint32_t ab = st + aoff;
        uint32_t bb = st + MATB + boff;
#pragma unroll
        for (int ks = 0; ks < 2; ks++) {
            uint32_t A4[4][4], B4[2][4];
#pragma unroll
            for (int i = 0; i < 4; i++) ldmx4(A4[i], ab + i * (16 * ROWB) + ks * 32);
#pragma unroll
            for (int jp = 0; jp < 2; jp++) ldmx4(B4[jp], bb + jp * (16 * ROWB) + ks * 32);
#pragma unroll
            for (int i = 0; i < 4; i++)
#pragma unroll
                for (int jn = 0; jn < 4; jn++)
                    mma16816h(D[i][jn], A4[i], B4[jn >> 1][(jn & 1) * 2], B4[jn >> 1][(jn & 1) * 2 + 1]);
        }
    }

    int g = lane >> 2, t = lane & 3;
#pragma unroll
    for (int i = 0; i < 4; i++) {
#pragma unroll
        for (int jn = 0; jn < 4; jn++) {
            int m0 = bm + wm * 64 + i * 16 + g;
            int n0 = bn + wn * 32 + jn * 8 + t * 2;
            float2 va = make_float2(D[i][jn][0] * OSCALE, D[i][jn][1] * OSCALE);
            float2 vb = make_float2(D[i][jn][2] * OSCALE, D[i][jn][3] * OSCALE);
            if (headout) {
                int bI = m0 >> 12;
                int t0 = m0 & 4095, t1 = (m0 + 8) & 4095;
                int hd = n0 >> 6, dh = n0 & 63;
                *(float2*)(headout + (((size_t)(bI * Hh + hd)) * Nn + t0) * DHd + dh) = va;
                *(float2*)(headout + (((size_t)(bI * Hh + hd)) * Nn + t1) * DHd + dh) = vb;
            } else {
                float2 bv = *(const float2*)(bias + n0);
                va.x += bv.x; va.y += bv.y; vb.x += bv.x; vb.y += bv.y;
                *(float2*)(outp + (size_t)m0 * Cc + n0) = va;
                *(float2*)(outp + (size_t)(m0 + 8) * Cc + n0) = vb;
            }
        }
    }
}

__global__ __launch_bounds__(256, 2) void mma_gemm(
        const __half* __restrict__ Asp, size_t Apl,
        const __half* __restrict__ Bsp, size_t Bpl,
        const float* __restrict__ bias, float* __restrict__ outp,
        float* __restrict__ headout, int npass, uint32_t paTbl, uint32_t pwTbl) {
    extern __shared__ char smem[];
    gemm_body(smem, Asp, Apl, Bsp, Bpl, bias, outp, headout, npass, paTbl, pwTbl,
              blockIdx.x * 128, blockIdx.y * 128);
}

// ---------------- LSH bucketing body ----------------
__device__ __forceinline__ void bucket_body(char* smemc, const float* __restrict__ rot,
                                            int bh, int tb) {
    float* rs = (float*)smemc;
    float* qs = rs + DHd * 128;
    int tid = threadIdx.x;

    for (int i = tid; i < DHd * 128; i += 256) rs[i] = rot[i];
    {
        int row = tid >> 2, seg = tid & 3;
        const float* src = g_qk + ((size_t)bh * Nn + tb + row) * DHd + seg * 16;
#pragma unroll
        for (int k = 0; k < 16; k++) qs[row * 65 + seg * 16 + k] = src[k];
    }
    __syncthreads();

    int warp = tid >> 5, lane = tid & 31;
    int h = warp & 3;
    int tok = (warp >> 2) * 32 + lane;

    float r[32];
#pragma unroll
    for (int i = 0; i < 32; i++) r[i] = 0.f;
    for (int d = 0; d < DHd; d++) {
        float qd = qs[tok * 65 + d];
        const float* rp = rs + d * 128 + h * 32;
#pragma unroll
        for (int i = 0; i < 32; i++) r[i] += qd * rp[i];
    }
    float best = r[0]; int bi = 0;
#pragma unroll
    for (int i = 1; i < 32; i++) if (r[i] > best) { best = r[i]; bi = i; }
#pragma unroll
    for (int i = 0; i < 32; i++) if (-r[i] > best) { best = -r[i]; bi = 32 + i; }
    g_bucket[((size_t)bh * NHASH + h) * Nn + tb + tok] = bi;
}

// ---------------- fused: v GEMM + bucketing ----------------
__global__ __launch_bounds__(256, 2) void vgemm_bucket(
        const __half* __restrict__ Asp, size_t Apl,
        const __half* __restrict__ Bsp, size_t Bpl,
        float* __restrict__ headout, const float* __restrict__ rot) {
    extern __shared__ char smem[];
    if (blockIdx.x < 8) {
        gemm_body(smem, Asp, Apl, Bsp, Bpl, nullptr, nullptr, headout, 3, PA3, PW3,
                  blockIdx.x * 128, blockIdx.y * 128);
    } else if (blockIdx.y < 32) {
        bucket_body(smem, rot, blockIdx.y, (blockIdx.x - 8) * 64);
    }
}

// ---------------- limb prep: q/k/v bf16 limb planes, once per token ----------------
// warp per (bh, t) row; lane handles dims {lane, lane+32}. Identical arithmetic to
// the previous in-attention conversions -> bitwise same limb values.
__global__ void prep_kernel() {
    int row = blockIdx.x * 8 + (threadIdx.x >> 5);   // bh*Nn + t
    int lane = threadIdx.x & 31;
    size_t off = (size_t)row * DHd;
    const float* src = g_qk + off;
    float a = src[lane], b = src[lane + 32];

    // q limbs (x 0.125, exact)
    float qa = a * 0.125f, qb = b * 0.125f;
    float qah = __bfloat162float(__float2bfloat16(qa));
    float qbh = __bfloat162float(__float2bfloat16(qb));
    g_qh[off + lane]      = __float2bfloat16(qah);
    g_qh[off + lane + 32] = __float2bfloat16(qbh);
    g_qm[off + lane]      = __float2bfloat16(qa - qah);
    g_qm[off + lane + 32] = __float2bfloat16(qb - qbh);

    // k limbs (normalized; same formula as before)
    float s = a * a + b * b;
#pragma unroll
    for (int o = 16; o > 0; o >>= 1) s += __shfl_xor_sync(0xffffffffu, s, o);
    float inv = 1.0f / fmaxf(sqrtf(s), 1e-12f);
    float ka = a * inv, kb = b * inv;
    float kah = __bfloat162float(__float2bfloat16(ka));
    float kbh = __bfloat162float(__float2bfloat16(kb));
    g_kh[off + lane]      = __float2bfloat16(kah);
    g_kh[off + lane + 32] = __float2bfloat16(kbh);
    g_km[off + lane]      = __float2bfloat16(ka - kah);
    g_km[off + lane + 32] = __float2bfloat16(kb - kbh);

    // v limbs
    const float* vs = g_v + off;
    float va = vs[lane], vb = vs[lane + 32];
    float vah = __bfloat162float(__float2bfloat16(va));
    float vbh = __bfloat162float(__float2bfloat16(vb));
    g_vh[off + lane]      = __float2bfloat16(vah);
    g_vh[off + lane + 32] = __float2bfloat16(vbh);
    g_vm[off + lane]      = __float2bfloat16(va - vah);
    g_vm[off + lane + 32] = __float2bfloat16(vb - vbh);
}

// ---------------- parallel stable counting sort per (bh, hash) ----------------
#define SORT_SMEM 49152
__global__ void sort_kernel() {
    extern __shared__ char ss[];
    unsigned char*  cnt    = (unsigned char*)ss;
    unsigned short* segoff = (unsigned short*)(ss + 16384);
    __shared__ int bbase[NBUCK];
    int bh = blockIdx.x, h = blockIdx.y;
    int tid = threadIdx.x;
    const int gb = (bh * NHASH + h) * Nn;

    uint32_t* ci = (uint32_t*)cnt;
    for (int i = tid; i < 4096; i += 256) ci[i] = 0;
    __syncthreads();

    int bb[16];
#pragma unroll
    for (int k = 0; k < 16; k++) {
        int b = g_bucket[gb + tid * 16 + k];
        bb[k] = b;
        cnt[tid * 64 + b]++;
    }
    __syncthreads();

    if (tid < NBUCK) {
        int run = 0;
        for (int seg = 0; seg < 256; seg++) {
            segoff[seg * 64 + tid] = (unsigned short)run;
            run += cnt[seg * 64 + tid];
        }
        bbase[tid] = run;
    }
    __syncthreads();
    if (tid == 0) {
        int acc = 0;
        for (int b = 0; b < NBUCK; b++) { int c = bbase[b]; bbase[b] = acc; acc += c; }
    }
    __syncthreads();

#pragma unroll
    for (int k = 0; k < 16; k++) {
        int b = bb[k];
        int pos = bbase[b] + segoff[tid * 64 + b];
        segoff[tid * 64 + b]++;
        g_st[gb + pos] = tid * 16 + k;
    }
}

// ---------------- chunked LSH attention: pure gather + HMMA ----------------
#define AT_KHI   3072
#define AT_KMID  21504
#define AT_VHI   39936
#define AT_VMID  58368
#define AT_QHI   76800
#define AT_QMID  86016
#define AT_PHI   76800
#define AT_PMID  94208
#define ATTN_SMEM_BYTES 111616

__global__ __launch_bounds__(256, 2) void attn_kernel() {
    extern __shared__ char sm[];
    int*   tkv     = (int*)sm;
    float* rsump   = (float*)(sm + 1536);
    float* rsuminv = (float*)(sm + 2560);
    uint32_t sb = smem_to_u32(sm);

    int c = blockIdx.x, bh = blockIdx.y;
    int h = c >> 6;
    int tid = threadIdx.x, lane = tid & 31, warp = tid >> 5;
    int g = lane >> 2, t = lane & 3;
    int wm = warp >> 2, wn = warp & 3;
    int pc = (c + NCHUNK - 1) & (NCHUNK - 1);
    const int stb = bh * (NHASH * Nn);

    if (tid < 64)       tkv[tid] = g_st[stb + c * BS + tid];
    else if (tid < 128) tkv[tid] = g_st[stb + pc * BS + (tid - 64)];
    __syncthreads();

    // gather q limbs (rows 0..63): 4 threads/row x 16 elems (32B per plane)
    {
        int i = tid >> 2, seg = tid & 3;
        size_t off = ((size_t)bh * Nn + tkv[i]) * DHd + seg * 16;
        const uint4* shq = (const uint4*)(g_qh + off);
        const uint4* smq = (const uint4*)(g_qm + off);
        uint4* dh = (uint4*)(sm + AT_QHI + i * 144 + seg * 32);
        uint4* dm = (uint4*)(sm + AT_QMID + i * 144 + seg * 32);
        dh[0] = shq[0]; dh[1] = shq[1];
        dm[0] = smq[0]; dm[1] = smq[1];
    }
    // gather k + v limbs (rows 0..127): 2 threads/row x 32 elems (64B per plane)
    {
        int j = tid >> 1, seg = tid & 1;
        size_t off = ((size_t)bh * Nn + tkv[j]) * DHd + seg * 32;
        const uint4* skh = (const uint4*)(g_kh + off);
        const uint4* skm = (const uint4*)(g_km + off);
        const uint4* svh = (const uint4*)(g_vh + off);
        const uint4* svm = (const uint4*)(g_vm + off);
        uint4* dkh = (uint4*)(sm + AT_KHI + j * 144 + seg * 64);
        uint4* dkm = (uint4*)(sm + AT_KMID + j * 144 + seg * 64);
        uint4* dvh = (uint4*)(sm + AT_VHI + j * 144 + seg * 64);
        uint4* dvm = (uint4*)(sm + AT_VMID + j * 144 + seg * 64);
#pragma unroll
        for (int k = 0; k < 4; k++) {
            dkh[k] = skh[k]; dkm[k] = skm[k];
            dvh[k] = svh[k]; dvm[k] = svm[k];
        }
    }
    __syncthreads();

    // dots MMA
    float Dd[2][4][4];
#pragma unroll
    for (int i = 0; i < 2; i++)
#pragma unroll
        for (int jn = 0; jn < 4; jn++)
#pragma unroll
            for (int q = 0; q < 4; q++) Dd[i][jn][q] = 0.f;

    uint32_t arow = (uint32_t)((wm * 32 + (lane & 15)) * 144 + (lane >> 4) * 16);
    uint32_t brow = (uint32_t)((wn * 32 + ((lane >> 4) & 1) * 8 + (lane & 7)) * 144
                               + ((lane >> 3) & 1) * 16);
    const uint32_t QL[3] = {sb + AT_QMID, sb + AT_QHI, sb + AT_QHI};
    const uint32_t KL[3] = {sb + AT_KHI, sb + AT_KMID, sb + AT_KHI};
#pragma unroll
    for (int p = 0; p < 3; p++) {
#pragma unroll
        for (int ks = 0; ks < 4; ks++) {
            uint32_t A4[2][4], B4[2][4];
#pragma unroll
            for (int i = 0; i < 2; i++) ldmx4(A4[i], QL[p] + arow + i * (16 * 144) + ks * 32);
#pragma unroll
            for (int jp = 0; jp < 2; jp++) ldmx4(B4[jp], KL[p] + brow + jp * (16 * 144) + ks * 32);
#pragma unroll
            for (int i = 0; i < 2; i++)
#pragma unroll
                for (int jn = 0; jn < 4; jn++)
                    mma16816(Dd[i][jn], A4[i], B4[jn >> 1][(jn & 1) * 2], B4[jn >> 1][(jn & 1) * 2 + 1]);
        }
    }

    // mask
    int trow[4] = { tkv[wm * 32 + g], tkv[wm * 32 + g + 8],
                    tkv[wm * 32 + 16 + g], tkv[wm * 32 + 16 + g + 8] };
    int tcol[8];
#pragma unroll
    for (int jn = 0; jn < 4; jn++) {
        int c0 = wn * 32 + jn * 8 + t * 2;
        tcol[jn * 2] = tkv[c0]; tcol[jn * 2 + 1] = tkv[c0 + 1];
    }
#pragma unroll
    for (int i = 0; i < 2; i++)
#pragma unroll
        for (int jn = 0; jn < 4; jn++)
#pragma unroll
            for (int q = 0; q < 4; q++)
                if (trow[i * 2 + (q >> 1)] == tcol[jn * 2 + (q & 1)]) Dd[i][jn][q] = -5e4f;

    // barrier: all warps done reading Q region before P stores overwrite it
    __syncthreads();

    // exp (unshifted; dots bounded) -> P limbs + partial sums
    float ps[4] = {0.f, 0.f, 0.f, 0.f};
#pragma unroll
    for (int i = 0; i < 2; i++) {
        int r0 = wm * 32 + i * 16 + g;
#pragma unroll
        for (int jn = 0; jn < 4; jn++) {
            float e0 = __expf(Dd[i][jn][0]);
            float e1 = __expf(Dd[i][jn][1]);
            float e2 = __expf(Dd[i][jn][2]);
            float e3 = __expf(Dd[i][jn][3]);
            ps[i * 2] += e0 + e1;
            ps[i * 2 + 1] += e2 + e3;
            int c0 = wn * 32 + jn * 8 + t * 2;
            uint32_t h0, m0, h1, m1;
            split2u(e0, e1, h0, m0);
            split2u(e2, e3, h1, m1);
            *(uint32_t*)(sm + AT_PHI  + r0 * 272 + c0 * 2)       = h0;
            *(uint32_t*)(sm + AT_PMID + r0 * 272 + c0 * 2)       = m0;
            *(uint32_t*)(sm + AT_PHI  + (r0 + 8) * 272 + c0 * 2) = h1;
            *(uint32_t*)(sm + AT_PMID + (r0 + 8) * 272 + c0 * 2) = m1;
        }
    }
#pragma unroll
    for (int k = 0; k < 4; k++) {
        ps[k] += __shfl_xor_sync(0xffffffffu, ps[k], 1);
        ps[k] += __shfl_xor_sync(0xffffffffu, ps[k], 2);
    }
    if (t == 0) {
#pragma unroll
        for (int k = 0; k < 4; k++)
            rsump[(wm * 32 + (k >> 1) * 16 + g + (k & 1) * 8) * 4 + wn] = ps[k];
    }
    __syncthreads();

    if (tid < 64) {
        const float* p = rsump + tid * 4;
        float s = p[0] + p[1] + p[2] + p[3];
        rsuminv[tid] = 1.0f / s;
        g_lse[(bh * NHASH + h) * Nn + tkv[tid]] = logf(s);
    }
    __syncthreads();

    // PV MMA
    float Dp[2][2][4];
#pragma unroll
    for (int i = 0; i < 2; i++)
#pragma unroll
        for (int jn = 0; jn < 2; jn++)
#pragma unroll
            for (int q = 0; q < 4; q++) Dp[i][jn][q] = 0.f;

    uint32_t parow = (uint32_t)((wm * 32 + (lane & 15)) * 272 + (lane >> 4) * 16);
    uint32_t vbrow = (uint32_t)((lane & 15) * 144 + (lane >> 4) * 16 + wn * 32);
    const uint32_t PL[3] = {sb + AT_PMID, sb + AT_PHI, sb + AT_PHI};
    const uint32_t VL[3] = {sb + AT_VHI, sb + AT_VMID, sb + AT_VHI};
#pragma unroll
    for (int p = 0; p < 3; p++) {
#pragma unroll
        for (int ks = 0; ks < 8; ks++) {
            uint32_t A4[2][4], B4[4];
#pragma unroll
            for (int i = 0; i < 2; i++) ldmx4(A4[i], PL[p] + parow + i * (16 * 272) + ks * 32);
            ldmx4t(B4, VL[p] + vbrow + ks * (16 * 144));
#pragma unroll
            for (int i = 0; i < 2; i++)
#pragma unroll
                for (int jn = 0; jn < 2; jn++)
                    mma16816(Dp[i][jn], A4[i], B4[jn * 2], B4[jn * 2 + 1]);
        }
    }

    // epilogue: normalize + scatter (fp16)
#pragma unroll
    for (int i = 0; i < 2; i++) {
        int r0 = wm * 32 + i * 16 + g;
        float inv0 = rsuminv[r0], inv1 = rsuminv[r0 + 8];
        size_t b0 = ((size_t)(bh * NHASH + h) * Nn + trow[i * 2]) * DHd;
        size_t b1 = ((size_t)(bh * NHASH + h) * Nn + trow[i * 2 + 1]) * DHd;
#pragma unroll
        for (int jn = 0; jn < 2; jn++) {
            int dh = wn * 16 + jn * 8 + t * 2;
            *(uint32_t*)(g_oph2 + b0 + dh) = pack_h2(Dp[i][jn][0] * inv0, Dp[i][jn][1] * inv0);
            *(uint32_t*)(g_oph2 + b1 + dh) = pack_h2(Dp[i][jn][2] * inv1, Dp[i][jn][3] * inv1);
        }
    }
}

// ---------------- fused combine + fp16 2-limb split ----------------
__global__ void combine_split_kernel(__half* __restrict__ hi, __half* __restrict__ mid) {
    int u = blockIdx.x * 256 + threadIdx.x;
    int slot = u >> 3;
    int dseg = (u & 7) * 8;
    int bh = slot >> 12;
    int t = slot & 4095;
    int base = bh * NHASH * Nn + t;
    float l0 = g_lse[base + 0 * Nn];
    float l1 = g_lse[base + 1 * Nn];
    float l2 = g_lse[base + 2 * Nn];
    float l3 = g_lse[base + 3 * Nn];
    float m = fmaxf(fmaxf(l0, l1), fmaxf(l2, l3));
    float w[4] = {expf(l0 - m), expf(l1 - m), expf(l2 - m), expf(l3 - m)};
    float sinv = 1.0f / (w[0] + w[1] + w[2] + w[3]);

    float acc[8];
#pragma unroll
    for (int j = 0; j < 8; j++) acc[j] = 0.f;
#pragma unroll
    for (int k = 0; k < 4; k++) {
        const uint4* p = (const uint4*)(g_oph2 + (((size_t)(bh * NHASH + k)) * Nn + t) * DHd + dseg);
        uint4 x = p[0];
        const __half2* hx = (const __half2*)&x;
#pragma unroll
        for (int j2 = 0; j2 < 4; j2++) {
            float2 f = __half22float2(hx[j2]);
            acc[j2 * 2]     += w[k] * f.x;
            acc[j2 * 2 + 1] += w[k] * f.y;
        }
    }
    float hf[8], mf[8];
#pragma unroll
    for (int j = 0; j < 8; j++) {
        float a = acc[j] * sinv;
        float h = __half2float(__float2half_rn(a));
        hf[j] = h; mf[j] = a - h;
    }
    int b = bh >> 4, head = bh & 15;
    size_t oidx = ((size_t)b * Nn + t) * Cc + head * DHd + dseg;
    *(uint4*)(hi + oidx) = make_uint4(pack_h2(hf[0], hf[1]), pack_h2(hf[2], hf[3]),
                                      pack_h2(hf[4], hf[5]), pack_h2(hf[6], hf[7]));
    *(uint4*)(mid + oidx) = make_uint4(pack_h2(mf[0], mf[1]), pack_h2(mf[2], mf[3]),
                                       pack_h2(mf[4], mf[5]), pack_h2(mf[6], mf[7]));
}

// ---------------- launch ----------------
extern "C" void kernel_launch(void* const* d_in, const int* in_sizes, int n_in,
                              void* d_out, int out_size) {
    const float* queries = (const float*)d_in[0];
    const float* Wqk  = (const float*)d_in[4];
    const float* Wv   = (const float*)d_in[5];
    const float* Wout = (const float*)d_in[6];
    const float* bout = (const float*)d_in[7];
    const float* rot  = (const float*)d_in[8];
    float* out = (float*)d_out;

    cudaFuncSetAttribute(attn_kernel, cudaFuncAttributeMaxDynamicSharedMemorySize, ATTN_SMEM_BYTES);
    cudaFuncSetAttribute(mma_gemm, cudaFuncAttributeMaxDynamicSharedMemorySize, GEMM_SMEM);
    cudaFuncSetAttribute(vgemm_bucket, cudaFuncAttributeMaxDynamicSharedMemorySize, GEMM_SMEM);
    cudaFuncSetAttribute(sort_kernel, cudaFuncAttributeMaxDynamicSharedMemorySize, SORT_SMEM);

    void *p_qk, *p_v, *p_asp, *p_wqkv, *p_wout;
    cudaGetSymbolAddress(&p_qk, g_qk);
    cudaGetSymbolAddress(&p_v, g_v);
    cudaGetSymbolAddress(&p_asp, g_asp);
    cudaGetSymbolAddress(&p_wqkv, g_wqkv_sp);
    cudaGetSymbolAddress(&p_wout, g_wout_sp);
    __half* asp  = (__half*)p_asp;
    __half* wqkv = (__half*)p_wqkv;
    __half* wout = (__half*)p_wout;
    const int NW = 1024 * 1024;

    split_all_kernel<<<5632, 256>>>(queries, Wqk, Wv, Wout, asp, wqkv, wout);

    // qk GEMM: 4-pass fp16 (feeds LSH argmax)
    mma_gemm<<<dim3(8, 64), 256, GEMM_SMEM>>>(asp, APL, wqkv, WQKV_PL,
                                              nullptr, nullptr, (float*)p_qk, 4, PA4, PW4);

    // fused: v GEMM (3-pass fp16) overlapped with bucketing
    vgemm_bucket<<<dim3(72, 64), 256, GEMM_SMEM>>>(asp, APL, wqkv + NW, WQKV_PL,
                                                   (float*)p_v, rot);

    // limb prep (needs g_qk + g_v), then sort (needs buckets)
    prep_kernel<<<BH * Nn / 8, 256>>>();
    sort_kernel<<<dim3(BH, NHASH), 256, SORT_SMEM>>>();

    attn_kernel<<<dim3(NCHUNK, BH), 256, ATTN_SMEM_BYTES>>>();

    combine_split_kernel<<<(BH * Nn * DHd / 8) / 256, 256>>>(asp, asp + APL);

    // Wout GEMM: 3-pass fp16, +bias -> d_out
    mma_gemm<<<dim3(8, 64), 256, GEMM_SMEM>>>(asp, APL, wout, WOUT_PL,
                                              bout, out, nullptr, 3, PA3, PW3);
}

// round 12
// speedup vs baseline: 3.4740x; 1.0778x over previous
#include <cuda_runtime.h>
#include <cuda_fp16.h>
#include <cuda_bf16.h>
#include <math.h>
#include <stdint.h>

// ---------------- problem constants ----------------
#define Bb      2
#define Nn      4096
#define Cc      1024
#define Hh      16
#define DHd     64
#define BH      32          // Bb*Hh
#define NHASH   4
#define NBUCK   64          // Nn / BUCKET
#define NCHUNK  256         // NHASH*NBUCK
#define BS      64          // bucket size
#define Kdim    1024
#define Mrows   8192        // Bb*Nn

// ---------------- device scratch ----------------
__device__ float g_qk  [BH * Nn * DHd];            // (bh, t, d)
__device__ float g_v   [BH * Nn * DHd];
__device__ int   g_bucket[BH * NHASH * Nn];
__device__ int   g_st  [BH * NHASH * Nn];
__device__ __half g_oph2[BH * NHASH * Nn * DHd];   // per-hash outputs, fp16
__device__ float g_lse [BH * NHASH * Nn];

// attention prep planes (once per token)
#define PLN ((size_t)BH * Nn * DHd)
__device__ __nv_bfloat16 g_kh[PLN], g_km[PLN];     // normalized k limbs (bf16)
__device__ __half g_vh2[PLN];                      // v single fp16 plane
__device__ float g_s[BH * Nn];                     // s = 0.125 * ||q||

// fp16 2-limb planes for GEMMs (W-side pre-scaled by 64; epilogue x 1/64)
#define APL ((size_t)Mrows * Kdim)
#define WQKV_PL ((size_t)2048 * 1024)
#define WOUT_PL ((size_t)1024 * 1024)
__device__ __half g_asp[2 * APL];
__device__ __half g_wqkv_sp[2 * WQKV_PL];
__device__ __half g_wout_sp[2 * WOUT_PL];
#define WSCALE 64.0f
#define OSCALE (1.0f / 64.0f)

// ================= helpers (sm_103-safe) =================
__device__ __forceinline__ uint32_t smem_to_u32(const void* p) {
    uint32_t a;
    asm("{ .reg .u64 t; cvta.to.shared.u64 t, %1; cvt.u32.u64 %0, t; }" : "=r"(a) : "l"(p));
    return a;
}
#define CP_ASYNC16(saddr, gptr) \
    asm volatile("cp.async.cg.shared.global [%0], [%1], 16;" \
        :: "r"(saddr), "l"(__cvta_generic_to_global(gptr)))
#define CP_COMMIT() asm volatile("cp.async.commit_group;" ::: "memory")
#define CP_WAIT(n)  asm volatile("cp.async.wait_group %0;" :: "n"(n) : "memory")

__device__ __forceinline__ void ldmx4(uint32_t* r, uint32_t addr) {
    asm volatile("ldmatrix.sync.aligned.m8n8.x4.shared.b16 {%0,%1,%2,%3}, [%4];"
        : "=r"(r[0]), "=r"(r[1]), "=r"(r[2]), "=r"(r[3]) : "r"(addr));
}
__device__ __forceinline__ void ldmx4t(uint32_t* r, uint32_t addr) {
    asm volatile("ldmatrix.sync.aligned.m8n8.x4.trans.shared.b16 {%0,%1,%2,%3}, [%4];"
        : "=r"(r[0]), "=r"(r[1]), "=r"(r[2]), "=r"(r[3]) : "r"(addr));
}
__device__ __forceinline__ void mma16816h(float* d, const uint32_t* a, uint32_t b0, uint32_t b1) {
    asm volatile("mma.sync.aligned.m16n8k16.row.col.f32.f16.f16.f32 "
        "{%0,%1,%2,%3}, {%4,%5,%6,%7}, {%8,%9}, {%0,%1,%2,%3};"
        : "+f"(d[0]), "+f"(d[1]), "+f"(d[2]), "+f"(d[3])
        : "r"(a[0]), "r"(a[1]), "r"(a[2]), "r"(a[3]), "r"(b0), "r"(b1));
}
__device__ __forceinline__ void mma16816(float* d, const uint32_t* a, uint32_t b0, uint32_t b1) {
    asm volatile("mma.sync.aligned.m16n8k16.row.col.f32.bf16.bf16.f32 "
        "{%0,%1,%2,%3}, {%4,%5,%6,%7}, {%8,%9}, {%0,%1,%2,%3};"
        : "+f"(d[0]), "+f"(d[1]), "+f"(d[2]), "+f"(d[3])
        : "r"(a[0]), "r"(a[1]), "r"(a[2]), "r"(a[3]), "r"(b0), "r"(b1));
}
__device__ __forceinline__ uint32_t pack_h2(float a, float b) {
    uint16_t ua = __half_as_ushort(__float2half_rn(a));
    uint16_t ub = __half_as_ushort(__float2half_rn(b));
    return (uint32_t)ua | ((uint32_t)ub << 16);
}
// fp16 split of (a,b) into hi/mid packed u32
__device__ __forceinline__ void split2h(float a, float b, uint32_t& hp, uint32_t& mp) {
    float ha = __half2float(__float2half_rn(a));
    float hb = __half2float(__float2half_rn(b));
    hp = pack_h2(ha, hb);
    mp = pack_h2(a - ha, b - hb);
}

// ================= merged fp16 2-limb split (all 4 GEMM tensors) =================
__device__ __forceinline__ void split8(const float* __restrict__ x,
                                       __half* __restrict__ hi, __half* __restrict__ mid,
                                       int i, float scale) {
    float4 v0 = *(const float4*)(x + i);
    float4 v1 = *(const float4*)(x + i + 4);
    float a[8] = {v0.x, v0.y, v0.z, v0.w, v1.x, v1.y, v1.z, v1.w};
    float hf[8], mf[8];
#pragma unroll
    for (int j = 0; j < 8; j++) {
        float s = a[j] * scale;
        float h = __half2float(__float2half_rn(s));
        hf[j] = h; mf[j] = s - h;
    }
    *(uint4*)(hi + i) = make_uint4(pack_h2(hf[0], hf[1]), pack_h2(hf[2], hf[3]),
                                   pack_h2(hf[4], hf[5]), pack_h2(hf[6], hf[7]));
    *(uint4*)(mid + i) = make_uint4(pack_h2(mf[0], mf[1]), pack_h2(mf[2], mf[3]),
                                    pack_h2(mf[4], mf[5]), pack_h2(mf[6], mf[7]));
}

__global__ void split_all_kernel(const float* __restrict__ q,
                                 const float* __restrict__ wqk,
                                 const float* __restrict__ wv,
                                 const float* __restrict__ wo,
                                 __half* __restrict__ asp,
                                 __half* __restrict__ wqkv,
                                 __half* __restrict__ wout) {
    int bid = blockIdx.x;
    int li = threadIdx.x * 8;
    const int NW = 1024 * 1024;
    if (bid < 4096) {
        int i = bid * 2048 + li;
        split8(q, asp, asp + APL, i, 1.0f);
    } else if (bid < 4608) {
        int i = (bid - 4096) * 2048 + li;
        split8(wqk, wqkv, wqkv + WQKV_PL, i, WSCALE);
    } else if (bid < 5120) {
        int i = (bid - 4608) * 2048 + li;
        split8(wv, wqkv + NW, wqkv + WQKV_PL + NW, i, WSCALE);
    } else {
        int i = (bid - 5120) * 2048 + li;
        split8(wo, wout, wout + WOUT_PL, i, WSCALE);
    }
}

// ================= HMMA GEMM body (fp16 limbs) =================
#define ROWB     80
#define MATB     (128 * ROWB)
#define STAGEB   (2 * MATB)
#define GEMM_SMEM (4 * STAGEB)   // 81920
#define PA4 0x0101u
#define PW4 0x0011u
#define PA3 0x010u
#define PW3 0x001u

__device__ __forceinline__ void gemm_issue(uint32_t st,
        const __half* Ap, const __half* Bp, int bm, int bn, int k0,
        uint32_t so0, uint32_t so1, int r0, int c0, int r1, int c1) {
    CP_ASYNC16(st + so0, Ap + (size_t)(bm + r0) * Kdim + k0 + c0 * 8);
    CP_ASYNC16(st + so1, Ap + (size_t)(bm + r1) * Kdim + k0 + c1 * 8);
    CP_ASYNC16(st + MATB + so0, Bp + (size_t)(bn + r0) * Kdim + k0 + c0 * 8);
    CP_ASYNC16(st + MATB + so1, Bp + (size_t)(bn + r1) * Kdim + k0 + c1 * 8);
    CP_COMMIT();
}

__device__ __forceinline__ void gemm_body(char* smem,
        const __half* __restrict__ Asp, size_t Apl,
        const __half* __restrict__ Bsp, size_t Bpl,
        const float* __restrict__ bias, float* __restrict__ outp,
        float* __restrict__ headout, int npass, uint32_t paTbl, uint32_t pwTbl,
        int bn, int bm) {
    uint32_t sbase = smem_to_u32(smem);
    int tid = threadIdx.x;
    int lane = tid & 31, warp = tid >> 5;
    int wm = warp >> 2, wn = warp & 3;
    int nstage = npass * 32;

    int v0 = tid, v1 = tid + 256;
    int r0 = v0 >> 2, c0 = v0 & 3;
    int r1 = v1 >> 2, c1 = v1 & 3;
    uint32_t so0 = (uint32_t)(r0 * ROWB + c0 * 16);
    uint32_t so1 = (uint32_t)(r1 * ROWB + c1 * 16);

    uint32_t aoff = (uint32_t)((wm * 64 + (lane & 15)) * ROWB + (lane >> 4) * 16);
    uint32_t boff = (uint32_t)((wn * 32 + ((lane >> 4) & 1) * 8 + (lane & 7)) * ROWB
                               + ((lane >> 3) & 1) * 16);

    float D[4][4][4];
#pragma unroll
    for (int i = 0; i < 4; i++)
#pragma unroll
        for (int j = 0; j < 4; j++)
#pragma unroll
            for (int q = 0; q < 4; q++) D[i][j][q] = 0.f;

#pragma unroll
    for (int s = 0; s < 3; s++) {
        const __half* Ap = Asp + (size_t)(paTbl & 7) * Apl;
        const __half* Bp = Bsp + (size_t)(pwTbl & 7) * Bpl;
        gemm_issue(sbase + s * STAGEB, Ap, Bp, bm, bn, s * 32, so0, so1, r0, c0, r1, c1);
    }

    for (int s = 0; s < nstage; s++) {
        if (s <= nstage - 3)      { CP_WAIT(2); }
        else if (s == nstage - 2) { CP_WAIT(1); }
        else                      { CP_WAIT(0); }
        __syncthreads();
        if (s + 3 < nstage) {
            int sn = s + 3;
            int p = sn >> 5, k0 = (sn & 31) << 5;
            const __half* Ap = Asp + (size_t)((paTbl >> (p * 4)) & 7) * Apl;
            const __half* Bp = Bsp + (size_t)((pwTbl >> (p * 4)) & 7) * Bpl;
            gemm_issue(sbase + (uint32_t)(sn & 3) * STAGEB, Ap, Bp, bm, bn, k0,
                       so0, so1, r0, c0, r1, c1);
        }
        uint32_t st = sbase + (uint32_t)(s & 3) * STAGEB;
        uint32_t ab = st + aoff;
        uint32_t bb = st + MATB + boff;
#pragma unroll
        for (int ks = 0; ks < 2; ks++) {
            uint32_t A4[4][4], B4[2][4];
#pragma unroll
            for (int i = 0; i < 4; i++) ldmx4(A4[i], ab + i * (16 * ROWB) + ks * 32);
#pragma unroll
            for (int jp = 0; jp < 2; jp++) ldmx4(B4[jp], bb + jp * (16 * ROWB) + ks * 32);
#pragma unroll
            for (int i = 0; i < 4; i++)
#pragma unroll
                for (int jn = 0; jn < 4; jn++)
                    mma16816h(D[i][jn], A4[i], B4[jn >> 1][(jn & 1) * 2], B4[jn >> 1][(jn & 1) * 2 + 1]);
        }
    }

    int g = lane >> 2, t = lane & 3;
#pragma unroll
    for (int i = 0; i < 4; i++) {
#pragma unroll
        for (int jn = 0; jn < 4; jn++) {
            int m0 = bm + wm * 64 + i * 16 + g;
            int n0 = bn + wn * 32 + jn * 8 + t * 2;
            float2 va = make_float2(D[i][jn][0] * OSCALE, D[i][jn][1] * OSCALE);
            float2 vb = make_float2(D[i][jn][2] * OSCALE, D[i][jn][3] * OSCALE);
            if (headout) {
                int bI = m0 >> 12;
                int t0 = m0 & 4095, t1 = (m0 + 8) & 4095;
                int hd = n0 >> 6, dh = n0 & 63;
                *(float2*)(headout + (((size_t)(bI * Hh + hd)) * Nn + t0) * DHd + dh) = va;
                *(float2*)(headout + (((size_t)(bI * Hh + hd)) * Nn + t1) * DHd + dh) = vb;
            } else {
                float2 bv = *(const float2*)(bias + n0);
                va.x += bv.x; va.y += bv.y; vb.x += bv.x; vb.y += bv.y;
                *(float2*)(outp + (size_t)m0 * Cc + n0) = va;
                *(float2*)(outp + (size_t)(m0 + 8) * Cc + n0) = vb;
            }
        }
    }
}

__global__ __launch_bounds__(256, 2) void mma_gemm(
        const __half* __restrict__ Asp, size_t Apl,
        const __half* __restrict__ Bsp, size_t Bpl,
        const float* __restrict__ bias, float* __restrict__ outp,
        float* __restrict__ headout, int npass, uint32_t paTbl, uint32_t pwTbl) {
    extern __shared__ char smem[];
    gemm_body(smem, Asp, Apl, Bsp, Bpl, bias, outp, headout, npass, paTbl, pwTbl,
              blockIdx.x * 128, blockIdx.y * 128);
}

// ---------------- LSH bucketing body ----------------
__device__ __forceinline__ void bucket_body(char* smemc, const float* __restrict__ rot,
                                            int bh, int tb) {
    float* rs = (float*)smemc;
    float* qs = rs + DHd * 128;
    int tid = threadIdx.x;

    for (int i = tid; i < DHd * 128; i += 256) rs[i] = rot[i];
    {
        int row = tid >> 2, seg = tid & 3;
        const float* src = g_qk + ((size_t)bh * Nn + tb + row) * DHd + seg * 16;
#pragma unroll
        for (int k = 0; k < 16; k++) qs[row * 65 + seg * 16 + k] = src[k];
    }
    __syncthreads();

    int warp = tid >> 5, lane = tid & 31;
    int h = warp & 3;
    int tok = (warp >> 2) * 32 + lane;

    float r[32];
#pragma unroll
    for (int i = 0; i < 32; i++) r[i] = 0.f;
    for (int d = 0; d < DHd; d++) {
        float qd = qs[tok * 65 + d];
        const float* rp = rs + d * 128 + h * 32;
#pragma unroll
        for (int i = 0; i < 32; i++) r[i] += qd * rp[i];
    }
    float best = r[0]; int bi = 0;
#pragma unroll
    for (int i = 1; i < 32; i++) if (r[i] > best) { best = r[i]; bi = i; }
#pragma unroll
    for (int i = 0; i < 32; i++) if (-r[i] > best) { best = -r[i]; bi = 32 + i; }
    g_bucket[((size_t)bh * NHASH + h) * Nn + tb + tok] = bi;
}

// ---------------- fused: v GEMM + bucketing ----------------
__global__ __launch_bounds__(256, 2) void vgemm_bucket(
        const __half* __restrict__ Asp, size_t Apl,
        const __half* __restrict__ Bsp, size_t Bpl,
        float* __restrict__ headout, const float* __restrict__ rot) {
    extern __shared__ char smem[];
    if (blockIdx.x < 8) {
        gemm_body(smem, Asp, Apl, Bsp, Bpl, nullptr, nullptr, headout, 3, PA3, PW3,
                  blockIdx.x * 128, blockIdx.y * 128);
    } else if (blockIdx.y < 32) {
        bucket_body(smem, rot, blockIdx.y, (blockIdx.x - 8) * 64);
    }
}

// ---------------- limb prep: k limbs (bf16), v (fp16), s = 0.125*||q|| ----------------
__global__ void prep_kernel() {
    int row = blockIdx.x * 8 + (threadIdx.x >> 5);   // bh*Nn + t
    int lane = threadIdx.x & 31;
    size_t off = (size_t)row * DHd;
    const float* src = g_qk + off;
    float a = src[lane], b = src[lane + 32];

    float s = a * a + b * b;
#pragma unroll
    for (int o = 16; o > 0; o >>= 1) s += __shfl_xor_sync(0xffffffffu, s, o);
    float norm = sqrtf(s);
    float inv = 1.0f / fmaxf(norm, 1e-12f);
    if (lane == 0) g_s[row] = 0.125f * norm;

    float ka = a * inv, kb = b * inv;
    float kah = __bfloat162float(__float2bfloat16(ka));
    float kbh = __bfloat162float(__float2bfloat16(kb));
    g_kh[off + lane]      = __float2bfloat16(kah);
    g_kh[off + lane + 32] = __float2bfloat16(kbh);
    g_km[off + lane]      = __float2bfloat16(ka - kah);
    g_km[off + lane + 32] = __float2bfloat16(kb - kbh);

    const float* vs = g_v + off;
    g_vh2[off + lane]      = __float2half_rn(vs[lane]);
    g_vh2[off + lane + 32] = __float2half_rn(vs[lane + 32]);
}

// ---------------- parallel stable counting sort per (bh, hash) ----------------
#define SORT_SMEM 49152
__global__ void sort_kernel() {
    extern __shared__ char ss[];
    unsigned char*  cnt    = (unsigned char*)ss;
    unsigned short* segoff = (unsigned short*)(ss + 16384);
    __shared__ int bbase[NBUCK];
    int bh = blockIdx.x, h = blockIdx.y;
    int tid = threadIdx.x;
    const int gb = (bh * NHASH + h) * Nn;

    uint32_t* ci = (uint32_t*)cnt;
    for (int i = tid; i < 4096; i += 256) ci[i] = 0;
    __syncthreads();

    int bb[16];
#pragma unroll
    for (int k = 0; k < 16; k++) {
        int b = g_bucket[gb + tid * 16 + k];
        bb[k] = b;
        cnt[tid * 64 + b]++;
    }
    __syncthreads();

    if (tid < NBUCK) {
        int run = 0;
        for (int seg = 0; seg < 256; seg++) {
            segoff[seg * 64 + tid] = (unsigned short)run;
            run += cnt[seg * 64 + tid];
        }
        bbase[tid] = run;
    }
    __syncthreads();
    if (tid == 0) {
        int acc = 0;
        for (int b = 0; b < NBUCK; b++) { int c = bbase[b]; bbase[b] = acc; acc += c; }
    }
    __syncthreads();

#pragma unroll
    for (int k = 0; k < 16; k++) {
        int b = bb[k];
        int pos = bbase[b] + segoff[tid * 64 + b];
        segoff[tid * 64 + b]++;
        g_st[gb + pos] = tid * 16 + k;
    }
}

// ---------------- chunked LSH attention: K-as-A dots, fp16 PV ----------------
// smem: tkv[128]@0 | s[64]f32@512 | rsump@1536 | rsuminv@2560 |
//       Khi@3072(18432) | Kmid@21504(18432) | V fp16@39936(18432) |
//       Phi@58368(17408) | Pmid@75776(17408)  -> total 93184
#define AT_S     512
#define AT_KHI   3072
#define AT_KMID  21504
#define AT_V     39936
#define AT_PHI   58368
#define AT_PMID  75776
#define ATTN_SMEM_BYTES 93184

__global__ __launch_bounds__(256, 2) void attn_kernel() {
    extern __shared__ char sm[];
    int*   tkv     = (int*)sm;
    float* sS      = (float*)(sm + AT_S);
    float* rsump   = (float*)(sm + 1536);
    float* rsuminv = (float*)(sm + 2560);
    uint32_t sb = smem_to_u32(sm);

    int c = blockIdx.x, bh = blockIdx.y;
    int h = c >> 6;
    int tid = threadIdx.x, lane = tid & 31, warp = tid >> 5;
    int g = lane >> 2, t = lane & 3;
    int wm = warp >> 2, wn = warp & 3;
    int pc = (c + NCHUNK - 1) & (NCHUNK - 1);
    const int stb = bh * (NHASH * Nn);

    if (tid < 64)       tkv[tid] = g_st[stb + c * BS + tid];
    else if (tid < 128) tkv[tid] = g_st[stb + pc * BS + (tid - 64)];
    __syncthreads();

    if (tid < 64) sS[tid] = g_s[(size_t)bh * Nn + tkv[tid]];

    // gather k limbs + v (rows 0..127): 2 threads/row x 32 elems
    {
        int j = tid >> 1, seg = tid & 1;
        size_t off = ((size_t)bh * Nn + tkv[j]) * DHd + seg * 32;
        const uint4* skh = (const uint4*)(g_kh + off);
        const uint4* skm = (const uint4*)(g_km + off);
        const uint4* svh = (const uint4*)(g_vh2 + off);
        uint4* dkh = (uint4*)(sm + AT_KHI + j * 144 + seg * 64);
        uint4* dkm = (uint4*)(sm + AT_KMID + j * 144 + seg * 64);
        uint4* dvh = (uint4*)(sm + AT_V + j * 144 + seg * 64);
#pragma unroll
        for (int k = 0; k < 4; k++) {
            dkh[k] = skh[k]; dkm[k] = skm[k]; dvh[k] = svh[k];
        }
    }
    __syncthreads();

    // dots MMA: A = K rows 0..63 (shared-QK), 3 bf16 limb passes
    float Dd[2][4][4];
#pragma unroll
    for (int i = 0; i < 2; i++)
#pragma unroll
        for (int jn = 0; jn < 4; jn++)
#pragma unroll
            for (int q = 0; q < 4; q++) Dd[i][jn][q] = 0.f;

    uint32_t arow = (uint32_t)((wm * 32 + (lane & 15)) * 144 + (lane >> 4) * 16);
    uint32_t brow = (uint32_t)((wn * 32 + ((lane >> 4) & 1) * 8 + (lane & 7)) * 144
                               + ((lane >> 3) & 1) * 16);
    const uint32_t QL[3] = {sb + AT_KMID, sb + AT_KHI, sb + AT_KHI};
    const uint32_t KL[3] = {sb + AT_KHI, sb + AT_KMID, sb + AT_KHI};
#pragma unroll
    for (int p = 0; p < 3; p++) {
#pragma unroll
        for (int ks = 0; ks < 4; ks++) {
            uint32_t A4[2][4], B4[2][4];
#pragma unroll
            for (int i = 0; i < 2; i++) ldmx4(A4[i], QL[p] + arow + i * (16 * 144) + ks * 32);
#pragma unroll
            for (int jp = 0; jp < 2; jp++) ldmx4(B4[jp], KL[p] + brow + jp * (16 * 144) + ks * 32);
#pragma unroll
            for (int i = 0; i < 2; i++)
#pragma unroll
                for (int jn = 0; jn < 4; jn++)
                    mma16816(Dd[i][jn], A4[i], B4[jn >> 1][(jn & 1) * 2], B4[jn >> 1][(jn & 1) * 2 + 1]);
        }
    }

    // scale rows by s, then mask
    float srow[4] = { sS[wm * 32 + g], sS[wm * 32 + g + 8],
                      sS[wm * 32 + 16 + g], sS[wm * 32 + 16 + g + 8] };
#pragma unroll
    for (int i = 0; i < 2; i++)
#pragma unroll
        for (int jn = 0; jn < 4; jn++) {
            Dd[i][jn][0] *= srow[i * 2];
            Dd[i][jn][1] *= srow[i * 2];
            Dd[i][jn][2] *= srow[i * 2 + 1];
            Dd[i][jn][3] *= srow[i * 2 + 1];
        }

    int trow[4] = { tkv[wm * 32 + g], tkv[wm * 32 + g + 8],
                    tkv[wm * 32 + 16 + g], tkv[wm * 32 + 16 + g + 8] };
    int tcol[8];
#pragma unroll
    for (int jn = 0; jn < 4; jn++) {
        int c0 = wn * 32 + jn * 8 + t * 2;
        tcol[jn * 2] = tkv[c0]; tcol[jn * 2 + 1] = tkv[c0 + 1];
    }
#pragma unroll
    for (int i = 0; i < 2; i++)
#pragma unroll
        for (int jn = 0; jn < 4; jn++)
#pragma unroll
            for (int q = 0; q < 4; q++)
                if (trow[i * 2 + (q >> 1)] == tcol[jn * 2 + (q & 1)]) Dd[i][jn][q] = -5e4f;

    // exp (unshifted; dots bounded by s ~ 0.7) -> P fp16 limbs + partial sums
    float ps[4] = {0.f, 0.f, 0.f, 0.f};
#pragma unroll
    for (int i = 0; i < 2; i++) {
        int r0 = wm * 32 + i * 16 + g;
#pragma unroll
        for (int jn = 0; jn < 4; jn++) {
            float e0 = __expf(Dd[i][jn][0]);
            float e1 = __expf(Dd[i][jn][1]);
            float e2 = __expf(Dd[i][jn][2]);
            float e3 = __expf(Dd[i][jn][3]);
            ps[i * 2] += e0 + e1;
            ps[i * 2 + 1] += e2 + e3;
            int c0 = wn * 32 + jn * 8 + t * 2;
            uint32_t h0, m0, h1, m1;
            split2h(e0, e1, h0, m0);
            split2h(e2, e3, h1, m1);
            *(uint32_t*)(sm + AT_PHI  + r0 * 272 + c0 * 2)       = h0;
            *(uint32_t*)(sm + AT_PMID + r0 * 272 + c0 * 2)       = m0;
            *(uint32_t*)(sm + AT_PHI  + (r0 + 8) * 272 + c0 * 2) = h1;
            *(uint32_t*)(sm + AT_PMID + (r0 + 8) * 272 + c0 * 2) = m1;
        }
    }
#pragma unroll
    for (int k = 0; k < 4; k++) {
        ps[k] += __shfl_xor_sync(0xffffffffu, ps[k], 1);
        ps[k] += __shfl_xor_sync(0xffffffffu, ps[k], 2);
    }
    if (t == 0) {
#pragma unroll
        for (int k = 0; k < 4; k++)
            rsump[(wm * 32 + (k >> 1) * 16 + g + (k & 1) * 8) * 4 + wn] = ps[k];
    }
    __syncthreads();

    if (tid < 64) {
        const float* p = rsump + tid * 4;
        float s = p[0] + p[1] + p[2] + p[3];
        rsuminv[tid] = 1.0f / s;
        g_lse[(bh * NHASH + h) * Nn + tkv[tid]] = logf(s);
    }
    __syncthreads();

    // PV MMA: 2 fp16 passes (P_mid*V, P_hi*V), shared V ldmatrix per k-step
    float Dp[2][2][4];
#pragma unroll
    for (int i = 0; i < 2; i++)
#pragma unroll
        for (int jn = 0; jn < 2; jn++)
#pragma unroll
            for (int q = 0; q < 4; q++) Dp[i][jn][q] = 0.f;

    uint32_t parow = (uint32_t)((wm * 32 + (lane & 15)) * 272 + (lane >> 4) * 16);
    uint32_t vbrow = (uint32_t)((lane & 15) * 144 + (lane >> 4) * 16 + wn * 32);
    const uint32_t PL[2] = {sb + AT_PMID, sb + AT_PHI};
#pragma unroll
    for (int ks = 0; ks < 8; ks++) {
        uint32_t B4[4];
        ldmx4t(B4, sb + AT_V + vbrow + ks * (16 * 144));
#pragma unroll
        for (int p = 0; p < 2; p++) {
            uint32_t A4[2][4];
#pragma unroll
            for (int i = 0; i < 2; i++) ldmx4(A4[i], PL[p] + parow + i * (16 * 272) + ks * 32);
#pragma unroll
            for (int i = 0; i < 2; i++)
#pragma unroll
                for (int jn = 0; jn < 2; jn++)
                    mma16816h(Dp[i][jn], A4[i], B4[jn * 2], B4[jn * 2 + 1]);
        }
    }

    // epilogue: normalize + scatter (fp16)
#pragma unroll
    for (int i = 0; i < 2; i++) {
        int r0 = wm * 32 + i * 16 + g;
        float inv0 = rsuminv[r0], inv1 = rsuminv[r0 + 8];
        size_t b0 = ((size_t)(bh * NHASH + h) * Nn + trow[i * 2]) * DHd;
        size_t b1 = ((size_t)(bh * NHASH + h) * Nn + trow[i * 2 + 1]) * DHd;
#pragma unroll
        for (int jn = 0; jn < 2; jn++) {
            int dh = wn * 16 + jn * 8 + t * 2;
            *(uint32_t*)(g_oph2 + b0 + dh) = pack_h2(Dp[i][jn][0] * inv0, Dp[i][jn][1] * inv0);
            *(uint32_t*)(g_oph2 + b1 + dh) = pack_h2(Dp[i][jn][2] * inv1, Dp[i][jn][3] * inv1);
        }
    }
}

// ---------------- fused combine + fp16 2-limb split ----------------
__global__ void combine_split_kernel(__half* __restrict__ hi, __half* __restrict__ mid) {
    int u = blockIdx.x * 256 + threadIdx.x;
    int slot = u >> 3;
    int dseg = (u & 7) * 8;
    int bh = slot >> 12;
    int t = slot & 4095;
    int base = bh * NHASH * Nn + t;
    float l0 = g_lse[base + 0 * Nn];
    float l1 = g_lse[base + 1 * Nn];
    float l2 = g_lse[base + 2 * Nn];
    float l3 = g_lse[base + 3 * Nn];
    float m = fmaxf(fmaxf(l0, l1), fmaxf(l2, l3));
    float w[4] = {expf(l0 - m), expf(l1 - m), expf(l2 - m), expf(l3 - m)};
    float sinv = 1.0f / (w[0] + w[1] + w[2] + w[3]);

    float acc[8];
#pragma unroll
    for (int j = 0; j < 8; j++) acc[j] = 0.f;
#pragma unroll
    for (int k = 0; k < 4; k++) {
        const uint4* p = (const uint4*)(g_oph2 + (((size_t)(bh * NHASH + k)) * Nn + t) * DHd + dseg);
        uint4 x = p[0];
        const __half2* hx = (const __half2*)&x;
#pragma unroll
        for (int j2 = 0; j2 < 4; j2++) {
            float2 f = __half22float2(hx[j2]);
            acc[j2 * 2]     += w[k] * f.x;
            acc[j2 * 2 + 1] += w[k] * f.y;
        }
    }
    float hf[8], mf[8];
#pragma unroll
    for (int j = 0; j < 8; j++) {
        float a = acc[j] * sinv;
        float h = __half2float(__float2half_rn(a));
        hf[j] = h; mf[j] = a - h;
    }
    int b = bh >> 4, head = bh & 15;
    size_t oidx = ((size_t)b * Nn + t) * Cc + head * DHd + dseg;
    *(uint4*)(hi + oidx) = make_uint4(pack_h2(hf[0], hf[1]), pack_h2(hf[2], hf[3]),
                                      pack_h2(hf[4], hf[5]), pack_h2(hf[6], hf[7]));
    *(uint4*)(mid + oidx) = make_uint4(pack_h2(mf[0], mf[1]), pack_h2(mf[2], mf[3]),
                                       pack_h2(mf[4], mf[5]), pack_h2(mf[6], mf[7]));
}

// ---------------- launch ----------------
extern "C" void kernel_launch(void* const* d_in, const int* in_sizes, int n_in,
                              void* d_out, int out_size) {
    const float* queries = (const float*)d_in[0];
    const float* Wqk  = (const float*)d_in[4];
    const float* Wv   = (const float*)d_in[5];
    const float* Wout = (const float*)d_in[6];
    const float* bout = (const float*)d_in[7];
    const float* rot  = (const float*)d_in[8];
    float* out = (float*)d_out;

    cudaFuncSetAttribute(attn_kernel, cudaFuncAttributeMaxDynamicSharedMemorySize, ATTN_SMEM_BYTES);
    cudaFuncSetAttribute(mma_gemm, cudaFuncAttributeMaxDynamicSharedMemorySize, GEMM_SMEM);
    cudaFuncSetAttribute(vgemm_bucket, cudaFuncAttributeMaxDynamicSharedMemorySize, GEMM_SMEM);
    cudaFuncSetAttribute(sort_kernel, cudaFuncAttributeMaxDynamicSharedMemorySize, SORT_SMEM);

    void *p_qk, *p_v, *p_asp, *p_wqkv, *p_wout;
    cudaGetSymbolAddress(&p_qk, g_qk);
    cudaGetSymbolAddress(&p_v, g_v);
    cudaGetSymbolAddress(&p_asp, g_asp);
    cudaGetSymbolAddress(&p_wqkv, g_wqkv_sp);
    cudaGetSymbolAddress(&p_wout, g_wout_sp);
    __half* asp  = (__half*)p_asp;
    __half* wqkv = (__half*)p_wqkv;
    __half* wout = (__half*)p_wout;
    const int NW = 1024 * 1024;

    split_all_kernel<<<5632, 256>>>(queries, Wqk, Wv, Wout, asp, wqkv, wout);

    // qk GEMM: 4-pass fp16 (feeds LSH argmax)
    mma_gemm<<<dim3(8, 64), 256, GEMM_SMEM>>>(asp, APL, wqkv, WQKV_PL,
                                              nullptr, nullptr, (float*)p_qk, 4, PA4, PW4);

    // fused: v GEMM (3-pass fp16) overlapped with bucketing
    vgemm_bucket<<<dim3(72, 64), 256, GEMM_SMEM>>>(asp, APL, wqkv + NW, WQKV_PL,
                                                   (float*)p_v, rot);

    // prep (needs g_qk + g_v) and sort (needs buckets)
    prep_kernel<<<BH * Nn / 8, 256>>>();
    sort_kernel<<<dim3(BH, NHASH), 256, SORT_SMEM>>>();

    attn_kernel<<<dim3(NCHUNK, BH), 256, ATTN_SMEM_BYTES>>>();

    combine_split_kernel<<<(BH * Nn * DHd / 8) / 256, 256>>>(asp, asp + APL);

    // Wout GEMM: 3-pass fp16, +bias -> d_out
    mma_gemm<<<dim3(8, 64), 256, GEMM_SMEM>>>(asp, APL, wout, WOUT_PL,
                                              bout, out, nullptr, 3, PA3, PW3);
}

// round 13
// speedup vs baseline: 3.6477x; 1.0500x over previous
#include <cuda_runtime.h>
#include <cuda_fp16.h>
#include <cuda_bf16.h>
#include <math.h>
#include <stdint.h>

// ---------------- problem constants ----------------
#define Bb      2
#define Nn      4096
#define Cc      1024
#define Hh      16
#define DHd     64
#define BH      32          // Bb*Hh
#define NHASH   4
#define NBUCK   64          // Nn / BUCKET
#define NCHUNK  256         // NHASH*NBUCK
#define BS      64          // bucket size
#define Kdim    1024
#define Mrows   8192        // Bb*Nn

// ---------------- device scratch ----------------
__device__ float g_qk  [BH * Nn * DHd];            // (bh, t, d)
__device__ int   g_bucket[BH * NHASH * Nn];
__device__ int   g_st  [BH * NHASH * Nn];
__device__ __half g_oph2[BH * NHASH * Nn * DHd];   // per-hash outputs, fp16
__device__ float g_lse [BH * NHASH * Nn];

// attention prep planes
#define PLN ((size_t)BH * Nn * DHd)
__device__ __nv_bfloat16 g_kh[PLN], g_km[PLN];     // normalized k limbs (bf16)
__device__ __half g_vh2[PLN];                      // v single fp16 plane (written by v GEMM)
__device__ float g_s[BH * Nn];                     // s = 0.125 * ||q||

// fp16 2-limb planes for GEMMs (W-side pre-scaled by 64; epilogue x 1/64)
#define APL ((size_t)Mrows * Kdim)
#define WQKV_PL ((size_t)2048 * 1024)
#define WOUT_PL ((size_t)1024 * 1024)
__device__ __half g_asp[2 * APL];
__device__ __half g_wqkv_sp[2 * WQKV_PL];
__device__ __half g_wout_sp[2 * WOUT_PL];
#define WSCALE 64.0f
#define OSCALE (1.0f / 64.0f)

// ================= helpers (sm_103-safe) =================
__device__ __forceinline__ uint32_t smem_to_u32(const void* p) {
    uint32_t a;
    asm("{ .reg .u64 t; cvta.to.shared.u64 t, %1; cvt.u32.u64 %0, t; }" : "=r"(a) : "l"(p));
    return a;
}
#define CP_ASYNC16(saddr, gptr) \
    asm volatile("cp.async.cg.shared.global [%0], [%1], 16;" \
        :: "r"(saddr), "l"(__cvta_generic_to_global(gptr)))
#define CP_COMMIT() asm volatile("cp.async.commit_group;" ::: "memory")
#define CP_WAIT(n)  asm volatile("cp.async.wait_group %0;" :: "n"(n) : "memory")

__device__ __forceinline__ void ldmx4(uint32_t* r, uint32_t addr) {
    asm volatile("ldmatrix.sync.aligned.m8n8.x4.shared.b16 {%0,%1,%2,%3}, [%4];"
        : "=r"(r[0]), "=r"(r[1]), "=r"(r[2]), "=r"(r[3]) : "r"(addr));
}
__device__ __forceinline__ void ldmx4t(uint32_t* r, uint32_t addr) {
    asm volatile("ldmatrix.sync.aligned.m8n8.x4.trans.shared.b16 {%0,%1,%2,%3}, [%4];"
        : "=r"(r[0]), "=r"(r[1]), "=r"(r[2]), "=r"(r[3]) : "r"(addr));
}
__device__ __forceinline__ void mma16816h(float* d, const uint32_t* a, uint32_t b0, uint32_t b1) {
    asm volatile("mma.sync.aligned.m16n8k16.row.col.f32.f16.f16.f32 "
        "{%0,%1,%2,%3}, {%4,%5,%6,%7}, {%8,%9}, {%0,%1,%2,%3};"
        : "+f"(d[0]), "+f"(d[1]), "+f"(d[2]), "+f"(d[3])
        : "r"(a[0]), "r"(a[1]), "r"(a[2]), "r"(a[3]), "r"(b0), "r"(b1));
}
__device__ __forceinline__ void mma16816(float* d, const uint32_t* a, uint32_t b0, uint32_t b1) {
    asm volatile("mma.sync.aligned.m16n8k16.row.col.f32.bf16.bf16.f32 "
        "{%0,%1,%2,%3}, {%4,%5,%6,%7}, {%8,%9}, {%0,%1,%2,%3};"
        : "+f"(d[0]), "+f"(d[1]), "+f"(d[2]), "+f"(d[3])
        : "r"(a[0]), "r"(a[1]), "r"(a[2]), "r"(a[3]), "r"(b0), "r"(b1));
}
__device__ __forceinline__ uint32_t pack_h2(float a, float b) {
    uint16_t ua = __half_as_ushort(__float2half_rn(a));
    uint16_t ub = __half_as_ushort(__float2half_rn(b));
    return (uint32_t)ua | ((uint32_t)ub << 16);
}
__device__ __forceinline__ void split2h(float a, float b, uint32_t& hp, uint32_t& mp) {
    float ha = __half2float(__float2half_rn(a));
    float hb = __half2float(__float2half_rn(b));
    hp = pack_h2(ha, hb);
    mp = pack_h2(a - ha, b - hb);
}

// ================= merged fp16 2-limb split (all 4 GEMM tensors) =================
__device__ __forceinline__ void split8(const float* __restrict__ x,
                                       __half* __restrict__ hi, __half* __restrict__ mid,
                                       int i, float scale) {
    float4 v0 = *(const float4*)(x + i);
    float4 v1 = *(const float4*)(x + i + 4);
    float a[8] = {v0.x, v0.y, v0.z, v0.w, v1.x, v1.y, v1.z, v1.w};
    float hf[8], mf[8];
#pragma unroll
    for (int j = 0; j < 8; j++) {
        float s = a[j] * scale;
        float h = __half2float(__float2half_rn(s));
        hf[j] = h; mf[j] = s - h;
    }
    *(uint4*)(hi + i) = make_uint4(pack_h2(hf[0], hf[1]), pack_h2(hf[2], hf[3]),
                                   pack_h2(hf[4], hf[5]), pack_h2(hf[6], hf[7]));
    *(uint4*)(mid + i) = make_uint4(pack_h2(mf[0], mf[1]), pack_h2(mf[2], mf[3]),
                                    pack_h2(mf[4], mf[5]), pack_h2(mf[6], mf[7]));
}

__global__ void split_all_kernel(const float* __restrict__ q,
                                 const float* __restrict__ wqk,
                                 const float* __restrict__ wv,
                                 const float* __restrict__ wo,
                                 __half* __restrict__ asp,
                                 __half* __restrict__ wqkv,
                                 __half* __restrict__ wout) {
    int bid = blockIdx.x;
    int li = threadIdx.x * 8;
    const int NW = 1024 * 1024;
    if (bid < 4096) {
        int i = bid * 2048 + li;
        split8(q, asp, asp + APL, i, 1.0f);
    } else if (bid < 4608) {
        int i = (bid - 4096) * 2048 + li;
        split8(wqk, wqkv, wqkv + WQKV_PL, i, WSCALE);
    } else if (bid < 5120) {
        int i = (bid - 4608) * 2048 + li;
        split8(wv, wqkv + NW, wqkv + WQKV_PL + NW, i, WSCALE);
    } else {
        int i = (bid - 5120) * 2048 + li;
        split8(wo, wout, wout + WOUT_PL, i, WSCALE);
    }
}

// ================= HMMA GEMM body (fp16 limbs) =================
#define ROWB     80
#define MATB     (128 * ROWB)
#define STAGEB   (2 * MATB)
#define GEMM_SMEM (4 * STAGEB)   // 81920
#define PA4 0x0101u
#define PW4 0x0011u
#define PA3 0x010u
#define PW3 0x001u

__device__ __forceinline__ void gemm_issue(uint32_t st,
        const __half* Ap, const __half* Bp, int bm, int bn, int k0,
        uint32_t so0, uint32_t so1, int r0, int c0, int r1, int c1) {
    CP_ASYNC16(st + so0, Ap + (size_t)(bm + r0) * Kdim + k0 + c0 * 8);
    CP_ASYNC16(st + so1, Ap + (size_t)(bm + r1) * Kdim + k0 + c1 * 8);
    CP_ASYNC16(st + MATB + so0, Bp + (size_t)(bn + r0) * Kdim + k0 + c0 * 8);
    CP_ASYNC16(st + MATB + so1, Bp + (size_t)(bn + r1) * Kdim + k0 + c1 * 8);
    CP_COMMIT();
}

// headout   != 0: fp32 head-layout store (qk)
// headout_h != 0: fp16 head-layout store (v plane)
// else: +bias row-major fp32 (Wout -> d_out)
__device__ __forceinline__ void gemm_body(char* smem,
        const __half* __restrict__ Asp, size_t Apl,
        const __half* __restrict__ Bsp, size_t Bpl,
        const float* __restrict__ bias, float* __restrict__ outp,
        float* __restrict__ headout, __half* __restrict__ headout_h,
        int npass, uint32_t paTbl, uint32_t pwTbl, int bn, int bm) {
    uint32_t sbase = smem_to_u32(smem);
    int tid = threadIdx.x;
    int lane = tid & 31, warp = tid >> 5;
    int wm = warp >> 2, wn = warp & 3;
    int nstage = npass * 32;

    int v0 = tid, v1 = tid + 256;
    int r0 = v0 >> 2, c0 = v0 & 3;
    int r1 = v1 >> 2, c1 = v1 & 3;
    uint32_t so0 = (uint32_t)(r0 * ROWB + c0 * 16);
    uint32_t so1 = (uint32_t)(r1 * ROWB + c1 * 16);

    uint32_t aoff = (uint32_t)((wm * 64 + (lane & 15)) * ROWB + (lane >> 4) * 16);
    uint32_t boff = (uint32_t)((wn * 32 + ((lane >> 4) & 1) * 8 + (lane & 7)) * ROWB
                               + ((lane >> 3) & 1) * 16);

    float D[4][4][4];
#pragma unroll
    for (int i = 0; i < 4; i++)
#pragma unroll
        for (int j = 0; j < 4; j++)
#pragma unroll
            for (int q = 0; q < 4; q++) D[i][j][q] = 0.f;

#pragma unroll
    for (int s = 0; s < 3; s++) {
        const __half* Ap = Asp + (size_t)(paTbl & 7) * Apl;
        const __half* Bp = Bsp + (size_t)(pwTbl & 7) * Bpl;
        gemm_issue(sbase + s * STAGEB, Ap, Bp, bm, bn, s * 32, so0, so1, r0, c0, r1, c1);
    }

    for (int s = 0; s < nstage; s++) {
        if (s <= nstage - 3)      { CP_WAIT(2); }
        else if (s == nstage - 2) { CP_WAIT(1); }
        else                      { CP_WAIT(0); }
        __syncthreads();
        if (s + 3 < nstage) {
            int sn = s + 3;
            int p = sn >> 5, k0 = (sn & 31) << 5;
            const __half* Ap = Asp + (size_t)((paTbl >> (p * 4)) & 7) * Apl;
            const __half* Bp = Bsp + (size_t)((pwTbl >> (p * 4)) & 7) * Bpl;
            gemm_issue(sbase + (uint32_t)(sn & 3) * STAGEB, Ap, Bp, bm, bn, k0,
                       so0, so1, r0, c0, r1, c1);
        }
        uint32_t st = sbase + (uint32_t)(s & 3) * STAGEB;
        uint32_t ab = st + aoff;
        uint32_t bb = st + MATB + boff;
#pragma unroll
        for (int ks = 0; ks < 2; ks++) {
            uint32_t A4[4][4], B4[2][4];
#pragma unroll
            for (int i = 0; i < 4; i++) ldmx4(A4[i], ab + i * (16 * ROWB) + ks * 32);
#pragma unroll
            for (int jp = 0; jp < 2; jp++) ldmx4(B4[jp], bb + jp * (16 * ROWB) + ks * 32);
#pragma unroll
            for (int i = 0; i < 4; i++)
#pragma unroll
                for (int jn = 0; jn < 4; jn++)
                    mma16816h(D[i][jn], A4[i], B4[jn >> 1][(jn & 1) * 2], B4[jn >> 1][(jn & 1) * 2 + 1]);
        }
    }

    int g = lane >> 2, t = lane & 3;
#pragma unroll
    for (int i = 0; i < 4; i++) {
#pragma unroll
        for (int jn = 0; jn < 4; jn++) {
            int m0 = bm + wm * 64 + i * 16 + g;
            int n0 = bn + wn * 32 + jn * 8 + t * 2;
            float2 va = make_float2(D[i][jn][0] * OSCALE, D[i][jn][1] * OSCALE);
            float2 vb = make_float2(D[i][jn][2] * OSCALE, D[i][jn][3] * OSCALE);
            if (headout) {
                int bI = m0 >> 12;
                int t0 = m0 & 4095, t1 = (m0 + 8) & 4095;
                int hd = n0 >> 6, dh = n0 & 63;
                *(float2*)(headout + (((size_t)(bI * Hh + hd)) * Nn + t0) * DHd + dh) = va;
                *(float2*)(headout + (((size_t)(bI * Hh + hd)) * Nn + t1) * DHd + dh) = vb;
            } else if (headout_h) {
                int bI = m0 >> 12;
                int t0 = m0 & 4095, t1 = (m0 + 8) & 4095;
                int hd = n0 >> 6, dh = n0 & 63;
                *(uint32_t*)(headout_h + (((size_t)(bI * Hh + hd)) * Nn + t0) * DHd + dh) = pack_h2(va.x, va.y);
                *(uint32_t*)(headout_h + (((size_t)(bI * Hh + hd)) * Nn + t1) * DHd + dh) = pack_h2(vb.x, vb.y);
            } else {
                float2 bv = *(const float2*)(bias + n0);
                va.x += bv.x; va.y += bv.y; vb.x += bv.x; vb.y += bv.y;
                *(float2*)(outp + (size_t)m0 * Cc + n0) = va;
                *(float2*)(outp + (size_t)(m0 + 8) * Cc + n0) = vb;
            }
        }
    }
}

// fused qk (4-pass, x<8) + v (3-pass -> fp16 plane, x>=8) GEMM
__global__ __launch_bounds__(256, 2) void qkv_gemm(
        const __half* __restrict__ Asp,
        const __half* __restrict__ Wqkv,
        float* __restrict__ qkout, __half* __restrict__ vout) {
    extern __shared__ char smem[];
    const int NW = 1024 * 1024;
    if (blockIdx.x < 8) {
        gemm_body(smem, Asp, APL, Wqkv, WQKV_PL, nullptr, nullptr, qkout, nullptr,
                  4, PA4, PW4, blockIdx.x * 128, blockIdx.y * 128);
    } else {
        gemm_body(smem, Asp, APL, Wqkv + NW, WQKV_PL, nullptr, nullptr, nullptr, vout,
                  3, PA3, PW3, (blockIdx.x - 8) * 128, blockIdx.y * 128);
    }
}

// Wout GEMM
__global__ __launch_bounds__(256, 2) void mma_gemm(
        const __half* __restrict__ Asp,
        const __half* __restrict__ Wout_,
        const float* __restrict__ bias, float* __restrict__ outp) {
    extern __shared__ char smem[];
    gemm_body(smem, Asp, APL, Wout_, WOUT_PL, bias, outp, nullptr, nullptr,
              3, PA3, PW3, blockIdx.x * 128, blockIdx.y * 128);
}

// ---------------- LSH bucketing body ----------------
__device__ __forceinline__ void bucket_body(char* smemc, const float* __restrict__ rot,
                                            int bh, int tb) {
    float* rs = (float*)smemc;
    float* qs = rs + DHd * 128;
    int tid = threadIdx.x;

    for (int i = tid; i < DHd * 128; i += 256) rs[i] = rot[i];
    {
        int row = tid >> 2, seg = tid & 3;
        const float* src = g_qk + ((size_t)bh * Nn + tb + row) * DHd + seg * 16;
#pragma unroll
        for (int k = 0; k < 16; k++) qs[row * 65 + seg * 16 + k] = src[k];
    }
    __syncthreads();

    int warp = tid >> 5, lane = tid & 31;
    int h = warp & 3;
    int tok = (warp >> 2) * 32 + lane;

    float r[32];
#pragma unroll
    for (int i = 0; i < 32; i++) r[i] = 0.f;
    for (int d = 0; d < DHd; d++) {
        float qd = qs[tok * 65 + d];
        const float* rp = rs + d * 128 + h * 32;
#pragma unroll
        for (int i = 0; i < 32; i++) r[i] += qd * rp[i];
    }
    float best = r[0]; int bi = 0;
#pragma unroll
    for (int i = 1; i < 32; i++) if (r[i] > best) { best = r[i]; bi = i; }
#pragma unroll
    for (int i = 0; i < 32; i++) if (-r[i] > best) { best = -r[i]; bi = 32 + i; }
    g_bucket[((size_t)bh * NHASH + h) * Nn + tb + tok] = bi;
}

// ---------------- fused bucket + k/s prep (both need only g_qk) ----------------
#define PB_SMEM 49408   // rs 32768 + qs 16640
__global__ void prep_bucket_kernel(const float* __restrict__ rot) {
    extern __shared__ char smem[];
    int bid = blockIdx.x;
    if (bid < 2048) {
        bucket_body(smem, rot, bid >> 6, (bid & 63) * 64);
        return;
    }
    // prep: 8 rows per block, warp per row
    int row = (bid - 2048) * 8 + (threadIdx.x >> 5);
    int lane = threadIdx.x & 31;
    size_t off = (size_t)row * DHd;
    const float* src = g_qk + off;
    float a = src[lane], b = src[lane + 32];

    float s = a * a + b * b;
#pragma unroll
    for (int o = 16; o > 0; o >>= 1) s += __shfl_xor_sync(0xffffffffu, s, o);
    float norm = sqrtf(s);
    float inv = 1.0f / fmaxf(norm, 1e-12f);
    if (lane == 0) g_s[row] = 0.125f * norm;

    float ka = a * inv, kb = b * inv;
    float kah = __bfloat162float(__float2bfloat16(ka));
    float kbh = __bfloat162float(__float2bfloat16(kb));
    g_kh[off + lane]      = __float2bfloat16(kah);
    g_kh[off + lane + 32] = __float2bfloat16(kbh);
    g_km[off + lane]      = __float2bfloat16(ka - kah);
    g_km[off + lane + 32] = __float2bfloat16(kb - kbh);
}

// ---------------- parallel stable counting sort per (bh, hash) ----------------
#define SORT_SMEM 49152
__global__ void sort_kernel() {
    extern __shared__ char ss[];
    unsigned char*  cnt    = (unsigned char*)ss;
    unsigned short* segoff = (unsigned short*)(ss + 16384);
    __shared__ int bbase[NBUCK];
    int bh = blockIdx.x, h = blockIdx.y;
    int tid = threadIdx.x;
    const int gb = (bh * NHASH + h) * Nn;

    uint32_t* ci = (uint32_t*)cnt;
    for (int i = tid; i < 4096; i += 256) ci[i] = 0;
    __syncthreads();

    int bb[16];
#pragma unroll
    for (int k = 0; k < 16; k++) {
        int b = g_bucket[gb + tid * 16 + k];
        bb[k] = b;
        cnt[tid * 64 + b]++;
    }
    __syncthreads();

    if (tid < NBUCK) {
        int run = 0;
        for (int seg = 0; seg < 256; seg++) {
            segoff[seg * 64 + tid] = (unsigned short)run;
            run += cnt[seg * 64 + tid];
        }
        bbase[tid] = run;
    }
    __syncthreads();
    if (tid == 0) {
        int acc = 0;
        for (int b = 0; b < NBUCK; b++) { int c = bbase[b]; bbase[b] = acc; acc += c; }
    }
    __syncthreads();

#pragma unroll
    for (int k = 0; k < 16; k++) {
        int b = bb[k];
        int pos = bbase[b] + segoff[tid * 64 + b];
        segoff[tid * 64 + b]++;
        g_st[gb + pos] = tid * 16 + k;
    }
}

// ---------------- chunked LSH attention: K-as-A dots, fp16 PV ----------------
#define AT_S     512
#define AT_KHI   3072
#define AT_KMID  21504
#define AT_V     39936
#define AT_PHI   58368
#define AT_PMID  75776
#define ATTN_SMEM_BYTES 93184

__global__ __launch_bounds__(256, 2) void attn_kernel() {
    extern __shared__ char sm[];
    int*   tkv     = (int*)sm;
    float* sS      = (float*)(sm + AT_S);
    float* rsump   = (float*)(sm + 1536);
    float* rsuminv = (float*)(sm + 2560);
    uint32_t sb = smem_to_u32(sm);

    int c = blockIdx.x, bh = blockIdx.y;
    int h = c >> 6;
    int tid = threadIdx.x, lane = tid & 31, warp = tid >> 5;
    int g = lane >> 2, t = lane & 3;
    int wm = warp >> 2, wn = warp & 3;
    int pc = (c + NCHUNK - 1) & (NCHUNK - 1);
    const int stb = bh * (NHASH * Nn);

    if (tid < 64)       tkv[tid] = g_st[stb + c * BS + tid];
    else if (tid < 128) tkv[tid] = g_st[stb + pc * BS + (tid - 64)];
    __syncthreads();

    if (tid < 64) sS[tid] = g_s[(size_t)bh * Nn + tkv[tid]];

    // gather k limbs + v via cp.async (2 threads/row x 32 elems; 12 x 16B each)
    {
        int j = tid >> 1, seg = tid & 1;
        size_t off = ((size_t)bh * Nn + tkv[j]) * DHd + seg * 32;
        const __nv_bfloat16* skh = g_kh + off;
        const __nv_bfloat16* skm = g_km + off;
        const __half* svh = g_vh2 + off;
        uint32_t dkh = sb + AT_KHI + j * 144 + seg * 64;
        uint32_t dkm = sb + AT_KMID + j * 144 + seg * 64;
        uint32_t dvh = sb + AT_V + j * 144 + seg * 64;
#pragma unroll
        for (int k = 0; k < 4; k++) {
            CP_ASYNC16(dkh + k * 16, skh + k * 8);
            CP_ASYNC16(dkm + k * 16, skm + k * 8);
            CP_ASYNC16(dvh + k * 16, svh + k * 8);
        }
        CP_COMMIT();
        CP_WAIT(0);
    }
    __syncthreads();

    // dots MMA: A = K rows 0..63 (shared-QK), 3 bf16 limb passes
    float Dd[2][4][4];
#pragma unroll
    for (int i = 0; i < 2; i++)
#pragma unroll
        for (int jn = 0; jn < 4; jn++)
#pragma unroll
            for (int q = 0; q < 4; q++) Dd[i][jn][q] = 0.f;

    uint32_t arow = (uint32_t)((wm * 32 + (lane & 15)) * 144 + (lane >> 4) * 16);
    uint32_t brow = (uint32_t)((wn * 32 + ((lane >> 4) & 1) * 8 + (lane & 7)) * 144
                               + ((lane >> 3) & 1) * 16);
    const uint32_t QL[3] = {sb + AT_KMID, sb + AT_KHI, sb + AT_KHI};
    const uint32_t KL[3] = {sb + AT_KHI, sb + AT_KMID, sb + AT_KHI};
#pragma unroll
    for (int p = 0; p < 3; p++) {
#pragma unroll
        for (int ks = 0; ks < 4; ks++) {
            uint32_t A4[2][4], B4[2][4];
#pragma unroll
            for (int i = 0; i < 2; i++) ldmx4(A4[i], QL[p] + arow + i * (16 * 144) + ks * 32);
#pragma unroll
            for (int jp = 0; jp < 2; jp++) ldmx4(B4[jp], KL[p] + brow + jp * (16 * 144) + ks * 32);
#pragma unroll
            for (int i = 0; i < 2; i++)
#pragma unroll
                for (int jn = 0; jn < 4; jn++)
                    mma16816(Dd[i][jn], A4[i], B4[jn >> 1][(jn & 1) * 2], B4[jn >> 1][(jn & 1) * 2 + 1]);
        }
    }

    // scale rows by s, then mask
    float srow[4] = { sS[wm * 32 + g], sS[wm * 32 + g + 8],
                      sS[wm * 32 + 16 + g], sS[wm * 32 + 16 + g + 8] };
#pragma unroll
    for (int i = 0; i < 2; i++)
#pragma unroll
        for (int jn = 0; jn < 4; jn++) {
            Dd[i][jn][0] *= srow[i * 2];
            Dd[i][jn][1] *= srow[i * 2];
            Dd[i][jn][2] *= srow[i * 2 + 1];
            Dd[i][jn][3] *= srow[i * 2 + 1];
        }

    int trow[4] = { tkv[wm * 32 + g], tkv[wm * 32 + g + 8],
                    tkv[wm * 32 + 16 + g], tkv[wm * 32 + 16 + g + 8] };
    int tcol[8];
#pragma unroll
    for (int jn = 0; jn < 4; jn++) {
        int c0 = wn * 32 + jn * 8 + t * 2;
        tcol[jn * 2] = tkv[c0]; tcol[jn * 2 + 1] = tkv[c0 + 1];
    }
#pragma unroll
    for (int i = 0; i < 2; i++)
#pragma unroll
        for (int jn = 0; jn < 4; jn++)
#pragma unroll
            for (int q = 0; q < 4; q++)
                if (trow[i * 2 + (q >> 1)] == tcol[jn * 2 + (q & 1)]) Dd[i][jn][q] = -5e4f;

    // exp (unshifted; dots bounded) -> P fp16 limbs + partial sums
    float ps[4] = {0.f, 0.f, 0.f, 0.f};
#pragma unroll
    for (int i = 0; i < 2; i++) {
        int r0 = wm * 32 + i * 16 + g;
#pragma unroll
        for (int jn = 0; jn < 4; jn++) {
            float e0 = __expf(Dd[i][jn][0]);
            float e1 = __expf(Dd[i][jn][1]);
            float e2 = __expf(Dd[i][jn][2]);
            float e3 = __expf(Dd[i][jn][3]);
            ps[i * 2] += e0 + e1;
            ps[i * 2 + 1] += e2 + e3;
            int c0 = wn * 32 + jn * 8 + t * 2;
            uint32_t h0, m0, h1, m1;
            split2h(e0, e1, h0, m0);
            split2h(e2, e3, h1, m1);
            *(uint32_t*)(sm + AT_PHI  + r0 * 272 + c0 * 2)       = h0;
            *(uint32_t*)(sm + AT_PMID + r0 * 272 + c0 * 2)       = m0;
            *(uint32_t*)(sm + AT_PHI  + (r0 + 8) * 272 + c0 * 2) = h1;
            *(uint32_t*)(sm + AT_PMID + (r0 + 8) * 272 + c0 * 2) = m1;
        }
    }
#pragma unroll
    for (int k = 0; k < 4; k++) {
        ps[k] += __shfl_xor_sync(0xffffffffu, ps[k], 1);
        ps[k] += __shfl_xor_sync(0xffffffffu, ps[k], 2);
    }
    if (t == 0) {
#pragma unroll
        for (int k = 0; k < 4; k++)
            rsump[(wm * 32 + (k >> 1) * 16 + g + (k & 1) * 8) * 4 + wn] = ps[k];
    }
    __syncthreads();

    if (tid < 64) {
        const float* p = rsump + tid * 4;
        float s = p[0] + p[1] + p[2] + p[3];
        rsuminv[tid] = 1.0f / s;
        g_lse[(bh * NHASH + h) * Nn + tkv[tid]] = logf(s);
    }
    __syncthreads();

    // PV MMA: 2 fp16 passes sharing V ldmatrix per k-step
    float Dp[2][2][4];
#pragma unroll
    for (int i = 0; i < 2; i++)
#pragma unroll
        for (int jn = 0; jn < 2; jn++)
#pragma unroll
            for (int q = 0; q < 4; q++) Dp[i][jn][q] = 0.f;

    uint32_t parow = (uint32_t)((wm * 32 + (lane & 15)) * 272 + (lane >> 4) * 16);
    uint32_t vbrow = (uint32_t)((lane & 15) * 144 + (lane >> 4) * 16 + wn * 32);
    const uint32_t PL[2] = {sb + AT_PMID, sb + AT_PHI};
#pragma unroll
    for (int ks = 0; ks < 8; ks++) {
        uint32_t B4[4];
        ldmx4t(B4, sb + AT_V + vbrow + ks * (16 * 144));
#pragma unroll
        for (int p = 0; p < 2; p++) {
            uint32_t A4[2][4];
#pragma unroll
            for (int i = 0; i < 2; i++) ldmx4(A4[i], PL[p] + parow + i * (16 * 272) + ks * 32);
#pragma unroll
            for (int i = 0; i < 2; i++)
#pragma unroll
                for (int jn = 0; jn < 2; jn++)
                    mma16816h(Dp[i][jn], A4[i], B4[jn * 2], B4[jn * 2 + 1]);
        }
    }

    // epilogue: normalize + scatter (fp16)
#pragma unroll
    for (int i = 0; i < 2; i++) {
        int r0 = wm * 32 + i * 16 + g;
        float inv0 = rsuminv[r0], inv1 = rsuminv[r0 + 8];
        size_t b0 = ((size_t)(bh * NHASH + h) * Nn + trow[i * 2]) * DHd;
        size_t b1 = ((size_t)(bh * NHASH + h) * Nn + trow[i * 2 + 1]) * DHd;
#pragma unroll
        for (int jn = 0; jn < 2; jn++) {
            int dh = wn * 16 + jn * 8 + t * 2;
            *(uint32_t*)(g_oph2 + b0 + dh) = pack_h2(Dp[i][jn][0] * inv0, Dp[i][jn][1] * inv0);
            *(uint32_t*)(g_oph2 + b1 + dh) = pack_h2(Dp[i][jn][2] * inv1, Dp[i][jn][3] * inv1);
        }
    }
}

// ---------------- fused combine + fp16 2-limb split ----------------
__global__ void combine_split_kernel(__half* __restrict__ hi, __half* __restrict__ mid) {
    int u = blockIdx.x * 256 + threadIdx.x;
    int slot = u >> 3;
    int dseg = (u & 7) * 8;
    int bh = slot >> 12;
    int t = slot & 4095;
    int base = bh * NHASH * Nn + t;
    float l0 = g_lse[base + 0 * Nn];
    float l1 = g_lse[base + 1 * Nn];
    float l2 = g_lse[base + 2 * Nn];
    float l3 = g_lse[base + 3 * Nn];
    float m = fmaxf(fmaxf(l0, l1), fmaxf(l2, l3));
    float w[4] = {expf(l0 - m), expf(l1 - m), expf(l2 - m), expf(l3 - m)};
    float sinv = 1.0f / (w[0] + w[1] + w[2] + w[3]);

    float acc[8];
#pragma unroll
    for (int j = 0; j < 8; j++) acc[j] = 0.f;
#pragma unroll
    for (int k = 0; k < 4; k++) {
        const uint4* p = (const uint4*)(g_oph2 + (((size_t)(bh * NHASH + k)) * Nn + t) * DHd + dseg);
        uint4 x = p[0];
        const __half2* hx = (const __half2*)&x;
#pragma unroll
        for (int j2 = 0; j2 < 4; j2++) {
            float2 f = __half22float2(hx[j2]);
            acc[j2 * 2]     += w[k] * f.x;
            acc[j2 * 2 + 1] += w[k] * f.y;
        }
    }
    float hf[8], mf[8];
#pragma unroll
    for (int j = 0; j < 8; j++) {
        float a = acc[j] * sinv;
        float h = __half2float(__float2half_rn(a));
        hf[j] = h; mf[j] = a - h;
    }
    int b = bh >> 4, head = bh & 15;
    size_t oidx = ((size_t)b * Nn + t) * Cc + head * DHd + dseg;
    *(uint4*)(hi + oidx) = make_uint4(pack_h2(hf[0], hf[1]), pack_h2(hf[2], hf[3]),
                                      pack_h2(hf[4], hf[5]), pack_h2(hf[6], hf[7]));
    *(uint4*)(mid + oidx) = make_uint4(pack_h2(mf[0], mf[1]), pack_h2(mf[2], mf[3]),
                                       pack_h2(mf[4], mf[5]), pack_h2(mf[6], mf[7]));
}

// ---------------- launch ----------------
extern "C" void kernel_launch(void* const* d_in, const int* in_sizes, int n_in,
                              void* d_out, int out_size) {
    const float* queries = (const float*)d_in[0];
    const float* Wqk  = (const float*)d_in[4];
    const float* Wv   = (const float*)d_in[5];
    const float* Wout = (const float*)d_in[6];
    const float* bout = (const float*)d_in[7];
    const float* rot  = (const float*)d_in[8];
    float* out = (float*)d_out;

    cudaFuncSetAttribute(attn_kernel, cudaFuncAttributeMaxDynamicSharedMemorySize, ATTN_SMEM_BYTES);
    cudaFuncSetAttribute(qkv_gemm, cudaFuncAttributeMaxDynamicSharedMemorySize, GEMM_SMEM);
    cudaFuncSetAttribute(mma_gemm, cudaFuncAttributeMaxDynamicSharedMemorySize, GEMM_SMEM);
    cudaFuncSetAttribute(prep_bucket_kernel, cudaFuncAttributeMaxDynamicSharedMemorySize, PB_SMEM);
    cudaFuncSetAttribute(sort_kernel, cudaFuncAttributeMaxDynamicSharedMemorySize, SORT_SMEM);

    void *p_qk, *p_vh2, *p_asp, *p_wqkv, *p_wout;
    cudaGetSymbolAddress(&p_qk, g_qk);
    cudaGetSymbolAddress(&p_vh2, g_vh2);
    cudaGetSymbolAddress(&p_asp, g_asp);
    cudaGetSymbolAddress(&p_wqkv, g_wqkv_sp);
    cudaGetSymbolAddress(&p_wout, g_wout_sp);
    __half* asp  = (__half*)p_asp;
    __half* wqkv = (__half*)p_wqkv;
    __half* wout = (__half*)p_wout;

    split_all_kernel<<<5632, 256>>>(queries, Wqk, Wv, Wout, asp, wqkv, wout);

    // fused qk (4-pass) + v (3-pass, fp16 plane) GEMM
    qkv_gemm<<<dim3(16, 64), 256, GEMM_SMEM>>>(asp, wqkv, (float*)p_qk, (__half*)p_vh2);

    // fused bucket + k/s prep (both need only g_qk)
    prep_bucket_kernel<<<2048 + BH * Nn / 8, 256, PB_SMEM>>>(rot);
    sort_kernel<<<dim3(BH, NHASH), 256, SORT_SMEM>>>();

    attn_kernel<<<dim3(NCHUNK, BH), 256, ATTN_SMEM_BYTES>>>();

    combine_split_kernel<<<(BH * Nn * DHd / 8) / 256, 256>>>(asp, asp + APL);

    // Wout GEMM: 3-pass fp16, +bias -> d_out
    mma_gemm<<<dim3(8, 64), 256, GEMM_SMEM>>>(asp, wout, bout, out);
}

// round 14
// speedup vs baseline: 4.2599x; 1.1678x over previous
#include <cuda_runtime.h>
#include <cuda_fp16.h>
#include <cuda_bf16.h>
#include <math.h>
#include <stdint.h>

// ---------------- problem constants ----------------
#define Bb      2
#define Nn      4096
#define Cc      1024
#define Hh      16
#define DHd     64
#define BH      32          // Bb*Hh
#define NHASH   4
#define NBUCK   64          // Nn / BUCKET
#define NCHUNK  256         // NHASH*NBUCK
#define BS      64          // bucket size
#define Kdim    1024
#define Mrows   8192        // Bb*Nn

// ---------------- device scratch ----------------
__device__ float g_qk  [BH * Nn * DHd];            // (bh, t, d)
__device__ int   g_bucket[BH * NHASH * Nn];
__device__ int   g_st  [BH * NHASH * Nn];
__device__ __half g_oph2[BH * NHASH * Nn * DHd];   // per-hash outputs, fp16
__device__ float g_lse [BH * NHASH * Nn];

// attention prep planes
#define PLN ((size_t)BH * Nn * DHd)
__device__ __half g_kh[PLN], g_km[PLN];            // normalized k limbs (fp16)
__device__ __half g_vh2[PLN];                      // v single fp16 plane (written by v GEMM)
__device__ float g_s[BH * Nn];                     // s = 0.125 * ||q||

// fp16 2-limb planes for GEMMs (W-side pre-scaled by 64; epilogue x 1/64)
#define APL ((size_t)Mrows * Kdim)
#define WQKV_PL ((size_t)2048 * 1024)
#define WOUT_PL ((size_t)1024 * 1024)
__device__ __half g_asp[2 * APL];
__device__ __half g_wqkv_sp[2 * WQKV_PL];
__device__ __half g_wout_sp[2 * WOUT_PL];
#define WSCALE 64.0f
#define OSCALE (1.0f / 64.0f)

// ================= helpers (sm_103-safe) =================
__device__ __forceinline__ uint32_t smem_to_u32(const void* p) {
    uint32_t a;
    asm("{ .reg .u64 t; cvta.to.shared.u64 t, %1; cvt.u32.u64 %0, t; }" : "=r"(a) : "l"(p));
    return a;
}
#define CP_ASYNC16(saddr, gptr) \
    asm volatile("cp.async.cg.shared.global [%0], [%1], 16;" \
        :: "r"(saddr), "l"(__cvta_generic_to_global(gptr)))
#define CP_COMMIT() asm volatile("cp.async.commit_group;" ::: "memory")
#define CP_WAIT(n)  asm volatile("cp.async.wait_group %0;" :: "n"(n) : "memory")

__device__ __forceinline__ void ldmx4(uint32_t* r, uint32_t addr) {
    asm volatile("ldmatrix.sync.aligned.m8n8.x4.shared.b16 {%0,%1,%2,%3}, [%4];"
        : "=r"(r[0]), "=r"(r[1]), "=r"(r[2]), "=r"(r[3]) : "r"(addr));
}
__device__ __forceinline__ void ldmx4t(uint32_t* r, uint32_t addr) {
    asm volatile("ldmatrix.sync.aligned.m8n8.x4.trans.shared.b16 {%0,%1,%2,%3}, [%4];"
        : "=r"(r[0]), "=r"(r[1]), "=r"(r[2]), "=r"(r[3]) : "r"(addr));
}
__device__ __forceinline__ void mma16816h(float* d, const uint32_t* a, uint32_t b0, uint32_t b1) {
    asm volatile("mma.sync.aligned.m16n8k16.row.col.f32.f16.f16.f32 "
        "{%0,%1,%2,%3}, {%4,%5,%6,%7}, {%8,%9}, {%0,%1,%2,%3};"
        : "+f"(d[0]), "+f"(d[1]), "+f"(d[2]), "+f"(d[3])
        : "r"(a[0]), "r"(a[1]), "r"(a[2]), "r"(a[3]), "r"(b0), "r"(b1));
}
__device__ __forceinline__ uint32_t pack_h2(float a, float b) {
    uint16_t ua = __half_as_ushort(__float2half_rn(a));
    uint16_t ub = __half_as_ushort(__float2half_rn(b));
    return (uint32_t)ua | ((uint32_t)ub << 16);
}

// ================= merged fp16 2-limb split (all 4 GEMM tensors) =================
__device__ __forceinline__ void split8(const float* __restrict__ x,
                                       __half* __restrict__ hi, __half* __restrict__ mid,
                                       int i, float scale) {
    float4 v0 = *(const float4*)(x + i);
    float4 v1 = *(const float4*)(x + i + 4);
    float a[8] = {v0.x, v0.y, v0.z, v0.w, v1.x, v1.y, v1.z, v1.w};
    float hf[8], mf[8];
#pragma unroll
    for (int j = 0; j < 8; j++) {
        float s = a[j] * scale;
        float h = __half2float(__float2half_rn(s));
        hf[j] = h; mf[j] = s - h;
    }
    *(uint4*)(hi + i) = make_uint4(pack_h2(hf[0], hf[1]), pack_h2(hf[2], hf[3]),
                                   pack_h2(hf[4], hf[5]), pack_h2(hf[6], hf[7]));
    *(uint4*)(mid + i) = make_uint4(pack_h2(mf[0], mf[1]), pack_h2(mf[2], mf[3]),
                                    pack_h2(mf[4], mf[5]), pack_h2(mf[6], mf[7]));
}

__global__ void split_all_kernel(const float* __restrict__ q,
                                 const float* __restrict__ wqk,
                                 const float* __restrict__ wv,
                                 const float* __restrict__ wo,
                                 __half* __restrict__ asp,
                                 __half* __restrict__ wqkv,
                                 __half* __restrict__ wout) {
    int bid = blockIdx.x;
    int li = threadIdx.x * 8;
    const int NW = 1024 * 1024;
    if (bid < 4096) {
        int i = bid * 2048 + li;
        split8(q, asp, asp + APL, i, 1.0f);
    } else if (bid < 4608) {
        int i = (bid - 4096) * 2048 + li;
        split8(wqk, wqkv, wqkv + WQKV_PL, i, WSCALE);
    } else if (bid < 5120) {
        int i = (bid - 4608) * 2048 + li;
        split8(wv, wqkv + NW, wqkv + WQKV_PL + NW, i, WSCALE);
    } else {
        int i = (bid - 5120) * 2048 + li;
        split8(wo, wout, wout + WOUT_PL, i, WSCALE);
    }
}

// ================= HMMA GEMM body (fp16 limbs) =================
#define ROWB     80
#define MATB     (128 * ROWB)
#define STAGEB   (2 * MATB)
#define GEMM_SMEM (4 * STAGEB)   // 81920
#define PA4 0x0101u
#define PW4 0x0011u
#define PA2 0x00u
#define PW2 0x01u

__device__ __forceinline__ void gemm_issue(uint32_t st,
        const __half* Ap, const __half* Bp, int bm, int bn, int k0,
        uint32_t so0, uint32_t so1, int r0, int c0, int r1, int c1) {
    CP_ASYNC16(st + so0, Ap + (size_t)(bm + r0) * Kdim + k0 + c0 * 8);
    CP_ASYNC16(st + so1, Ap + (size_t)(bm + r1) * Kdim + k0 + c1 * 8);
    CP_ASYNC16(st + MATB + so0, Bp + (size_t)(bn + r0) * Kdim + k0 + c0 * 8);
    CP_ASYNC16(st + MATB + so1, Bp + (size_t)(bn + r1) * Kdim + k0 + c1 * 8);
    CP_COMMIT();
}

// headout   != 0: fp32 head-layout store (qk)
// headout_h != 0: fp16 head-layout store (v plane)
// else: +bias row-major fp32 (Wout -> d_out)
__device__ __forceinline__ void gemm_body(char* smem,
        const __half* __restrict__ Asp, size_t Apl,
        const __half* __restrict__ Bsp, size_t Bpl,
        const float* __restrict__ bias, float* __restrict__ outp,
        float* __restrict__ headout, __half* __restrict__ headout_h,
        int npass, uint32_t paTbl, uint32_t pwTbl, int bn, int bm) {
    uint32_t sbase = smem_to_u32(smem);
    int tid = threadIdx.x;
    int lane = tid & 31, warp = tid >> 5;
    int wm = warp >> 2, wn = warp & 3;
    int nstage = npass * 32;

    int v0 = tid, v1 = tid + 256;
    int r0 = v0 >> 2, c0 = v0 & 3;
    int r1 = v1 >> 2, c1 = v1 & 3;
    uint32_t so0 = (uint32_t)(r0 * ROWB + c0 * 16);
    uint32_t so1 = (uint32_t)(r1 * ROWB + c1 * 16);

    uint32_t aoff = (uint32_t)((wm * 64 + (lane & 15)) * ROWB + (lane >> 4) * 16);
    uint32_t boff = (uint32_t)((wn * 32 + ((lane >> 4) & 1) * 8 + (lane & 7)) * ROWB
                               + ((lane >> 3) & 1) * 16);

    float D[4][4][4];
#pragma unroll
    for (int i = 0; i < 4; i++)
#pragma unroll
        for (int j = 0; j < 4; j++)
#pragma unroll
            for (int q = 0; q < 4; q++) D[i][j][q] = 0.f;

#pragma unroll
    for (int s = 0; s < 3; s++) {
        const __half* Ap = Asp + (size_t)(paTbl & 7) * Apl;
        const __half* Bp = Bsp + (size_t)(pwTbl & 7) * Bpl;
        gemm_issue(sbase + s * STAGEB, Ap, Bp, bm, bn, (s & 31) * 32, so0, so1, r0, c0, r1, c1);
    }

    for (int s = 0; s < nstage; s++) {
        if (s <= nstage - 3)      { CP_WAIT(2); }
        else if (s == nstage - 2) { CP_WAIT(1); }
        else                      { CP_WAIT(0); }
        __syncthreads();
        if (s + 3 < nstage) {
            int sn = s + 3;
            int p = sn >> 5, k0 = (sn & 31) << 5;
            const __half* Ap = Asp + (size_t)((paTbl >> (p * 4)) & 7) * Apl;
            const __half* Bp = Bsp + (size_t)((pwTbl >> (p * 4)) & 7) * Bpl;
            gemm_issue(sbase + (uint32_t)(sn & 3) * STAGEB, Ap, Bp, bm, bn, k0,
                       so0, so1, r0, c0, r1, c1);
        }
        uint32_t st = sbase + (uint32_t)(s & 3) * STAGEB;
        uint32_t ab = st + aoff;
        uint32_t bb = st + MATB + boff;
#pragma unroll
        for (int ks = 0; ks < 2; ks++) {
            uint32_t A4[4][4], B4[2][4];
#pragma unroll
            for (int i = 0; i < 4; i++) ldmx4(A4[i], ab + i * (16 * ROWB) + ks * 32);
#pragma unroll
            for (int jp = 0; jp < 2; jp++) ldmx4(B4[jp], bb + jp * (16 * ROWB) + ks * 32);
#pragma unroll
            for (int i = 0; i < 4; i++)
#pragma unroll
                for (int jn = 0; jn < 4; jn++)
                    mma16816h(D[i][jn], A4[i], B4[jn >> 1][(jn & 1) * 2], B4[jn >> 1][(jn & 1) * 2 + 1]);
        }
    }

    int g = lane >> 2, t = lane & 3;
#pragma unroll
    for (int i = 0; i < 4; i++) {
#pragma unroll
        for (int jn = 0; jn < 4; jn++) {
            int m0 = bm + wm * 64 + i * 16 + g;
            int n0 = bn + wn * 32 + jn * 8 + t * 2;
            float2 va = make_float2(D[i][jn][0] * OSCALE, D[i][jn][1] * OSCALE);
            float2 vb = make_float2(D[i][jn][2] * OSCALE, D[i][jn][3] * OSCALE);
            if (headout) {
                int bI = m0 >> 12;
                int t0 = m0 & 4095, t1 = (m0 + 8) & 4095;
                int hd = n0 >> 6, dh = n0 & 63;
                *(float2*)(headout + (((size_t)(bI * Hh + hd)) * Nn + t0) * DHd + dh) = va;
                *(float2*)(headout + (((size_t)(bI * Hh + hd)) * Nn + t1) * DHd + dh) = vb;
            } else if (headout_h) {
                int bI = m0 >> 12;
                int t0 = m0 & 4095, t1 = (m0 + 8) & 4095;
                int hd = n0 >> 6, dh = n0 & 63;
                *(uint32_t*)(headout_h + (((size_t)(bI * Hh + hd)) * Nn + t0) * DHd + dh) = pack_h2(va.x, va.y);
                *(uint32_t*)(headout_h + (((size_t)(bI * Hh + hd)) * Nn + t1) * DHd + dh) = pack_h2(vb.x, vb.y);
            } else {
                float2 bv = *(const float2*)(bias + n0);
                va.x += bv.x; va.y += bv.y; vb.x += bv.x; vb.y += bv.y;
                *(float2*)(outp + (size_t)m0 * Cc + n0) = va;
                *(float2*)(outp + (size_t)(m0 + 8) * Cc + n0) = vb;
            }
        }
    }
}

// fused qk (4-pass, x<8) + v (2-pass -> fp16 plane, x>=8) GEMM
__global__ __launch_bounds__(256, 2) void qkv_gemm(
        const __half* __restrict__ Asp,
        const __half* __restrict__ Wqkv,
        float* __restrict__ qkout, __half* __restrict__ vout) {
    extern __shared__ char smem[];
    const int NW = 1024 * 1024;
    if (blockIdx.x < 8) {
        gemm_body(smem, Asp, APL, Wqkv, WQKV_PL, nullptr, nullptr, qkout, nullptr,
                  4, PA4, PW4, blockIdx.x * 128, blockIdx.y * 128);
    } else {
        gemm_body(smem, Asp, APL, Wqkv + NW, WQKV_PL, nullptr, nullptr, nullptr, vout,
                  2, PA2, PW2, (blockIdx.x - 8) * 128, blockIdx.y * 128);
    }
}

// Wout GEMM: 2-pass, A single plane (combine writes hi only)
__global__ __launch_bounds__(256, 2) void mma_gemm(
        const __half* __restrict__ Asp,
        const __half* __restrict__ Wout_,
        const float* __restrict__ bias, float* __restrict__ outp) {
    extern __shared__ char smem[];
    gemm_body(smem, Asp, APL, Wout_, WOUT_PL, bias, outp, nullptr, nullptr,
              2, PA2, PW2, blockIdx.x * 128, blockIdx.y * 128);
}

// ---------------- LSH bucketing body ----------------
__device__ __forceinline__ void bucket_body(char* smemc, const float* __restrict__ rot,
                                            int bh, int tb) {
    float* rs = (float*)smemc;
    float* qs = rs + DHd * 128;
    int tid = threadIdx.x;

    for (int i = tid; i < DHd * 128; i += 256) rs[i] = rot[i];
    {
        int row = tid >> 2, seg = tid & 3;
        const float* src = g_qk + ((size_t)bh * Nn + tb + row) * DHd + seg * 16;
#pragma unroll
        for (int k = 0; k < 16; k++) qs[row * 65 + seg * 16 + k] = src[k];
    }
    __syncthreads();

    int warp = tid >> 5, lane = tid & 31;
    int h = warp & 3;
    int tok = (warp >> 2) * 32 + lane;

    float r[32];
#pragma unroll
    for (int i = 0; i < 32; i++) r[i] = 0.f;
    for (int d = 0; d < DHd; d++) {
        float qd = qs[tok * 65 + d];
        const float* rp = rs + d * 128 + h * 32;
#pragma unroll
        for (int i = 0; i < 32; i++) r[i] += qd * rp[i];
    }
    float best = r[0]; int bi = 0;
#pragma unroll
    for (int i = 1; i < 32; i++) if (r[i] > best) { best = r[i]; bi = i; }
#pragma unroll
    for (int i = 0; i < 32; i++) if (-r[i] > best) { best = -r[i]; bi = 32 + i; }
    g_bucket[((size_t)bh * NHASH + h) * Nn + tb + tok] = bi;
}

// ---------------- fused bucket + k/s prep (both need only g_qk) ----------------
#define PB_SMEM 49408   // rs 32768 + qs 16640
__global__ void prep_bucket_kernel(const float* __restrict__ rot) {
    extern __shared__ char smem[];
    int bid = blockIdx.x;
    if (bid < 2048) {
        bucket_body(smem, rot, bid >> 6, (bid & 63) * 64);
        return;
    }
    // prep: 8 rows per block, warp per row; k limbs in fp16
    int row = (bid - 2048) * 8 + (threadIdx.x >> 5);
    int lane = threadIdx.x & 31;
    size_t off = (size_t)row * DHd;
    const float* src = g_qk + off;
    float a = src[lane], b = src[lane + 32];

    float s = a * a + b * b;
#pragma unroll
    for (int o = 16; o > 0; o >>= 1) s += __shfl_xor_sync(0xffffffffu, s, o);
    float norm = sqrtf(s);
    float inv = 1.0f / fmaxf(norm, 1e-12f);
    if (lane == 0) g_s[row] = 0.125f * norm;

    float ka = a * inv, kb = b * inv;
    float kah = __half2float(__float2half_rn(ka));
    float kbh = __half2float(__float2half_rn(kb));
    g_kh[off + lane]      = __float2half_rn(kah);
    g_kh[off + lane + 32] = __float2half_rn(kbh);
    g_km[off + lane]      = __float2half_rn(ka - kah);
    g_km[off + lane + 32] = __float2half_rn(kb - kbh);
}

// ---------------- parallel stable counting sort per (bh, hash) ----------------
#define SORT_SMEM 49152
__global__ void sort_kernel() {
    extern __shared__ char ss[];
    unsigned char*  cnt    = (unsigned char*)ss;
    unsigned short* segoff = (unsigned short*)(ss + 16384);
    __shared__ int bbase[NBUCK];
    int bh = blockIdx.x, h = blockIdx.y;
    int tid = threadIdx.x;
    const int gb = (bh * NHASH + h) * Nn;

    uint32_t* ci = (uint32_t*)cnt;
    for (int i = tid; i < 4096; i += 256) ci[i] = 0;
    __syncthreads();

    int bb[16];
#pragma unroll
    for (int k = 0; k < 16; k++) {
        int b = g_bucket[gb + tid * 16 + k];
        bb[k] = b;
        cnt[tid * 64 + b]++;
    }
    __syncthreads();

    if (tid < NBUCK) {
        int run = 0;
        for (int seg = 0; seg < 256; seg++) {
            segoff[seg * 64 + tid] = (unsigned short)run;
            run += cnt[seg * 64 + tid];
        }
        bbase[tid] = run;
    }
    __syncthreads();
    if (tid == 0) {
        int acc = 0;
        for (int b = 0; b < NBUCK; b++) { int c = bbase[b]; bbase[b] = acc; acc += c; }
    }
    __syncthreads();

#pragma unroll
    for (int k = 0; k < 16; k++) {
        int b = bb[k];
        int pos = bbase[b] + segoff[tid * 64 + b];
        segoff[tid * 64 + b]++;
        g_st[gb + pos] = tid * 16 + k;
    }
}

// ---------------- chunked LSH attention: K-as-A fp16 dots (2-pass), fp16 P (1-pass PV) ----------------
// smem: tkv[128]@0 | s[64]@512 | rsump@1536 | rsuminv@2560 |
//       Khi@3072(18432) | Kmid@21504(18432) | V@39936(18432) | P@58368(17408) -> 75776
#define AT_S     512
#define AT_KHI   3072
#define AT_KMID  21504
#define AT_V     39936
#define AT_P     58368
#define ATTN_SMEM_BYTES 75776

__global__ __launch_bounds__(256, 2) void attn_kernel() {
    extern __shared__ char sm[];
    int*   tkv     = (int*)sm;
    float* sS      = (float*)(sm + AT_S);
    float* rsump   = (float*)(sm + 1536);
    float* rsuminv = (float*)(sm + 2560);
    uint32_t sb = smem_to_u32(sm);

    int c = blockIdx.x, bh = blockIdx.y;
    int h = c >> 6;
    int tid = threadIdx.x, lane = tid & 31, warp = tid >> 5;
    int g = lane >> 2, t = lane & 3;
    int wm = warp >> 2, wn = warp & 3;
    int pc = (c + NCHUNK - 1) & (NCHUNK - 1);
    const int stb = bh * (NHASH * Nn);

    if (tid < 64)       tkv[tid] = g_st[stb + c * BS + tid];
    else if (tid < 128) tkv[tid] = g_st[stb + pc * BS + (tid - 64)];
    __syncthreads();

    if (tid < 64) sS[tid] = g_s[(size_t)bh * Nn + tkv[tid]];

    // gather k limbs + v via cp.async (2 threads/row x 32 elems; 12 x 16B each)
    {
        int j = tid >> 1, seg = tid & 1;
        size_t off = ((size_t)bh * Nn + tkv[j]) * DHd + seg * 32;
        const __half* skh = g_kh + off;
        const __half* skm = g_km + off;
        const __half* svh = g_vh2 + off;
        uint32_t dkh = sb + AT_KHI + j * 144 + seg * 64;
        uint32_t dkm = sb + AT_KMID + j * 144 + seg * 64;
        uint32_t dvh = sb + AT_V + j * 144 + seg * 64;
#pragma unroll
        for (int k = 0; k < 4; k++) {
            CP_ASYNC16(dkh + k * 16, skh + k * 8);
            CP_ASYNC16(dkm + k * 16, skm + k * 8);
            CP_ASYNC16(dvh + k * 16, svh + k * 8);
        }
        CP_COMMIT();
        CP_WAIT(0);
    }
    __syncthreads();

    // dots MMA: A = Khi rows 0..63 (shared-QK); 2 fp16 passes, A ldmatrix shared
    float Dd[2][4][4];
#pragma unroll
    for (int i = 0; i < 2; i++)
#pragma unroll
        for (int jn = 0; jn < 4; jn++)
#pragma unroll
            for (int q = 0; q < 4; q++) Dd[i][jn][q] = 0.f;

    uint32_t arow = (uint32_t)((wm * 32 + (lane & 15)) * 144 + (lane >> 4) * 16);
    uint32_t brow = (uint32_t)((wn * 32 + ((lane >> 4) & 1) * 8 + (lane & 7)) * 144
                               + ((lane >> 3) & 1) * 16);
    const uint32_t KL[2] = {sb + AT_KMID, sb + AT_KHI};   // small pass first
#pragma unroll
    for (int ks = 0; ks < 4; ks++) {
        uint32_t A4[2][4];
#pragma unroll
        for (int i = 0; i < 2; i++) ldmx4(A4[i], sb + AT_KHI + arow + i * (16 * 144) + ks * 32);
#pragma unroll
        for (int p = 0; p < 2; p++) {
            uint32_t B4[2][4];
#pragma unroll
            for (int jp = 0; jp < 2; jp++) ldmx4(B4[jp], KL[p] + brow + jp * (16 * 144) + ks * 32);
#pragma unroll
            for (int i = 0; i < 2; i++)
#pragma unroll
                for (int jn = 0; jn < 4; jn++)
                    mma16816h(Dd[i][jn], A4[i], B4[jn >> 1][(jn & 1) * 2], B4[jn >> 1][(jn & 1) * 2 + 1]);
        }
    }

    // scale rows by s, then mask
    float srow[4] = { sS[wm * 32 + g], sS[wm * 32 + g + 8],
                      sS[wm * 32 + 16 + g], sS[wm * 32 + 16 + g + 8] };
#pragma unroll
    for (int i = 0; i < 2; i++)
#pragma unroll
        for (int jn = 0; jn < 4; jn++) {
            Dd[i][jn][0] *= srow[i * 2];
            Dd[i][jn][1] *= srow[i * 2];
            Dd[i][jn][2] *= srow[i * 2 + 1];
            Dd[i][jn][3] *= srow[i * 2 + 1];
        }

    int trow[4] = { tkv[wm * 32 + g], tkv[wm * 32 + g + 8],
                    tkv[wm * 32 + 16 + g], tkv[wm * 32 + 16 + g + 8] };
    int tcol[8];
#pragma unroll
    for (int jn = 0; jn < 4; jn++) {
        int c0 = wn * 32 + jn * 8 + t * 2;
        tcol[jn * 2] = tkv[c0]; tcol[jn * 2 + 1] = tkv[c0 + 1];
    }
#pragma unroll
    for (int i = 0; i < 2; i++)
#pragma unroll
        for (int jn = 0; jn < 4; jn++)
#pragma unroll
            for (int q = 0; q < 4; q++)
                if (trow[i * 2 + (q >> 1)] == tcol[jn * 2 + (q & 1)]) Dd[i][jn][q] = -5e4f;

    // exp (unshifted; dots bounded) -> P fp16 (single) + partial sums
    float ps[4] = {0.f, 0.f, 0.f, 0.f};
#pragma unroll
    for (int i = 0; i < 2; i++) {
        int r0 = wm * 32 + i * 16 + g;
#pragma unroll
        for (int jn = 0; jn < 4; jn++) {
            float e0 = __expf(Dd[i][jn][0]);
            float e1 = __expf(Dd[i][jn][1]);
            float e2 = __expf(Dd[i][jn][2]);
            float e3 = __expf(Dd[i][jn][3]);
            ps[i * 2] += e0 + e1;
            ps[i * 2 + 1] += e2 + e3;
            int c0 = wn * 32 + jn * 8 + t * 2;
            *(uint32_t*)(sm + AT_P + r0 * 272 + c0 * 2)       = pack_h2(e0, e1);
            *(uint32_t*)(sm + AT_P + (r0 + 8) * 272 + c0 * 2) = pack_h2(e2, e3);
        }
    }
#pragma unroll
    for (int k = 0; k < 4; k++) {
        ps[k] += __shfl_xor_sync(0xffffffffu, ps[k], 1);
        ps[k] += __shfl_xor_sync(0xffffffffu, ps[k], 2);
    }
    if (t == 0) {
#pragma unroll
        for (int k = 0; k < 4; k++)
            rsump[(wm * 32 + (k >> 1) * 16 + g + (k & 1) * 8) * 4 + wn] = ps[k];
    }
    __syncthreads();

    if (tid < 64) {
        const float* p = rsump + tid * 4;
        float s = p[0] + p[1] + p[2] + p[3];
        rsuminv[tid] = 1.0f / s;
        g_lse[(bh * NHASH + h) * Nn + tkv[tid]] = logf(s);
    }
    __syncthreads();

    // PV MMA: single fp16 pass
    float Dp[2][2][4];
#pragma unroll
    for (int i = 0; i < 2; i++)
#pragma unroll
        for (int jn = 0; jn < 2; jn++)
#pragma unroll
            for (int q = 0; q < 4; q++) Dp[i][jn][q] = 0.f;

    uint32_t parow = (uint32_t)((wm * 32 + (lane & 15)) * 272 + (lane >> 4) * 16);
    uint32_t vbrow = (uint32_t)((lane & 15) * 144 + (lane >> 4) * 16 + wn * 32);
#pragma unroll
    for (int ks = 0; ks < 8; ks++) {
        uint32_t B4[4];
        ldmx4t(B4, sb + AT_V + vbrow + ks * (16 * 144));
        uint32_t A4[2][4];
#pragma unroll
        for (int i = 0; i < 2; i++) ldmx4(A4[i], sb + AT_P + parow + i * (16 * 272) + ks * 32);
#pragma unroll
        for (int i = 0; i < 2; i++)
#pragma unroll
            for (int jn = 0; jn < 2; jn++)
                mma16816h(Dp[i][jn], A4[i], B4[jn * 2], B4[jn * 2 + 1]);
    }

    // epilogue: normalize + scatter (fp16)
#pragma unroll
    for (int i = 0; i < 2; i++) {
        int r0 = wm * 32 + i * 16 + g;
        float inv0 = rsuminv[r0], inv1 = rsuminv[r0 + 8];
        size_t b0 = ((size_t)(bh * NHASH + h) * Nn + trow[i * 2]) * DHd;
        size_t b1 = ((size_t)(bh * NHASH + h) * Nn + trow[i * 2 + 1]) * DHd;
#pragma unroll
        for (int jn = 0; jn < 2; jn++) {
            int dh = wn * 16 + jn * 8 + t * 2;
            *(uint32_t*)(g_oph2 + b0 + dh) = pack_h2(Dp[i][jn][0] * inv0, Dp[i][jn][1] * inv0);
            *(uint32_t*)(g_oph2 + b1 + dh) = pack_h2(Dp[i][jn][2] * inv1, Dp[i][jn][3] * inv1);
        }
    }
}

// ---------------- fused combine + single fp16 plane write (Wout A_hi) ----------------
__global__ void combine_split_kernel(__half* __restrict__ hi) {
    int u = blockIdx.x * 256 + threadIdx.x;
    int slot = u >> 3;
    int dseg = (u & 7) * 8;
    int bh = slot >> 12;
    int t = slot & 4095;
    int base = bh * NHASH * Nn + t;
    float l0 = g_lse[base + 0 * Nn];
    float l1 = g_lse[base + 1 * Nn];
    float l2 = g_lse[base + 2 * Nn];
    float l3 = g_lse[base + 3 * Nn];
    float m = fmaxf(fmaxf(l0, l1), fmaxf(l2, l3));
    float w[4] = {expf(l0 - m), expf(l1 - m), expf(l2 - m), expf(l3 - m)};
    float sinv = 1.0f / (w[0] + w[1] + w[2] + w[3]);

    float acc[8];
#pragma unroll
    for (int j = 0; j < 8; j++) acc[j] = 0.f;
#pragma unroll
    for (int k = 0; k < 4; k++) {
        const uint4* p = (const uint4*)(g_oph2 + (((size_t)(bh * NHASH + k)) * Nn + t) * DHd + dseg);
        uint4 x = p[0];
        const __half2* hx = (const __half2*)&x;
#pragma unroll
        for (int j2 = 0; j2 < 4; j2++) {
            float2 f = __half22float2(hx[j2]);
            acc[j2 * 2]     += w[k] * f.x;
            acc[j2 * 2 + 1] += w[k] * f.y;
        }
    }
    float hf[8];
#pragma unroll
    for (int j = 0; j < 8; j++) hf[j] = acc[j] * sinv;
    int b = bh >> 4, head = bh & 15;
    size_t oidx = ((size_t)b * Nn + t) * Cc + head * DHd + dseg;
    *(uint4*)(hi + oidx) = make_uint4(pack_h2(hf[0], hf[1]), pack_h2(hf[2], hf[3]),
                                      pack_h2(hf[4], hf[5]), pack_h2(hf[6], hf[7]));
}

// ---------------- launch ----------------
extern "C" void kernel_launch(void* const* d_in, const int* in_sizes, int n_in,
                              void* d_out, int out_size) {
    const float* queries = (const float*)d_in[0];
    const float* Wqk  = (const float*)d_in[4];
    const float* Wv   = (const float*)d_in[5];
    const float* Wout = (const float*)d_in[6];
    const float* bout = (const float*)d_in[7];
    const float* rot  = (const float*)d_in[8];
    float* out = (float*)d_out;

    cudaFuncSetAttribute(attn_kernel, cudaFuncAttributeMaxDynamicSharedMemorySize, ATTN_SMEM_BYTES);
    cudaFuncSetAttribute(qkv_gemm, cudaFuncAttributeMaxDynamicSharedMemorySize, GEMM_SMEM);
    cudaFuncSetAttribute(mma_gemm, cudaFuncAttributeMaxDynamicSharedMemorySize, GEMM_SMEM);
    cudaFuncSetAttribute(prep_bucket_kernel, cudaFuncAttributeMaxDynamicSharedMemorySize, PB_SMEM);
    cudaFuncSetAttribute(sort_kernel, cudaFuncAttributeMaxDynamicSharedMemorySize, SORT_SMEM);

    void *p_qk, *p_vh2, *p_asp, *p_wqkv, *p_wout;
    cudaGetSymbolAddress(&p_qk, g_qk);
    cudaGetSymbolAddress(&p_vh2, g_vh2);
    cudaGetSymbolAddress(&p_asp, g_asp);
    cudaGetSymbolAddress(&p_wqkv, g_wqkv_sp);
    cudaGetSymbolAddress(&p_wout, g_wout_sp);
    __half* asp  = (__half*)p_asp;
    __half* wqkv = (__half*)p_wqkv;
    __half* wout = (__half*)p_wout;

    split_all_kernel<<<5632, 256>>>(queries, Wqk, Wv, Wout, asp, wqkv, wout);

    // fused qk (4-pass) + v (2-pass, fp16 plane) GEMM
    qkv_gemm<<<dim3(16, 64), 256, GEMM_SMEM>>>(asp, wqkv, (float*)p_qk, (__half*)p_vh2);

    // fused bucket + k/s prep (both need only g_qk)
    prep_bucket_kernel<<<2048 + BH * Nn / 8, 256, PB_SMEM>>>(rot);
    sort_kernel<<<dim3(BH, NHASH), 256, SORT_SMEM>>>();

    attn_kernel<<<dim3(NCHUNK, BH), 256, ATTN_SMEM_BYTES>>>();

    combine_split_kernel<<<(BH * Nn * DHd / 8) / 256, 256>>>(asp);

    // Wout GEMM: 2-pass fp16 (A single plane), +bias -> d_out
    mma_gemm<<<dim3(8, 64), 256, GEMM_SMEM>>>(asp, wout, bout, out);
}

// round 15
// speedup vs baseline: 4.8956x; 1.1492x over previous
#include <cuda_runtime.h>
#include <cuda_fp16.h>
#include <cuda_bf16.h>
#include <math.h>
#include <stdint.h>

// ---------------- problem constants ----------------
#define Bb      2
#define Nn      4096
#define Cc      1024
#define Hh      16
#define DHd     64
#define BH      32          // Bb*Hh
#define NHASH   4
#define NBUCK   64          // Nn / BUCKET
#define NCHUNK  256         // NHASH*NBUCK
#define BS      64          // bucket size
#define Kdim    1024
#define Mrows   8192        // Bb*Nn

// ---------------- device scratch ----------------
__device__ float g_qk  [BH * Nn * DHd];            // (bh, t, d)
__device__ int   g_bucket[BH * NHASH * Nn];
__device__ int   g_st  [BH * NHASH * Nn];
__device__ __half g_oph2[BH * NHASH * Nn * DHd];   // per-hash outputs, fp16
__device__ float g_lse [BH * NHASH * Nn];

// attention prep planes
#define PLN ((size_t)BH * Nn * DHd)
__device__ __half g_kh[PLN], g_km[PLN];            // normalized k limbs (fp16)
__device__ __half g_vh2[PLN];                      // v single fp16 plane (written by v GEMM)
__device__ float g_s[BH * Nn];                     // s = 0.125 * ||q||

// fp16 2-limb planes for GEMMs (W-side pre-scaled by 64; epilogue x 1/64)
#define APL ((size_t)Mrows * Kdim)
#define WQKV_PL ((size_t)2048 * 1024)
#define WOUT_PL ((size_t)1024 * 1024)
__device__ __half g_asp[2 * APL];
__device__ __half g_wqkv_sp[2 * WQKV_PL];
__device__ __half g_wout_sp[2 * WOUT_PL];
#define WSCALE 64.0f
#define OSCALE (1.0f / 64.0f)

// ================= helpers (sm_103-safe) =================
__device__ __forceinline__ uint32_t smem_to_u32(const void* p) {
    uint32_t a;
    asm("{ .reg .u64 t; cvta.to.shared.u64 t, %1; cvt.u32.u64 %0, t; }" : "=r"(a) : "l"(p));
    return a;
}
#define CP_ASYNC16(saddr, gptr) \
    asm volatile("cp.async.cg.shared.global [%0], [%1], 16;" \
        :: "r"(saddr), "l"(__cvta_generic_to_global(gptr)))
#define CP_COMMIT() asm volatile("cp.async.commit_group;" ::: "memory")
#define CP_WAIT(n)  asm volatile("cp.async.wait_group %0;" :: "n"(n) : "memory")

__device__ __forceinline__ void ldmx4(uint32_t* r, uint32_t addr) {
    asm volatile("ldmatrix.sync.aligned.m8n8.x4.shared.b16 {%0,%1,%2,%3}, [%4];"
        : "=r"(r[0]), "=r"(r[1]), "=r"(r[2]), "=r"(r[3]) : "r"(addr));
}
__device__ __forceinline__ void ldmx4t(uint32_t* r, uint32_t addr) {
    asm volatile("ldmatrix.sync.aligned.m8n8.x4.trans.shared.b16 {%0,%1,%2,%3}, [%4];"
        : "=r"(r[0]), "=r"(r[1]), "=r"(r[2]), "=r"(r[3]) : "r"(addr));
}
__device__ __forceinline__ void mma16816h(float* d, const uint32_t* a, uint32_t b0, uint32_t b1) {
    asm volatile("mma.sync.aligned.m16n8k16.row.col.f32.f16.f16.f32 "
        "{%0,%1,%2,%3}, {%4,%5,%6,%7}, {%8,%9}, {%0,%1,%2,%3};"
        : "+f"(d[0]), "+f"(d[1]), "+f"(d[2]), "+f"(d[3])
        : "r"(a[0]), "r"(a[1]), "r"(a[2]), "r"(a[3]), "r"(b0), "r"(b1));
}
__device__ __forceinline__ uint32_t pack_h2(float a, float b) {
    uint16_t ua = __half_as_ushort(__float2half_rn(a));
    uint16_t ub = __half_as_ushort(__float2half_rn(b));
    return (uint32_t)ua | ((uint32_t)ub << 16);
}

// ================= merged fp16 2-limb split (all 4 GEMM tensors) =================
__device__ __forceinline__ void split8(const float* __restrict__ x,
                                       __half* __restrict__ hi, __half* __restrict__ mid,
                                       int i, float scale) {
    float4 v0 = *(const float4*)(x + i);
    float4 v1 = *(const float4*)(x + i + 4);
    float a[8] = {v0.x, v0.y, v0.z, v0.w, v1.x, v1.y, v1.z, v1.w};
    float hf[8], mf[8];
#pragma unroll
    for (int j = 0; j < 8; j++) {
        float s = a[j] * scale;
        float h = __half2float(__float2half_rn(s));
        hf[j] = h; mf[j] = s - h;
    }
    *(uint4*)(hi + i) = make_uint4(pack_h2(hf[0], hf[1]), pack_h2(hf[2], hf[3]),
                                   pack_h2(hf[4], hf[5]), pack_h2(hf[6], hf[7]));
    *(uint4*)(mid + i) = make_uint4(pack_h2(mf[0], mf[1]), pack_h2(mf[2], mf[3]),
                                    pack_h2(mf[4], mf[5]), pack_h2(mf[6], mf[7]));
}

__global__ void split_all_kernel(const float* __restrict__ q,
                                 const float* __restrict__ wqk,
                                 const float* __restrict__ wv,
                                 const float* __restrict__ wo,
                                 __half* __restrict__ asp,
                                 __half* __restrict__ wqkv,
                                 __half* __restrict__ wout) {
    int bid = blockIdx.x;
    int li = threadIdx.x * 8;
    const int NW = 1024 * 1024;
    if (bid < 4096) {
        int i = bid * 2048 + li;
        split8(q, asp, asp + APL, i, 1.0f);
    } else if (bid < 4608) {
        int i = (bid - 4096) * 2048 + li;
        split8(wqk, wqkv, wqkv + WQKV_PL, i, WSCALE);
    } else if (bid < 5120) {
        int i = (bid - 4608) * 2048 + li;
        split8(wv, wqkv + NW, wqkv + WQKV_PL + NW, i, WSCALE);
    } else {
        int i = (bid - 5120) * 2048 + li;
        split8(wo, wout, wout + WOUT_PL, i, WSCALE);
    }
}

// ================= HMMA GEMM body (fp16 limbs) =================
#define ROWB     80
#define MATB     (128 * ROWB)
#define STAGEB   (2 * MATB)
#define GEMM_SMEM (4 * STAGEB)   // 81920
// 3-pass (fp32-equivalent; drops only A_mid*W_mid ~ 2^-24): (0,1)(1,0)(0,0)
#define PA3 0x010u
#define PW3 0x001u
// 2-pass: (0,1)(0,0)
#define PA2 0x00u
#define PW2 0x01u

__device__ __forceinline__ void gemm_issue(uint32_t st,
        const __half* Ap, const __half* Bp, int bm, int bn, int k0,
        uint32_t so0, uint32_t so1, int r0, int c0, int r1, int c1) {
    CP_ASYNC16(st + so0, Ap + (size_t)(bm + r0) * Kdim + k0 + c0 * 8);
    CP_ASYNC16(st + so1, Ap + (size_t)(bm + r1) * Kdim + k0 + c1 * 8);
    CP_ASYNC16(st + MATB + so0, Bp + (size_t)(bn + r0) * Kdim + k0 + c0 * 8);
    CP_ASYNC16(st + MATB + so1, Bp + (size_t)(bn + r1) * Kdim + k0 + c1 * 8);
    CP_COMMIT();
}

__device__ __forceinline__ void gemm_body(char* smem,
        const __half* __restrict__ Asp, size_t Apl,
        const __half* __restrict__ Bsp, size_t Bpl,
        const float* __restrict__ bias, float* __restrict__ outp,
        float* __restrict__ headout, __half* __restrict__ headout_h,
        int npass, uint32_t paTbl, uint32_t pwTbl, int bn, int bm) {
    uint32_t sbase = smem_to_u32(smem);
    int tid = threadIdx.x;
    int lane = tid & 31, warp = tid >> 5;
    int wm = warp >> 2, wn = warp & 3;
    int nstage = npass * 32;

    int v0 = tid, v1 = tid + 256;
    int r0 = v0 >> 2, c0 = v0 & 3;
    int r1 = v1 >> 2, c1 = v1 & 3;
    uint32_t so0 = (uint32_t)(r0 * ROWB + c0 * 16);
    uint32_t so1 = (uint32_t)(r1 * ROWB + c1 * 16);

    uint32_t aoff = (uint32_t)((wm * 64 + (lane & 15)) * ROWB + (lane >> 4) * 16);
    uint32_t boff = (uint32_t)((wn * 32 + ((lane >> 4) & 1) * 8 + (lane & 7)) * ROWB
                               + ((lane >> 3) & 1) * 16);

    float D[4][4][4];
#pragma unroll
    for (int i = 0; i < 4; i++)
#pragma unroll
        for (int j = 0; j < 4; j++)
#pragma unroll
            for (int q = 0; q < 4; q++) D[i][j][q] = 0.f;

#pragma unroll
    for (int s = 0; s < 3; s++) {
        const __half* Ap = Asp + (size_t)(paTbl & 7) * Apl;
        const __half* Bp = Bsp + (size_t)(pwTbl & 7) * Bpl;
        gemm_issue(sbase + s * STAGEB, Ap, Bp, bm, bn, (s & 31) * 32, so0, so1, r0, c0, r1, c1);
    }

    for (int s = 0; s < nstage; s++) {
        if (s <= nstage - 3)      { CP_WAIT(2); }
        else if (s == nstage - 2) { CP_WAIT(1); }
        else                      { CP_WAIT(0); }
        __syncthreads();
        if (s + 3 < nstage) {
            int sn = s + 3;
            int p = sn >> 5, k0 = (sn & 31) << 5;
            const __half* Ap = Asp + (size_t)((paTbl >> (p * 4)) & 7) * Apl;
            const __half* Bp = Bsp + (size_t)((pwTbl >> (p * 4)) & 7) * Bpl;
            gemm_issue(sbase + (uint32_t)(sn & 3) * STAGEB, Ap, Bp, bm, bn, k0,
                       so0, so1, r0, c0, r1, c1);
        }
        uint32_t st = sbase + (uint32_t)(s & 3) * STAGEB;
        uint32_t ab = st + aoff;
        uint32_t bb = st + MATB + boff;
#pragma unroll
        for (int ks = 0; ks < 2; ks++) {
            uint32_t A4[4][4], B4[2][4];
#pragma unroll
            for (int i = 0; i < 4; i++) ldmx4(A4[i], ab + i * (16 * ROWB) + ks * 32);
#pragma unroll
            for (int jp = 0; jp < 2; jp++) ldmx4(B4[jp], bb + jp * (16 * ROWB) + ks * 32);
#pragma unroll
            for (int i = 0; i < 4; i++)
#pragma unroll
                for (int jn = 0; jn < 4; jn++)
                    mma16816h(D[i][jn], A4[i], B4[jn >> 1][(jn & 1) * 2], B4[jn >> 1][(jn & 1) * 2 + 1]);
        }
    }

    int g = lane >> 2, t = lane & 3;
#pragma unroll
    for (int i = 0; i < 4; i++) {
#pragma unroll
        for (int jn = 0; jn < 4; jn++) {
            int m0 = bm + wm * 64 + i * 16 + g;
            int n0 = bn + wn * 32 + jn * 8 + t * 2;
            float2 va = make_float2(D[i][jn][0] * OSCALE, D[i][jn][1] * OSCALE);
            float2 vb = make_float2(D[i][jn][2] * OSCALE, D[i][jn][3] * OSCALE);
            if (headout) {
                int bI = m0 >> 12;
                int t0 = m0 & 4095, t1 = (m0 + 8) & 4095;
                int hd = n0 >> 6, dh = n0 & 63;
                *(float2*)(headout + (((size_t)(bI * Hh + hd)) * Nn + t0) * DHd + dh) = va;
                *(float2*)(headout + (((size_t)(bI * Hh + hd)) * Nn + t1) * DHd + dh) = vb;
            } else if (headout_h) {
                int bI = m0 >> 12;
                int t0 = m0 & 4095, t1 = (m0 + 8) & 4095;
                int hd = n0 >> 6, dh = n0 & 63;
                *(uint32_t*)(headout_h + (((size_t)(bI * Hh + hd)) * Nn + t0) * DHd + dh) = pack_h2(va.x, va.y);
                *(uint32_t*)(headout_h + (((size_t)(bI * Hh + hd)) * Nn + t1) * DHd + dh) = pack_h2(vb.x, vb.y);
            } else {
                float2 bv = *(const float2*)(bias + n0);
                va.x += bv.x; va.y += bv.y; vb.x += bv.x; vb.y += bv.y;
                *(float2*)(outp + (size_t)m0 * Cc + n0) = va;
                *(float2*)(outp + (size_t)(m0 + 8) * Cc + n0) = vb;
            }
        }
    }
}

// fused qk (3-pass, x<8) + v (2-pass -> fp16 plane, x>=8) GEMM
__global__ __launch_bounds__(256, 2) void qkv_gemm(
        const __half* __restrict__ Asp,
        const __half* __restrict__ Wqkv,
        float* __restrict__ qkout, __half* __restrict__ vout) {
    extern __shared__ char smem[];
    const int NW = 1024 * 1024;
    if (blockIdx.x < 8) {
        gemm_body(smem, Asp, APL, Wqkv, WQKV_PL, nullptr, nullptr, qkout, nullptr,
                  3, PA3, PW3, blockIdx.x * 128, blockIdx.y * 128);
    } else {
        gemm_body(smem, Asp, APL, Wqkv + NW, WQKV_PL, nullptr, nullptr, nullptr, vout,
                  2, PA2, PW2, (blockIdx.x - 8) * 128, blockIdx.y * 128);
    }
}

// Wout GEMM: 2-pass, A single plane (combine writes hi only)
__global__ __launch_bounds__(256, 2) void mma_gemm(
        const __half* __restrict__ Asp,
        const __half* __restrict__ Wout_,
        const float* __restrict__ bias, float* __restrict__ outp) {
    extern __shared__ char smem[];
    gemm_body(smem, Asp, APL, Wout_, WOUT_PL, bias, outp, nullptr, nullptr,
              2, PA2, PW2, blockIdx.x * 128, blockIdx.y * 128);
}

// ---------------- HMMA LSH bucketing: rotated = q . R via fp16 limbs (3 passes) ----------------
// A: q rows (64 x 64), B: R^T rows (128 x 64). Same fragment geometry as attention dots.
#define BK_AHI  0
#define BK_AMID 9216
#define BK_BHI  18432
#define BK_BMID 36864
#define PB_SMEM 55296

__device__ __forceinline__ void bucket_body(char* smemc, const float* __restrict__ rot,
                                            int bh, int tb) {
    uint32_t sb = smem_to_u32(smemc);
    int tid = threadIdx.x, lane = tid & 31, warp = tid >> 5;
    int g = lane >> 2, t = lane & 3;
    int wm = warp >> 2, wn = warp & 3;

    // load A: 64 q rows -> fp16 limbs (4 threads/row x 16 dims)
    {
        int row = tid >> 2, seg = tid & 3;
        const float* src = g_qk + ((size_t)bh * Nn + tb + row) * DHd + seg * 16;
        char* dh_ = smemc + BK_AHI + row * 144 + seg * 32;
        char* dm_ = smemc + BK_AMID + row * 144 + seg * 32;
#pragma unroll
        for (int k4 = 0; k4 < 4; k4++) {
            float4 v = *(const float4*)(src + k4 * 4);
            float h0 = __half2float(__float2half_rn(v.x));
            float h1 = __half2float(__float2half_rn(v.y));
            float h2 = __half2float(__float2half_rn(v.z));
            float h3 = __half2float(__float2half_rn(v.w));
            *(uint32_t*)(dh_ + k4 * 8)     = pack_h2(h0, h1);
            *(uint32_t*)(dh_ + k4 * 8 + 4) = pack_h2(h2, h3);
            *(uint32_t*)(dm_ + k4 * 8)     = pack_h2(v.x - h0, v.y - h1);
            *(uint32_t*)(dm_ + k4 * 8 + 4) = pack_h2(v.z - h2, v.w - h3);
        }
    }
    // load B = R^T: 128 rows (n), 64 cols (d); rot is (d, n)
    {
        int n = tid >> 1, seg = tid & 1;
        char* dh_ = smemc + BK_BHI + n * 144 + seg * 64;
        char* dm_ = smemc + BK_BMID + n * 144 + seg * 64;
#pragma unroll
        for (int k2 = 0; k2 < 16; k2++) {
            int d = seg * 32 + k2 * 2;
            float a = rot[(size_t)d * 128 + n];
            float b = rot[(size_t)(d + 1) * 128 + n];
            float ha = __half2float(__float2half_rn(a));
            float hb = __half2float(__float2half_rn(b));
            *(uint32_t*)(dh_ + k2 * 4) = pack_h2(ha, hb);
            *(uint32_t*)(dm_ + k2 * 4) = pack_h2(a - ha, b - hb);
        }
    }
    __syncthreads();

    // MMA: 3 limb passes, small->large
    float Dd[2][4][4];
#pragma unroll
    for (int i = 0; i < 2; i++)
#pragma unroll
        for (int jn = 0; jn < 4; jn++)
#pragma unroll
            for (int q = 0; q < 4; q++) Dd[i][jn][q] = 0.f;

    uint32_t arow = (uint32_t)((wm * 32 + (lane & 15)) * 144 + (lane >> 4) * 16);
    uint32_t brow = (uint32_t)((wn * 32 + ((lane >> 4) & 1) * 8 + (lane & 7)) * 144
                               + ((lane >> 3) & 1) * 16);
    const uint32_t AL[3] = {sb + BK_AMID, sb + BK_AHI, sb + BK_AHI};
    const uint32_t BL[3] = {sb + BK_BHI, sb + BK_BMID, sb + BK_BHI};
#pragma unroll
    for (int p = 0; p < 3; p++) {
#pragma unroll
        for (int ks = 0; ks < 4; ks++) {
            uint32_t A4[2][4], B4[2][4];
#pragma unroll
            for (int i = 0; i < 2; i++) ldmx4(A4[i], AL[p] + arow + i * (16 * 144) + ks * 32);
#pragma unroll
            for (int jp = 0; jp < 2; jp++) ldmx4(B4[jp], BL[p] + brow + jp * (16 * 144) + ks * 32);
#pragma unroll
            for (int i = 0; i < 2; i++)
#pragma unroll
                for (int jn = 0; jn < 4; jn++)
                    mma16816h(Dd[i][jn], A4[i], B4[jn >> 1][(jn & 1) * 2], B4[jn >> 1][(jn & 1) * 2 + 1]);
        }
    }

    // argmax over [r, -r] per (row, hash=wn); first-index tie-break (order-independent compare)
#pragma unroll
    for (int i = 0; i < 2; i++) {
#pragma unroll
        for (int half = 0; half < 2; half++) {
            int row = wm * 32 + i * 16 + g + half * 8;
            float bv = -3.0e38f; int bidx = 0;
#pragma unroll
            for (int jn = 0; jn < 4; jn++) {
#pragma unroll
                for (int z = 0; z < 2; z++) {
                    float v = Dd[i][jn][half * 2 + z];
                    int ri = jn * 8 + t * 2 + z;
                    if (v > bv || (v == bv && ri < bidx)) { bv = v; bidx = ri; }
                    float nv = -v; int ni = 32 + ri;
                    if (nv > bv || (nv == bv && ni < bidx)) { bv = nv; bidx = ni; }
                }
            }
#pragma unroll
            for (int o = 1; o <= 2; o <<= 1) {
                float ov = __shfl_xor_sync(0xffffffffu, bv, o);
                int oi = __shfl_xor_sync(0xffffffffu, bidx, o);
                if (ov > bv || (ov == bv && oi < bidx)) { bv = ov; bidx = oi; }
            }
            if (t == 0)
                g_bucket[((size_t)bh * NHASH + wn) * Nn + tb + row] = bidx;
        }
    }
}

// ---------------- fused bucket (HMMA) + k/s prep (both need only g_qk) ----------------
__global__ void prep_bucket_kernel(const float* __restrict__ rot) {
    extern __shared__ char smem[];
    int bid = blockIdx.x;
    if (bid < 2048) {
        bucket_body(smem, rot, bid >> 6, (bid & 63) * 64);
        return;
    }
    // prep: 8 rows per block, warp per row; k limbs in fp16
    int row = (bid - 2048) * 8 + (threadIdx.x >> 5);
    int lane = threadIdx.x & 31;
    size_t off = (size_t)row * DHd;
    const float* src = g_qk + off;
    float a = src[lane], b = src[lane + 32];

    float s = a * a + b * b;
#pragma unroll
    for (int o = 16; o > 0; o >>= 1) s += __shfl_xor_sync(0xffffffffu, s, o);
    float norm = sqrtf(s);
    float inv = 1.0f / fmaxf(norm, 1e-12f);
    if (lane == 0) g_s[row] = 0.125f * norm;

    float ka = a * inv, kb = b * inv;
    float kah = __half2float(__float2half_rn(ka));
    float kbh = __half2float(__float2half_rn(kb));
    g_kh[off + lane]      = __float2half_rn(kah);
    g_kh[off + lane + 32] = __float2half_rn(kbh);
    g_km[off + lane]      = __float2half_rn(ka - kah);
    g_km[off + lane + 32] = __float2half_rn(kb - kbh);
}

// ---------------- parallel stable counting sort per (bh, hash) ----------------
#define SORT_SMEM 49152
__global__ void sort_kernel() {
    extern __shared__ char ss[];
    unsigned char*  cnt    = (unsigned char*)ss;
    unsigned short* segoff = (unsigned short*)(ss + 16384);
    __shared__ int bbase[NBUCK];
    int bh = blockIdx.x, h = blockIdx.y;
    int tid = threadIdx.x;
    const int gb = (bh * NHASH + h) * Nn;

    uint32_t* ci = (uint32_t*)cnt;
    for (int i = tid; i < 4096; i += 256) ci[i] = 0;
    __syncthreads();

    int bb[16];
#pragma unroll
    for (int k = 0; k < 16; k++) {
        int b = g_bucket[gb + tid * 16 + k];
        bb[k] = b;
        cnt[tid * 64 + b]++;
    }
    __syncthreads();

    if (tid < NBUCK) {
        int run = 0;
        for (int seg = 0; seg < 256; seg++) {
            segoff[seg * 64 + tid] = (unsigned short)run;
            run += cnt[seg * 64 + tid];
        }
        bbase[tid] = run;
    }
    __syncthreads();
    if (tid == 0) {
        int acc = 0;
        for (int b = 0; b < NBUCK; b++) { int c = bbase[b]; bbase[b] = acc; acc += c; }
    }
    __syncthreads();

#pragma unroll
    for (int k = 0; k < 16; k++) {
        int b = bb[k];
        int pos = bbase[b] + segoff[tid * 64 + b];
        segoff[tid * 64 + b]++;
        g_st[gb + pos] = tid * 16 + k;
    }
}

// ---------------- chunked LSH attention: K-as-A fp16 dots (2-pass), fp16 P (1-pass PV) ----------------
#define AT_S     512
#define AT_KHI   3072
#define AT_KMID  21504
#define AT_V     39936
#define AT_P     58368
#define ATTN_SMEM_BYTES 75776

__global__ __launch_bounds__(256, 2) void attn_kernel() {
    extern __shared__ char sm[];
    int*   tkv     = (int*)sm;
    float* sS      = (float*)(sm + AT_S);
    float* rsump   = (float*)(sm + 1536);
    float* rsuminv = (float*)(sm + 2560);
    uint32_t sb = smem_to_u32(sm);

    int c = blockIdx.x, bh = blockIdx.y;
    int h = c >> 6;
    int tid = threadIdx.x, lane = tid & 31, warp = tid >> 5;
    int g = lane >> 2, t = lane & 3;
    int wm = warp >> 2, wn = warp & 3;
    int pc = (c + NCHUNK - 1) & (NCHUNK - 1);
    const int stb = bh * (NHASH * Nn);

    if (tid < 64)       tkv[tid] = g_st[stb + c * BS + tid];
    else if (tid < 128) tkv[tid] = g_st[stb + pc * BS + (tid - 64)];
    __syncthreads();

    if (tid < 64) sS[tid] = g_s[(size_t)bh * Nn + tkv[tid]];

    // gather k limbs + v via cp.async (2 threads/row x 32 elems; 12 x 16B each)
    {
        int j = tid >> 1, seg = tid & 1;
        size_t off = ((size_t)bh * Nn + tkv[j]) * DHd + seg * 32;
        const __half* skh = g_kh + off;
        const __half* skm = g_km + off;
        const __half* svh = g_vh2 + off;
        uint32_t dkh = sb + AT_KHI + j * 144 + seg * 64;
        uint32_t dkm = sb + AT_KMID + j * 144 + seg * 64;
        uint32_t dvh = sb + AT_V + j * 144 + seg * 64;
#pragma unroll
        for (int k = 0; k < 4; k++) {
            CP_ASYNC16(dkh + k * 16, skh + k * 8);
            CP_ASYNC16(dkm + k * 16, skm + k * 8);
            CP_ASYNC16(dvh + k * 16, svh + k * 8);
        }
        CP_COMMIT();
        CP_WAIT(0);
    }
    __syncthreads();

    // dots MMA: A = Khi rows 0..63 (shared-QK); 2 fp16 passes, A ldmatrix shared
    float Dd[2][4][4];
#pragma unroll
    for (int i = 0; i < 2; i++)
#pragma unroll
        for (int jn = 0; jn < 4; jn++)
#pragma unroll
            for (int q = 0; q < 4; q++) Dd[i][jn][q] = 0.f;

    uint32_t arow = (uint32_t)((wm * 32 + (lane & 15)) * 144 + (lane >> 4) * 16);
    uint32_t brow = (uint32_t)((wn * 32 + ((lane >> 4) & 1) * 8 + (lane & 7)) * 144
                               + ((lane >> 3) & 1) * 16);
    const uint32_t KL[2] = {sb + AT_KMID, sb + AT_KHI};   // small pass first
#pragma unroll
    for (int ks = 0; ks < 4; ks++) {
        uint32_t A4[2][4];
#pragma unroll
        for (int i = 0; i < 2; i++) ldmx4(A4[i], sb + AT_KHI + arow + i * (16 * 144) + ks * 32);
#pragma unroll
        for (int p = 0; p < 2; p++) {
            uint32_t B4[2][4];
#pragma unroll
            for (int jp = 0; jp < 2; jp++) ldmx4(B4[jp], KL[p] + brow + jp * (16 * 144) + ks * 32);
#pragma unroll
            for (int i = 0; i < 2; i++)
#pragma unroll
                for (int jn = 0; jn < 4; jn++)
                    mma16816h(Dd[i][jn], A4[i], B4[jn >> 1][(jn & 1) * 2], B4[jn >> 1][(jn & 1) * 2 + 1]);
        }
    }

    // scale rows by s, then mask
    float srow[4] = { sS[wm * 32 + g], sS[wm * 32 + g + 8],
                      sS[wm * 32 + 16 + g], sS[wm * 32 + 16 + g + 8] };
#pragma unroll
    for (int i = 0; i < 2; i++)
#pragma unroll
        for (int jn = 0; jn < 4; jn++) {
            Dd[i][jn][0] *= srow[i * 2];
            Dd[i][jn][1] *= srow[i * 2];
            Dd[i][jn][2] *= srow[i * 2 + 1];
            Dd[i][jn][3] *= srow[i * 2 + 1];
        }

    int trow[4] = { tkv[wm * 32 + g], tkv[wm * 32 + g + 8],
                    tkv[wm * 32 + 16 + g], tkv[wm * 32 + 16 + g + 8] };
    int tcol[8];
#pragma unroll
    for (int jn = 0; jn < 4; jn++) {
        int c0 = wn * 32 + jn * 8 + t * 2;
        tcol[jn * 2] = tkv[c0]; tcol[jn * 2 + 1] = tkv[c0 + 1];
    }
#pragma unroll
    for (int i = 0; i < 2; i++)
#pragma unroll
        for (int jn = 0; jn < 4; jn++)
#pragma unroll
            for (int q = 0; q < 4; q++)
                if (trow[i * 2 + (q >> 1)] == tcol[jn * 2 + (q & 1)]) Dd[i][jn][q] = -5e4f;

    // exp (unshifted; dots bounded) -> P fp16 (single) + partial sums
    float ps[4] = {0.f, 0.f, 0.f, 0.f};
#pragma unroll
    for (int i = 0; i < 2; i++) {
        int r0 = wm * 32 + i * 16 + g;
#pragma unroll
        for (int jn = 0; jn < 4; jn++) {
            float e0 = __expf(Dd[i][jn][0]);
            float e1 = __expf(Dd[i][jn][1]);
            float e2 = __expf(Dd[i][jn][2]);
            float e3 = __expf(Dd[i][jn][3]);
            ps[i * 2] += e0 + e1;
            ps[i * 2 + 1] += e2 + e3;
            int c0 = wn * 32 + jn * 8 + t * 2;
            *(uint32_t*)(sm + AT_P + r0 * 272 + c0 * 2)       = pack_h2(e0, e1);
            *(uint32_t*)(sm + AT_P + (r0 + 8) * 272 + c0 * 2) = pack_h2(e2, e3);
        }
    }
#pragma unroll
    for (int k = 0; k < 4; k++) {
        ps[k] += __shfl_xor_sync(0xffffffffu, ps[k], 1);
        ps[k] += __shfl_xor_sync(0xffffffffu, ps[k], 2);
    }
    if (t == 0) {
#pragma unroll
        for (int k = 0; k < 4; k++)
            rsump[(wm * 32 + (k >> 1) * 16 + g + (k & 1) * 8) * 4 + wn] = ps[k];
    }
    __syncthreads();

    if (tid < 64) {
        const float* p = rsump + tid * 4;
        float s = p[0] + p[1] + p[2] + p[3];
        rsuminv[tid] = 1.0f / s;
        g_lse[(bh * NHASH + h) * Nn + tkv[tid]] = logf(s);
    }
    __syncthreads();

    // PV MMA: single fp16 pass
    float Dp[2][2][4];
#pragma unroll
    for (int i = 0; i < 2; i++)
#pragma unroll
        for (int jn = 0; jn < 2; jn++)
#pragma unroll
            for (int q = 0; q < 4; q++) Dp[i][jn][q] = 0.f;

    uint32_t parow = (uint32_t)((wm * 32 + (lane & 15)) * 272 + (lane >> 4) * 16);
    uint32_t vbrow = (uint32_t)((lane & 15) * 144 + (lane >> 4) * 16 + wn * 32);
#pragma unroll
    for (int ks = 0; ks < 8; ks++) {
        uint32_t B4[4];
        ldmx4t(B4, sb + AT_V + vbrow + ks * (16 * 144));
        uint32_t A4[2][4];
#pragma unroll
        for (int i = 0; i < 2; i++) ldmx4(A4[i], sb + AT_P + parow + i * (16 * 272) + ks * 32);
#pragma unroll
        for (int i = 0; i < 2; i++)
#pragma unroll
            for (int jn = 0; jn < 2; jn++)
                mma16816h(Dp[i][jn], A4[i], B4[jn * 2], B4[jn * 2 + 1]);
    }

    // epilogue: normalize + scatter (fp16)
#pragma unroll
    for (int i = 0; i < 2; i++) {
        int r0 = wm * 32 + i * 16 + g;
        float inv0 = rsuminv[r0], inv1 = rsuminv[r0 + 8];
        size_t b0 = ((size_t)(bh * NHASH + h) * Nn + trow[i * 2]) * DHd;
        size_t b1 = ((size_t)(bh * NHASH + h) * Nn + trow[i * 2 + 1]) * DHd;
#pragma unroll
        for (int jn = 0; jn < 2; jn++) {
            int dh = wn * 16 + jn * 8 + t * 2;
            *(uint32_t*)(g_oph2 + b0 + dh) = pack_h2(Dp[i][jn][0] * inv0, Dp[i][jn][1] * inv0);
            *(uint32_t*)(g_oph2 + b1 + dh) = pack_h2(Dp[i][jn][2] * inv1, Dp[i][jn][3] * inv1);
        }
    }
}

// ---------------- fused combine + single fp16 plane write (Wout A_hi) ----------------
__global__ void combine_split_kernel(__half* __restrict__ hi) {
    int u = blockIdx.x * 256 + threadIdx.x;
    int slot = u >> 3;
    int dseg = (u & 7) * 8;
    int bh = slot >> 12;
    int t = slot & 4095;
    int base = bh * NHASH * Nn + t;
    float l0 = g_lse[base + 0 * Nn];
    float l1 = g_lse[base + 1 * Nn];
    float l2 = g_lse[base + 2 * Nn];
    float l3 = g_lse[base + 3 * Nn];
    float m = fmaxf(fmaxf(l0, l1), fmaxf(l2, l3));
    float w[4] = {expf(l0 - m), expf(l1 - m), expf(l2 - m), expf(l3 - m)};
    float sinv = 1.0f / (w[0] + w[1] + w[2] + w[3]);

    float acc[8];
#pragma unroll
    for (int j = 0; j < 8; j++) acc[j] = 0.f;
#pragma unroll
    for (int k = 0; k < 4; k++) {
        const uint4* p = (const uint4*)(g_oph2 + (((size_t)(bh * NHASH + k)) * Nn + t) * DHd + dseg);
        uint4 x = p[0];
        const __half2* hx = (const __half2*)&x;
#pragma unroll
        for (int j2 = 0; j2 < 4; j2++) {
            float2 f = __half22float2(hx[j2]);
            acc[j2 * 2]     += w[k] * f.x;
            acc[j2 * 2 + 1] += w[k] * f.y;
        }
    }
    float hf[8];
#pragma unroll
    for (int j = 0; j < 8; j++) hf[j] = acc[j] * sinv;
    int b = bh >> 4, head = bh & 15;
    size_t oidx = ((size_t)b * Nn + t) * Cc + head * DHd + dseg;
    *(uint4*)(hi + oidx) = make_uint4(pack_h2(hf[0], hf[1]), pack_h2(hf[2], hf[3]),
                                      pack_h2(hf[4], hf[5]), pack_h2(hf[6], hf[7]));
}

// ---------------- launch ----------------
extern "C" void kernel_launch(void* const* d_in, const int* in_sizes, int n_in,
                              void* d_out, int out_size) {
    const float* queries = (const float*)d_in[0];
    const float* Wqk  = (const float*)d_in[4];
    const float* Wv   = (const float*)d_in[5];
    const float* Wout = (const float*)d_in[6];
    const float* bout = (const float*)d_in[7];
    const float* rot  = (const float*)d_in[8];
    float* out = (float*)d_out;

    cudaFuncSetAttribute(attn_kernel, cudaFuncAttributeMaxDynamicSharedMemorySize, ATTN_SMEM_BYTES);
    cudaFuncSetAttribute(qkv_gemm, cudaFuncAttributeMaxDynamicSharedMemorySize, GEMM_SMEM);
    cudaFuncSetAttribute(mma_gemm, cudaFuncAttributeMaxDynamicSharedMemorySize, GEMM_SMEM);
    cudaFuncSetAttribute(prep_bucket_kernel, cudaFuncAttributeMaxDynamicSharedMemorySize, PB_SMEM);
    cudaFuncSetAttribute(sort_kernel, cudaFuncAttributeMaxDynamicSharedMemorySize, SORT_SMEM);

    void *p_qk, *p_vh2, *p_asp, *p_wqkv, *p_wout;
    cudaGetSymbolAddress(&p_qk, g_qk);
    cudaGetSymbolAddress(&p_vh2, g_vh2);
    cudaGetSymbolAddress(&p_asp, g_asp);
    cudaGetSymbolAddress(&p_wqkv, g_wqkv_sp);
    cudaGetSymbolAddress(&p_wout, g_wout_sp);
    __half* asp  = (__half*)p_asp;
    __half* wqkv = (__half*)p_wqkv;
    __half* wout = (__half*)p_wout;

    split_all_kernel<<<5632, 256>>>(queries, Wqk, Wv, Wout, asp, wqkv, wout);

    // fused qk (3-pass) + v (2-pass, fp16 plane) GEMM
    qkv_gemm<<<dim3(16, 64), 256, GEMM_SMEM>>>(asp, wqkv, (float*)p_qk, (__half*)p_vh2);

    // fused HMMA bucket + k/s prep (both need only g_qk)
    prep_bucket_kernel<<<2048 + BH * Nn / 8, 256, PB_SMEM>>>(rot);
    sort_kernel<<<dim3(BH, NHASH), 256, SORT_SMEM>>>();

    attn_kernel<<<dim3(NCHUNK, BH), 256, ATTN_SMEM_BYTES>>>();

    combine_split_kernel<<<(BH * Nn * DHd / 8) / 256, 256>>>(asp);

    // Wout GEMM: 2-pass fp16 (A single plane), +bias -> d_out
    mma_gemm<<<dim3(8, 64), 256, GEMM_SMEM>>>(asp, wout, bout, out);
}

// round 16
// speedup vs baseline: 5.7467x; 1.1738x over previous
#include <cuda_runtime.h>
#include <cuda_fp16.h>
#include <cuda_bf16.h>
#include <math.h>
#include <stdint.h>

// ---------------- problem constants ----------------
#define Bb      2
#define Nn      4096
#define Cc      1024
#define Hh      16
#define DHd     64
#define BH      32          // Bb*Hh
#define NHASH   4
#define NBUCK   64          // Nn / BUCKET
#define NCHUNK  256         // NHASH*NBUCK
#define BS      64          // bucket size
#define Kdim    1024
#define Mrows   8192        // Bb*Nn

// ---------------- device scratch ----------------
__device__ float g_qk  [BH * Nn * DHd];            // (bh, t, d)
__device__ int   g_bucket[BH * NHASH * Nn];
__device__ int   g_st  [BH * NHASH * Nn];
__device__ __half g_oph2[BH * NHASH * Nn * DHd];   // per-hash outputs, fp16
__device__ float g_lse [BH * NHASH * Nn];

// attention prep planes
#define PLN ((size_t)BH * Nn * DHd)
__device__ __half g_kh[PLN], g_km[PLN];            // normalized k limbs (fp16)
__device__ __half g_vh2[PLN];                      // v single fp16 plane (written by v GEMM)
__device__ float g_s[BH * Nn];                     // s = 0.125 * ||q||

// fp16 limb planes for GEMMs (W-side pre-scaled by 64; epilogue x 1/64)
#define APL ((size_t)Mrows * Kdim)
#define WQKV_PL ((size_t)2048 * 1024)
#define WOUT_PL ((size_t)1024 * 1024)
__device__ __half g_asp[2 * APL];
__device__ __half g_wqkv_sp[2 * WQKV_PL];
__device__ __half g_wout_sp[WOUT_PL];              // hi plane only (1-pass Wout)
#define WSCALE 64.0f
#define OSCALE (1.0f / 64.0f)

// ================= helpers (sm_103-safe) =================
__device__ __forceinline__ uint32_t smem_to_u32(const void* p) {
    uint32_t a;
    asm("{ .reg .u64 t; cvta.to.shared.u64 t, %1; cvt.u32.u64 %0, t; }" : "=r"(a) : "l"(p));
    return a;
}
#define CP_ASYNC16(saddr, gptr) \
    asm volatile("cp.async.cg.shared.global [%0], [%1], 16;" \
        :: "r"(saddr), "l"(__cvta_generic_to_global(gptr)))
#define CP_COMMIT() asm volatile("cp.async.commit_group;" ::: "memory")
#define CP_WAIT(n)  asm volatile("cp.async.wait_group %0;" :: "n"(n) : "memory")

__device__ __forceinline__ void ldmx4(uint32_t* r, uint32_t addr) {
    asm volatile("ldmatrix.sync.aligned.m8n8.x4.shared.b16 {%0,%1,%2,%3}, [%4];"
        : "=r"(r[0]), "=r"(r[1]), "=r"(r[2]), "=r"(r[3]) : "r"(addr));
}
__device__ __forceinline__ void ldmx4t(uint32_t* r, uint32_t addr) {
    asm volatile("ldmatrix.sync.aligned.m8n8.x4.trans.shared.b16 {%0,%1,%2,%3}, [%4];"
        : "=r"(r[0]), "=r"(r[1]), "=r"(r[2]), "=r"(r[3]) : "r"(addr));
}
__device__ __forceinline__ void mma16816h(float* d, const uint32_t* a, uint32_t b0, uint32_t b1) {
    asm volatile("mma.sync.aligned.m16n8k16.row.col.f32.f16.f16.f32 "
        "{%0,%1,%2,%3}, {%4,%5,%6,%7}, {%8,%9}, {%0,%1,%2,%3};"
        : "+f"(d[0]), "+f"(d[1]), "+f"(d[2]), "+f"(d[3])
        : "r"(a[0]), "r"(a[1]), "r"(a[2]), "r"(a[3]), "r"(b0), "r"(b1));
}
__device__ __forceinline__ uint32_t pack_h2(float a, float b) {
    uint16_t ua = __half_as_ushort(__float2half_rn(a));
    uint16_t ub = __half_as_ushort(__float2half_rn(b));
    return (uint32_t)ua | ((uint32_t)ub << 16);
}

// ================= merged fp16 limb split =================
__device__ __forceinline__ void split8(const float* __restrict__ x,
                                       __half* __restrict__ hi, __half* __restrict__ mid,
                                       int i, float scale) {
    float4 v0 = *(const float4*)(x + i);
    float4 v1 = *(const float4*)(x + i + 4);
    float a[8] = {v0.x, v0.y, v0.z, v0.w, v1.x, v1.y, v1.z, v1.w};
    float hf[8], mf[8];
#pragma unroll
    for (int j = 0; j < 8; j++) {
        float s = a[j] * scale;
        float h = __half2float(__float2half_rn(s));
        hf[j] = h; mf[j] = s - h;
    }
    *(uint4*)(hi + i) = make_uint4(pack_h2(hf[0], hf[1]), pack_h2(hf[2], hf[3]),
                                   pack_h2(hf[4], hf[5]), pack_h2(hf[6], hf[7]));
    *(uint4*)(mid + i) = make_uint4(pack_h2(mf[0], mf[1]), pack_h2(mf[2], mf[3]),
                                    pack_h2(mf[4], mf[5]), pack_h2(mf[6], mf[7]));
}
__device__ __forceinline__ void split8_hi(const float* __restrict__ x,
                                          __half* __restrict__ hi, int i, float scale) {
    float4 v0 = *(const float4*)(x + i);
    float4 v1 = *(const float4*)(x + i + 4);
    float a[8] = {v0.x, v0.y, v0.z, v0.w, v1.x, v1.y, v1.z, v1.w};
    uint32_t p[4];
#pragma unroll
    for (int j = 0; j < 4; j++)
        p[j] = pack_h2(a[j * 2] * scale, a[j * 2 + 1] * scale);
    *(uint4*)(hi + i) = make_uint4(p[0], p[1], p[2], p[3]);
}

__global__ void split_all_kernel(const float* __restrict__ q,
                                 const float* __restrict__ wqk,
                                 const float* __restrict__ wv,
                                 const float* __restrict__ wo,
                                 __half* __restrict__ asp,
                                 __half* __restrict__ wqkv,
                                 __half* __restrict__ wout) {
    int bid = blockIdx.x;
    int li = threadIdx.x * 8;
    const int NW = 1024 * 1024;
    if (bid < 4096) {                      // activations: 2 limbs (qk needs mid)
        int i = bid * 2048 + li;
        split8(q, asp, asp + APL, i, 1.0f);
    } else if (bid < 4608) {               // Wqk: 2 limbs (qk 3-pass)
        int i = (bid - 4096) * 2048 + li;
        split8(wqk, wqkv, wqkv + WQKV_PL, i, WSCALE);
    } else if (bid < 5120) {               // Wv: hi only (v 1-pass)
        int i = (bid - 4608) * 2048 + li;
        split8_hi(wv, wqkv + NW, i, WSCALE);
    } else {                               // Wout: hi only (1-pass)
        int i = (bid - 5120) * 2048 + li;
        split8_hi(wo, wout, i, WSCALE);
    }
}

// ================= HMMA GEMM body (fp16 limbs) =================
#define ROWB     80
#define MATB     (128 * ROWB)
#define STAGEB   (2 * MATB)
#define GEMM_SMEM (4 * STAGEB)   // 81920
// 3-pass (fp32-equivalent for argmax): (0,1)(1,0)(0,0)
#define PA3 0x010u
#define PW3 0x001u
// 1-pass: (0,0)
#define PA1 0x0u
#define PW1 0x0u

__device__ __forceinline__ void gemm_issue(uint32_t st,
        const __half* Ap, const __half* Bp, int bm, int bn, int k0,
        uint32_t so0, uint32_t so1, int r0, int c0, int r1, int c1) {
    CP_ASYNC16(st + so0, Ap + (size_t)(bm + r0) * Kdim + k0 + c0 * 8);
    CP_ASYNC16(st + so1, Ap + (size_t)(bm + r1) * Kdim + k0 + c1 * 8);
    CP_ASYNC16(st + MATB + so0, Bp + (size_t)(bn + r0) * Kdim + k0 + c0 * 8);
    CP_ASYNC16(st + MATB + so1, Bp + (size_t)(bn + r1) * Kdim + k0 + c1 * 8);
    CP_COMMIT();
}

__device__ __forceinline__ void gemm_body(char* smem,
        const __half* __restrict__ Asp, size_t Apl,
        const __half* __restrict__ Bsp, size_t Bpl,
        const float* __restrict__ bias, float* __restrict__ outp,
        float* __restrict__ headout, __half* __restrict__ headout_h,
        int npass, uint32_t paTbl, uint32_t pwTbl, int bn, int bm) {
    uint32_t sbase = smem_to_u32(smem);
    int tid = threadIdx.x;
    int lane = tid & 31, warp = tid >> 5;
    int wm = warp >> 2, wn = warp & 3;
    int nstage = npass * 32;

    int v0 = tid, v1 = tid + 256;
    int r0 = v0 >> 2, c0 = v0 & 3;
    int r1 = v1 >> 2, c1 = v1 & 3;
    uint32_t so0 = (uint32_t)(r0 * ROWB + c0 * 16);
    uint32_t so1 = (uint32_t)(r1 * ROWB + c1 * 16);

    uint32_t aoff = (uint32_t)((wm * 64 + (lane & 15)) * ROWB + (lane >> 4) * 16);
    uint32_t boff = (uint32_t)((wn * 32 + ((lane >> 4) & 1) * 8 + (lane & 7)) * ROWB
                               + ((lane >> 3) & 1) * 16);

    float D[4][4][4];
#pragma unroll
    for (int i = 0; i < 4; i++)
#pragma unroll
        for (int j = 0; j < 4; j++)
#pragma unroll
            for (int q = 0; q < 4; q++) D[i][j][q] = 0.f;

#pragma unroll
    for (int s = 0; s < 3; s++) {
        const __half* Ap = Asp + (size_t)(paTbl & 7) * Apl;
        const __half* Bp = Bsp + (size_t)(pwTbl & 7) * Bpl;
        gemm_issue(sbase + s * STAGEB, Ap, Bp, bm, bn, (s & 31) * 32, so0, so1, r0, c0, r1, c1);
    }

    for (int s = 0; s < nstage; s++) {
        if (s <= nstage - 3)      { CP_WAIT(2); }
        else if (s == nstage - 2) { CP_WAIT(1); }
        else                      { CP_WAIT(0); }
        __syncthreads();
        if (s + 3 < nstage) {
            int sn = s + 3;
            int p = sn >> 5, k0 = (sn & 31) << 5;
            const __half* Ap = Asp + (size_t)((paTbl >> (p * 4)) & 7) * Apl;
            const __half* Bp = Bsp + (size_t)((pwTbl >> (p * 4)) & 7) * Bpl;
            gemm_issue(sbase + (uint32_t)(sn & 3) * STAGEB, Ap, Bp, bm, bn, k0,
                       so0, so1, r0, c0, r1, c1);
        }
        uint32_t st = sbase + (uint32_t)(s & 3) * STAGEB;
        uint32_t ab = st + aoff;
        uint32_t bb = st + MATB + boff;
#pragma unroll
        for (int ks = 0; ks < 2; ks++) {
            uint32_t A4[4][4], B4[2][4];
#pragma unroll
            for (int i = 0; i < 4; i++) ldmx4(A4[i], ab + i * (16 * ROWB) + ks * 32);
#pragma unroll
            for (int jp = 0; jp < 2; jp++) ldmx4(B4[jp], bb + jp * (16 * ROWB) + ks * 32);
#pragma unroll
            for (int i = 0; i < 4; i++)
#pragma unroll
                for (int jn = 0; jn < 4; jn++)
                    mma16816h(D[i][jn], A4[i], B4[jn >> 1][(jn & 1) * 2], B4[jn >> 1][(jn & 1) * 2 + 1]);
        }
    }

    int g = lane >> 2, t = lane & 3;
#pragma unroll
    for (int i = 0; i < 4; i++) {
#pragma unroll
        for (int jn = 0; jn < 4; jn++) {
            int m0 = bm + wm * 64 + i * 16 + g;
            int n0 = bn + wn * 32 + jn * 8 + t * 2;
            float2 va = make_float2(D[i][jn][0] * OSCALE, D[i][jn][1] * OSCALE);
            float2 vb = make_float2(D[i][jn][2] * OSCALE, D[i][jn][3] * OSCALE);
            if (headout) {
                int bI = m0 >> 12;
                int t0 = m0 & 4095, t1 = (m0 + 8) & 4095;
                int hd = n0 >> 6, dh = n0 & 63;
                *(float2*)(headout + (((size_t)(bI * Hh + hd)) * Nn + t0) * DHd + dh) = va;
                *(float2*)(headout + (((size_t)(bI * Hh + hd)) * Nn + t1) * DHd + dh) = vb;
            } else if (headout_h) {
                int bI = m0 >> 12;
                int t0 = m0 & 4095, t1 = (m0 + 8) & 4095;
                int hd = n0 >> 6, dh = n0 & 63;
                *(uint32_t*)(headout_h + (((size_t)(bI * Hh + hd)) * Nn + t0) * DHd + dh) = pack_h2(va.x, va.y);
                *(uint32_t*)(headout_h + (((size_t)(bI * Hh + hd)) * Nn + t1) * DHd + dh) = pack_h2(vb.x, vb.y);
            } else {
                float2 bv = *(const float2*)(bias + n0);
                va.x += bv.x; va.y += bv.y; vb.x += bv.x; vb.y += bv.y;
                *(float2*)(outp + (size_t)m0 * Cc + n0) = va;
                *(float2*)(outp + (size_t)(m0 + 8) * Cc + n0) = vb;
            }
        }
    }
}

// fused qk (3-pass, x<8) + v (1-pass -> fp16 plane, x>=8) GEMM
__global__ __launch_bounds__(256, 2) void qkv_gemm(
        const __half* __restrict__ Asp,
        const __half* __restrict__ Wqkv,
        float* __restrict__ qkout, __half* __restrict__ vout) {
    extern __shared__ char smem[];
    const int NW = 1024 * 1024;
    if (blockIdx.x < 8) {
        gemm_body(smem, Asp, APL, Wqkv, WQKV_PL, nullptr, nullptr, qkout, nullptr,
                  3, PA3, PW3, blockIdx.x * 128, blockIdx.y * 128);
    } else {
        gemm_body(smem, Asp, APL, Wqkv + NW, WQKV_PL, nullptr, nullptr, nullptr, vout,
                  1, PA1, PW1, (blockIdx.x - 8) * 128, blockIdx.y * 128);
    }
}

// Wout GEMM: 1-pass (A hi plane x W hi plane)
__global__ __launch_bounds__(256, 2) void mma_gemm(
        const __half* __restrict__ Asp,
        const __half* __restrict__ Wout_,
        const float* __restrict__ bias, float* __restrict__ outp) {
    extern __shared__ char smem[];
    gemm_body(smem, Asp, APL, Wout_, WOUT_PL, bias, outp, nullptr, nullptr,
              1, PA1, PW1, blockIdx.x * 128, blockIdx.y * 128);
}

// ---------------- HMMA LSH bucketing (3 limb passes, exact first-index argmax) ----------------
#define BK_AHI  0
#define BK_AMID 9216
#define BK_BHI  18432
#define BK_BMID 36864
#define PB_SMEM 55296

__device__ __forceinline__ void bucket_body(char* smemc, const float* __restrict__ rot,
                                            int bh, int tb) {
    uint32_t sb = smem_to_u32(smemc);
    int tid = threadIdx.x, lane = tid & 31, warp = tid >> 5;
    int g = lane >> 2, t = lane & 3;
    int wm = warp >> 2, wn = warp & 3;

    {
        int row = tid >> 2, seg = tid & 3;
        const float* src = g_qk + ((size_t)bh * Nn + tb + row) * DHd + seg * 16;
        char* dh_ = smemc + BK_AHI + row * 144 + seg * 32;
        char* dm_ = smemc + BK_AMID + row * 144 + seg * 32;
#pragma unroll
        for (int k4 = 0; k4 < 4; k4++) {
            float4 v = *(const float4*)(src + k4 * 4);
            float h0 = __half2float(__float2half_rn(v.x));
            float h1 = __half2float(__float2half_rn(v.y));
            float h2 = __half2float(__float2half_rn(v.z));
            float h3 = __half2float(__float2half_rn(v.w));
            *(uint32_t*)(dh_ + k4 * 8)     = pack_h2(h0, h1);
            *(uint32_t*)(dh_ + k4 * 8 + 4) = pack_h2(h2, h3);
            *(uint32_t*)(dm_ + k4 * 8)     = pack_h2(v.x - h0, v.y - h1);
            *(uint32_t*)(dm_ + k4 * 8 + 4) = pack_h2(v.z - h2, v.w - h3);
        }
    }
    {
        int n = tid >> 1, seg = tid & 1;
        char* dh_ = smemc + BK_BHI + n * 144 + seg * 64;
        char* dm_ = smemc + BK_BMID + n * 144 + seg * 64;
#pragma unroll
        for (int k2 = 0; k2 < 16; k2++) {
            int d = seg * 32 + k2 * 2;
            float a = rot[(size_t)d * 128 + n];
            float b = rot[(size_t)(d + 1) * 128 + n];
            float ha = __half2float(__float2half_rn(a));
            float hb = __half2float(__float2half_rn(b));
            *(uint32_t*)(dh_ + k2 * 4) = pack_h2(ha, hb);
            *(uint32_t*)(dm_ + k2 * 4) = pack_h2(a - ha, b - hb);
        }
    }
    __syncthreads();

    float Dd[2][4][4];
#pragma unroll
    for (int i = 0; i < 2; i++)
#pragma unroll
        for (int jn = 0; jn < 4; jn++)
#pragma unroll
            for (int q = 0; q < 4; q++) Dd[i][jn][q] = 0.f;

    uint32_t arow = (uint32_t)((wm * 32 + (lane & 15)) * 144 + (lane >> 4) * 16);
    uint32_t brow = (uint32_t)((wn * 32 + ((lane >> 4) & 1) * 8 + (lane & 7)) * 144
                               + ((lane >> 3) & 1) * 16);
    const uint32_t AL[3] = {sb + BK_AMID, sb + BK_AHI, sb + BK_AHI};
    const uint32_t BL[3] = {sb + BK_BHI, sb + BK_BMID, sb + BK_BHI};
#pragma unroll
    for (int p = 0; p < 3; p++) {
#pragma unroll
        for (int ks = 0; ks < 4; ks++) {
            uint32_t A4[2][4], B4[2][4];
#pragma unroll
            for (int i = 0; i < 2; i++) ldmx4(A4[i], AL[p] + arow + i * (16 * 144) + ks * 32);
#pragma unroll
            for (int jp = 0; jp < 2; jp++) ldmx4(B4[jp], BL[p] + brow + jp * (16 * 144) + ks * 32);
#pragma unroll
            for (int i = 0; i < 2; i++)
#pragma unroll
                for (int jn = 0; jn < 4; jn++)
                    mma16816h(Dd[i][jn], A4[i], B4[jn >> 1][(jn & 1) * 2], B4[jn >> 1][(jn & 1) * 2 + 1]);
        }
    }

#pragma unroll
    for (int i = 0; i < 2; i++) {
#pragma unroll
        for (int half = 0; half < 2; half++) {
            int row = wm * 32 + i * 16 + g + half * 8;
            float bv = -3.0e38f; int bidx = 0;
#pragma unroll
            for (int jn = 0; jn < 4; jn++) {
#pragma unroll
                for (int z = 0; z < 2; z++) {
                    float v = Dd[i][jn][half * 2 + z];
                    int ri = jn * 8 + t * 2 + z;
                    if (v > bv || (v == bv && ri < bidx)) { bv = v; bidx = ri; }
                    float nv = -v; int ni = 32 + ri;
                    if (nv > bv || (nv == bv && ni < bidx)) { bv = nv; bidx = ni; }
                }
            }
#pragma unroll
            for (int o = 1; o <= 2; o <<= 1) {
                float ov = __shfl_xor_sync(0xffffffffu, bv, o);
                int oi = __shfl_xor_sync(0xffffffffu, bidx, o);
                if (ov > bv || (ov == bv && oi < bidx)) { bv = ov; bidx = oi; }
            }
            if (t == 0)
                g_bucket[((size_t)bh * NHASH + wn) * Nn + tb + row] = bidx;
        }
    }
}

// ---------------- fused bucket (HMMA) + k/s prep ----------------
__global__ void prep_bucket_kernel(const float* __restrict__ rot) {
    extern __shared__ char smem[];
    int bid = blockIdx.x;
    if (bid < 2048) {
        bucket_body(smem, rot, bid >> 6, (bid & 63) * 64);
        return;
    }
    int row = (bid - 2048) * 8 + (threadIdx.x >> 5);
    int lane = threadIdx.x & 31;
    size_t off = (size_t)row * DHd;
    const float* src = g_qk + off;
    float a = src[lane], b = src[lane + 32];

    float s = a * a + b * b;
#pragma unroll
    for (int o = 16; o > 0; o >>= 1) s += __shfl_xor_sync(0xffffffffu, s, o);
    float norm = sqrtf(s);
    float inv = 1.0f / fmaxf(norm, 1e-12f);
    if (lane == 0) g_s[row] = 0.125f * norm;

    float ka = a * inv, kb = b * inv;
    float kah = __half2float(__float2half_rn(ka));
    float kbh = __half2float(__float2half_rn(kb));
    g_kh[off + lane]      = __float2half_rn(kah);
    g_kh[off + lane + 32] = __float2half_rn(kbh);
    g_km[off + lane]      = __float2half_rn(ka - kah);
    g_km[off + lane + 32] = __float2half_rn(kb - kbh);
}

// ---------------- parallel stable counting sort per (bh, hash) ----------------
#define SORT_SMEM 49152
__global__ void sort_kernel() {
    extern __shared__ char ss[];
    unsigned char*  cnt    = (unsigned char*)ss;
    unsigned short* segoff = (unsigned short*)(ss + 16384);
    __shared__ int bbase[NBUCK];
    int bh = blockIdx.x, h = blockIdx.y;
    int tid = threadIdx.x;
    const int gb = (bh * NHASH + h) * Nn;

    uint32_t* ci = (uint32_t*)cnt;
    for (int i = tid; i < 4096; i += 256) ci[i] = 0;
    __syncthreads();

    int bb[16];
#pragma unroll
    for (int k = 0; k < 16; k++) {
        int b = g_bucket[gb + tid * 16 + k];
        bb[k] = b;
        cnt[tid * 64 + b]++;
    }
    __syncthreads();

    if (tid < NBUCK) {
        int run = 0;
        for (int seg = 0; seg < 256; seg++) {
            segoff[seg * 64 + tid] = (unsigned short)run;
            run += cnt[seg * 64 + tid];
        }
        bbase[tid] = run;
    }
    __syncthreads();
    if (tid == 0) {
        int acc = 0;
        for (int b = 0; b < NBUCK; b++) { int c = bbase[b]; bbase[b] = acc; acc += c; }
    }
    __syncthreads();

#pragma unroll
    for (int k = 0; k < 16; k++) {
        int b = bb[k];
        int pos = bbase[b] + segoff[tid * 64 + b];
        segoff[tid * 64 + b]++;
        g_st[gb + pos] = tid * 16 + k;
    }
}

// ---------------- chunked LSH attention: K-as-A fp16 dots (2-pass), fp16 P (1-pass PV) ----------------
#define AT_S     512
#define AT_KHI   3072
#define AT_KMID  21504
#define AT_V     39936
#define AT_P     58368
#define ATTN_SMEM_BYTES 75776

__global__ __launch_bounds__(256, 2) void attn_kernel() {
    extern __shared__ char sm[];
    int*   tkv     = (int*)sm;
    float* sS      = (float*)(sm + AT_S);
    float* rsump   = (float*)(sm + 1536);
    float* rsuminv = (float*)(sm + 2560);
    uint32_t sb = smem_to_u32(sm);

    int c = blockIdx.x, bh = blockIdx.y;
    int h = c >> 6;
    int tid = threadIdx.x, lane = tid & 31, warp = tid >> 5;
    int g = lane >> 2, t = lane & 3;
    int wm = warp >> 2, wn = warp & 3;
    int pc = (c + NCHUNK - 1) & (NCHUNK - 1);
    const int stb = bh * (NHASH * Nn);

    if (tid < 64)       tkv[tid] = g_st[stb + c * BS + tid];
    else if (tid < 128) tkv[tid] = g_st[stb + pc * BS + (tid - 64)];
    __syncthreads();

    if (tid < 64) sS[tid] = g_s[(size_t)bh * Nn + tkv[tid]];

    // gather k limbs + v via cp.async
    {
        int j = tid >> 1, seg = tid & 1;
        size_t off = ((size_t)bh * Nn + tkv[j]) * DHd + seg * 32;
        const __half* skh = g_kh + off;
        const __half* skm = g_km + off;
        const __half* svh = g_vh2 + off;
        uint32_t dkh = sb + AT_KHI + j * 144 + seg * 64;
        uint32_t dkm = sb + AT_KMID + j * 144 + seg * 64;
        uint32_t dvh = sb + AT_V + j * 144 + seg * 64;
#pragma unroll
        for (int k = 0; k < 4; k++) {
            CP_ASYNC16(dkh + k * 16, skh + k * 8);
            CP_ASYNC16(dkm + k * 16, skm + k * 8);
            CP_ASYNC16(dvh + k * 16, svh + k * 8);
        }
        CP_COMMIT();
        CP_WAIT(0);
    }
    __syncthreads();

    // dots MMA: A = Khi rows 0..63; 2 fp16 passes, A ldmatrix shared
    float Dd[2][4][4];
#pragma unroll
    for (int i = 0; i < 2; i++)
#pragma unroll
        for (int jn = 0; jn < 4; jn++)
#pragma unroll
            for (int q = 0; q < 4; q++) Dd[i][jn][q] = 0.f;

    uint32_t arow = (uint32_t)((wm * 32 + (lane & 15)) * 144 + (lane >> 4) * 16);
    uint32_t brow = (uint32_t)((wn * 32 + ((lane >> 4) & 1) * 8 + (lane & 7)) * 144
                               + ((lane >> 3) & 1) * 16);
    const uint32_t KL[2] = {sb + AT_KMID, sb + AT_KHI};
#pragma unroll
    for (int ks = 0; ks < 4; ks++) {
        uint32_t A4[2][4];
#pragma unroll
        for (int i = 0; i < 2; i++) ldmx4(A4[i], sb + AT_KHI + arow + i * (16 * 144) + ks * 32);
#pragma unroll
        for (int p = 0; p < 2; p++) {
            uint32_t B4[2][4];
#pragma unroll
            for (int jp = 0; jp < 2; jp++) ldmx4(B4[jp], KL[p] + brow + jp * (16 * 144) + ks * 32);
#pragma unroll
            for (int i = 0; i < 2; i++)
#pragma unroll
                for (int jn = 0; jn < 4; jn++)
                    mma16816h(Dd[i][jn], A4[i], B4[jn >> 1][(jn & 1) * 2], B4[jn >> 1][(jn & 1) * 2 + 1]);
        }
    }

    // scale rows by s, then mask
    float srow[4] = { sS[wm * 32 + g], sS[wm * 32 + g + 8],
                      sS[wm * 32 + 16 + g], sS[wm * 32 + 16 + g + 8] };
#pragma unroll
    for (int i = 0; i < 2; i++)
#pragma unroll
        for (int jn = 0; jn < 4; jn++) {
            Dd[i][jn][0] *= srow[i * 2];
            Dd[i][jn][1] *= srow[i * 2];
            Dd[i][jn][2] *= srow[i * 2 + 1];
            Dd[i][jn][3] *= srow[i * 2 + 1];
        }

    int trow[4] = { tkv[wm * 32 + g], tkv[wm * 32 + g + 8],
                    tkv[wm * 32 + 16 + g], tkv[wm * 32 + 16 + g + 8] };
    int tcol[8];
#pragma unroll
    for (int jn = 0; jn < 4; jn++) {
        int c0 = wn * 32 + jn * 8 + t * 2;
        tcol[jn * 2] = tkv[c0]; tcol[jn * 2 + 1] = tkv[c0 + 1];
    }
#pragma unroll
    for (int i = 0; i < 2; i++)
#pragma unroll
        for (int jn = 0; jn < 4; jn++)
#pragma unroll
            for (int q = 0; q < 4; q++)
                if (trow[i * 2 + (q >> 1)] == tcol[jn * 2 + (q & 1)]) Dd[i][jn][q] = -5e4f;

    // exp -> P fp16 + partial sums
    float ps[4] = {0.f, 0.f, 0.f, 0.f};
#pragma unroll
    for (int i = 0; i < 2; i++) {
        int r0 = wm * 32 + i * 16 + g;
#pragma unroll
        for (int jn = 0; jn < 4; jn++) {
            float e0 = __expf(Dd[i][jn][0]);
            float e1 = __expf(Dd[i][jn][1]);
            float e2 = __expf(Dd[i][jn][2]);
            float e3 = __expf(Dd[i][jn][3]);
            ps[i * 2] += e0 + e1;
            ps[i * 2 + 1] += e2 + e3;
            int c0 = wn * 32 + jn * 8 + t * 2;
            *(uint32_t*)(sm + AT_P + r0 * 272 + c0 * 2)       = pack_h2(e0, e1);
            *(uint32_t*)(sm + AT_P + (r0 + 8) * 272 + c0 * 2) = pack_h2(e2, e3);
        }
    }
#pragma unroll
    for (int k = 0; k < 4; k++) {
        ps[k] += __shfl_xor_sync(0xffffffffu, ps[k], 1);
        ps[k] += __shfl_xor_sync(0xffffffffu, ps[k], 2);
    }
    if (t == 0) {
#pragma unroll
        for (int k = 0; k < 4; k++)
            rsump[(wm * 32 + (k >> 1) * 16 + g + (k & 1) * 8) * 4 + wn] = ps[k];
    }
    __syncthreads();

    if (tid < 64) {
        const float* p = rsump + tid * 4;
        float s = p[0] + p[1] + p[2] + p[3];
        rsuminv[tid] = 1.0f / s;
        g_lse[(bh * NHASH + h) * Nn + tkv[tid]] = logf(s);
    }
    __syncthreads();

    // PV MMA: single fp16 pass
    float Dp[2][2][4];
#pragma unroll
    for (int i = 0; i < 2; i++)
#pragma unroll
        for (int jn = 0; jn < 2; jn++)
#pragma unroll
            for (int q = 0; q < 4; q++) Dp[i][jn][q] = 0.f;

    uint32_t parow = (uint32_t)((wm * 32 + (lane & 15)) * 272 + (lane >> 4) * 16);
    uint32_t vbrow = (uint32_t)((lane & 15) * 144 + (lane >> 4) * 16 + wn * 32);
#pragma unroll
    for (int ks = 0; ks < 8; ks++) {
        uint32_t B4[4];
        ldmx4t(B4, sb + AT_V + vbrow + ks * (16 * 144));
        uint32_t A4[2][4];
#pragma unroll
        for (int i = 0; i < 2; i++) ldmx4(A4[i], sb + AT_P + parow + i * (16 * 272) + ks * 32);
#pragma unroll
        for (int i = 0; i < 2; i++)
#pragma unroll
            for (int jn = 0; jn < 2; jn++)
                mma16816h(Dp[i][jn], A4[i], B4[jn * 2], B4[jn * 2 + 1]);
    }

    // epilogue: normalize + scatter (fp16)
#pragma unroll
    for (int i = 0; i < 2; i++) {
        int r0 = wm * 32 + i * 16 + g;
        float inv0 = rsuminv[r0], inv1 = rsuminv[r0 + 8];
        size_t b0 = ((size_t)(bh * NHASH + h) * Nn + trow[i * 2]) * DHd;
        size_t b1 = ((size_t)(bh * NHASH + h) * Nn + trow[i * 2 + 1]) * DHd;
#pragma unroll
        for (int jn = 0; jn < 2; jn++) {
            int dh = wn * 16 + jn * 8 + t * 2;
            *(uint32_t*)(g_oph2 + b0 + dh) = pack_h2(Dp[i][jn][0] * inv0, Dp[i][jn][1] * inv0);
            *(uint32_t*)(g_oph2 + b1 + dh) = pack_h2(Dp[i][jn][2] * inv1, Dp[i][jn][3] * inv1);
        }
    }
}

// ---------------- fused combine + single fp16 plane write (Wout A_hi) ----------------
__global__ void combine_split_kernel(__half* __restrict__ hi) {
    int u = blockIdx.x * 256 + threadIdx.x;
    int slot = u >> 3;
    int dseg = (u & 7) * 8;
    int bh = slot >> 12;
    int t = slot & 4095;
    int base = bh * NHASH * Nn + t;
    float l0 = g_lse[base + 0 * Nn];
    float l1 = g_lse[base + 1 * Nn];
    float l2 = g_lse[base + 2 * Nn];
    float l3 = g_lse[base + 3 * Nn];
    float m = fmaxf(fmaxf(l0, l1), fmaxf(l2, l3));
    float w[4] = {expf(l0 - m), expf(l1 - m), expf(l2 - m), expf(l3 - m)};
    float sinv = 1.0f / (w[0] + w[1] + w[2] + w[3]);

    float acc[8];
#pragma unroll
    for (int j = 0; j < 8; j++) acc[j] = 0.f;
#pragma unroll
    for (int k = 0; k < 4; k++) {
        const uint4* p = (const uint4*)(g_oph2 + (((size_t)(bh * NHASH + k)) * Nn + t) * DHd + dseg);
        uint4 x = p[0];
        const __half2* hx = (const __half2*)&x;
#pragma unroll
        for (int j2 = 0; j2 < 4; j2++) {
            float2 f = __half22float2(hx[j2]);
            acc[j2 * 2]     += w[k] * f.x;
            acc[j2 * 2 + 1] += w[k] * f.y;
        }
    }
    float hf[8];
#pragma unroll
    for (int j = 0; j < 8; j++) hf[j] = acc[j] * sinv;
    int b = bh >> 4, head = bh & 15;
    size_t oidx = ((size_t)b * Nn + t) * Cc + head * DHd + dseg;
    *(uint4*)(hi + oidx) = make_uint4(pack_h2(hf[0], hf[1]), pack_h2(hf[2], hf[3]),
                                      pack_h2(hf[4], hf[5]), pack_h2(hf[6], hf[7]));
}

// ---------------- launch ----------------
extern "C" void kernel_launch(void* const* d_in, const int* in_sizes, int n_in,
                              void* d_out, int out_size) {
    const float* queries = (const float*)d_in[0];
    const float* Wqk  = (const float*)d_in[4];
    const float* Wv   = (const float*)d_in[5];
    const float* Wout = (const float*)d_in[6];
    const float* bout = (const float*)d_in[7];
    const float* rot  = (const float*)d_in[8];
    float* out = (float*)d_out;

    cudaFuncSetAttribute(attn_kernel, cudaFuncAttributeMaxDynamicSharedMemorySize, ATTN_SMEM_BYTES);
    cudaFuncSetAttribute(qkv_gemm, cudaFuncAttributeMaxDynamicSharedMemorySize, GEMM_SMEM);
    cudaFuncSetAttribute(mma_gemm, cudaFuncAttributeMaxDynamicSharedMemorySize, GEMM_SMEM);
    cudaFuncSetAttribute(prep_bucket_kernel, cudaFuncAttributeMaxDynamicSharedMemorySize, PB_SMEM);
    cudaFuncSetAttribute(sort_kernel, cudaFuncAttributeMaxDynamicSharedMemorySize, SORT_SMEM);

    void *p_qk, *p_vh2, *p_asp, *p_wqkv, *p_wout;
    cudaGetSymbolAddress(&p_qk, g_qk);
    cudaGetSymbolAddress(&p_vh2, g_vh2);
    cudaGetSymbolAddress(&p_asp, g_asp);
    cudaGetSymbolAddress(&p_wqkv, g_wqkv_sp);
    cudaGetSymbolAddress(&p_wout, g_wout_sp);
    __half* asp  = (__half*)p_asp;
    __half* wqkv = (__half*)p_wqkv;
    __half* wout = (__half*)p_wout;

    split_all_kernel<<<5632, 256>>>(queries, Wqk, Wv, Wout, asp, wqkv, wout);

    // fused qk (3-pass) + v (1-pass, fp16 plane) GEMM
    qkv_gemm<<<dim3(16, 64), 256, GEMM_SMEM>>>(asp, wqkv, (float*)p_qk, (__half*)p_vh2);

    // fused HMMA bucket + k/s prep (both need only g_qk)
    prep_bucket_kernel<<<2048 + BH * Nn / 8, 256, PB_SMEM>>>(rot);
    sort_kernel<<<dim3(BH, NHASH), 256, SORT_SMEM>>>();

    attn_kernel<<<dim3(NCHUNK, BH), 256, ATTN_SMEM_BYTES>>>();

    combine_split_kernel<<<(BH * Nn * DHd / 8) / 256, 256>>>(asp);

    // Wout GEMM: 1-pass fp16, +bias -> d_out
    mma_gemm<<<dim3(8, 64), 256, GEMM_SMEM>>>(asp, wout, bout, out);
}

// round 17
// speedup vs baseline: 6.2052x; 1.0798x over previous
#include <cuda_runtime.h>
#include <cuda_fp16.h>
#include <cuda_bf16.h>
#include <math.h>
#include <stdint.h>

// ---------------- problem constants ----------------
#define Bb      2
#define Nn      4096
#define Cc      1024
#define Hh      16
#define DHd     64
#define BH      32          // Bb*Hh
#define NHASH   4
#define NBUCK   64          // Nn / BUCKET
#define NCHUNK  256         // NHASH*NBUCK
#define BS      64          // bucket size
#define Kdim    1024
#define Mrows   8192        // Bb*Nn

// ---------------- device scratch ----------------
__device__ float g_qk  [BH * Nn * DHd];            // (bh, t, d)
__device__ int   g_bucket[BH * NHASH * Nn];
__device__ int   g_st  [BH * NHASH * Nn];
__device__ __half g_oph2[BH * NHASH * Nn * DHd];   // per-hash outputs, fp16
__device__ float g_lse [BH * NHASH * Nn];

// attention prep planes
#define PLN ((size_t)BH * Nn * DHd)
__device__ __half g_kh[PLN];                       // normalized k, fp16 hi (single plane)
__device__ __half g_vh2[PLN];                      // v single fp16 plane (written by v GEMM)
__device__ float g_s[BH * Nn];                     // s = 0.125 * ||q||

// fp16 limb planes for GEMMs (W-side pre-scaled by 64; epilogue x 1/64)
#define APL ((size_t)Mrows * Kdim)
#define WQKV_PL ((size_t)2048 * 1024)
#define WOUT_PL ((size_t)1024 * 1024)
__device__ __half g_asp[2 * APL];
__device__ __half g_wqkv_sp[2 * WQKV_PL];
__device__ __half g_wout_sp[WOUT_PL];              // hi plane only (1-pass Wout)
#define WSCALE 64.0f
#define OSCALE (1.0f / 64.0f)

// ================= helpers (sm_103-safe) =================
__device__ __forceinline__ uint32_t smem_to_u32(const void* p) {
    uint32_t a;
    asm("{ .reg .u64 t; cvta.to.shared.u64 t, %1; cvt.u32.u64 %0, t; }" : "=r"(a) : "l"(p));
    return a;
}
#define CP_ASYNC16(saddr, gptr) \
    asm volatile("cp.async.cg.shared.global [%0], [%1], 16;" \
        :: "r"(saddr), "l"(__cvta_generic_to_global(gptr)))
#define CP_COMMIT() asm volatile("cp.async.commit_group;" ::: "memory")
#define CP_WAIT(n)  asm volatile("cp.async.wait_group %0;" :: "n"(n) : "memory")

__device__ __forceinline__ void ldmx4(uint32_t* r, uint32_t addr) {
    asm volatile("ldmatrix.sync.aligned.m8n8.x4.shared.b16 {%0,%1,%2,%3}, [%4];"
        : "=r"(r[0]), "=r"(r[1]), "=r"(r[2]), "=r"(r[3]) : "r"(addr));
}
__device__ __forceinline__ void ldmx4t(uint32_t* r, uint32_t addr) {
    asm volatile("ldmatrix.sync.aligned.m8n8.x4.trans.shared.b16 {%0,%1,%2,%3}, [%4];"
        : "=r"(r[0]), "=r"(r[1]), "=r"(r[2]), "=r"(r[3]) : "r"(addr));
}
__device__ __forceinline__ void mma16816h(float* d, const uint32_t* a, uint32_t b0, uint32_t b1) {
    asm volatile("mma.sync.aligned.m16n8k16.row.col.f32.f16.f16.f32 "
        "{%0,%1,%2,%3}, {%4,%5,%6,%7}, {%8,%9}, {%0,%1,%2,%3};"
        : "+f"(d[0]), "+f"(d[1]), "+f"(d[2]), "+f"(d[3])
        : "r"(a[0]), "r"(a[1]), "r"(a[2]), "r"(a[3]), "r"(b0), "r"(b1));
}
__device__ __forceinline__ uint32_t pack_h2(float a, float b) {
    uint16_t ua = __half_as_ushort(__float2half_rn(a));
    uint16_t ub = __half_as_ushort(__float2half_rn(b));
    return (uint32_t)ua | ((uint32_t)ub << 16);
}

// ================= merged fp16 limb split =================
__device__ __forceinline__ void split8(const float* __restrict__ x,
                                       __half* __restrict__ hi, __half* __restrict__ mid,
                                       int i, float scale) {
    float4 v0 = *(const float4*)(x + i);
    float4 v1 = *(const float4*)(x + i + 4);
    float a[8] = {v0.x, v0.y, v0.z, v0.w, v1.x, v1.y, v1.z, v1.w};
    float hf[8], mf[8];
#pragma unroll
    for (int j = 0; j < 8; j++) {
        float s = a[j] * scale;
        float h = __half2float(__float2half_rn(s));
        hf[j] = h; mf[j] = s - h;
    }
    *(uint4*)(hi + i) = make_uint4(pack_h2(hf[0], hf[1]), pack_h2(hf[2], hf[3]),
                                   pack_h2(hf[4], hf[5]), pack_h2(hf[6], hf[7]));
    *(uint4*)(mid + i) = make_uint4(pack_h2(mf[0], mf[1]), pack_h2(mf[2], mf[3]),
                                    pack_h2(mf[4], mf[5]), pack_h2(mf[6], mf[7]));
}
__device__ __forceinline__ void split8_hi(const float* __restrict__ x,
                                          __half* __restrict__ hi, int i, float scale) {
    float4 v0 = *(const float4*)(x + i);
    float4 v1 = *(const float4*)(x + i + 4);
    float a[8] = {v0.x, v0.y, v0.z, v0.w, v1.x, v1.y, v1.z, v1.w};
    uint32_t p[4];
#pragma unroll
    for (int j = 0; j < 4; j++)
        p[j] = pack_h2(a[j * 2] * scale, a[j * 2 + 1] * scale);
    *(uint4*)(hi + i) = make_uint4(p[0], p[1], p[2], p[3]);
}

__global__ void split_all_kernel(const float* __restrict__ q,
                                 const float* __restrict__ wqk,
                                 const float* __restrict__ wv,
                                 const float* __restrict__ wo,
                                 __half* __restrict__ asp,
                                 __half* __restrict__ wqkv,
                                 __half* __restrict__ wout) {
    int bid = blockIdx.x;
    int li = threadIdx.x * 8;
    const int NW = 1024 * 1024;
    if (bid < 4096) {                      // activations: 2 limbs (qk needs mid)
        int i = bid * 2048 + li;
        split8(q, asp, asp + APL, i, 1.0f);
    } else if (bid < 4608) {               // Wqk: 2 limbs (qk 3-pass)
        int i = (bid - 4096) * 2048 + li;
        split8(wqk, wqkv, wqkv + WQKV_PL, i, WSCALE);
    } else if (bid < 5120) {               // Wv: hi only (v 1-pass)
        int i = (bid - 4608) * 2048 + li;
        split8_hi(wv, wqkv + NW, i, WSCALE);
    } else {                               // Wout: hi only (1-pass)
        int i = (bid - 5120) * 2048 + li;
        split8_hi(wo, wout, i, WSCALE);
    }
}

// ================= HMMA GEMM body (fp16 limbs) =================
#define ROWB     80
#define MATB     (128 * ROWB)
#define STAGEB   (2 * MATB)
#define GEMM_SMEM (4 * STAGEB)   // 81920
#define PA3 0x010u
#define PW3 0x001u
#define PA1 0x0u
#define PW1 0x0u

__device__ __forceinline__ void gemm_issue(uint32_t st,
        const __half* Ap, const __half* Bp, int bm, int bn, int k0,
        uint32_t so0, uint32_t so1, int r0, int c0, int r1, int c1) {
    CP_ASYNC16(st + so0, Ap + (size_t)(bm + r0) * Kdim + k0 + c0 * 8);
    CP_ASYNC16(st + so1, Ap + (size_t)(bm + r1) * Kdim + k0 + c1 * 8);
    CP_ASYNC16(st + MATB + so0, Bp + (size_t)(bn + r0) * Kdim + k0 + c0 * 8);
    CP_ASYNC16(st + MATB + so1, Bp + (size_t)(bn + r1) * Kdim + k0 + c1 * 8);
    CP_COMMIT();
}

__device__ __forceinline__ void gemm_body(char* smem,
        const __half* __restrict__ Asp, size_t Apl,
        const __half* __restrict__ Bsp, size_t Bpl,
        const float* __restrict__ bias, float* __restrict__ outp,
        float* __restrict__ headout, __half* __restrict__ headout_h,
        int npass, uint32_t paTbl, uint32_t pwTbl, int bn, int bm) {
    uint32_t sbase = smem_to_u32(smem);
    int tid = threadIdx.x;
    int lane = tid & 31, warp = tid >> 5;
    int wm = warp >> 2, wn = warp & 3;
    int nstage = npass * 32;

    int v0 = tid, v1 = tid + 256;
    int r0 = v0 >> 2, c0 = v0 & 3;
    int r1 = v1 >> 2, c1 = v1 & 3;
    uint32_t so0 = (uint32_t)(r0 * ROWB + c0 * 16);
    uint32_t so1 = (uint32_t)(r1 * ROWB + c1 * 16);

    uint32_t aoff = (uint32_t)((wm * 64 + (lane & 15)) * ROWB + (lane >> 4) * 16);
    uint32_t boff = (uint32_t)((wn * 32 + ((lane >> 4) & 1) * 8 + (lane & 7)) * ROWB
                               + ((lane >> 3) & 1) * 16);

    float D[4][4][4];
#pragma unroll
    for (int i = 0; i < 4; i++)
#pragma unroll
        for (int j = 0; j < 4; j++)
#pragma unroll
            for (int q = 0; q < 4; q++) D[i][j][q] = 0.f;

#pragma unroll
    for (int s = 0; s < 3; s++) {
        const __half* Ap = Asp + (size_t)(paTbl & 7) * Apl;
        const __half* Bp = Bsp + (size_t)(pwTbl & 7) * Bpl;
        gemm_issue(sbase + s * STAGEB, Ap, Bp, bm, bn, (s & 31) * 32, so0, so1, r0, c0, r1, c1);
    }

    for (int s = 0; s < nstage; s++) {
        if (s <= nstage - 3)      { CP_WAIT(2); }
        else if (s == nstage - 2) { CP_WAIT(1); }
        else                      { CP_WAIT(0); }
        __syncthreads();
        if (s + 3 < nstage) {
            int sn = s + 3;
            int p = sn >> 5, k0 = (sn & 31) << 5;
            const __half* Ap = Asp + (size_t)((paTbl >> (p * 4)) & 7) * Apl;
            const __half* Bp = Bsp + (size_t)((pwTbl >> (p * 4)) & 7) * Bpl;
            gemm_issue(sbase + (uint32_t)(sn & 3) * STAGEB, Ap, Bp, bm, bn, k0,
                       so0, so1, r0, c0, r1, c1);
        }
        uint32_t st = sbase + (uint32_t)(s & 3) * STAGEB;
        uint32_t ab = st + aoff;
        uint32_t bb = st + MATB + boff;
#pragma unroll
        for (int ks = 0; ks < 2; ks++) {
            uint32_t A4[4][4], B4[2][4];
#pragma unroll
            for (int i = 0; i < 4; i++) ldmx4(A4[i], ab + i * (16 * ROWB) + ks * 32);
#pragma unroll
            for (int jp = 0; jp < 2; jp++) ldmx4(B4[jp], bb + jp * (16 * ROWB) + ks * 32);
#pragma unroll
            for (int i = 0; i < 4; i++)
#pragma unroll
                for (int jn = 0; jn < 4; jn++)
                    mma16816h(D[i][jn], A4[i], B4[jn >> 1][(jn & 1) * 2], B4[jn >> 1][(jn & 1) * 2 + 1]);
        }
    }

    int g = lane >> 2, t = lane & 3;
#pragma unroll
    for (int i = 0; i < 4; i++) {
#pragma unroll
        for (int jn = 0; jn < 4; jn++) {
            int m0 = bm + wm * 64 + i * 16 + g;
            int n0 = bn + wn * 32 + jn * 8 + t * 2;
            float2 va = make_float2(D[i][jn][0] * OSCALE, D[i][jn][1] * OSCALE);
            float2 vb = make_float2(D[i][jn][2] * OSCALE, D[i][jn][3] * OSCALE);
            if (headout) {
                int bI = m0 >> 12;
                int t0 = m0 & 4095, t1 = (m0 + 8) & 4095;
                int hd = n0 >> 6, dh = n0 & 63;
                *(float2*)(headout + (((size_t)(bI * Hh + hd)) * Nn + t0) * DHd + dh) = va;
                *(float2*)(headout + (((size_t)(bI * Hh + hd)) * Nn + t1) * DHd + dh) = vb;
            } else if (headout_h) {
                int bI = m0 >> 12;
                int t0 = m0 & 4095, t1 = (m0 + 8) & 4095;
                int hd = n0 >> 6, dh = n0 & 63;
                *(uint32_t*)(headout_h + (((size_t)(bI * Hh + hd)) * Nn + t0) * DHd + dh) = pack_h2(va.x, va.y);
                *(uint32_t*)(headout_h + (((size_t)(bI * Hh + hd)) * Nn + t1) * DHd + dh) = pack_h2(vb.x, vb.y);
            } else {
                float2 bv = *(const float2*)(bias + n0);
                va.x += bv.x; va.y += bv.y; vb.x += bv.x; vb.y += bv.y;
                *(float2*)(outp + (size_t)m0 * Cc + n0) = va;
                *(float2*)(outp + (size_t)(m0 + 8) * Cc + n0) = vb;
            }
        }
    }
}

// fused qk (3-pass, x<8) + v (1-pass -> fp16 plane, x>=8) GEMM
__global__ __launch_bounds__(256, 2) void qkv_gemm(
        const __half* __restrict__ Asp,
        const __half* __restrict__ Wqkv,
        float* __restrict__ qkout, __half* __restrict__ vout) {
    extern __shared__ char smem[];
    const int NW = 1024 * 1024;
    if (blockIdx.x < 8) {
        gemm_body(smem, Asp, APL, Wqkv, WQKV_PL, nullptr, nullptr, qkout, nullptr,
                  3, PA3, PW3, blockIdx.x * 128, blockIdx.y * 128);
    } else {
        gemm_body(smem, Asp, APL, Wqkv + NW, WQKV_PL, nullptr, nullptr, nullptr, vout,
                  1, PA1, PW1, (blockIdx.x - 8) * 128, blockIdx.y * 128);
    }
}

// Wout GEMM: 1-pass (A hi plane x W hi plane)
__global__ __launch_bounds__(256, 2) void mma_gemm(
        const __half* __restrict__ Asp,
        const __half* __restrict__ Wout_,
        const float* __restrict__ bias, float* __restrict__ outp) {
    extern __shared__ char smem[];
    gemm_body(smem, Asp, APL, Wout_, WOUT_PL, bias, outp, nullptr, nullptr,
              1, PA1, PW1, blockIdx.x * 128, blockIdx.y * 128);
}

// ---------------- HMMA LSH bucketing (3 limb passes, exact first-index argmax) ----------------
#define BK_AHI  0
#define BK_AMID 9216
#define BK_BHI  18432
#define BK_BMID 36864
#define PB_SMEM 55296

__device__ __forceinline__ void bucket_body(char* smemc, const float* __restrict__ rot,
                                            int bh, int tb) {
    uint32_t sb = smem_to_u32(smemc);
    int tid = threadIdx.x, lane = tid & 31, warp = tid >> 5;
    int g = lane >> 2, t = lane & 3;
    int wm = warp >> 2, wn = warp & 3;

    {
        int row = tid >> 2, seg = tid & 3;
        const float* src = g_qk + ((size_t)bh * Nn + tb + row) * DHd + seg * 16;
        char* dh_ = smemc + BK_AHI + row * 144 + seg * 32;
        char* dm_ = smemc + BK_AMID + row * 144 + seg * 32;
#pragma unroll
        for (int k4 = 0; k4 < 4; k4++) {
            float4 v = *(const float4*)(src + k4 * 4);
            float h0 = __half2float(__float2half_rn(v.x));
            float h1 = __half2float(__float2half_rn(v.y));
            float h2 = __half2float(__float2half_rn(v.z));
            float h3 = __half2float(__float2half_rn(v.w));
            *(uint32_t*)(dh_ + k4 * 8)     = pack_h2(h0, h1);
            *(uint32_t*)(dh_ + k4 * 8 + 4) = pack_h2(h2, h3);
            *(uint32_t*)(dm_ + k4 * 8)     = pack_h2(v.x - h0, v.y - h1);
            *(uint32_t*)(dm_ + k4 * 8 + 4) = pack_h2(v.z - h2, v.w - h3);
        }
    }
    {
        int n = tid >> 1, seg = tid & 1;
        char* dh_ = smemc + BK_BHI + n * 144 + seg * 64;
        char* dm_ = smemc + BK_BMID + n * 144 + seg * 64;
#pragma unroll
        for (int k2 = 0; k2 < 16; k2++) {
            int d = seg * 32 + k2 * 2;
            float a = rot[(size_t)d * 128 + n];
            float b = rot[(size_t)(d + 1) * 128 + n];
            float ha = __half2float(__float2half_rn(a));
            float hb = __half2float(__float2half_rn(b));
            *(uint32_t*)(dh_ + k2 * 4) = pack_h2(ha, hb);
            *(uint32_t*)(dm_ + k2 * 4) = pack_h2(a - ha, b - hb);
        }
    }
    __syncthreads();

    float Dd[2][4][4];
#pragma unroll
    for (int i = 0; i < 2; i++)
#pragma unroll
        for (int jn = 0; jn < 4; jn++)
#pragma unroll
            for (int q = 0; q < 4; q++) Dd[i][jn][q] = 0.f;

    uint32_t arow = (uint32_t)((wm * 32 + (lane & 15)) * 144 + (lane >> 4) * 16);
    uint32_t brow = (uint32_t)((wn * 32 + ((lane >> 4) & 1) * 8 + (lane & 7)) * 144
                               + ((lane >> 3) & 1) * 16);
    const uint32_t AL[3] = {sb + BK_AMID, sb + BK_AHI, sb + BK_AHI};
    const uint32_t BL[3] = {sb + BK_BHI, sb + BK_BMID, sb + BK_BHI};
#pragma unroll
    for (int p = 0; p < 3; p++) {
#pragma unroll
        for (int ks = 0; ks < 4; ks++) {
            uint32_t A4[2][4], B4[2][4];
#pragma unroll
            for (int i = 0; i < 2; i++) ldmx4(A4[i], AL[p] + arow + i * (16 * 144) + ks * 32);
#pragma unroll
            for (int jp = 0; jp < 2; jp++) ldmx4(B4[jp], BL[p] + brow + jp * (16 * 144) + ks * 32);
#pragma unroll
            for (int i = 0; i < 2; i++)
#pragma unroll
                for (int jn = 0; jn < 4; jn++)
                    mma16816h(Dd[i][jn], A4[i], B4[jn >> 1][(jn & 1) * 2], B4[jn >> 1][(jn & 1) * 2 + 1]);
        }
    }

#pragma unroll
    for (int i = 0; i < 2; i++) {
#pragma unroll
        for (int half = 0; half < 2; half++) {
            int row = wm * 32 + i * 16 + g + half * 8;
            float bv = -3.0e38f; int bidx = 0;
#pragma unroll
            for (int jn = 0; jn < 4; jn++) {
#pragma unroll
                for (int z = 0; z < 2; z++) {
                    float v = Dd[i][jn][half * 2 + z];
                    int ri = jn * 8 + t * 2 + z;
                    if (v > bv || (v == bv && ri < bidx)) { bv = v; bidx = ri; }
                    float nv = -v; int ni = 32 + ri;
                    if (nv > bv || (nv == bv && ni < bidx)) { bv = nv; bidx = ni; }
                }
            }
#pragma unroll
            for (int o = 1; o <= 2; o <<= 1) {
                float ov = __shfl_xor_sync(0xffffffffu, bv, o);
                int oi = __shfl_xor_sync(0xffffffffu, bidx, o);
                if (ov > bv || (ov == bv && oi < bidx)) { bv = ov; bidx = oi; }
            }
            if (t == 0)
                g_bucket[((size_t)bh * NHASH + wn) * Nn + tb + row] = bidx;
        }
    }
}

// ---------------- fused bucket (HMMA) + k/s prep ----------------
__global__ void prep_bucket_kernel(const float* __restrict__ rot) {
    extern __shared__ char smem[];
    int bid = blockIdx.x;
    if (bid < 2048) {
        bucket_body(smem, rot, bid >> 6, (bid & 63) * 64);
        return;
    }
    int row = (bid - 2048) * 8 + (threadIdx.x >> 5);
    int lane = threadIdx.x & 31;
    size_t off = (size_t)row * DHd;
    const float* src = g_qk + off;
    float a = src[lane], b = src[lane + 32];

    float s = a * a + b * b;
#pragma unroll
    for (int o = 16; o > 0; o >>= 1) s += __shfl_xor_sync(0xffffffffu, s, o);
    float norm = sqrtf(s);
    float inv = 1.0f / fmaxf(norm, 1e-12f);
    if (lane == 0) g_s[row] = 0.125f * norm;

    g_kh[off + lane]      = __float2half_rn(a * inv);
    g_kh[off + lane + 32] = __float2half_rn(b * inv);
}

// ---------------- parallel stable counting sort per (bh, hash) ----------------
#define SORT_SMEM 49152
__global__ void sort_kernel() {
    extern __shared__ char ss[];
    unsigned char*  cnt    = (unsigned char*)ss;
    unsigned short* segoff = (unsigned short*)(ss + 16384);
    __shared__ int bbase[NBUCK];
    int bh = blockIdx.x, h = blockIdx.y;
    int tid = threadIdx.x;
    const int gb = (bh * NHASH + h) * Nn;

    uint32_t* ci = (uint32_t*)cnt;
    for (int i = tid; i < 4096; i += 256) ci[i] = 0;
    __syncthreads();

    int bb[16];
#pragma unroll
    for (int k = 0; k < 16; k++) {
        int b = g_bucket[gb + tid * 16 + k];
        bb[k] = b;
        cnt[tid * 64 + b]++;
    }
    __syncthreads();

    if (tid < NBUCK) {
        int run = 0;
        for (int seg = 0; seg < 256; seg++) {
            segoff[seg * 64 + tid] = (unsigned short)run;
            run += cnt[seg * 64 + tid];
        }
        bbase[tid] = run;
    }
    __syncthreads();
    if (tid == 0) {
        int acc = 0;
        for (int b = 0; b < NBUCK; b++) { int c = bbase[b]; bbase[b] = acc; acc += c; }
    }
    __syncthreads();

#pragma unroll
    for (int k = 0; k < 16; k++) {
        int b = bb[k];
        int pos = bbase[b] + segoff[tid * 64 + b];
        segoff[tid * 64 + b]++;
        g_st[gb + pos] = tid * 16 + k;
    }
}

// ---------------- chunked LSH attention: K-as-A fp16 dots (1 pass), fp16 P (1-pass PV) ----------------
// smem: tkv[128]@0 | s[64]@512 | rsump@1536 | rsuminv@2560 |
//       Khi@3072(18432) | V@21504(18432) | P@39936(17408) -> total 57344; occ 3
#define AT_S     512
#define AT_KHI   3072
#define AT_V     21504
#define AT_P     39936
#define ATTN_SMEM_BYTES 57344

__global__ __launch_bounds__(256, 3) void attn_kernel() {
    extern __shared__ char sm[];
    int*   tkv     = (int*)sm;
    float* sS      = (float*)(sm + AT_S);
    float* rsump   = (float*)(sm + 1536);
    float* rsuminv = (float*)(sm + 2560);
    uint32_t sb = smem_to_u32(sm);

    int c = blockIdx.x, bh = blockIdx.y;
    int h = c >> 6;
    int tid = threadIdx.x, lane = tid & 31, warp = tid >> 5;
    int g = lane >> 2, t = lane & 3;
    int wm = warp >> 2, wn = warp & 3;
    int pc = (c + NCHUNK - 1) & (NCHUNK - 1);
    const int stb = bh * (NHASH * Nn);

    if (tid < 64)       tkv[tid] = g_st[stb + c * BS + tid];
    else if (tid < 128) tkv[tid] = g_st[stb + pc * BS + (tid - 64)];
    __syncthreads();

    if (tid < 64) sS[tid] = g_s[(size_t)bh * Nn + tkv[tid]];

    // gather k + v via cp.async (2 threads/row x 32 elems; 8 x 16B each)
    {
        int j = tid >> 1, seg = tid & 1;
        size_t off = ((size_t)bh * Nn + tkv[j]) * DHd + seg * 32;
        const __half* skh = g_kh + off;
        const __half* svh = g_vh2 + off;
        uint32_t dkh = sb + AT_KHI + j * 144 + seg * 64;
        uint32_t dvh = sb + AT_V + j * 144 + seg * 64;
#pragma unroll
        for (int k = 0; k < 4; k++) {
            CP_ASYNC16(dkh + k * 16, skh + k * 8);
            CP_ASYNC16(dvh + k * 16, svh + k * 8);
        }
        CP_COMMIT();
        CP_WAIT(0);
    }
    __syncthreads();

    // dots MMA: A = Khi rows 0..63, B = Khi rows 0..127; single fp16 pass
    float Dd[2][4][4];
#pragma unroll
    for (int i = 0; i < 2; i++)
#pragma unroll
        for (int jn = 0; jn < 4; jn++)
#pragma unroll
            for (int q = 0; q < 4; q++) Dd[i][jn][q] = 0.f;

    uint32_t arow = (uint32_t)((wm * 32 + (lane & 15)) * 144 + (lane >> 4) * 16);
    uint32_t brow = (uint32_t)((wn * 32 + ((lane >> 4) & 1) * 8 + (lane & 7)) * 144
                               + ((lane >> 3) & 1) * 16);
#pragma unroll
    for (int ks = 0; ks < 4; ks++) {
        uint32_t A4[2][4], B4[2][4];
#pragma unroll
        for (int i = 0; i < 2; i++) ldmx4(A4[i], sb + AT_KHI + arow + i * (16 * 144) + ks * 32);
#pragma unroll
        for (int jp = 0; jp < 2; jp++) ldmx4(B4[jp], sb + AT_KHI + brow + jp * (16 * 144) + ks * 32);
#pragma unroll
        for (int i = 0; i < 2; i++)
#pragma unroll
            for (int jn = 0; jn < 4; jn++)
                mma16816h(Dd[i][jn], A4[i], B4[jn >> 1][(jn & 1) * 2], B4[jn >> 1][(jn & 1) * 2 + 1]);
    }

    // scale rows by s, then mask
    float srow[4] = { sS[wm * 32 + g], sS[wm * 32 + g + 8],
                      sS[wm * 32 + 16 + g], sS[wm * 32 + 16 + g + 8] };
#pragma unroll
    for (int i = 0; i < 2; i++)
#pragma unroll
        for (int jn = 0; jn < 4; jn++) {
            Dd[i][jn][0] *= srow[i * 2];
            Dd[i][jn][1] *= srow[i * 2];
            Dd[i][jn][2] *= srow[i * 2 + 1];
            Dd[i][jn][3] *= srow[i * 2 + 1];
        }

    int trow[4] = { tkv[wm * 32 + g], tkv[wm * 32 + g + 8],
                    tkv[wm * 32 + 16 + g], tkv[wm * 32 + 16 + g + 8] };
    int tcol[8];
#pragma unroll
    for (int jn = 0; jn < 4; jn++) {
        int c0 = wn * 32 + jn * 8 + t * 2;
        tcol[jn * 2] = tkv[c0]; tcol[jn * 2 + 1] = tkv[c0 + 1];
    }
#pragma unroll
    for (int i = 0; i < 2; i++)
#pragma unroll
        for (int jn = 0; jn < 4; jn++)
#pragma unroll
            for (int q = 0; q < 4; q++)
                if (trow[i * 2 + (q >> 1)] == tcol[jn * 2 + (q & 1)]) Dd[i][jn][q] = -5e4f;

    // exp -> P fp16 + partial sums
    float ps[4] = {0.f, 0.f, 0.f, 0.f};
#pragma unroll
    for (int i = 0; i < 2; i++) {
        int r0 = wm * 32 + i * 16 + g;
#pragma unroll
        for (int jn = 0; jn < 4; jn++) {
            float e0 = __expf(Dd[i][jn][0]);
            float e1 = __expf(Dd[i][jn][1]);
            float e2 = __expf(Dd[i][jn][2]);
            float e3 = __expf(Dd[i][jn][3]);
            ps[i * 2] += e0 + e1;
            ps[i * 2 + 1] += e2 + e3;
            int c0 = wn * 32 + jn * 8 + t * 2;
            *(uint32_t*)(sm + AT_P + r0 * 272 + c0 * 2)       = pack_h2(e0, e1);
            *(uint32_t*)(sm + AT_P + (r0 + 8) * 272 + c0 * 2) = pack_h2(e2, e3);
        }
    }
#pragma unroll
    for (int k = 0; k < 4; k++) {
        ps[k] += __shfl_xor_sync(0xffffffffu, ps[k], 1);
        ps[k] += __shfl_xor_sync(0xffffffffu, ps[k], 2);
    }
    if (t == 0) {
#pragma unroll
        for (int k = 0; k < 4; k++)
            rsump[(wm * 32 + (k >> 1) * 16 + g + (k & 1) * 8) * 4 + wn] = ps[k];
    }
    __syncthreads();

    if (tid < 64) {
        const float* p = rsump + tid * 4;
        float s = p[0] + p[1] + p[2] + p[3];
        rsuminv[tid] = 1.0f / s;
        g_lse[(bh * NHASH + h) * Nn + tkv[tid]] = logf(s);
    }
    __syncthreads();

    // PV MMA: single fp16 pass
    float Dp[2][2][4];
#pragma unroll
    for (int i = 0; i < 2; i++)
#pragma unroll
        for (int jn = 0; jn < 2; jn++)
#pragma unroll
            for (int q = 0; q < 4; q++) Dp[i][jn][q] = 0.f;

    uint32_t parow = (uint32_t)((wm * 32 + (lane & 15)) * 272 + (lane >> 4) * 16);
    uint32_t vbrow = (uint32_t)((lane & 15) * 144 + (lane >> 4) * 16 + wn * 32);
#pragma unroll
    for (int ks = 0; ks < 8; ks++) {
        uint32_t B4[4];
        ldmx4t(B4, sb + AT_V + vbrow + ks * (16 * 144));
        uint32_t A4[2][4];
#pragma unroll
        for (int i = 0; i < 2; i++) ldmx4(A4[i], sb + AT_P + parow + i * (16 * 272) + ks * 32);
#pragma unroll
        for (int i = 0; i < 2; i++)
#pragma unroll
            for (int jn = 0; jn < 2; jn++)
                mma16816h(Dp[i][jn], A4[i], B4[jn * 2], B4[jn * 2 + 1]);
    }

    // epilogue: normalize + scatter (fp16)
#pragma unroll
    for (int i = 0; i < 2; i++) {
        int r0 = wm * 32 + i * 16 + g;
        float inv0 = rsuminv[r0], inv1 = rsuminv[r0 + 8];
        size_t b0 = ((size_t)(bh * NHASH + h) * Nn + trow[i * 2]) * DHd;
        size_t b1 = ((size_t)(bh * NHASH + h) * Nn + trow[i * 2 + 1]) * DHd;
#pragma unroll
        for (int jn = 0; jn < 2; jn++) {
            int dh = wn * 16 + jn * 8 + t * 2;
            *(uint32_t*)(g_oph2 + b0 + dh) = pack_h2(Dp[i][jn][0] * inv0, Dp[i][jn][1] * inv0);
            *(uint32_t*)(g_oph2 + b1 + dh) = pack_h2(Dp[i][jn][2] * inv1, Dp[i][jn][3] * inv1);
        }
    }
}

// ---------------- fused combine + single fp16 plane write (Wout A_hi) ----------------
__global__ void combine_split_kernel(__half* __restrict__ hi) {
    int u = blockIdx.x * 256 + threadIdx.x;
    int slot = u >> 3;
    int dseg = (u & 7) * 8;
    int bh = slot >> 12;
    int t = slot & 4095;
    int base = bh * NHASH * Nn + t;
    float l0 = g_lse[base + 0 * Nn];
    float l1 = g_lse[base + 1 * Nn];
    float l2 = g_lse[base + 2 * Nn];
    float l3 = g_lse[base + 3 * Nn];
    float m = fmaxf(fmaxf(l0, l1), fmaxf(l2, l3));
    float w[4] = {expf(l0 - m), expf(l1 - m), expf(l2 - m), expf(l3 - m)};
    float sinv = 1.0f / (w[0] + w[1] + w[2] + w[3]);

    float acc[8];
#pragma unroll
    for (int j = 0; j < 8; j++) acc[j] = 0.f;
#pragma unroll
    for (int k = 0; k < 4; k++) {
        const uint4* p = (const uint4*)(g_oph2 + (((size_t)(bh * NHASH + k)) * Nn + t) * DHd + dseg);
        uint4 x = p[0];
        const __half2* hx = (const __half2*)&x;
#pragma unroll
        for (int j2 = 0; j2 < 4; j2++) {
            float2 f = __half22float2(hx[j2]);
            acc[j2 * 2]     += w[k] * f.x;
            acc[j2 * 2 + 1] += w[k] * f.y;
        }
    }
    float hf[8];
#pragma unroll
    for (int j = 0; j < 8; j++) hf[j] = acc[j] * sinv;
    int b = bh >> 4, head = bh & 15;
    size_t oidx = ((size_t)b * Nn + t) * Cc + head * DHd + dseg;
    *(uint4*)(hi + oidx) = make_uint4(pack_h2(hf[0], hf[1]), pack_h2(hf[2], hf[3]),
                                      pack_h2(hf[4], hf[5]), pack_h2(hf[6], hf[7]));
}

// ---------------- launch ----------------
extern "C" void kernel_launch(void* const* d_in, const int* in_sizes, int n_in,
                              void* d_out, int out_size) {
    const float* queries = (const float*)d_in[0];
    const float* Wqk  = (const float*)d_in[4];
    const float* Wv   = (const float*)d_in[5];
    const float* Wout = (const float*)d_in[6];
    const float* bout = (const float*)d_in[7];
    const float* rot  = (const float*)d_in[8];
    float* out = (float*)d_out;

    cudaFuncSetAttribute(attn_kernel, cudaFuncAttributeMaxDynamicSharedMemorySize, ATTN_SMEM_BYTES);
    cudaFuncSetAttribute(qkv_gemm, cudaFuncAttributeMaxDynamicSharedMemorySize, GEMM_SMEM);
    cudaFuncSetAttribute(mma_gemm, cudaFuncAttributeMaxDynamicSharedMemorySize, GEMM_SMEM);
    cudaFuncSetAttribute(prep_bucket_kernel, cudaFuncAttributeMaxDynamicSharedMemorySize, PB_SMEM);
    cudaFuncSetAttribute(sort_kernel, cudaFuncAttributeMaxDynamicSharedMemorySize, SORT_SMEM);

    void *p_qk, *p_vh2, *p_asp, *p_wqkv, *p_wout;
    cudaGetSymbolAddress(&p_qk, g_qk);
    cudaGetSymbolAddress(&p_vh2, g_vh2);
    cudaGetSymbolAddress(&p_asp, g_asp);
    cudaGetSymbolAddress(&p_wqkv, g_wqkv_sp);
    cudaGetSymbolAddress(&p_wout, g_wout_sp);
    __half* asp  = (__half*)p_asp;
    __half* wqkv = (__half*)p_wqkv;
    __half* wout = (__half*)p_wout;

    split_all_kernel<<<5632, 256>>>(queries, Wqk, Wv, Wout, asp, wqkv, wout);

    // fused qk (3-pass) + v (1-pass, fp16 plane) GEMM
    qkv_gemm<<<dim3(16, 64), 256, GEMM_SMEM>>>(asp, wqkv, (float*)p_qk, (__half*)p_vh2);

    // fused HMMA bucket + k/s prep (both need only g_qk)
    prep_bucket_kernel<<<2048 + BH * Nn / 8, 256, PB_SMEM>>>(rot);
    sort_kernel<<<dim3(BH, NHASH), 256, SORT_SMEM>>>();

    attn_kernel<<<dim3(NCHUNK, BH), 256, ATTN_SMEM_BYTES>>>();

    combine_split_kernel<<<(BH * Nn * DHd / 8) / 256, 256>>>(asp);

    // Wout GEMM: 1-pass fp16, +bias -> d_out
    mma_gemm<<<dim3(8, 64), 256, GEMM_SMEM>>>(asp, wout, bout, out);
}